// round 1
// baseline (speedup 1.0000x reference)
#include <cuda_runtime.h>
#include <math.h>

#define BB   4
#define N0   4096
#define C0   1536
#define EMB  512
#define NH   8
#define HD   64
#define NT   4097
#define NPAD 4352
#define PADR 255
#define NLM  256
#define LCH  17
#define GRD  64
#define QSCALE 0.125f

// ---------------- static device scratch (no allocations allowed) ----------------
__device__ float g_h   [BB*NT*EMB];
__device__ float g_x   [BB*NPAD*EMB];
__device__ float g_qkv [BB*NPAD*3*EMB];
__device__ float g_q   [BB*NH*NPAD*HD];
__device__ float g_k   [BB*NH*NPAD*HD];
__device__ float g_v   [BB*NH*NPAD*HD];
__device__ float g_ql  [BB*NH*NLM*HD];
__device__ float g_kl  [BB*NH*NLM*HD];
__device__ float g_s1  [(long long)BB*NH*NPAD*NLM];
__device__ float g_s2  [BB*NH*NLM*NLM];
__device__ float g_s3  [(long long)BB*NH*NLM*NPAD];
__device__ float g_z   [BB*NH*NLM*NLM];
__device__ float g_z2  [BB*NH*NLM*NLM];
__device__ float g_t0  [BB*NH*NLM*NLM];
__device__ float g_t1  [BB*NH*NLM*NLM];
__device__ float g_t2  [BB*NH*NLM*NLM];
__device__ float g_av  [BB*NH*NLM*HD];
__device__ float g_u   [BB*NH*NLM*HD];
__device__ float g_oh  [BB*NH*NPAD*HD];
__device__ float g_attn[BB*NPAD*EMB];
__device__ float g_y   [BB*NPAD*EMB];
__device__ float g_cnn [BB*EMB*GRD*GRD];
__device__ float g_cnn2[BB*EMB*GRD*GRD];
__device__ unsigned g_red[2];

// ---------------- generic batched SGEMM: C = alpha*A@op(B) + betaI*I + bias, relu ----------------
// A: (M,K) row-major.  TRANSB: B is (N,K) row-major (C=A·B^T), else B is (K,N).
// Requires M%64==0, N%64==0, K%16==0 (true for every call site here).
template<bool TRANSB>
__global__ void gemm_k(const float* __restrict__ A, const float* __restrict__ Bm,
                       float* __restrict__ C,
                       int Mdim, int Ndim, int Kdim,
                       long long sA, long long sB, long long sC,
                       float alpha, float betaI,
                       const float* __restrict__ bias, int relu)
{
    __shared__ __align__(16) float As[16][68];
    __shared__ __align__(16) float Bs[16][68];
    A  += (long long)blockIdx.z * sA;
    Bm += (long long)blockIdx.z * sB;
    C  += (long long)blockIdx.z * sC;
    const int m0 = blockIdx.y * 64;
    const int n0 = blockIdx.x * 64;
    const int tid = threadIdx.x;
    const int tx = tid & 15, ty = tid >> 4;
    float acc[4][4] = {};
    for (int kt = 0; kt < Kdim; kt += 16) {
        #pragma unroll
        for (int i = tid; i < 1024; i += 256) {
            int m = i >> 4, kk = i & 15;
            As[kk][m] = A[(long long)(m0 + m) * Kdim + kt + kk];
        }
        if (TRANSB) {
            #pragma unroll
            for (int i = tid; i < 1024; i += 256) {
                int n = i >> 4, kk = i & 15;
                Bs[kk][n] = Bm[(long long)(n0 + n) * Kdim + kt + kk];
            }
        } else {
            #pragma unroll
            for (int i = tid; i < 1024; i += 256) {
                int kk = i >> 6, n = i & 63;
                Bs[kk][n] = Bm[(long long)(kt + kk) * Ndim + n0 + n];
            }
        }
        __syncthreads();
        #pragma unroll
        for (int kk = 0; kk < 16; kk++) {
            float4 a4 = *(const float4*)&As[kk][ty * 4];
            float4 b4 = *(const float4*)&Bs[kk][tx * 4];
            float a_[4] = {a4.x, a4.y, a4.z, a4.w};
            float b_[4] = {b4.x, b4.y, b4.z, b4.w};
            #pragma unroll
            for (int i = 0; i < 4; i++)
                #pragma unroll
                for (int j = 0; j < 4; j++)
                    acc[i][j] += a_[i] * b_[j];
        }
        __syncthreads();
    }
    #pragma unroll
    for (int i = 0; i < 4; i++) {
        int m = m0 + ty * 4 + i;
        #pragma unroll
        for (int j = 0; j < 4; j++) {
            int n = n0 + tx * 4 + j;
            float vv = alpha * acc[i][j];
            if (betaI != 0.f && m == n) vv += betaI;
            if (bias) vv += bias[n];
            if (relu) vv = fmaxf(vv, 0.f);
            C[(long long)m * Ndim + n] = vv;
        }
    }
}

static void gemm(const float* A, const float* Bm, float* C,
                 int M_, int N_, int K_,
                 long long sA, long long sB, long long sC, int batch, bool transB,
                 float alpha = 1.f, float betaI = 0.f,
                 const float* bias = nullptr, int relu = 0)
{
    dim3 grid(N_ / 64, M_ / 64, batch);
    if (transB) gemm_k<true ><<<grid, 256>>>(A, Bm, C, M_, N_, K_, sA, sB, sC, alpha, betaI, bias, relu);
    else        gemm_k<false><<<grid, 256>>>(A, Bm, C, M_, N_, K_, sA, sB, sC, alpha, betaI, bias, relu);
}

// ---------------- build h = [cls; gemm1_out] ----------------
__global__ void build_h_k(const float* __restrict__ cls)
{
    long long idx = (long long)blockIdx.x * 256 + threadIdx.x;
    int c = idx % EMB;
    long long bn = idx / EMB;
    int n = (int)(bn % NT);
    int b = (int)(bn / NT);
    g_h[idx] = (n == 0) ? cls[c] : g_attn[((long long)b * N0 + (n - 1)) * EMB + c];
}

// ---------------- layer norm + front zero-pad into g_x ----------------
__global__ void ln_pad_k(const float* __restrict__ gg, const float* __restrict__ bb)
{
    int n = blockIdx.x, b = blockIdx.y;
    int tid = threadIdx.x;
    float* out = g_x + ((long long)b * NPAD + n) * EMB;
    if (n < PADR) { out[tid] = 0.f; out[tid + 256] = 0.f; return; }
    const float* in = g_h + ((long long)b * NT + (n - PADR)) * EMB;
    float x0 = in[tid], x1 = in[tid + 256];
    __shared__ float sd[256];
    sd[tid] = x0 + x1; __syncthreads();
    for (int s = 128; s > 0; s >>= 1) { if (tid < s) sd[tid] += sd[tid + s]; __syncthreads(); }
    float mu = sd[0] * (1.f / EMB);
    __syncthreads();
    float d0 = x0 - mu, d1 = x1 - mu;
    sd[tid] = d0 * d0 + d1 * d1; __syncthreads();
    for (int s = 128; s > 0; s >>= 1) { if (tid < s) sd[tid] += sd[tid + s]; __syncthreads(); }
    float rs = rsqrtf(sd[0] * (1.f / EMB) + 1e-5f);
    out[tid]       = d0 * rs * gg[tid]       + bb[tid];
    out[tid + 256] = d1 * rs * gg[tid + 256] + bb[tid + 256];
}

// ---------------- split qkv into per-head q (scaled), k, v ----------------
__global__ void split_k()
{
    long long idx = (long long)blockIdx.x * 256 + threadIdx.x;
    float val = g_qkv[idx];
    int c = idx % (3 * EMB);
    long long bn = idx / (3 * EMB);
    int n = (int)(bn % NPAD);
    int b = (int)(bn / NPAD);
    int kind = c >> 9;
    int cc = c & 511;
    int hh = cc >> 6, d = cc & 63;
    long long dst = (((long long)(b * NH + hh)) * NPAD + n) * HD + d;
    if (kind == 0) g_q[dst] = val * QSCALE;
    else if (kind == 1) g_k[dst] = val;
    else g_v[dst] = val;
}

// ---------------- landmark means (mean over LCH consecutive tokens) ----------------
__global__ void land_k(const float* __restrict__ src, float* __restrict__ dst)
{
    int d = threadIdx.x;
    int m = blockIdx.x;
    int bh = blockIdx.y;
    const float* p = src + (((long long)bh * NPAD) + (long long)m * LCH) * HD + d;
    float s = 0.f;
    #pragma unroll
    for (int i = 0; i < LCH; i++) s += p[(long long)i * HD];
    dst[(((long long)bh * NLM) + m) * HD + d] = s * (1.f / LCH);
}

// ---------------- row softmax ----------------
__global__ void softmax_k(float* __restrict__ x, int len)
{
    long long row = blockIdx.x;
    float* p = x + row * (long long)len;
    int tid = threadIdx.x;
    __shared__ float sd[256];
    float m = -1e30f;
    for (int i = tid; i < len; i += 256) m = fmaxf(m, p[i]);
    sd[tid] = m; __syncthreads();
    for (int s = 128; s > 0; s >>= 1) { if (tid < s) sd[tid] = fmaxf(sd[tid], sd[tid + s]); __syncthreads(); }
    m = sd[0]; __syncthreads();
    float sum = 0.f;
    for (int i = tid; i < len; i += 256) { float e = expf(p[i] - m); p[i] = e; sum += e; }
    sd[tid] = sum; __syncthreads();
    for (int s = 128; s > 0; s >>= 1) { if (tid < s) sd[tid] += sd[tid + s]; __syncthreads(); }
    float r = 1.f / sd[0];
    __syncthreads();
    for (int i = tid; i < len; i += 256) p[i] *= r;
}

// ---------------- pinv: denom reductions, z init, 7I - xz ----------------
__global__ void reset_red_k() { if (threadIdx.x < 2) g_red[threadIdx.x] = 0u; }

__global__ void denom_k()
{
    int bh = blockIdx.x, tid = threadIdx.x;
    const float* mat = g_s2 + (long long)bh * NLM * NLM;
    float col = 0.f, rs = 0.f;
    for (int i = 0; i < NLM; i++) col += mat[i * NLM + tid];
    for (int j = 0; j < NLM; j++) rs  += mat[tid * NLM + j];
    __shared__ float sd[256];
    sd[tid] = rs; __syncthreads();
    for (int s = 128; s > 0; s >>= 1) { if (tid < s) sd[tid] = fmaxf(sd[tid], sd[tid + s]); __syncthreads(); }
    if (tid == 0) atomicMax(&g_red[0], __float_as_uint(sd[0]));
    __syncthreads();
    sd[tid] = col; __syncthreads();
    for (int s = 128; s > 0; s >>= 1) { if (tid < s) sd[tid] = fmaxf(sd[tid], sd[tid + s]); __syncthreads(); }
    if (tid == 0) atomicMax(&g_red[1], __float_as_uint(sd[0]));
}

__global__ void initz_k()
{
    long long idx = (long long)blockIdx.x * 256 + threadIdx.x;
    float rd = 1.f / (__uint_as_float(g_red[0]) * __uint_as_float(g_red[1]));
    int ij = (int)(idx & 65535);
    long long bh = idx >> 16;
    int i = ij >> 8, j = ij & 255;
    g_z[idx] = g_s2[(bh << 16) + (long long)j * NLM + i] * rd;
}

__global__ void ident7_k()
{
    long long idx = (long long)blockIdx.x * 256 + threadIdx.x;
    int ij = (int)(idx & 65535);
    int i = ij >> 8, j = ij & 255;
    g_t1[idx] = ((i == j) ? 7.f : 0.f) - g_t0[idx];
}

// ---------------- depthwise 33-tap residual conv on v, added to g_oh ----------------
__global__ void resconv_k(const float* __restrict__ w)
{
    int d = threadIdx.x;
    int n = blockIdx.x;
    int bh = blockIdx.y;
    int hh = bh % NH;
    __shared__ float sw[33];
    if (d < 33) sw[d] = w[hh * 33 + d];
    __syncthreads();
    const float* vp = g_v + ((long long)bh * NPAD) * HD + d;
    float acc = 0.f;
    #pragma unroll
    for (int j = 0; j < 33; j++) {
        int nn = n + j - 16;
        if (nn >= 0 && nn < NPAD) acc += sw[j] * vp[(long long)nn * HD];
    }
    g_oh[((long long)bh * NPAD + n) * HD + d] += acc;
}

// ---------------- merge heads, residual add of unpadded slice ----------------
__global__ void merge_k()
{
    long long idx = (long long)blockIdx.x * 256 + threadIdx.x;
    int c = idx % EMB;
    long long bn = idx / EMB;
    int n = (int)(bn % NPAD);
    int b = (int)(bn / NPAD);
    int hh = c >> 6, d = c & 63;
    g_attn[idx] = g_oh[(((long long)(b * NH + hh)) * NPAD + n) * HD + d];
}

__global__ void addres_k()
{
    long long idx = (long long)blockIdx.x * 256 + threadIdx.x;
    int c = idx % EMB;
    long long bn = idx / EMB;
    int n = (int)(bn % NT);
    int b = (int)(bn / NT);
    g_h[idx] += g_y[(((long long)b * NPAD) + PADR + n) * EMB + c];
}

// ---------------- token<->image transposes ----------------
__global__ void tok2img_k()
{
    __shared__ float t[32][33];
    int b = blockIdx.z;
    int c0 = blockIdx.x * 32, p0 = blockIdx.y * 32;
    int tx = threadIdx.x, ty = threadIdx.y;
    #pragma unroll
    for (int j = 0; j < 32; j += 8)
        t[ty + j][tx] = g_h[((long long)b * NT + 1 + p0 + ty + j) * EMB + c0 + tx];
    __syncthreads();
    #pragma unroll
    for (int j = 0; j < 32; j += 8)
        g_cnn[((long long)b * EMB + c0 + ty + j) * (GRD * GRD) + p0 + tx] = t[tx][ty + j];
}

__global__ void img2tok_k()
{
    __shared__ float t[32][33];
    int b = blockIdx.z;
    int c0 = blockIdx.x * 32, p0 = blockIdx.y * 32;
    int tx = threadIdx.x, ty = threadIdx.y;
    #pragma unroll
    for (int j = 0; j < 32; j += 8)
        t[ty + j][tx] = g_cnn2[((long long)b * EMB + c0 + ty + j) * (GRD * GRD) + p0 + tx];
    __syncthreads();
    #pragma unroll
    for (int j = 0; j < 32; j += 8)
        g_h[((long long)b * NT + 1 + p0 + ty + j) * EMB + c0 + tx] = t[tx][ty + j];
}

// ---------------- fused 7x7 + 5x5 + 3x3 depthwise conv + identity ----------------
__global__ void dwconv_k(const float* __restrict__ w7, const float* __restrict__ b7,
                         const float* __restrict__ w5, const float* __restrict__ b5,
                         const float* __restrict__ w3, const float* __restrict__ b3)
{
    int bc = blockIdx.z;
    int c  = bc % EMB;
    const float* img = g_cnn + (long long)bc * GRD * GRD;
    __shared__ float tile[22][22];
    __shared__ float sw7[49], sw5[25], sw3[9];
    int tx = threadIdx.x, ty = threadIdx.y;
    int tid = ty * 16 + tx;
    if (tid < 49) sw7[tid] = w7[c * 49 + tid];
    if (tid < 25) sw5[tid] = w5[c * 25 + tid];
    if (tid < 9)  sw3[tid] = w3[c * 9  + tid];
    int ox0 = blockIdx.x * 16, oy0 = blockIdx.y * 16;
    for (int i = tid; i < 22 * 22; i += 256) {
        int yy = i / 22, xx = i % 22;
        int gy = oy0 - 3 + yy, gx = ox0 - 3 + xx;
        tile[yy][xx] = (gy >= 0 && gy < GRD && gx >= 0 && gx < GRD) ? img[gy * GRD + gx] : 0.f;
    }
    __syncthreads();
    float acc = tile[ty + 3][tx + 3] + b7[c] + b5[c] + b3[c];
    #pragma unroll
    for (int ky = 0; ky < 7; ky++)
        #pragma unroll
        for (int kx = 0; kx < 7; kx++)
            acc += sw7[ky * 7 + kx] * tile[ty + ky][tx + kx];
    #pragma unroll
    for (int ky = 0; ky < 5; ky++)
        #pragma unroll
        for (int kx = 0; kx < 5; kx++)
            acc += sw5[ky * 5 + kx] * tile[ty + 1 + ky][tx + 1 + kx];
    #pragma unroll
    for (int ky = 0; ky < 3; ky++)
        #pragma unroll
        for (int kx = 0; kx < 3; kx++)
            acc += sw3[ky * 3 + kx] * tile[ty + 2 + ky][tx + 2 + kx];
    g_cnn2[(long long)bc * GRD * GRD + (oy0 + ty) * GRD + ox0 + tx] = acc;
}

// ---------------- final LN(cls) -> logits -> softmax -> argmax ----------------
__global__ void head_k(const float* __restrict__ gg, const float* __restrict__ bb,
                       const float* __restrict__ W2, const float* __restrict__ b2,
                       float* __restrict__ out, int out_size)
{
    int tid = threadIdx.x; // 512
    __shared__ float sd[512];
    __shared__ float res[20];
    for (int b = 0; b < BB; b++) {
        float x = g_h[(long long)b * NT * EMB + tid];
        sd[tid] = x; __syncthreads();
        for (int s = 256; s > 0; s >>= 1) { if (tid < s) sd[tid] += sd[tid + s]; __syncthreads(); }
        float mu = sd[0] * (1.f / EMB); __syncthreads();
        float dx = x - mu;
        sd[tid] = dx * dx; __syncthreads();
        for (int s = 256; s > 0; s >>= 1) { if (tid < s) sd[tid] += sd[tid + s]; __syncthreads(); }
        float rs = rsqrtf(sd[0] * (1.f / EMB) + 1e-5f); __syncthreads();
        float xn = dx * rs * gg[tid] + bb[tid];
        sd[tid] = xn * W2[tid]; __syncthreads();
        for (int s = 256; s > 0; s >>= 1) { if (tid < s) sd[tid] += sd[tid + s]; __syncthreads(); }
        float l0 = sd[0] + b2[0]; __syncthreads();
        sd[tid] = xn * W2[EMB + tid]; __syncthreads();
        for (int s = 256; s > 0; s >>= 1) { if (tid < s) sd[tid] += sd[tid + s]; __syncthreads(); }
        float l1 = sd[0] + b2[1]; __syncthreads();
        if (tid == 0) {
            float mx = fmaxf(l0, l1);
            float e0 = expf(l0 - mx), e1 = expf(l1 - mx);
            float s = e0 + e1;
            res[b * 2]     = l0;
            res[b * 2 + 1] = l1;
            res[8 + b * 2]     = e0 / s;
            res[8 + b * 2 + 1] = e1 / s;
            res[16 + b] = (l1 > l0) ? 1.f : 0.f;
        }
        __syncthreads();
    }
    if (tid < 20 && tid < out_size) out[tid] = res[tid];
}

// ---------------- host orchestration ----------------
#define SYM(p, s) do { void* _t = nullptr; cudaGetSymbolAddress(&_t, s); p = (float*)_t; } while (0)

static void run_attn(const float* ln_g, const float* ln_b, const float* Wqkv,
                     const float* Wo, const float* bo, const float* res)
{
    float *x_, *qkv_, *q_, *k_, *v_, *ql_, *kl_, *s1_, *s2_, *s3_;
    float *z_, *z2_, *t0_, *t1_, *t2_, *av_, *u_, *oh_, *attn_, *y_;
    SYM(x_, g_x); SYM(qkv_, g_qkv); SYM(q_, g_q); SYM(k_, g_k); SYM(v_, g_v);
    SYM(ql_, g_ql); SYM(kl_, g_kl); SYM(s1_, g_s1); SYM(s2_, g_s2); SYM(s3_, g_s3);
    SYM(z_, g_z); SYM(z2_, g_z2); SYM(t0_, g_t0); SYM(t1_, g_t1); SYM(t2_, g_t2);
    SYM(av_, g_av); SYM(u_, g_u); SYM(oh_, g_oh); SYM(attn_, g_attn); SYM(y_, g_y);

    ln_pad_k<<<dim3(NPAD, BB), 256>>>(ln_g, ln_b);
    gemm(x_, Wqkv, qkv_, BB * NPAD, 3 * EMB, EMB, 0, 0, 0, 1, true);
    split_k<<<(BB * NPAD * 3 * EMB) / 256, 256>>>();
    land_k<<<dim3(NLM, BB * NH), 64>>>(q_, ql_);
    land_k<<<dim3(NLM, BB * NH), 64>>>(k_, kl_);

    gemm(q_, kl_, s1_, NPAD, NLM, HD,
         (long long)NPAD * HD, (long long)NLM * HD, (long long)NPAD * NLM, BB * NH, true);
    softmax_k<<<BB * NH * NPAD, 256>>>(s1_, NLM);
    gemm(ql_, kl_, s2_, NLM, NLM, HD,
         (long long)NLM * HD, (long long)NLM * HD, (long long)NLM * NLM, BB * NH, true);
    softmax_k<<<BB * NH * NLM, 256>>>(s2_, NLM);
    gemm(ql_, k_, s3_, NLM, NPAD, HD,
         (long long)NLM * HD, (long long)NPAD * HD, (long long)NLM * NPAD, BB * NH, true);
    softmax_k<<<BB * NH * NLM, 256>>>(s3_, NPAD);

    reset_red_k<<<1, 32>>>();
    denom_k<<<BB * NH, 256>>>();
    initz_k<<<(BB * NH * NLM * NLM) / 256, 256>>>();

    float* zi = z_;
    float* zo = z2_;
    for (int it = 0; it < 6; it++) {
        gemm(s2_, zi, t0_, NLM, NLM, NLM, 65536, 65536, 65536, BB * NH, false);
        ident7_k<<<(BB * NH * NLM * NLM) / 256, 256>>>();
        gemm(t0_, t1_, t2_, NLM, NLM, NLM, 65536, 65536, 65536, BB * NH, false, -1.f, 15.f);
        gemm(t0_, t2_, t1_, NLM, NLM, NLM, 65536, 65536, 65536, BB * NH, false, -1.f, 13.f);
        gemm(zi, t1_, zo, NLM, NLM, NLM, 65536, 65536, 65536, BB * NH, false, 0.25f, 0.f);
        float* tmp = zi; zi = zo; zo = tmp;
    }

    gemm(s3_, v_, av_, NLM, HD, NPAD,
         (long long)NLM * NPAD, (long long)NPAD * HD, (long long)NLM * HD, BB * NH, false);
    gemm(zi, av_, u_, NLM, HD, NLM,
         65536, (long long)NLM * HD, (long long)NLM * HD, BB * NH, false);
    gemm(s1_, u_, oh_, NPAD, HD, NLM,
         (long long)NPAD * NLM, (long long)NLM * HD, (long long)NPAD * HD, BB * NH, false);

    resconv_k<<<dim3(NPAD, BB * NH), 64>>>(res);
    merge_k<<<(BB * NPAD * EMB) / 256, 256>>>();
    gemm(attn_, Wo, y_, BB * NPAD, EMB, EMB, 0, 0, 0, 1, true, 1.f, 0.f, bo, 0);
    addres_k<<<(BB * NT * EMB) / 256, 256>>>();
}

extern "C" void kernel_launch(void* const* d_in, const int* in_sizes, int n_in,
                              void* d_out, int out_size)
{
    const float* data  = (const float*)d_in[0];
    const float* W1    = (const float*)d_in[1];
    const float* b1    = (const float*)d_in[2];
    const float* cls   = (const float*)d_in[3];
    const float* ln1_g = (const float*)d_in[4];
    const float* ln1_b = (const float*)d_in[5];
    const float* Wqkv1 = (const float*)d_in[6];
    const float* Wo1   = (const float*)d_in[7];
    const float* bo1   = (const float*)d_in[8];
    const float* res1  = (const float*)d_in[9];
    const float* ln2_g = (const float*)d_in[10];
    const float* ln2_b = (const float*)d_in[11];
    const float* Wqkv2 = (const float*)d_in[12];
    const float* Wo2   = (const float*)d_in[13];
    const float* bo2   = (const float*)d_in[14];
    const float* res2  = (const float*)d_in[15];
    const float* pw7   = (const float*)d_in[16];
    const float* pb7   = (const float*)d_in[17];
    const float* pw5   = (const float*)d_in[18];
    const float* pb5   = (const float*)d_in[19];
    const float* pw3   = (const float*)d_in[20];
    const float* pb3   = (const float*)d_in[21];
    const float* lnf_g = (const float*)d_in[22];
    const float* lnf_b = (const float*)d_in[23];
    const float* W2    = (const float*)d_in[24];
    const float* b2    = (const float*)d_in[25];

    float* attn_;
    SYM(attn_, g_attn);

    // stage 1: h = relu(data @ W1^T + b1) -> g_attn, then prepend cls into g_h
    gemm(data, W1, attn_, BB * N0, EMB, C0, 0, 0, 0, 1, true, 1.f, 0.f, b1, 1);
    build_h_k<<<(BB * NT * EMB) / 256, 256>>>(cls);

    // stage 2: first Nystrom attention block (residual)
    run_attn(ln1_g, ln1_b, Wqkv1, Wo1, bo1, res1);

    // stage 3: PPEG conv block on the 64x64 token grid (cls row untouched)
    tok2img_k<<<dim3(EMB / 32, (GRD * GRD) / 32, BB), dim3(32, 8)>>>();
    dwconv_k<<<dim3(GRD / 16, GRD / 16, BB * EMB), dim3(16, 16)>>>(pw7, pb7, pw5, pb5, pw3, pb3);
    img2tok_k<<<dim3(EMB / 32, (GRD * GRD) / 32, BB), dim3(32, 8)>>>();

    // stage 4: second Nystrom attention block (residual)
    run_attn(ln2_g, ln2_b, Wqkv2, Wo2, bo2, res2);

    // stage 5: final LN on cls token + classification head
    head_k<<<1, 512>>>(lnf_g, lnf_b, W2, b2, (float*)d_out, out_size);
}

// round 2
// speedup vs baseline: 1.4027x; 1.4027x over previous
#include <cuda_runtime.h>
#include <math.h>

#define BB   4
#define N0   4096
#define C0   1536
#define EMB  512
#define NH   8
#define HD   64
#define NT   4097
#define NPAD 4352
#define PADR 255
#define NLM  256
#define LCH  17
#define GRD  64
#define QSCALE 0.125f

// ---------------- static device scratch (no allocations allowed) ----------------
__device__ float g_h   [BB*NT*EMB];
__device__ float g_x   [BB*NPAD*EMB];
__device__ float g_qkv [BB*NPAD*3*EMB];
__device__ float g_q   [BB*NH*NPAD*HD];
__device__ float g_k   [BB*NH*NPAD*HD];
__device__ float g_v   [BB*NH*NPAD*HD];
__device__ float g_ql  [BB*NH*NLM*HD];
__device__ float g_kl  [BB*NH*NLM*HD];
__device__ float g_s1  [(long long)BB*NH*NPAD*NLM];
__device__ float g_s2  [BB*NH*NLM*NLM];
__device__ float g_s3  [(long long)BB*NH*NLM*NPAD];
__device__ float g_z   [BB*NH*NLM*NLM];
__device__ float g_z2  [BB*NH*NLM*NLM];
__device__ float g_t0  [BB*NH*NLM*NLM];
__device__ float g_t1  [BB*NH*NLM*NLM];
__device__ float g_t2  [BB*NH*NLM*NLM];
__device__ float g_av  [BB*NH*NLM*HD];
__device__ float g_u   [BB*NH*NLM*HD];
__device__ float g_oh  [BB*NH*NPAD*HD];
__device__ float g_attn[BB*NPAD*EMB];
__device__ float g_y   [BB*NPAD*EMB];
__device__ float g_cnn [BB*EMB*GRD*GRD];
__device__ float g_cnn2[BB*EMB*GRD*GRD];
__device__ unsigned g_red[2];

// ---------------- batched SGEMM: C = alpha*A@op(B) + betaI*I + bias, relu ----------------
// 128x64 block tile, 8x4 register microtile, double-buffered smem.
// A: (M,K) row-major. TRANSB: B is (N,K) row-major (C=A*B^T), else B is (K,N).
// Requires M%128==0, N%64==0, K%16==0 (true at every call site).
template<bool TRANSB>
__global__ void __launch_bounds__(256, 2)
gemm_k(const float* __restrict__ A, const float* __restrict__ Bm,
       float* __restrict__ C,
       int Mdim, int Ndim, int Kdim,
       long long sA, long long sB, long long sC,
       float alpha, float betaI,
       const float* __restrict__ bias, int relu)
{
    __shared__ __align__(16) float As[2][16][132];
    __shared__ __align__(16) float Bs[2][16][68];
    A  += (long long)blockIdx.z * sA;
    Bm += (long long)blockIdx.z * sB;
    C  += (long long)blockIdx.z * sC;
    const int m0 = blockIdx.y * 128;
    const int n0 = blockIdx.x * 64;
    const int tid = threadIdx.x;
    const int tx = tid & 15, ty = tid >> 4;   // tx: 4 cols, ty: 8 rows

    float acc[8][4] = {};
    float ra[8], rb[4];

    const int nsteps = Kdim >> 4;

    // ---- load first tile directly to smem[0] ----
    {
        #pragma unroll
        for (int r = 0; r < 8; r++) {
            int i = tid + r * 256;
            int m = i >> 4, kk = i & 15;
            As[0][kk][m] = A[(long long)(m0 + m) * Kdim + kk];
        }
        if (TRANSB) {
            #pragma unroll
            for (int r = 0; r < 4; r++) {
                int i = tid + r * 256;
                int n = i >> 4, kk = i & 15;
                Bs[0][kk][n] = Bm[(long long)(n0 + n) * Kdim + kk];
            }
        } else {
            #pragma unroll
            for (int r = 0; r < 4; r++) {
                int i = tid + r * 256;
                int kk = i >> 6, n = i & 63;
                Bs[0][kk][n] = Bm[(long long)kk * Ndim + n0 + n];
            }
        }
    }
    __syncthreads();

    int buf = 0;
    for (int s = 0; s < nsteps; s++) {
        const int ktn = (s + 1) << 4;
        if (s + 1 < nsteps) {
            #pragma unroll
            for (int r = 0; r < 8; r++) {
                int i = tid + r * 256;
                int m = i >> 4, kk = i & 15;
                ra[r] = A[(long long)(m0 + m) * Kdim + ktn + kk];
            }
            if (TRANSB) {
                #pragma unroll
                for (int r = 0; r < 4; r++) {
                    int i = tid + r * 256;
                    int n = i >> 4, kk = i & 15;
                    rb[r] = Bm[(long long)(n0 + n) * Kdim + ktn + kk];
                }
            } else {
                #pragma unroll
                for (int r = 0; r < 4; r++) {
                    int i = tid + r * 256;
                    int kk = i >> 6, n = i & 63;
                    rb[r] = Bm[(long long)(ktn + kk) * Ndim + n0 + n];
                }
            }
        }
        #pragma unroll
        for (int kk = 0; kk < 16; kk++) {
            float4 a0 = *(const float4*)&As[buf][kk][ty * 8];
            float4 a1 = *(const float4*)&As[buf][kk][ty * 8 + 4];
            float4 b0 = *(const float4*)&Bs[buf][kk][tx * 4];
            float a_[8] = {a0.x, a0.y, a0.z, a0.w, a1.x, a1.y, a1.z, a1.w};
            float b_[4] = {b0.x, b0.y, b0.z, b0.w};
            #pragma unroll
            for (int i = 0; i < 8; i++)
                #pragma unroll
                for (int j = 0; j < 4; j++)
                    acc[i][j] += a_[i] * b_[j];
        }
        if (s + 1 < nsteps) {
            int nb = buf ^ 1;
            #pragma unroll
            for (int r = 0; r < 8; r++) {
                int i = tid + r * 256;
                As[nb][i & 15][i >> 4] = ra[r];
            }
            if (TRANSB) {
                #pragma unroll
                for (int r = 0; r < 4; r++) {
                    int i = tid + r * 256;
                    Bs[nb][i & 15][i >> 4] = rb[r];
                }
            } else {
                #pragma unroll
                for (int r = 0; r < 4; r++) {
                    int i = tid + r * 256;
                    Bs[nb][i >> 6][i & 63] = rb[r];
                }
            }
            __syncthreads();
            buf = nb;
        }
    }

    // ---- epilogue ----
    const int nbase = n0 + tx * 4;
    float4 bias4 = make_float4(0.f, 0.f, 0.f, 0.f);
    if (bias) bias4 = *(const float4*)&bias[nbase];
    #pragma unroll
    for (int i = 0; i < 8; i++) {
        int m = m0 + ty * 8 + i;
        float4 v;
        v.x = alpha * acc[i][0] + bias4.x;
        v.y = alpha * acc[i][1] + bias4.y;
        v.z = alpha * acc[i][2] + bias4.z;
        v.w = alpha * acc[i][3] + bias4.w;
        if (betaI != 0.f) {
            if (m == nbase)     v.x += betaI;
            if (m == nbase + 1) v.y += betaI;
            if (m == nbase + 2) v.z += betaI;
            if (m == nbase + 3) v.w += betaI;
        }
        if (relu) {
            v.x = fmaxf(v.x, 0.f); v.y = fmaxf(v.y, 0.f);
            v.z = fmaxf(v.z, 0.f); v.w = fmaxf(v.w, 0.f);
        }
        *(float4*)&C[(long long)m * Ndim + nbase] = v;
    }
}

static void gemm(const float* A, const float* Bm, float* C,
                 int M_, int N_, int K_,
                 long long sA, long long sB, long long sC, int batch, bool transB,
                 float alpha = 1.f, float betaI = 0.f,
                 const float* bias = nullptr, int relu = 0)
{
    dim3 grid(N_ / 64, M_ / 128, batch);
    if (transB) gemm_k<true ><<<grid, 256>>>(A, Bm, C, M_, N_, K_, sA, sB, sC, alpha, betaI, bias, relu);
    else        gemm_k<false><<<grid, 256>>>(A, Bm, C, M_, N_, K_, sA, sB, sC, alpha, betaI, bias, relu);
}

// ---------------- build h = [cls; gemm1_out] ----------------
__global__ void build_h_k(const float* __restrict__ cls)
{
    long long idx = (long long)blockIdx.x * 256 + threadIdx.x;
    int c = idx % EMB;
    long long bn = idx / EMB;
    int n = (int)(bn % NT);
    int b = (int)(bn / NT);
    g_h[idx] = (n == 0) ? cls[c] : g_attn[((long long)b * N0 + (n - 1)) * EMB + c];
}

// ---------------- layer norm + front zero-pad into g_x ----------------
__global__ void ln_pad_k(const float* __restrict__ gg, const float* __restrict__ bb)
{
    int n = blockIdx.x, b = blockIdx.y;
    int tid = threadIdx.x;
    float* out = g_x + ((long long)b * NPAD + n) * EMB;
    if (n < PADR) { out[tid] = 0.f; out[tid + 256] = 0.f; return; }
    const float* in = g_h + ((long long)b * NT + (n - PADR)) * EMB;
    float x0 = in[tid], x1 = in[tid + 256];
    __shared__ float sd[256];
    sd[tid] = x0 + x1; __syncthreads();
    for (int s = 128; s > 0; s >>= 1) { if (tid < s) sd[tid] += sd[tid + s]; __syncthreads(); }
    float mu = sd[0] * (1.f / EMB);
    __syncthreads();
    float d0 = x0 - mu, d1 = x1 - mu;
    sd[tid] = d0 * d0 + d1 * d1; __syncthreads();
    for (int s = 128; s > 0; s >>= 1) { if (tid < s) sd[tid] += sd[tid + s]; __syncthreads(); }
    float rs = rsqrtf(sd[0] * (1.f / EMB) + 1e-5f);
    out[tid]       = d0 * rs * gg[tid]       + bb[tid];
    out[tid + 256] = d1 * rs * gg[tid + 256] + bb[tid + 256];
}

// ---------------- split qkv into per-head q (scaled), k, v ----------------
__global__ void split_k()
{
    long long idx = (long long)blockIdx.x * 256 + threadIdx.x;
    float val = g_qkv[idx];
    int c = idx % (3 * EMB);
    long long bn = idx / (3 * EMB);
    int n = (int)(bn % NPAD);
    int b = (int)(bn / NPAD);
    int kind = c >> 9;
    int cc = c & 511;
    int hh = cc >> 6, d = cc & 63;
    long long dst = (((long long)(b * NH + hh)) * NPAD + n) * HD + d;
    if (kind == 0) g_q[dst] = val * QSCALE;
    else if (kind == 1) g_k[dst] = val;
    else g_v[dst] = val;
}

// ---------------- landmark means (mean over LCH consecutive tokens) ----------------
__global__ void land_k(const float* __restrict__ src, float* __restrict__ dst)
{
    int d = threadIdx.x;
    int m = blockIdx.x;
    int bh = blockIdx.y;
    const float* p = src + (((long long)bh * NPAD) + (long long)m * LCH) * HD + d;
    float s = 0.f;
    #pragma unroll
    for (int i = 0; i < LCH; i++) s += p[(long long)i * HD];
    dst[(((long long)bh * NLM) + m) * HD + d] = s * (1.f / LCH);
}

// ---------------- row softmax ----------------
__global__ void softmax_k(float* __restrict__ x, int len)
{
    long long row = blockIdx.x;
    float* p = x + row * (long long)len;
    int tid = threadIdx.x;
    __shared__ float sd[256];
    float m = -1e30f;
    for (int i = tid; i < len; i += 256) m = fmaxf(m, p[i]);
    sd[tid] = m; __syncthreads();
    for (int s = 128; s > 0; s >>= 1) { if (tid < s) sd[tid] = fmaxf(sd[tid], sd[tid + s]); __syncthreads(); }
    m = sd[0]; __syncthreads();
    float sum = 0.f;
    for (int i = tid; i < len; i += 256) { float e = expf(p[i] - m); p[i] = e; sum += e; }
    sd[tid] = sum; __syncthreads();
    for (int s = 128; s > 0; s >>= 1) { if (tid < s) sd[tid] += sd[tid + s]; __syncthreads(); }
    float r = 1.f / sd[0];
    __syncthreads();
    for (int i = tid; i < len; i += 256) p[i] *= r;
}

// ---------------- pinv: denom reductions, z init, 7I - xz ----------------
__global__ void reset_red_k() { if (threadIdx.x < 2) g_red[threadIdx.x] = 0u; }

__global__ void denom_k()
{
    int bh = blockIdx.x, tid = threadIdx.x;
    const float* mat = g_s2 + (long long)bh * NLM * NLM;
    float col = 0.f, rs = 0.f;
    for (int i = 0; i < NLM; i++) col += mat[i * NLM + tid];
    for (int j = 0; j < NLM; j++) rs  += mat[tid * NLM + j];
    __shared__ float sd[256];
    sd[tid] = rs; __syncthreads();
    for (int s = 128; s > 0; s >>= 1) { if (tid < s) sd[tid] = fmaxf(sd[tid], sd[tid + s]); __syncthreads(); }
    if (tid == 0) atomicMax(&g_red[0], __float_as_uint(sd[0]));
    __syncthreads();
    sd[tid] = col; __syncthreads();
    for (int s = 128; s > 0; s >>= 1) { if (tid < s) sd[tid] = fmaxf(sd[tid], sd[tid + s]); __syncthreads(); }
    if (tid == 0) atomicMax(&g_red[1], __float_as_uint(sd[0]));
}

__global__ void initz_k()
{
    long long idx = (long long)blockIdx.x * 256 + threadIdx.x;
    float rd = 1.f / (__uint_as_float(g_red[0]) * __uint_as_float(g_red[1]));
    int ij = (int)(idx & 65535);
    long long bh = idx >> 16;
    int i = ij >> 8, j = ij & 255;
    g_z[idx] = g_s2[(bh << 16) + (long long)j * NLM + i] * rd;
}

__global__ void ident7_k()
{
    long long idx = (long long)blockIdx.x * 256 + threadIdx.x;
    int ij = (int)(idx & 65535);
    int i = ij >> 8, j = ij & 255;
    g_t1[idx] = ((i == j) ? 7.f : 0.f) - g_t0[idx];
}

// ---------------- depthwise 33-tap residual conv on v, added to g_oh ----------------
__global__ void resconv_k(const float* __restrict__ w)
{
    int d = threadIdx.x;
    int n = blockIdx.x;
    int bh = blockIdx.y;
    int hh = bh % NH;
    __shared__ float sw[33];
    if (d < 33) sw[d] = w[hh * 33 + d];
    __syncthreads();
    const float* vp = g_v + ((long long)bh * NPAD) * HD + d;
    float acc = 0.f;
    #pragma unroll
    for (int j = 0; j < 33; j++) {
        int nn = n + j - 16;
        if (nn >= 0 && nn < NPAD) acc += sw[j] * vp[(long long)nn * HD];
    }
    g_oh[((long long)bh * NPAD + n) * HD + d] += acc;
}

// ---------------- merge heads ----------------
__global__ void merge_k()
{
    long long idx = (long long)blockIdx.x * 256 + threadIdx.x;
    int c = idx % EMB;
    long long bn = idx / EMB;
    int n = (int)(bn % NPAD);
    int b = (int)(bn / NPAD);
    int hh = c >> 6, d = c & 63;
    g_attn[idx] = g_oh[(((long long)(b * NH + hh)) * NPAD + n) * HD + d];
}

__global__ void addres_k()
{
    long long idx = (long long)blockIdx.x * 256 + threadIdx.x;
    int c = idx % EMB;
    long long bn = idx / EMB;
    int n = (int)(bn % NT);
    int b = (int)(bn / NT);
    g_h[idx] += g_y[(((long long)b * NPAD) + PADR + n) * EMB + c];
}

// ---------------- token<->image transposes ----------------
__global__ void tok2img_k()
{
    __shared__ float t[32][33];
    int b = blockIdx.z;
    int c0 = blockIdx.x * 32, p0 = blockIdx.y * 32;
    int tx = threadIdx.x, ty = threadIdx.y;
    #pragma unroll
    for (int j = 0; j < 32; j += 8)
        t[ty + j][tx] = g_h[((long long)b * NT + 1 + p0 + ty + j) * EMB + c0 + tx];
    __syncthreads();
    #pragma unroll
    for (int j = 0; j < 32; j += 8)
        g_cnn[((long long)b * EMB + c0 + ty + j) * (GRD * GRD) + p0 + tx] = t[tx][ty + j];
}

__global__ void img2tok_k()
{
    __shared__ float t[32][33];
    int b = blockIdx.z;
    int c0 = blockIdx.x * 32, p0 = blockIdx.y * 32;
    int tx = threadIdx.x, ty = threadIdx.y;
    #pragma unroll
    for (int j = 0; j < 32; j += 8)
        t[ty + j][tx] = g_cnn2[((long long)b * EMB + c0 + ty + j) * (GRD * GRD) + p0 + tx];
    __syncthreads();
    #pragma unroll
    for (int j = 0; j < 32; j += 8)
        g_h[((long long)b * NT + 1 + p0 + ty + j) * EMB + c0 + tx] = t[tx][ty + j];
}

// ---------------- fused 7x7 + 5x5 + 3x3 depthwise conv + identity ----------------
__global__ void dwconv_k(const float* __restrict__ w7, const float* __restrict__ b7,
                         const float* __restrict__ w5, const float* __restrict__ b5,
                         const float* __restrict__ w3, const float* __restrict__ b3)
{
    int bc = blockIdx.z;
    int c  = bc % EMB;
    const float* img = g_cnn + (long long)bc * GRD * GRD;
    __shared__ float tile[22][22];
    __shared__ float sw7[49], sw5[25], sw3[9];
    int tx = threadIdx.x, ty = threadIdx.y;
    int tid = ty * 16 + tx;
    if (tid < 49) sw7[tid] = w7[c * 49 + tid];
    if (tid < 25) sw5[tid] = w5[c * 25 + tid];
    if (tid < 9)  sw3[tid] = w3[c * 9  + tid];
    int ox0 = blockIdx.x * 16, oy0 = blockIdx.y * 16;
    for (int i = tid; i < 22 * 22; i += 256) {
        int yy = i / 22, xx = i % 22;
        int gy = oy0 - 3 + yy, gx = ox0 - 3 + xx;
        tile[yy][xx] = (gy >= 0 && gy < GRD && gx >= 0 && gx < GRD) ? img[gy * GRD + gx] : 0.f;
    }
    __syncthreads();
    float acc = tile[ty + 3][tx + 3] + b7[c] + b5[c] + b3[c];
    #pragma unroll
    for (int ky = 0; ky < 7; ky++)
        #pragma unroll
        for (int kx = 0; kx < 7; kx++)
            acc += sw7[ky * 7 + kx] * tile[ty + ky][tx + kx];
    #pragma unroll
    for (int ky = 0; ky < 5; ky++)
        #pragma unroll
        for (int kx = 0; kx < 5; kx++)
            acc += sw5[ky * 5 + kx] * tile[ty + 1 + ky][tx + 1 + kx];
    #pragma unroll
    for (int ky = 0; ky < 3; ky++)
        #pragma unroll
        for (int kx = 0; kx < 3; kx++)
            acc += sw3[ky * 3 + kx] * tile[ty + 2 + ky][tx + 2 + kx];
    g_cnn2[(long long)bc * GRD * GRD + (oy0 + ty) * GRD + ox0 + tx] = acc;
}

// ---------------- final LN(cls) -> logits -> softmax -> argmax ----------------
__global__ void head_k(const float* __restrict__ gg, const float* __restrict__ bb,
                       const float* __restrict__ W2, const float* __restrict__ b2,
                       float* __restrict__ out, int out_size)
{
    int tid = threadIdx.x; // 512
    __shared__ float sd[512];
    __shared__ float res[20];
    for (int b = 0; b < BB; b++) {
        float x = g_h[(long long)b * NT * EMB + tid];
        sd[tid] = x; __syncthreads();
        for (int s = 256; s > 0; s >>= 1) { if (tid < s) sd[tid] += sd[tid + s]; __syncthreads(); }
        float mu = sd[0] * (1.f / EMB); __syncthreads();
        float dx = x - mu;
        sd[tid] = dx * dx; __syncthreads();
        for (int s = 256; s > 0; s >>= 1) { if (tid < s) sd[tid] += sd[tid + s]; __syncthreads(); }
        float rs = rsqrtf(sd[0] * (1.f / EMB) + 1e-5f); __syncthreads();
        float xn = dx * rs * gg[tid] + bb[tid];
        sd[tid] = xn * W2[tid]; __syncthreads();
        for (int s = 256; s > 0; s >>= 1) { if (tid < s) sd[tid] += sd[tid + s]; __syncthreads(); }
        float l0 = sd[0] + b2[0]; __syncthreads();
        sd[tid] = xn * W2[EMB + tid]; __syncthreads();
        for (int s = 256; s > 0; s >>= 1) { if (tid < s) sd[tid] += sd[tid + s]; __syncthreads(); }
        float l1 = sd[0] + b2[1]; __syncthreads();
        if (tid == 0) {
            float mx = fmaxf(l0, l1);
            float e0 = expf(l0 - mx), e1 = expf(l1 - mx);
            float s = e0 + e1;
            res[b * 2]     = l0;
            res[b * 2 + 1] = l1;
            res[8 + b * 2]     = e0 / s;
            res[8 + b * 2 + 1] = e1 / s;
            res[16 + b] = (l1 > l0) ? 1.f : 0.f;
        }
        __syncthreads();
    }
    if (tid < 20 && tid < out_size) out[tid] = res[tid];
}

// ---------------- host orchestration ----------------
#define SYM(p, s) do { void* _t = nullptr; cudaGetSymbolAddress(&_t, s); p = (float*)_t; } while (0)

static void run_attn(const float* ln_g, const float* ln_b, const float* Wqkv,
                     const float* Wo, const float* bo, const float* res)
{
    float *x_, *qkv_, *q_, *k_, *v_, *ql_, *kl_, *s1_, *s2_, *s3_;
    float *z_, *z2_, *t0_, *t1_, *t2_, *av_, *u_, *oh_, *attn_, *y_;
    SYM(x_, g_x); SYM(qkv_, g_qkv); SYM(q_, g_q); SYM(k_, g_k); SYM(v_, g_v);
    SYM(ql_, g_ql); SYM(kl_, g_kl); SYM(s1_, g_s1); SYM(s2_, g_s2); SYM(s3_, g_s3);
    SYM(z_, g_z); SYM(z2_, g_z2); SYM(t0_, g_t0); SYM(t1_, g_t1); SYM(t2_, g_t2);
    SYM(av_, g_av); SYM(u_, g_u); SYM(oh_, g_oh); SYM(attn_, g_attn); SYM(y_, g_y);

    ln_pad_k<<<dim3(NPAD, BB), 256>>>(ln_g, ln_b);
    gemm(x_, Wqkv, qkv_, BB * NPAD, 3 * EMB, EMB, 0, 0, 0, 1, true);
    split_k<<<(BB * NPAD * 3 * EMB) / 256, 256>>>();
    land_k<<<dim3(NLM, BB * NH), 64>>>(q_, ql_);
    land_k<<<dim3(NLM, BB * NH), 64>>>(k_, kl_);

    gemm(q_, kl_, s1_, NPAD, NLM, HD,
         (long long)NPAD * HD, (long long)NLM * HD, (long long)NPAD * NLM, BB * NH, true);
    softmax_k<<<BB * NH * NPAD, 256>>>(s1_, NLM);
    gemm(ql_, kl_, s2_, NLM, NLM, HD,
         (long long)NLM * HD, (long long)NLM * HD, (long long)NLM * NLM, BB * NH, true);
    softmax_k<<<BB * NH * NLM, 256>>>(s2_, NLM);
    gemm(ql_, k_, s3_, NLM, NPAD, HD,
         (long long)NLM * HD, (long long)NPAD * HD, (long long)NLM * NPAD, BB * NH, true);
    softmax_k<<<BB * NH * NLM, 256>>>(s3_, NPAD);

    reset_red_k<<<1, 32>>>();
    denom_k<<<BB * NH, 256>>>();
    initz_k<<<(BB * NH * NLM * NLM) / 256, 256>>>();

    float* zi = z_;
    float* zo = z2_;
    for (int it = 0; it < 6; it++) {
        gemm(s2_, zi, t0_, NLM, NLM, NLM, 65536, 65536, 65536, BB * NH, false);
        ident7_k<<<(BB * NH * NLM * NLM) / 256, 256>>>();
        gemm(t0_, t1_, t2_, NLM, NLM, NLM, 65536, 65536, 65536, BB * NH, false, -1.f, 15.f);
        gemm(t0_, t2_, t1_, NLM, NLM, NLM, 65536, 65536, 65536, BB * NH, false, -1.f, 13.f);
        gemm(zi, t1_, zo, NLM, NLM, NLM, 65536, 65536, 65536, BB * NH, false, 0.25f, 0.f);
        float* tmp = zi; zi = zo; zo = tmp;
    }

    gemm(s3_, v_, av_, NLM, HD, NPAD,
         (long long)NLM * NPAD, (long long)NPAD * HD, (long long)NLM * HD, BB * NH, false);
    gemm(zi, av_, u_, NLM, HD, NLM,
         65536, (long long)NLM * HD, (long long)NLM * HD, BB * NH, false);
    gemm(s1_, u_, oh_, NPAD, HD, NLM,
         (long long)NPAD * NLM, (long long)NLM * HD, (long long)NPAD * HD, BB * NH, false);

    resconv_k<<<dim3(NPAD, BB * NH), 64>>>(res);
    merge_k<<<(BB * NPAD * EMB) / 256, 256>>>();
    gemm(attn_, Wo, y_, BB * NPAD, EMB, EMB, 0, 0, 0, 1, true, 1.f, 0.f, bo, 0);
    addres_k<<<(BB * NT * EMB) / 256, 256>>>();
}

extern "C" void kernel_launch(void* const* d_in, const int* in_sizes, int n_in,
                              void* d_out, int out_size)
{
    const float* data  = (const float*)d_in[0];
    const float* W1    = (const float*)d_in[1];
    const float* b1    = (const float*)d_in[2];
    const float* cls   = (const float*)d_in[3];
    const float* ln1_g = (const float*)d_in[4];
    const float* ln1_b = (const float*)d_in[5];
    const float* Wqkv1 = (const float*)d_in[6];
    const float* Wo1   = (const float*)d_in[7];
    const float* bo1   = (const float*)d_in[8];
    const float* res1  = (const float*)d_in[9];
    const float* ln2_g = (const float*)d_in[10];
    const float* ln2_b = (const float*)d_in[11];
    const float* Wqkv2 = (const float*)d_in[12];
    const float* Wo2   = (const float*)d_in[13];
    const float* bo2   = (const float*)d_in[14];
    const float* res2  = (const float*)d_in[15];
    const float* pw7   = (const float*)d_in[16];
    const float* pb7   = (const float*)d_in[17];
    const float* pw5   = (const float*)d_in[18];
    const float* pb5   = (const float*)d_in[19];
    const float* pw3   = (const float*)d_in[20];
    const float* pb3   = (const float*)d_in[21];
    const float* lnf_g = (const float*)d_in[22];
    const float* lnf_b = (const float*)d_in[23];
    const float* W2    = (const float*)d_in[24];
    const float* b2    = (const float*)d_in[25];

    float* attn_;
    SYM(attn_, g_attn);

    // stage 1: h = relu(data @ W1^T + b1) -> g_attn, then prepend cls into g_h
    gemm(data, W1, attn_, BB * N0, EMB, C0, 0, 0, 0, 1, true, 1.f, 0.f, b1, 1);
    build_h_k<<<(BB * NT * EMB) / 256, 256>>>(cls);

    // stage 2: first Nystrom attention block (residual)
    run_attn(ln1_g, ln1_b, Wqkv1, Wo1, bo1, res1);

    // stage 3: PPEG conv block on the 64x64 token grid (cls row untouched)
    tok2img_k<<<dim3(EMB / 32, (GRD * GRD) / 32, BB), dim3(32, 8)>>>();
    dwconv_k<<<dim3(GRD / 16, GRD / 16, BB * EMB), dim3(16, 16)>>>(pw7, pb7, pw5, pb5, pw3, pb3);
    img2tok_k<<<dim3(EMB / 32, (GRD * GRD) / 32, BB), dim3(32, 8)>>>();

    // stage 4: second Nystrom attention block (residual)
    run_attn(ln2_g, ln2_b, Wqkv2, Wo2, bo2, res2);

    // stage 5: final LN on cls token + classification head
    head_k<<<1, 512>>>(lnf_g, lnf_b, W2, b2, (float*)d_out, out_size);
}

// round 4
// speedup vs baseline: 1.4470x; 1.0316x over previous
#include <cuda_runtime.h>
#include <math.h>

#define BB   4
#define N0   4096
#define C0   1536
#define EMB  512
#define NH   8
#define HD   64
#define NT   4097
#define NPAD 4352
#define PADR 255
#define NLM  256
#define LCH  17
#define GRD  64
#define QSCALE 0.125f

// ---------------- static device scratch (no allocations allowed) ----------------
__device__ float g_h   [BB*NT*EMB];
__device__ float g_x   [BB*NPAD*EMB];
__device__ float g_qkv [BB*NPAD*3*EMB];
__device__ float g_q   [BB*NH*NPAD*HD];
__device__ float g_k   [BB*NH*NPAD*HD];
__device__ float g_v   [BB*NH*NPAD*HD];
__device__ float g_ql  [BB*NH*NLM*HD];
__device__ float g_kl  [BB*NH*NLM*HD];
__device__ float g_s1  [(long long)BB*NH*NPAD*NLM];
__device__ float g_s2  [BB*NH*NLM*NLM];
__device__ float g_s3  [(long long)BB*NH*NLM*NPAD];
__device__ float g_z   [BB*NH*NLM*NLM];
__device__ float g_z2  [BB*NH*NLM*NLM];
__device__ float g_t0  [BB*NH*NLM*NLM];
__device__ float g_t1  [BB*NH*NLM*NLM];
__device__ float g_t2  [BB*NH*NLM*NLM];
__device__ float g_av  [BB*NH*NLM*HD];
__device__ float g_u   [BB*NH*NLM*HD];
__device__ float g_oh  [BB*NH*NPAD*HD];
__device__ float g_attn[BB*NPAD*EMB];
__device__ float g_y   [BB*NPAD*EMB];
__device__ float g_cnn [BB*EMB*GRD*GRD];
__device__ float g_cnn2[BB*EMB*GRD*GRD];
__device__ unsigned g_red[2];

// ---------------- tf32 helpers ----------------
__device__ __forceinline__ unsigned f2tf(float v)
{
    unsigned r;
    asm("cvt.rna.tf32.f32 %0, %1;" : "=r"(r) : "f"(v));
    return r;
}

__device__ __forceinline__ void mma_tf32(float c[4], const unsigned a[4], const unsigned b[2])
{
    asm volatile("mma.sync.aligned.m16n8k8.row.col.f32.tf32.tf32.f32 "
                 "{%0,%1,%2,%3}, {%4,%5,%6,%7}, {%8,%9}, {%0,%1,%2,%3};"
                 : "+f"(c[0]), "+f"(c[1]), "+f"(c[2]), "+f"(c[3])
                 : "r"(a[0]), "r"(a[1]), "r"(a[2]), "r"(a[3]), "r"(b[0]), "r"(b[1]));
}

// ---------------- batched 3xTF32 tensor-core GEMM ----------------
// C = alpha*A@op(B) + betaI*I + bias + addScale*Add, optional relu.
// A: (M,K) row-major. TRANSB: B is (N,K) row-major (C=A*B^T), else (K,N).
// Block tile 128x64, 8 warps of 32x32 (2x4 m16n8k8 tiles), K-step 8, double buffer.
// Requires M%128==0, N%64==0, K%8==0.
template<bool TRANSB>
__global__ void __launch_bounds__(256, 2)
gemm_tc(const float* __restrict__ A, const float* __restrict__ Bm,
        float* __restrict__ C,
        int Mdim, int Ndim, int Kdim,
        long long sA, long long sB, long long sC,
        float alpha, float betaI,
        const float* __restrict__ bias, int relu,
        const float* __restrict__ addp, float addScale, long long sAdd)
{
    // strides 136/72 are ≡ 8 (mod 32): fragment LDS are bank-conflict-free
    __shared__ unsigned Ah[2][8][136], Al[2][8][136];
    __shared__ unsigned Bh[2][8][72],  Bl[2][8][72];

    A  += (long long)blockIdx.z * sA;
    Bm += (long long)blockIdx.z * sB;
    C  += (long long)blockIdx.z * sC;
    if (addp) addp += (long long)blockIdx.z * sAdd;

    const int m0 = blockIdx.y * 128;
    const int n0 = blockIdx.x * 64;
    const int tid  = threadIdx.x;
    const int lane = tid & 31;
    const int warp = tid >> 5;
    const int wm = warp & 3;       // 4 warps over M (32 rows each)
    const int wn = warp >> 2;      // 2 warps over N (32 cols each)
    const int g  = lane >> 2;      // 0..7
    const int tg = lane & 3;       // 0..3

    float c[2][4][4];
    #pragma unroll
    for (int i = 0; i < 2; i++)
        #pragma unroll
        for (int j = 0; j < 4; j++)
            #pragma unroll
            for (int r = 0; r < 4; r++) c[i][j][r] = 0.f;

    const int nsteps = Kdim >> 3;
    float ra[4], rb[2];

    // ---- prime buffer 0 ----
    {
        #pragma unroll
        for (int r = 0; r < 4; r++) {
            int i = tid + r * 256;
            int m = i >> 3, kk = i & 7;
            float v = A[(long long)(m0 + m) * Kdim + kk];
            unsigned h = f2tf(v);
            Ah[0][kk][m] = h;
            Al[0][kk][m] = f2tf(v - __uint_as_float(h));
        }
        #pragma unroll
        for (int r = 0; r < 2; r++) {
            int i = tid + r * 256;
            float v;
            int kk, n;
            if (TRANSB) { n = i >> 3; kk = i & 7; v = Bm[(long long)(n0 + n) * Kdim + kk]; }
            else        { kk = i >> 6; n = i & 63; v = Bm[(long long)kk * Ndim + n0 + n]; }
            unsigned h = f2tf(v);
            Bh[0][kk][n] = h;
            Bl[0][kk][n] = f2tf(v - __uint_as_float(h));
        }
    }
    __syncthreads();

    int buf = 0;
    for (int s = 0; s < nsteps; s++) {
        const int ktn = (s + 1) << 3;
        if (s + 1 < nsteps) {
            #pragma unroll
            for (int r = 0; r < 4; r++) {
                int i = tid + r * 256;
                int m = i >> 3, kk = i & 7;
                ra[r] = A[(long long)(m0 + m) * Kdim + ktn + kk];
            }
            #pragma unroll
            for (int r = 0; r < 2; r++) {
                int i = tid + r * 256;
                if (TRANSB) { int n = i >> 3, kk = i & 7; rb[r] = Bm[(long long)(n0 + n) * Kdim + ktn + kk]; }
                else        { int kk = i >> 6, n = i & 63; rb[r] = Bm[(long long)(ktn + kk) * Ndim + n0 + n]; }
            }
        }

        // ---- compute on buf ----
        {
            unsigned ah[2][4], al[2][4];
            #pragma unroll
            for (int i = 0; i < 2; i++) {
                int m = wm * 32 + i * 16 + g;
                ah[i][0] = Ah[buf][tg][m];
                ah[i][1] = Ah[buf][tg][m + 8];
                ah[i][2] = Ah[buf][tg + 4][m];
                ah[i][3] = Ah[buf][tg + 4][m + 8];
                al[i][0] = Al[buf][tg][m];
                al[i][1] = Al[buf][tg][m + 8];
                al[i][2] = Al[buf][tg + 4][m];
                al[i][3] = Al[buf][tg + 4][m + 8];
            }
            unsigned bh[4][2], bl[4][2];
            #pragma unroll
            for (int j = 0; j < 4; j++) {
                int n = wn * 32 + j * 8 + g;
                bh[j][0] = Bh[buf][tg][n];
                bh[j][1] = Bh[buf][tg + 4][n];
                bl[j][0] = Bl[buf][tg][n];
                bl[j][1] = Bl[buf][tg + 4][n];
            }
            #pragma unroll
            for (int i = 0; i < 2; i++)
                #pragma unroll
                for (int j = 0; j < 4; j++) {
                    mma_tf32(c[i][j], ah[i], bh[j]);
                    mma_tf32(c[i][j], ah[i], bl[j]);
                    mma_tf32(c[i][j], al[i], bh[j]);
                }
        }

        if (s + 1 < nsteps) {
            int nb = buf ^ 1;
            #pragma unroll
            for (int r = 0; r < 4; r++) {
                int i = tid + r * 256;
                int m = i >> 3, kk = i & 7;
                unsigned h = f2tf(ra[r]);
                Ah[nb][kk][m] = h;
                Al[nb][kk][m] = f2tf(ra[r] - __uint_as_float(h));
            }
            #pragma unroll
            for (int r = 0; r < 2; r++) {
                int i = tid + r * 256;
                int kk, n;
                if (TRANSB) { n = i >> 3; kk = i & 7; }
                else        { kk = i >> 6; n = i & 63; }
                unsigned h = f2tf(rb[r]);
                Bh[nb][kk][n] = h;
                Bl[nb][kk][n] = f2tf(rb[r] - __uint_as_float(h));
            }
            __syncthreads();
            buf = nb;
        }
    }

    // ---- epilogue ----
    #pragma unroll
    for (int i = 0; i < 2; i++) {
        #pragma unroll
        for (int j = 0; j < 4; j++) {
            int row0 = m0 + wm * 32 + i * 16 + g;
            int row1 = row0 + 8;
            int col  = n0 + wn * 32 + j * 8 + 2 * tg;
            float2 v0, v1;
            v0.x = alpha * c[i][j][0]; v0.y = alpha * c[i][j][1];
            v1.x = alpha * c[i][j][2]; v1.y = alpha * c[i][j][3];
            if (bias) {
                float2 bb2 = *(const float2*)&bias[col];
                v0.x += bb2.x; v0.y += bb2.y;
                v1.x += bb2.x; v1.y += bb2.y;
            }
            if (betaI != 0.f) {
                if (row0 == col)     v0.x += betaI;
                if (row0 == col + 1) v0.y += betaI;
                if (row1 == col)     v1.x += betaI;
                if (row1 == col + 1) v1.y += betaI;
            }
            if (addp) {
                float2 a0 = *(const float2*)&addp[(long long)row0 * Ndim + col];
                float2 a1 = *(const float2*)&addp[(long long)row1 * Ndim + col];
                v0.x += addScale * a0.x; v0.y += addScale * a0.y;
                v1.x += addScale * a1.x; v1.y += addScale * a1.y;
            }
            if (relu) {
                v0.x = fmaxf(v0.x, 0.f); v0.y = fmaxf(v0.y, 0.f);
                v1.x = fmaxf(v1.x, 0.f); v1.y = fmaxf(v1.y, 0.f);
            }
            *(float2*)&C[(long long)row0 * Ndim + col] = v0;
            *(float2*)&C[(long long)row1 * Ndim + col] = v1;
        }
    }
}

static void gemm(const float* A, const float* Bm, float* C,
                 int M_, int N_, int K_,
                 long long sA, long long sB, long long sC, int batch, bool transB,
                 float alpha = 1.f, float betaI = 0.f,
                 const float* bias = nullptr, int relu = 0,
                 const float* addp = nullptr, float addScale = 0.f, long long sAdd = 0)
{
    dim3 grid(N_ / 64, M_ / 128, batch);
    if (transB) gemm_tc<true ><<<grid, 256>>>(A, Bm, C, M_, N_, K_, sA, sB, sC, alpha, betaI, bias, relu, addp, addScale, sAdd);
    else        gemm_tc<false><<<grid, 256>>>(A, Bm, C, M_, N_, K_, sA, sB, sC, alpha, betaI, bias, relu, addp, addScale, sAdd);
}

// ---------------- build h = [cls; gemm1_out] ----------------
__global__ void build_h_k(const float* __restrict__ cls)
{
    long long idx = (long long)blockIdx.x * 256 + threadIdx.x;
    int c = idx % EMB;
    long long bn = idx / EMB;
    int n = (int)(bn % NT);
    int b = (int)(bn / NT);
    g_h[idx] = (n == 0) ? cls[c] : g_attn[((long long)b * N0 + (n - 1)) * EMB + c];
}

// ---------------- layer norm + front zero-pad into g_x ----------------
__global__ void ln_pad_k(const float* __restrict__ gg, const float* __restrict__ bb)
{
    int n = blockIdx.x, b = blockIdx.y;
    int tid = threadIdx.x;
    float* out = g_x + ((long long)b * NPAD + n) * EMB;
    if (n < PADR) { out[tid] = 0.f; out[tid + 256] = 0.f; return; }
    const float* in = g_h + ((long long)b * NT + (n - PADR)) * EMB;
    float x0 = in[tid], x1 = in[tid + 256];
    __shared__ float sd[256];
    sd[tid] = x0 + x1; __syncthreads();
    for (int s = 128; s > 0; s >>= 1) { if (tid < s) sd[tid] += sd[tid + s]; __syncthreads(); }
    float mu = sd[0] * (1.f / EMB);
    __syncthreads();
    float d0 = x0 - mu, d1 = x1 - mu;
    sd[tid] = d0 * d0 + d1 * d1; __syncthreads();
    for (int s = 128; s > 0; s >>= 1) { if (tid < s) sd[tid] += sd[tid + s]; __syncthreads(); }
    float rs = rsqrtf(sd[0] * (1.f / EMB) + 1e-5f);
    out[tid]       = d0 * rs * gg[tid]       + bb[tid];
    out[tid + 256] = d1 * rs * gg[tid + 256] + bb[tid + 256];
}

// ---------------- split qkv into per-head q (scaled), k, v ----------------
__global__ void split_k()
{
    long long idx = (long long)blockIdx.x * 256 + threadIdx.x;
    float val = g_qkv[idx];
    int c = idx % (3 * EMB);
    long long bn = idx / (3 * EMB);
    int n = (int)(bn % NPAD);
    int b = (int)(bn / NPAD);
    int kind = c >> 9;
    int cc = c & 511;
    int hh = cc >> 6, d = cc & 63;
    long long dst = (((long long)(b * NH + hh)) * NPAD + n) * HD + d;
    if (kind == 0) g_q[dst] = val * QSCALE;
    else if (kind == 1) g_k[dst] = val;
    else g_v[dst] = val;
}

// ---------------- landmark means ----------------
__global__ void land_k(const float* __restrict__ src, float* __restrict__ dst)
{
    int d = threadIdx.x;
    int m = blockIdx.x;
    int bh = blockIdx.y;
    const float* p = src + (((long long)bh * NPAD) + (long long)m * LCH) * HD + d;
    float s = 0.f;
    #pragma unroll
    for (int i = 0; i < LCH; i++) s += p[(long long)i * HD];
    dst[(((long long)bh * NLM) + m) * HD + d] = s * (1.f / LCH);
}

// ---------------- row softmax ----------------
__global__ void softmax_k(float* __restrict__ x, int len)
{
    long long row = blockIdx.x;
    float* p = x + row * (long long)len;
    int tid = threadIdx.x;
    __shared__ float sd[256];
    float m = -1e30f;
    for (int i = tid; i < len; i += 256) m = fmaxf(m, p[i]);
    sd[tid] = m; __syncthreads();
    for (int s = 128; s > 0; s >>= 1) { if (tid < s) sd[tid] = fmaxf(sd[tid], sd[tid + s]); __syncthreads(); }
    m = sd[0]; __syncthreads();
    float sum = 0.f;
    for (int i = tid; i < len; i += 256) { float e = expf(p[i] - m); p[i] = e; sum += e; }
    sd[tid] = sum; __syncthreads();
    for (int s = 128; s > 0; s >>= 1) { if (tid < s) sd[tid] += sd[tid + s]; __syncthreads(); }
    float r = 1.f / sd[0];
    __syncthreads();
    for (int i = tid; i < len; i += 256) p[i] *= r;
}

// ---------------- pinv helpers ----------------
__global__ void reset_red_k() { if (threadIdx.x < 2) g_red[threadIdx.x] = 0u; }

__global__ void denom_k()
{
    int bh = blockIdx.x, tid = threadIdx.x;
    const float* mat = g_s2 + (long long)bh * NLM * NLM;
    float col = 0.f, rs = 0.f;
    for (int i = 0; i < NLM; i++) col += mat[i * NLM + tid];
    for (int j = 0; j < NLM; j++) rs  += mat[tid * NLM + j];
    __shared__ float sd[256];
    sd[tid] = rs; __syncthreads();
    for (int s = 128; s > 0; s >>= 1) { if (tid < s) sd[tid] = fmaxf(sd[tid], sd[tid + s]); __syncthreads(); }
    if (tid == 0) atomicMax(&g_red[0], __float_as_uint(sd[0]));
    __syncthreads();
    sd[tid] = col; __syncthreads();
    for (int s = 128; s > 0; s >>= 1) { if (tid < s) sd[tid] = fmaxf(sd[tid], sd[tid + s]); __syncthreads(); }
    if (tid == 0) atomicMax(&g_red[1], __float_as_uint(sd[0]));
}

__global__ void initz_k()
{
    long long idx = (long long)blockIdx.x * 256 + threadIdx.x;
    float rd = 1.f / (__uint_as_float(g_red[0]) * __uint_as_float(g_red[1]));
    int ij = (int)(idx & 65535);
    long long bh = idx >> 16;
    int i = ij >> 8, j = ij & 255;
    g_z[idx] = g_s2[(bh << 16) + (long long)j * NLM + i] * rd;
}

// ---------------- depthwise 33-tap residual conv on v, added to g_oh ----------------
__global__ void resconv_k(const float* __restrict__ w)
{
    int d = threadIdx.x;
    int n = blockIdx.x;
    int bh = blockIdx.y;
    int hh = bh % NH;
    __shared__ float sw[33];
    if (d < 33) sw[d] = w[hh * 33 + d];
    __syncthreads();
    const float* vp = g_v + ((long long)bh * NPAD) * HD + d;
    float acc = 0.f;
    #pragma unroll
    for (int j = 0; j < 33; j++) {
        int nn = n + j - 16;
        if (nn >= 0 && nn < NPAD) acc += sw[j] * vp[(long long)nn * HD];
    }
    g_oh[((long long)bh * NPAD + n) * HD + d] += acc;
}

// ---------------- merge heads ----------------
__global__ void merge_k()
{
    long long idx = (long long)blockIdx.x * 256 + threadIdx.x;
    int c = idx % EMB;
    long long bn = idx / EMB;
    int n = (int)(bn % NPAD);
    int b = (int)(bn / NPAD);
    int hh = c >> 6, d = c & 63;
    g_attn[idx] = g_oh[(((long long)(b * NH + hh)) * NPAD + n) * HD + d];
}

__global__ void addres_k()
{
    long long idx = (long long)blockIdx.x * 256 + threadIdx.x;
    int c = idx % EMB;
    long long bn = idx / EMB;
    int n = (int)(bn % NT);
    int b = (int)(bn / NT);
    g_h[idx] += g_y[(((long long)b * NPAD) + PADR + n) * EMB + c];
}

// ---------------- token<->image transposes ----------------
__global__ void tok2img_k()
{
    __shared__ float t[32][33];
    int b = blockIdx.z;
    int c0 = blockIdx.x * 32, p0 = blockIdx.y * 32;
    int tx = threadIdx.x, ty = threadIdx.y;
    #pragma unroll
    for (int j = 0; j < 32; j += 8)
        t[ty + j][tx] = g_h[((long long)b * NT + 1 + p0 + ty + j) * EMB + c0 + tx];
    __syncthreads();
    #pragma unroll
    for (int j = 0; j < 32; j += 8)
        g_cnn[((long long)b * EMB + c0 + ty + j) * (GRD * GRD) + p0 + tx] = t[tx][ty + j];
}

__global__ void img2tok_k()
{
    __shared__ float t[32][33];
    int b = blockIdx.z;
    int c0 = blockIdx.x * 32, p0 = blockIdx.y * 32;
    int tx = threadIdx.x, ty = threadIdx.y;
    #pragma unroll
    for (int j = 0; j < 32; j += 8)
        t[ty + j][tx] = g_cnn2[((long long)b * EMB + c0 + ty + j) * (GRD * GRD) + p0 + tx];
    __syncthreads();
    #pragma unroll
    for (int j = 0; j < 32; j += 8)
        g_h[((long long)b * NT + 1 + p0 + ty + j) * EMB + c0 + tx] = t[tx][ty + j];
}

// ---------------- fused 7x7 + 5x5 + 3x3 depthwise conv + identity ----------------
__global__ void dwconv_k(const float* __restrict__ w7, const float* __restrict__ b7,
                         const float* __restrict__ w5, const float* __restrict__ b5,
                         const float* __restrict__ w3, const float* __restrict__ b3)
{
    int bc = blockIdx.z;
    int c  = bc % EMB;
    const float* img = g_cnn + (long long)bc * GRD * GRD;
    __shared__ float tile[22][22];
    __shared__ float sw7[49], sw5[25], sw3[9];
    int tx = threadIdx.x, ty = threadIdx.y;
    int tid = ty * 16 + tx;
    if (tid < 49) sw7[tid] = w7[c * 49 + tid];
    if (tid < 25) sw5[tid] = w5[c * 25 + tid];
    if (tid < 9)  sw3[tid] = w3[c * 9  + tid];
    int ox0 = blockIdx.x * 16, oy0 = blockIdx.y * 16;
    for (int i = tid; i < 22 * 22; i += 256) {
        int yy = i / 22, xx = i % 22;
        int gy = oy0 - 3 + yy, gx = ox0 - 3 + xx;
        tile[yy][xx] = (gy >= 0 && gy < GRD && gx >= 0 && gx < GRD) ? img[gy * GRD + gx] : 0.f;
    }
    __syncthreads();
    float acc = tile[ty + 3][tx + 3] + b7[c] + b5[c] + b3[c];
    #pragma unroll
    for (int ky = 0; ky < 7; ky++)
        #pragma unroll
        for (int kx = 0; kx < 7; kx++)
            acc += sw7[ky * 7 + kx] * tile[ty + ky][tx + kx];
    #pragma unroll
    for (int ky = 0; ky < 5; ky++)
        #pragma unroll
        for (int kx = 0; kx < 5; kx++)
            acc += sw5[ky * 5 + kx] * tile[ty + 1 + ky][tx + 1 + kx];
    #pragma unroll
    for (int ky = 0; ky < 3; ky++)
        #pragma unroll
        for (int kx = 0; kx < 3; kx++)
            acc += sw3[ky * 3 + kx] * tile[ty + 2 + ky][tx + 2 + kx];
    g_cnn2[(long long)bc * GRD * GRD + (oy0 + ty) * GRD + ox0 + tx] = acc;
}

// ---------------- final LN(cls) -> logits -> softmax -> argmax ----------------
__global__ void head_k(const float* __restrict__ gg, const float* __restrict__ bb,
                       const float* __restrict__ W2, const float* __restrict__ b2,
                       float* __restrict__ out, int out_size)
{
    int tid = threadIdx.x; // 512
    __shared__ float sd[512];
    __shared__ float res[20];
    for (int b = 0; b < BB; b++) {
        float x = g_h[(long long)b * NT * EMB + tid];
        sd[tid] = x; __syncthreads();
        for (int s = 256; s > 0; s >>= 1) { if (tid < s) sd[tid] += sd[tid + s]; __syncthreads(); }
        float mu = sd[0] * (1.f / EMB); __syncthreads();
        float dx = x - mu;
        sd[tid] = dx * dx; __syncthreads();
        for (int s = 256; s > 0; s >>= 1) { if (tid < s) sd[tid] += sd[tid + s]; __syncthreads(); }
        float rs = rsqrtf(sd[0] * (1.f / EMB) + 1e-5f); __syncthreads();
        float xn = dx * rs * gg[tid] + bb[tid];
        sd[tid] = xn * W2[tid]; __syncthreads();
        for (int s = 256; s > 0; s >>= 1) { if (tid < s) sd[tid] += sd[tid + s]; __syncthreads(); }
        float l0 = sd[0] + b2[0]; __syncthreads();
        sd[tid] = xn * W2[EMB + tid]; __syncthreads();
        for (int s = 256; s > 0; s >>= 1) { if (tid < s) sd[tid] += sd[tid + s]; __syncthreads(); }
        float l1 = sd[0] + b2[1]; __syncthreads();
        if (tid == 0) {
            float mx = fmaxf(l0, l1);
            float e0 = expf(l0 - mx), e1 = expf(l1 - mx);
            float s = e0 + e1;
            res[b * 2]     = l0;
            res[b * 2 + 1] = l1;
            res[8 + b * 2]     = e0 / s;
            res[8 + b * 2 + 1] = e1 / s;
            res[16 + b] = (l1 > l0) ? 1.f : 0.f;
        }
        __syncthreads();
    }
    if (tid < 20 && tid < out_size) out[tid] = res[tid];
}

// ---------------- host orchestration ----------------
#define SYM(p, s) do { void* _t = nullptr; cudaGetSymbolAddress(&_t, s); p = (float*)_t; } while (0)

static void run_attn(const float* ln_g, const float* ln_b, const float* Wqkv,
                     const float* Wo, const float* bo, const float* res)
{
    float *x_, *qkv_, *q_, *k_, *v_, *ql_, *kl_, *s1_, *s2_, *s3_;
    float *z_, *z2_, *t0_, *t1_, *t2_, *av_, *u_, *oh_, *attn_, *y_;
    SYM(x_, g_x); SYM(qkv_, g_qkv); SYM(q_, g_q); SYM(k_, g_k); SYM(v_, g_v);
    SYM(ql_, g_ql); SYM(kl_, g_kl); SYM(s1_, g_s1); SYM(s2_, g_s2); SYM(s3_, g_s3);
    SYM(z_, g_z); SYM(z2_, g_z2); SYM(t0_, g_t0); SYM(t1_, g_t1); SYM(t2_, g_t2);
    SYM(av_, g_av); SYM(u_, g_u); SYM(oh_, g_oh); SYM(attn_, g_attn); SYM(y_, g_y);

    ln_pad_k<<<dim3(NPAD, BB), 256>>>(ln_g, ln_b);
    gemm(x_, Wqkv, qkv_, BB * NPAD, 3 * EMB, EMB, 0, 0, 0, 1, true);
    split_k<<<(BB * NPAD * 3 * EMB) / 256, 256>>>();
    land_k<<<dim3(NLM, BB * NH), 64>>>(q_, ql_);
    land_k<<<dim3(NLM, BB * NH), 64>>>(k_, kl_);

    gemm(q_, kl_, s1_, NPAD, NLM, HD,
         (long long)NPAD * HD, (long long)NLM * HD, (long long)NPAD * NLM, BB * NH, true);
    softmax_k<<<BB * NH * NPAD, 256>>>(s1_, NLM);
    gemm(ql_, kl_, s2_, NLM, NLM, HD,
         (long long)NLM * HD, (long long)NLM * HD, (long long)NLM * NLM, BB * NH, true);
    softmax_k<<<BB * NH * NLM, 256>>>(s2_, NLM);
    gemm(ql_, k_, s3_, NLM, NPAD, HD,
         (long long)NLM * HD, (long long)NPAD * HD, (long long)NLM * NPAD, BB * NH, true);
    softmax_k<<<BB * NH * NLM, 256>>>(s3_, NPAD);

    reset_red_k<<<1, 32>>>();
    denom_k<<<BB * NH, 256>>>();
    initz_k<<<(BB * NH * NLM * NLM) / 256, 256>>>();

    // Newton iteration: z' = 0.25 z (13I - P(15I - P(7I - P))), P = s2@z
    // inner2 = P@P + 15I - 7P   (fused: alpha=1, betaI=15, add=P, addScale=-7)
    // inner3 = -(P@inner2) + 13I
    // z' = 0.25 z@inner3
    float* zi = z_;
    float* zo = z2_;
    for (int it = 0; it < 6; it++) {
        gemm(s2_, zi, t0_, NLM, NLM, NLM, 65536, 65536, 65536, BB * NH, false);
        gemm(t0_, t0_, t2_, NLM, NLM, NLM, 65536, 65536, 65536, BB * NH, false,
             1.f, 15.f, nullptr, 0, t0_, -7.f, 65536);
        gemm(t0_, t2_, t1_, NLM, NLM, NLM, 65536, 65536, 65536, BB * NH, false, -1.f, 13.f);
        gemm(zi, t1_, zo, NLM, NLM, NLM, 65536, 65536, 65536, BB * NH, false, 0.25f, 0.f);
        float* tmp = zi; zi = zo; zo = tmp;
    }

    gemm(s3_, v_, av_, NLM, HD, NPAD,
         (long long)NLM * NPAD, (long long)NPAD * HD, (long long)NLM * HD, BB * NH, false);
    gemm(zi, av_, u_, NLM, HD, NLM,
         65536, (long long)NLM * HD, (long long)NLM * HD, BB * NH, false);
    gemm(s1_, u_, oh_, NPAD, HD, NLM,
         (long long)NPAD * NLM, (long long)NLM * HD, (long long)NPAD * HD, BB * NH, false);

    resconv_k<<<dim3(NPAD, BB * NH), 64>>>(res);
    merge_k<<<(BB * NPAD * EMB) / 256, 256>>>();
    gemm(attn_, Wo, y_, BB * NPAD, EMB, EMB, 0, 0, 0, 1, true, 1.f, 0.f, bo, 0);
    addres_k<<<(BB * NT * EMB) / 256, 256>>>();
}

extern "C" void kernel_launch(void* const* d_in, const int* in_sizes, int n_in,
                              void* d_out, int out_size)
{
    const float* data  = (const float*)d_in[0];
    const float* W1    = (const float*)d_in[1];
    const float* b1    = (const float*)d_in[2];
    const float* cls   = (const float*)d_in[3];
    const float* ln1_g = (const float*)d_in[4];
    const float* ln1_b = (const float*)d_in[5];
    const float* Wqkv1 = (const float*)d_in[6];
    const float* Wo1   = (const float*)d_in[7];
    const float* bo1   = (const float*)d_in[8];
    const float* res1  = (const float*)d_in[9];
    const float* ln2_g = (const float*)d_in[10];
    const float* ln2_b = (const float*)d_in[11];
    const float* Wqkv2 = (const float*)d_in[12];
    const float* Wo2   = (const float*)d_in[13];
    const float* bo2   = (const float*)d_in[14];
    const float* res2  = (const float*)d_in[15];
    const float* pw7   = (const float*)d_in[16];
    const float* pb7   = (const float*)d_in[17];
    const float* pw5   = (const float*)d_in[18];
    const float* pb5   = (const float*)d_in[19];
    const float* pw3   = (const float*)d_in[20];
    const float* pb3   = (const float*)d_in[21];
    const float* lnf_g = (const float*)d_in[22];
    const float* lnf_b = (const float*)d_in[23];
    const float* W2    = (const float*)d_in[24];
    const float* b2    = (const float*)d_in[25];

    float* attn_;
    SYM(attn_, g_attn);

    // stage 1: h = relu(data @ W1^T + b1) -> g_attn, then prepend cls into g_h
    gemm(data, W1, attn_, BB * N0, EMB, C0, 0, 0, 0, 1, true, 1.f, 0.f, b1, 1);
    build_h_k<<<(BB * NT * EMB) / 256, 256>>>(cls);

    // stage 2: first Nystrom attention block (residual)
    run_attn(ln1_g, ln1_b, Wqkv1, Wo1, bo1, res1);

    // stage 3: PPEG conv block on the 64x64 token grid (cls row untouched)
    tok2img_k<<<dim3(EMB / 32, (GRD * GRD) / 32, BB), dim3(32, 8)>>>();
    dwconv_k<<<dim3(GRD / 16, GRD / 16, BB * EMB), dim3(16, 16)>>>(pw7, pb7, pw5, pb5, pw3, pb3);
    img2tok_k<<<dim3(EMB / 32, (GRD * GRD) / 32, BB), dim3(32, 8)>>>();

    // stage 4: second Nystrom attention block (residual)
    run_attn(ln2_g, ln2_b, Wqkv2, Wo2, bo2, res2);

    // stage 5: final LN on cls token + classification head
    head_k<<<1, 512>>>(lnf_g, lnf_b, W2, b2, (float*)d_out, out_size);
}

// round 5
// speedup vs baseline: 1.5366x; 1.0619x over previous
#include <cuda_runtime.h>
#include <math.h>

#define BB   4
#define N0   4096
#define C0   1536
#define EMB  512
#define NH   8
#define HD   64
#define NT   4097
#define NPAD 4352
#define PADR 255
#define NLM  256
#define LCH  17
#define GRD  64
#define QSCALE 0.125f

// ---------------- static device scratch (no allocations allowed) ----------------
__device__ float g_h   [BB*NT*EMB];
__device__ float g_x   [BB*NPAD*EMB];
__device__ float g_qkv [BB*NPAD*3*EMB];
__device__ float g_q   [BB*NH*NPAD*HD];
__device__ float g_k   [BB*NH*NPAD*HD];
__device__ float g_v   [BB*NH*NPAD*HD];
__device__ float g_ql  [BB*NH*NLM*HD];
__device__ float g_kl  [BB*NH*NLM*HD];
__device__ float g_s1  [(long long)BB*NH*NPAD*NLM];
__device__ float g_s2  [BB*NH*NLM*NLM];
__device__ float g_s3  [(long long)BB*NH*NLM*NPAD];
__device__ float g_z   [BB*NH*NLM*NLM];
__device__ float g_z2  [BB*NH*NLM*NLM];
__device__ float g_t0  [BB*NH*NLM*NLM];
__device__ float g_t1  [BB*NH*NLM*NLM];
__device__ float g_t2  [BB*NH*NLM*NLM];
__device__ float g_av  [BB*NH*NLM*HD];
__device__ float g_u   [BB*NH*NLM*HD];
__device__ float g_oh  [BB*NH*NPAD*HD];
__device__ float g_attn[BB*NPAD*EMB];
__device__ float g_y   [BB*NPAD*EMB];
__device__ float g_cnn [BB*EMB*GRD*GRD];
__device__ float g_cnn2[BB*EMB*GRD*GRD];
__device__ unsigned g_red[2];

// ---------------- tf32 helpers ----------------
__device__ __forceinline__ unsigned f2tf(float v)
{
    unsigned r;
    asm("cvt.rna.tf32.f32 %0, %1;" : "=r"(r) : "f"(v));
    return r;
}

__device__ __forceinline__ void mma_tf32(float c[4], const unsigned a[4], const unsigned b[2])
{
    asm volatile("mma.sync.aligned.m16n8k8.row.col.f32.tf32.tf32.f32 "
                 "{%0,%1,%2,%3}, {%4,%5,%6,%7}, {%8,%9}, {%0,%1,%2,%3};"
                 : "+f"(c[0]), "+f"(c[1]), "+f"(c[2]), "+f"(c[3])
                 : "r"(a[0]), "r"(a[1]), "r"(a[2]), "r"(a[3]), "r"(b[0]), "r"(b[1]));
}

// ---------------- batched 3xTF32 tensor-core GEMM, fragment-packed smem ----------------
// C = alpha*A@op(B) + betaI*I + bias + addScale*Add, optional relu.
// A: (M,K) row-major. TRANSB: B is (N,K) row-major (C=A*B^T), else (K,N).
// Block tile 128x64, 8 warps of 32x32 (2x4 m16n8k8 tiles), K-step 8, double buffer.
// Smem holds tf32 hi/lo in MMA FRAGMENT ORDER:
//   A: 8 m16-tiles, lane's 4 regs contiguous at  tile*128 + lane*4      (LDS.128)
//   B: 8 n8-tiles,  lane's 2 regs at  tile*64 + ((2*lane+2*tile)&63)    (LDS.64, rotated)
// Requires M%128==0, N%64==0, K%8==0.
template<bool TRANSB>
__global__ void __launch_bounds__(256, 2)
gemm_tc(const float* __restrict__ A, const float* __restrict__ Bm,
        float* __restrict__ C,
        int Mdim, int Ndim, int Kdim,
        long long sA, long long sB, long long sC,
        float alpha, float betaI,
        const float* __restrict__ bias, int relu,
        const float* __restrict__ addp, float addScale, long long sAdd)
{
    __shared__ unsigned Ah[2][1024], Al[2][1024];   // 8 tiles * 32 lanes * 4 regs
    __shared__ unsigned Bhs[2][512], Bls[2][512];   // 8 tiles * 32 lanes * 2 regs

    A  += (long long)blockIdx.z * sA;
    Bm += (long long)blockIdx.z * sB;
    C  += (long long)blockIdx.z * sC;
    if (addp) addp += (long long)blockIdx.z * sAdd;

    const int m0 = blockIdx.y * 128;
    const int n0 = blockIdx.x * 64;
    const int tid  = threadIdx.x;
    const int lane = tid & 31;
    const int warp = tid >> 5;
    const int wm = warp & 3;       // 4 warps over M (32 rows each)
    const int wn = warp >> 2;      // 2 warps over N (32 cols each)
    const int g  = lane >> 2;      // 0..7
    const int tg = lane & 3;       // 0..3

    // precomputed smem write addresses (per-thread constant across k-steps)
    // A element r: i = tid + r*256 -> m = i>>3, kk = i&7
    int aAddr[4], bAddr[2];
    #pragma unroll
    for (int r = 0; r < 4; r++) {
        int i = tid + r * 256;
        int m = i >> 3, kk = i & 7;
        int t = m >> 4, gg2 = m & 7, hi8 = (m >> 3) & 1;
        int ttg = kk & 3, kh = kk >> 2;
        aAddr[r] = t * 128 + (gg2 * 4 + ttg) * 4 + hi8 + 2 * kh;
    }
    #pragma unroll
    for (int r = 0; r < 2; r++) {
        int i = tid + r * 256;
        int n, kk;
        if (TRANSB) { n = i >> 3; kk = i & 7; }
        else        { kk = i >> 6; n = i & 63; }
        int j = n >> 3, gg2 = n & 7;
        int ttg = kk & 3, kh = kk >> 2;
        int ln = gg2 * 4 + ttg;
        bAddr[r] = j * 64 + ((2 * ln + 2 * j) & 63) + kh;
    }

    float c[2][4][4];
    #pragma unroll
    for (int i = 0; i < 2; i++)
        #pragma unroll
        for (int j = 0; j < 4; j++)
            #pragma unroll
            for (int r = 0; r < 4; r++) c[i][j][r] = 0.f;

    const int nsteps = Kdim >> 3;
    float ra[4], rb[2];

    // ---- prime buffer 0 ----
    {
        #pragma unroll
        for (int r = 0; r < 4; r++) {
            int i = tid + r * 256;
            int m = i >> 3, kk = i & 7;
            float v = A[(long long)(m0 + m) * Kdim + kk];
            unsigned h = f2tf(v);
            Ah[0][aAddr[r]] = h;
            Al[0][aAddr[r]] = f2tf(v - __uint_as_float(h));
        }
        #pragma unroll
        for (int r = 0; r < 2; r++) {
            int i = tid + r * 256;
            float v;
            if (TRANSB) { int n = i >> 3, kk = i & 7; v = Bm[(long long)(n0 + n) * Kdim + kk]; }
            else        { int kk = i >> 6, n = i & 63; v = Bm[(long long)kk * Ndim + n0 + n]; }
            unsigned h = f2tf(v);
            Bhs[0][bAddr[r]] = h;
            Bls[0][bAddr[r]] = f2tf(v - __uint_as_float(h));
        }
    }
    __syncthreads();

    int buf = 0;
    for (int s = 0; s < nsteps; s++) {
        const int ktn = (s + 1) << 3;
        if (s + 1 < nsteps) {
            #pragma unroll
            for (int r = 0; r < 4; r++) {
                int i = tid + r * 256;
                int m = i >> 3, kk = i & 7;
                ra[r] = A[(long long)(m0 + m) * Kdim + ktn + kk];
            }
            #pragma unroll
            for (int r = 0; r < 2; r++) {
                int i = tid + r * 256;
                if (TRANSB) { int n = i >> 3, kk = i & 7; rb[r] = Bm[(long long)(n0 + n) * Kdim + ktn + kk]; }
                else        { int kk = i >> 6, n = i & 63; rb[r] = Bm[(long long)(ktn + kk) * Ndim + n0 + n]; }
            }
        }

        // ---- compute on buf: vectorized fragment loads ----
        {
            unsigned ah[2][4], al[2][4];
            #pragma unroll
            for (int i = 0; i < 2; i++) {
                int base = (wm * 2 + i) * 128 + lane * 4;
                uint4 vh = *(const uint4*)&Ah[buf][base];
                uint4 vl = *(const uint4*)&Al[buf][base];
                ah[i][0] = vh.x; ah[i][1] = vh.y; ah[i][2] = vh.z; ah[i][3] = vh.w;
                al[i][0] = vl.x; al[i][1] = vl.y; al[i][2] = vl.z; al[i][3] = vl.w;
            }
            unsigned bh[4][2], bl[4][2];
            #pragma unroll
            for (int j = 0; j < 4; j++) {
                int jt = wn * 4 + j;
                int base = jt * 64 + ((2 * lane + 2 * jt) & 63);
                uint2 vh = *(const uint2*)&Bhs[buf][base];
                uint2 vl = *(const uint2*)&Bls[buf][base];
                bh[j][0] = vh.x; bh[j][1] = vh.y;
                bl[j][0] = vl.x; bl[j][1] = vl.y;
            }
            #pragma unroll
            for (int i = 0; i < 2; i++)
                #pragma unroll
                for (int j = 0; j < 4; j++) {
                    mma_tf32(c[i][j], ah[i], bh[j]);
                    mma_tf32(c[i][j], ah[i], bl[j]);
                    mma_tf32(c[i][j], al[i], bh[j]);
                }
        }

        if (s + 1 < nsteps) {
            int nb = buf ^ 1;
            #pragma unroll
            for (int r = 0; r < 4; r++) {
                unsigned h = f2tf(ra[r]);
                Ah[nb][aAddr[r]] = h;
                Al[nb][aAddr[r]] = f2tf(ra[r] - __uint_as_float(h));
            }
            #pragma unroll
            for (int r = 0; r < 2; r++) {
                unsigned h = f2tf(rb[r]);
                Bhs[nb][bAddr[r]] = h;
                Bls[nb][bAddr[r]] = f2tf(rb[r] - __uint_as_float(h));
            }
            __syncthreads();
            buf = nb;
        }
    }

    // ---- epilogue ----
    #pragma unroll
    for (int i = 0; i < 2; i++) {
        #pragma unroll
        for (int j = 0; j < 4; j++) {
            int row0 = m0 + wm * 32 + i * 16 + g;
            int row1 = row0 + 8;
            int col  = n0 + wn * 32 + j * 8 + 2 * tg;
            float2 v0, v1;
            v0.x = alpha * c[i][j][0]; v0.y = alpha * c[i][j][1];
            v1.x = alpha * c[i][j][2]; v1.y = alpha * c[i][j][3];
            if (bias) {
                float2 bb2 = *(const float2*)&bias[col];
                v0.x += bb2.x; v0.y += bb2.y;
                v1.x += bb2.x; v1.y += bb2.y;
            }
            if (betaI != 0.f) {
                if (row0 == col)     v0.x += betaI;
                if (row0 == col + 1) v0.y += betaI;
                if (row1 == col)     v1.x += betaI;
                if (row1 == col + 1) v1.y += betaI;
            }
            if (addp) {
                float2 a0 = *(const float2*)&addp[(long long)row0 * Ndim + col];
                float2 a1 = *(const float2*)&addp[(long long)row1 * Ndim + col];
                v0.x += addScale * a0.x; v0.y += addScale * a0.y;
                v1.x += addScale * a1.x; v1.y += addScale * a1.y;
            }
            if (relu) {
                v0.x = fmaxf(v0.x, 0.f); v0.y = fmaxf(v0.y, 0.f);
                v1.x = fmaxf(v1.x, 0.f); v1.y = fmaxf(v1.y, 0.f);
            }
            *(float2*)&C[(long long)row0 * Ndim + col] = v0;
            *(float2*)&C[(long long)row1 * Ndim + col] = v1;
        }
    }
}

static void gemm(const float* A, const float* Bm, float* C,
                 int M_, int N_, int K_,
                 long long sA, long long sB, long long sC, int batch, bool transB,
                 float alpha = 1.f, float betaI = 0.f,
                 const float* bias = nullptr, int relu = 0,
                 const float* addp = nullptr, float addScale = 0.f, long long sAdd = 0)
{
    dim3 grid(N_ / 64, M_ / 128, batch);
    if (transB) gemm_tc<true ><<<grid, 256>>>(A, Bm, C, M_, N_, K_, sA, sB, sC, alpha, betaI, bias, relu, addp, addScale, sAdd);
    else        gemm_tc<false><<<grid, 256>>>(A, Bm, C, M_, N_, K_, sA, sB, sC, alpha, betaI, bias, relu, addp, addScale, sAdd);
}

// ---------------- build h = [cls; gemm1_out] ----------------
__global__ void build_h_k(const float* __restrict__ cls)
{
    long long idx = (long long)blockIdx.x * 256 + threadIdx.x;
    int c = idx % EMB;
    long long bn = idx / EMB;
    int n = (int)(bn % NT);
    int b = (int)(bn / NT);
    g_h[idx] = (n == 0) ? cls[c] : g_attn[((long long)b * N0 + (n - 1)) * EMB + c];
}

// ---------------- layer norm + front zero-pad into g_x ----------------
__global__ void ln_pad_k(const float* __restrict__ gg, const float* __restrict__ bb)
{
    int n = blockIdx.x, b = blockIdx.y;
    int tid = threadIdx.x;
    float* out = g_x + ((long long)b * NPAD + n) * EMB;
    if (n < PADR) { out[tid] = 0.f; out[tid + 256] = 0.f; return; }
    const float* in = g_h + ((long long)b * NT + (n - PADR)) * EMB;
    float x0 = in[tid], x1 = in[tid + 256];
    __shared__ float sd[256];
    sd[tid] = x0 + x1; __syncthreads();
    for (int s = 128; s > 0; s >>= 1) { if (tid < s) sd[tid] += sd[tid + s]; __syncthreads(); }
    float mu = sd[0] * (1.f / EMB);
    __syncthreads();
    float d0 = x0 - mu, d1 = x1 - mu;
    sd[tid] = d0 * d0 + d1 * d1; __syncthreads();
    for (int s = 128; s > 0; s >>= 1) { if (tid < s) sd[tid] += sd[tid + s]; __syncthreads(); }
    float rs = rsqrtf(sd[0] * (1.f / EMB) + 1e-5f);
    out[tid]       = d0 * rs * gg[tid]       + bb[tid];
    out[tid + 256] = d1 * rs * gg[tid + 256] + bb[tid + 256];
}

// ---------------- split qkv into per-head q (scaled), k, v ----------------
__global__ void split_k()
{
    long long idx = (long long)blockIdx.x * 256 + threadIdx.x;
    float val = g_qkv[idx];
    int c = idx % (3 * EMB);
    long long bn = idx / (3 * EMB);
    int n = (int)(bn % NPAD);
    int b = (int)(bn / NPAD);
    int kind = c >> 9;
    int cc = c & 511;
    int hh = cc >> 6, d = cc & 63;
    long long dst = (((long long)(b * NH + hh)) * NPAD + n) * HD + d;
    if (kind == 0) g_q[dst] = val * QSCALE;
    else if (kind == 1) g_k[dst] = val;
    else g_v[dst] = val;
}

// ---------------- landmark means ----------------
__global__ void land_k(const float* __restrict__ src, float* __restrict__ dst)
{
    int d = threadIdx.x;
    int m = blockIdx.x;
    int bh = blockIdx.y;
    const float* p = src + (((long long)bh * NPAD) + (long long)m * LCH) * HD + d;
    float s = 0.f;
    #pragma unroll
    for (int i = 0; i < LCH; i++) s += p[(long long)i * HD];
    dst[(((long long)bh * NLM) + m) * HD + d] = s * (1.f / LCH);
}

// ---------------- row softmax ----------------
__global__ void softmax_k(float* __restrict__ x, int len)
{
    long long row = blockIdx.x;
    float* p = x + row * (long long)len;
    int tid = threadIdx.x;
    __shared__ float sd[256];
    float m = -1e30f;
    for (int i = tid; i < len; i += 256) m = fmaxf(m, p[i]);
    sd[tid] = m; __syncthreads();
    for (int s = 128; s > 0; s >>= 1) { if (tid < s) sd[tid] = fmaxf(sd[tid], sd[tid + s]); __syncthreads(); }
    m = sd[0]; __syncthreads();
    float sum = 0.f;
    for (int i = tid; i < len; i += 256) { float e = expf(p[i] - m); p[i] = e; sum += e; }
    sd[tid] = sum; __syncthreads();
    for (int s = 128; s > 0; s >>= 1) { if (tid < s) sd[tid] += sd[tid + s]; __syncthreads(); }
    float r = 1.f / sd[0];
    __syncthreads();
    for (int i = tid; i < len; i += 256) p[i] *= r;
}

// ---------------- pinv helpers ----------------
__global__ void reset_red_k() { if (threadIdx.x < 2) g_red[threadIdx.x] = 0u; }

__global__ void denom_k()
{
    int bh = blockIdx.x, tid = threadIdx.x;
    const float* mat = g_s2 + (long long)bh * NLM * NLM;
    float col = 0.f, rs = 0.f;
    for (int i = 0; i < NLM; i++) col += mat[i * NLM + tid];
    for (int j = 0; j < NLM; j++) rs  += mat[tid * NLM + j];
    __shared__ float sd[256];
    sd[tid] = rs; __syncthreads();
    for (int s = 128; s > 0; s >>= 1) { if (tid < s) sd[tid] = fmaxf(sd[tid], sd[tid + s]); __syncthreads(); }
    if (tid == 0) atomicMax(&g_red[0], __float_as_uint(sd[0]));
    __syncthreads();
    sd[tid] = col; __syncthreads();
    for (int s = 128; s > 0; s >>= 1) { if (tid < s) sd[tid] = fmaxf(sd[tid], sd[tid + s]); __syncthreads(); }
    if (tid == 0) atomicMax(&g_red[1], __float_as_uint(sd[0]));
}

__global__ void initz_k()
{
    long long idx = (long long)blockIdx.x * 256 + threadIdx.x;
    float rd = 1.f / (__uint_as_float(g_red[0]) * __uint_as_float(g_red[1]));
    int ij = (int)(idx & 65535);
    long long bh = idx >> 16;
    int i = ij >> 8, j = ij & 255;
    g_z[idx] = g_s2[(bh << 16) + (long long)j * NLM + i] * rd;
}

// ---------------- depthwise 33-tap residual conv on v, added to g_oh ----------------
__global__ void resconv_k(const float* __restrict__ w)
{
    int d = threadIdx.x;
    int n = blockIdx.x;
    int bh = blockIdx.y;
    int hh = bh % NH;
    __shared__ float sw[33];
    if (d < 33) sw[d] = w[hh * 33 + d];
    __syncthreads();
    const float* vp = g_v + ((long long)bh * NPAD) * HD + d;
    float acc = 0.f;
    #pragma unroll
    for (int j = 0; j < 33; j++) {
        int nn = n + j - 16;
        if (nn >= 0 && nn < NPAD) acc += sw[j] * vp[(long long)nn * HD];
    }
    g_oh[((long long)bh * NPAD + n) * HD + d] += acc;
}

// ---------------- merge heads ----------------
__global__ void merge_k()
{
    long long idx = (long long)blockIdx.x * 256 + threadIdx.x;
    int c = idx % EMB;
    long long bn = idx / EMB;
    int n = (int)(bn % NPAD);
    int b = (int)(bn / NPAD);
    int hh = c >> 6, d = c & 63;
    g_attn[idx] = g_oh[(((long long)(b * NH + hh)) * NPAD + n) * HD + d];
}

__global__ void addres_k()
{
    long long idx = (long long)blockIdx.x * 256 + threadIdx.x;
    int c = idx % EMB;
    long long bn = idx / EMB;
    int n = (int)(bn % NT);
    int b = (int)(bn / NT);
    g_h[idx] += g_y[(((long long)b * NPAD) + PADR + n) * EMB + c];
}

// ---------------- token<->image transposes ----------------
__global__ void tok2img_k()
{
    __shared__ float t[32][33];
    int b = blockIdx.z;
    int c0 = blockIdx.x * 32, p0 = blockIdx.y * 32;
    int tx = threadIdx.x, ty = threadIdx.y;
    #pragma unroll
    for (int j = 0; j < 32; j += 8)
        t[ty + j][tx] = g_h[((long long)b * NT + 1 + p0 + ty + j) * EMB + c0 + tx];
    __syncthreads();
    #pragma unroll
    for (int j = 0; j < 32; j += 8)
        g_cnn[((long long)b * EMB + c0 + ty + j) * (GRD * GRD) + p0 + tx] = t[tx][ty + j];
}

__global__ void img2tok_k()
{
    __shared__ float t[32][33];
    int b = blockIdx.z;
    int c0 = blockIdx.x * 32, p0 = blockIdx.y * 32;
    int tx = threadIdx.x, ty = threadIdx.y;
    #pragma unroll
    for (int j = 0; j < 32; j += 8)
        t[ty + j][tx] = g_cnn2[((long long)b * EMB + c0 + ty + j) * (GRD * GRD) + p0 + tx];
    __syncthreads();
    #pragma unroll
    for (int j = 0; j < 32; j += 8)
        g_h[((long long)b * NT + 1 + p0 + ty + j) * EMB + c0 + tx] = t[tx][ty + j];
}

// ---------------- fused 7x7 + 5x5 + 3x3 depthwise conv + identity ----------------
__global__ void dwconv_k(const float* __restrict__ w7, const float* __restrict__ b7,
                         const float* __restrict__ w5, const float* __restrict__ b5,
                         const float* __restrict__ w3, const float* __restrict__ b3)
{
    int bc = blockIdx.z;
    int c  = bc % EMB;
    const float* img = g_cnn + (long long)bc * GRD * GRD;
    __shared__ float tile[22][22];
    __shared__ float sw7[49], sw5[25], sw3[9];
    int tx = threadIdx.x, ty = threadIdx.y;
    int tid = ty * 16 + tx;
    if (tid < 49) sw7[tid] = w7[c * 49 + tid];
    if (tid < 25) sw5[tid] = w5[c * 25 + tid];
    if (tid < 9)  sw3[tid] = w3[c * 9  + tid];
    int ox0 = blockIdx.x * 16, oy0 = blockIdx.y * 16;
    for (int i = tid; i < 22 * 22; i += 256) {
        int yy = i / 22, xx = i % 22;
        int gy = oy0 - 3 + yy, gx = ox0 - 3 + xx;
        tile[yy][xx] = (gy >= 0 && gy < GRD && gx >= 0 && gx < GRD) ? img[gy * GRD + gx] : 0.f;
    }
    __syncthreads();
    float acc = tile[ty + 3][tx + 3] + b7[c] + b5[c] + b3[c];
    #pragma unroll
    for (int ky = 0; ky < 7; ky++)
        #pragma unroll
        for (int kx = 0; kx < 7; kx++)
            acc += sw7[ky * 7 + kx] * tile[ty + ky][tx + kx];
    #pragma unroll
    for (int ky = 0; ky < 5; ky++)
        #pragma unroll
        for (int kx = 0; kx < 5; kx++)
            acc += sw5[ky * 5 + kx] * tile[ty + 1 + ky][tx + 1 + kx];
    #pragma unroll
    for (int ky = 0; ky < 3; ky++)
        #pragma unroll
        for (int kx = 0; kx < 3; kx++)
            acc += sw3[ky * 3 + kx] * tile[ty + 2 + ky][tx + 2 + kx];
    g_cnn2[(long long)bc * GRD * GRD + (oy0 + ty) * GRD + ox0 + tx] = acc;
}

// ---------------- final LN(cls) -> logits -> softmax -> argmax ----------------
__global__ void head_k(const float* __restrict__ gg, const float* __restrict__ bb,
                       const float* __restrict__ W2, const float* __restrict__ b2,
                       float* __restrict__ out, int out_size)
{
    int tid = threadIdx.x; // 512
    __shared__ float sd[512];
    __shared__ float res[20];
    for (int b = 0; b < BB; b++) {
        float x = g_h[(long long)b * NT * EMB + tid];
        sd[tid] = x; __syncthreads();
        for (int s = 256; s > 0; s >>= 1) { if (tid < s) sd[tid] += sd[tid + s]; __syncthreads(); }
        float mu = sd[0] * (1.f / EMB); __syncthreads();
        float dx = x - mu;
        sd[tid] = dx * dx; __syncthreads();
        for (int s = 256; s > 0; s >>= 1) { if (tid < s) sd[tid] += sd[tid + s]; __syncthreads(); }
        float rs = rsqrtf(sd[0] * (1.f / EMB) + 1e-5f); __syncthreads();
        float xn = dx * rs * gg[tid] + bb[tid];
        sd[tid] = xn * W2[tid]; __syncthreads();
        for (int s = 256; s > 0; s >>= 1) { if (tid < s) sd[tid] += sd[tid + s]; __syncthreads(); }
        float l0 = sd[0] + b2[0]; __syncthreads();
        sd[tid] = xn * W2[EMB + tid]; __syncthreads();
        for (int s = 256; s > 0; s >>= 1) { if (tid < s) sd[tid] += sd[tid + s]; __syncthreads(); }
        float l1 = sd[0] + b2[1]; __syncthreads();
        if (tid == 0) {
            float mx = fmaxf(l0, l1);
            float e0 = expf(l0 - mx), e1 = expf(l1 - mx);
            float s = e0 + e1;
            res[b * 2]     = l0;
            res[b * 2 + 1] = l1;
            res[8 + b * 2]     = e0 / s;
            res[8 + b * 2 + 1] = e1 / s;
            res[16 + b] = (l1 > l0) ? 1.f : 0.f;
        }
        __syncthreads();
    }
    if (tid < 20 && tid < out_size) out[tid] = res[tid];
}

// ---------------- host orchestration ----------------
#define SYM(p, s) do { void* _t = nullptr; cudaGetSymbolAddress(&_t, s); p = (float*)_t; } while (0)

static void run_attn(const float* ln_g, const float* ln_b, const float* Wqkv,
                     const float* Wo, const float* bo, const float* res)
{
    float *x_, *qkv_, *q_, *k_, *v_, *ql_, *kl_, *s1_, *s2_, *s3_;
    float *z_, *z2_, *t0_, *t1_, *t2_, *av_, *u_, *oh_, *attn_, *y_;
    SYM(x_, g_x); SYM(qkv_, g_qkv); SYM(q_, g_q); SYM(k_, g_k); SYM(v_, g_v);
    SYM(ql_, g_ql); SYM(kl_, g_kl); SYM(s1_, g_s1); SYM(s2_, g_s2); SYM(s3_, g_s3);
    SYM(z_, g_z); SYM(z2_, g_z2); SYM(t0_, g_t0); SYM(t1_, g_t1); SYM(t2_, g_t2);
    SYM(av_, g_av); SYM(u_, g_u); SYM(oh_, g_oh); SYM(attn_, g_attn); SYM(y_, g_y);

    ln_pad_k<<<dim3(NPAD, BB), 256>>>(ln_g, ln_b);
    gemm(x_, Wqkv, qkv_, BB * NPAD, 3 * EMB, EMB, 0, 0, 0, 1, true);
    split_k<<<(BB * NPAD * 3 * EMB) / 256, 256>>>();
    land_k<<<dim3(NLM, BB * NH), 64>>>(q_, ql_);
    land_k<<<dim3(NLM, BB * NH), 64>>>(k_, kl_);

    gemm(q_, kl_, s1_, NPAD, NLM, HD,
         (long long)NPAD * HD, (long long)NLM * HD, (long long)NPAD * NLM, BB * NH, true);
    softmax_k<<<BB * NH * NPAD, 256>>>(s1_, NLM);
    gemm(ql_, kl_, s2_, NLM, NLM, HD,
         (long long)NLM * HD, (long long)NLM * HD, (long long)NLM * NLM, BB * NH, true);
    softmax_k<<<BB * NH * NLM, 256>>>(s2_, NLM);
    gemm(ql_, k_, s3_, NLM, NPAD, HD,
         (long long)NLM * HD, (long long)NPAD * HD, (long long)NLM * NPAD, BB * NH, true);
    softmax_k<<<BB * NH * NLM, 256>>>(s3_, NPAD);

    reset_red_k<<<1, 32>>>();
    denom_k<<<BB * NH, 256>>>();
    initz_k<<<(BB * NH * NLM * NLM) / 256, 256>>>();

    // Newton iteration: z' = 0.25 z (13I - P(15I - P(7I - P))), P = s2@z
    // inner2 = P@P + 15I - 7P   (fused: alpha=1, betaI=15, add=P, addScale=-7)
    // inner3 = -(P@inner2) + 13I
    // z' = 0.25 z@inner3
    float* zi = z_;
    float* zo = z2_;
    for (int it = 0; it < 6; it++) {
        gemm(s2_, zi, t0_, NLM, NLM, NLM, 65536, 65536, 65536, BB * NH, false);
        gemm(t0_, t0_, t2_, NLM, NLM, NLM, 65536, 65536, 65536, BB * NH, false,
             1.f, 15.f, nullptr, 0, t0_, -7.f, 65536);
        gemm(t0_, t2_, t1_, NLM, NLM, NLM, 65536, 65536, 65536, BB * NH, false, -1.f, 13.f);
        gemm(zi, t1_, zo, NLM, NLM, NLM, 65536, 65536, 65536, BB * NH, false, 0.25f, 0.f);
        float* tmp = zi; zi = zo; zo = tmp;
    }

    gemm(s3_, v_, av_, NLM, HD, NPAD,
         (long long)NLM * NPAD, (long long)NPAD * HD, (long long)NLM * HD, BB * NH, false);
    gemm(zi, av_, u_, NLM, HD, NLM,
         65536, (long long)NLM * HD, (long long)NLM * HD, BB * NH, false);
    gemm(s1_, u_, oh_, NPAD, HD, NLM,
         (long long)NPAD * NLM, (long long)NLM * HD, (long long)NPAD * HD, BB * NH, false);

    resconv_k<<<dim3(NPAD, BB * NH), 64>>>(res);
    merge_k<<<(BB * NPAD * EMB) / 256, 256>>>();
    gemm(attn_, Wo, y_, BB * NPAD, EMB, EMB, 0, 0, 0, 1, true, 1.f, 0.f, bo, 0);
    addres_k<<<(BB * NT * EMB) / 256, 256>>>();
}

extern "C" void kernel_launch(void* const* d_in, const int* in_sizes, int n_in,
                              void* d_out, int out_size)
{
    const float* data  = (const float*)d_in[0];
    const float* W1    = (const float*)d_in[1];
    const float* b1    = (const float*)d_in[2];
    const float* cls   = (const float*)d_in[3];
    const float* ln1_g = (const float*)d_in[4];
    const float* ln1_b = (const float*)d_in[5];
    const float* Wqkv1 = (const float*)d_in[6];
    const float* Wo1   = (const float*)d_in[7];
    const float* bo1   = (const float*)d_in[8];
    const float* res1  = (const float*)d_in[9];
    const float* ln2_g = (const float*)d_in[10];
    const float* ln2_b = (const float*)d_in[11];
    const float* Wqkv2 = (const float*)d_in[12];
    const float* Wo2   = (const float*)d_in[13];
    const float* bo2   = (const float*)d_in[14];
    const float* res2  = (const float*)d_in[15];
    const float* pw7   = (const float*)d_in[16];
    const float* pb7   = (const float*)d_in[17];
    const float* pw5   = (const float*)d_in[18];
    const float* pb5   = (const float*)d_in[19];
    const float* pw3   = (const float*)d_in[20];
    const float* pb3   = (const float*)d_in[21];
    const float* lnf_g = (const float*)d_in[22];
    const float* lnf_b = (const float*)d_in[23];
    const float* W2    = (const float*)d_in[24];
    const float* b2    = (const float*)d_in[25];

    float* attn_;
    SYM(attn_, g_attn);

    // stage 1: h = relu(data @ W1^T + b1) -> g_attn, then prepend cls into g_h
    gemm(data, W1, attn_, BB * N0, EMB, C0, 0, 0, 0, 1, true, 1.f, 0.f, b1, 1);
    build_h_k<<<(BB * NT * EMB) / 256, 256>>>(cls);

    // stage 2: first Nystrom attention block (residual)
    run_attn(ln1_g, ln1_b, Wqkv1, Wo1, bo1, res1);

    // stage 3: PPEG conv block on the 64x64 token grid (cls row untouched)
    tok2img_k<<<dim3(EMB / 32, (GRD * GRD) / 32, BB), dim3(32, 8)>>>();
    dwconv_k<<<dim3(GRD / 16, GRD / 16, BB * EMB), dim3(16, 16)>>>(pw7, pb7, pw5, pb5, pw3, pb3);
    img2tok_k<<<dim3(EMB / 32, (GRD * GRD) / 32, BB), dim3(32, 8)>>>();

    // stage 4: second Nystrom attention block (residual)
    run_attn(ln2_g, ln2_b, Wqkv2, Wo2, bo2, res2);

    // stage 5: final LN on cls token + classification head
    head_k<<<1, 512>>>(lnf_g, lnf_b, W2, b2, (float*)d_out, out_size);
}

// round 10
// speedup vs baseline: 1.7871x; 1.1630x over previous
#include <cuda_runtime.h>
#include <math.h>

#define BB   4
#define N0   4096
#define C0   1536
#define EMB  512
#define NH   8
#define HD   64
#define NT   4097
#define NPAD 4352
#define PADR 255
#define NLM  256
#define LCH  17
#define GRD  64
#define QSCALE 0.125f

// ---------------- static device scratch (no allocations allowed) ----------------
__device__ float g_h   [BB*NT*EMB];
__device__ float g_x   [BB*NPAD*EMB];
__device__ float g_q   [BB*NH*NPAD*HD];
__device__ float g_k   [BB*NH*NPAD*HD];
__device__ float g_v   [BB*NH*NPAD*HD];
__device__ float g_ql  [BB*NH*NLM*HD];
__device__ float g_kl  [BB*NH*NLM*HD];
__device__ float g_s1  [(long long)BB*NH*NPAD*NLM];
__device__ float g_s2  [BB*NH*NLM*NLM];
__device__ float g_s3  [(long long)BB*NH*NLM*NPAD];
__device__ float g_z   [BB*NH*NLM*NLM];
__device__ float g_z2  [BB*NH*NLM*NLM];
__device__ float g_t0  [BB*NH*NLM*NLM];
__device__ float g_t1  [BB*NH*NLM*NLM];
__device__ float g_t2  [BB*NH*NLM*NLM];
__device__ float g_av  [BB*NH*NLM*HD];
__device__ float g_u   [BB*NH*NLM*HD];
__device__ float g_attn[BB*NPAD*EMB];
__device__ float g_cnn [BB*EMB*GRD*GRD];
__device__ float g_cnn2[BB*EMB*GRD*GRD];
__device__ unsigned g_red[2];

// ---------------- tf32 helpers ----------------
__device__ __forceinline__ unsigned f2tf(float v)
{
    unsigned r;
    asm("cvt.rna.tf32.f32 %0, %1;" : "=r"(r) : "f"(v));
    return r;
}

__device__ __forceinline__ void mma_tf32(float c[4], const unsigned a[4], const unsigned b[2])
{
    asm volatile("mma.sync.aligned.m16n8k8.row.col.f32.tf32.tf32.f32 "
                 "{%0,%1,%2,%3}, {%4,%5,%6,%7}, {%8,%9}, {%0,%1,%2,%3};"
                 : "+f"(c[0]), "+f"(c[1]), "+f"(c[2]), "+f"(c[3])
                 : "r"(a[0]), "r"(a[1]), "r"(a[2]), "r"(a[3]), "r"(b[0]), "r"(b[1]));
}

// ---------------- batched 3xTF32 tensor-core GEMM, fragment-packed smem ----------------
// Epilogue modes:
//  0: C[row*Ndim+col]  (alpha, betaI*I, bias, addScale*Add, relu)
//  1: QKV split: C=q(out scaled), out2=k, out3=v, per-head layout
//  2: merge heads: C=g_attn, z=b*8+h, addr=((b*NPAD+row)*EMB + h*64 + col)
//  3: Wo+residual: C=g_h, row->(b,n); if n>=PADR: h[(b*NT+n-PADR)*EMB+col] += v
//  4: stage1 shift: C=g_h, row->(b,n); h[(b*NT+1+n)*EMB+col] = v
template<bool TRANSB>
__global__ void __launch_bounds__(256, 2)
gemm_tc(const float* __restrict__ A, const float* __restrict__ Bm,
        float* __restrict__ C,
        int Mdim, int Ndim, int Kdim,
        long long sA, long long sB, long long sC,
        float alpha, float betaI,
        const float* __restrict__ bias, int relu,
        const float* __restrict__ addp, float addScale, long long sAdd,
        int mode, float* __restrict__ out2, float* __restrict__ out3)
{
    __shared__ float    Af[2][1024];               // f32, fragment order
    __shared__ unsigned Bhs[2][512], Bls[2][512];  // tf32 hi/lo, fragment order

    const int zb = blockIdx.z;
    A  += (long long)zb * sA;
    Bm += (long long)zb * sB;
    C  += (long long)zb * sC;
    if (addp) addp += (long long)zb * sAdd;

    const int m0 = blockIdx.y * 128;
    const int n0 = blockIdx.x * 64;
    const int tid  = threadIdx.x;
    const int lane = tid & 31;
    const int warp = tid >> 5;
    const int wm = warp & 3;
    const int wn = warp >> 2;
    const int g  = lane >> 2;
    const int tg = lane & 3;

    // smem write addresses + global element offsets (constant per thread)
    int aAddr[4], bAddr[2];
    long long offA[4], offB[2];
    #pragma unroll
    for (int r = 0; r < 4; r++) {
        int i = tid + r * 256;
        int m = i >> 3, kk = i & 7;
        int t = m >> 4, gg2 = m & 7, hi8 = (m >> 3) & 1;
        int ttg = kk & 3, kh = kk >> 2;
        aAddr[r] = t * 128 + (gg2 * 4 + ttg) * 4 + hi8 + 2 * kh;
        offA[r]  = (long long)(m0 + m) * Kdim + kk;
    }
    #pragma unroll
    for (int r = 0; r < 2; r++) {
        int i = tid + r * 256;
        int n, kk;
        if (TRANSB) { n = i >> 3; kk = i & 7; offB[r] = (long long)(n0 + n) * Kdim + kk; }
        else        { kk = i >> 6; n = i & 63; offB[r] = (long long)kk * Ndim + n0 + n; }
        int j = n >> 3, gg2 = n & 7;
        int ttg = kk & 3, kh = kk >> 2;
        int ln = gg2 * 4 + ttg;
        bAddr[r] = j * 64 + ((2 * ln + 2 * j) & 63) + kh;
    }
    const long long bStep = TRANSB ? 8 : (long long)8 * Ndim;

    float c[2][4][4];
    #pragma unroll
    for (int i = 0; i < 2; i++)
        #pragma unroll
        for (int j = 0; j < 4; j++)
            #pragma unroll
            for (int r = 0; r < 4; r++) c[i][j][r] = 0.f;

    const int nsteps = Kdim >> 3;
    float ra[4], rb[2];

    // ---- prime buffer 0 ----
    {
        #pragma unroll
        for (int r = 0; r < 4; r++) Af[0][aAddr[r]] = A[offA[r]];
        #pragma unroll
        for (int r = 0; r < 2; r++) {
            float v = Bm[offB[r]];
            unsigned h = f2tf(v);
            Bhs[0][bAddr[r]] = h;
            Bls[0][bAddr[r]] = f2tf(v - __uint_as_float(h));
        }
    }
    __syncthreads();
    const float* Ap = A + 8;
    const float* Bp = Bm + bStep;

    int buf = 0;
    for (int s = 0; s < nsteps; s++) {
        if (s + 1 < nsteps) {
            #pragma unroll
            for (int r = 0; r < 4; r++) ra[r] = Ap[offA[r]];
            #pragma unroll
            for (int r = 0; r < 2; r++) rb[r] = Bp[offB[r]];
            Ap += 8;
            Bp += bStep;
        }

        // ---- compute on buf ----
        {
            unsigned ah[2][4], al[2][4];
            #pragma unroll
            for (int i = 0; i < 2; i++) {
                int base = (wm * 2 + i) * 128 + lane * 4;
                float4 v4 = *(const float4*)&Af[buf][base];
                float vv[4] = {v4.x, v4.y, v4.z, v4.w};
                #pragma unroll
                for (int r = 0; r < 4; r++) {
                    unsigned h = f2tf(vv[r]);
                    ah[i][r] = h;
                    al[i][r] = f2tf(vv[r] - __uint_as_float(h));
                }
            }
            unsigned bh[4][2], bl[4][2];
            #pragma unroll
            for (int j = 0; j < 4; j++) {
                int jt = wn * 4 + j;
                int base = jt * 64 + ((2 * lane + 2 * jt) & 63);
                uint2 vh = *(const uint2*)&Bhs[buf][base];
                uint2 vl = *(const uint2*)&Bls[buf][base];
                bh[j][0] = vh.x; bh[j][1] = vh.y;
                bl[j][0] = vl.x; bl[j][1] = vl.y;
            }
            #pragma unroll
            for (int i = 0; i < 2; i++)
                #pragma unroll
                for (int j = 0; j < 4; j++) {
                    mma_tf32(c[i][j], ah[i], bh[j]);
                    mma_tf32(c[i][j], ah[i], bl[j]);
                    mma_tf32(c[i][j], al[i], bh[j]);
                }
        }

        if (s + 1 < nsteps) {
            int nb = buf ^ 1;
            #pragma unroll
            for (int r = 0; r < 4; r++) Af[nb][aAddr[r]] = ra[r];
            #pragma unroll
            for (int r = 0; r < 2; r++) {
                unsigned h = f2tf(rb[r]);
                Bhs[nb][bAddr[r]] = h;
                Bls[nb][bAddr[r]] = f2tf(rb[r] - __uint_as_float(h));
            }
            __syncthreads();
            buf = nb;
        }
    }

    // ---- epilogue ----
    #pragma unroll
    for (int i = 0; i < 2; i++) {
        #pragma unroll
        for (int j = 0; j < 4; j++) {
            int row0 = m0 + wm * 32 + i * 16 + g;
            int row1 = row0 + 8;
            int col  = n0 + wn * 32 + j * 8 + 2 * tg;
            float2 v0, v1;
            v0.x = alpha * c[i][j][0]; v0.y = alpha * c[i][j][1];
            v1.x = alpha * c[i][j][2]; v1.y = alpha * c[i][j][3];
            if (bias) {
                float2 bb2 = *(const float2*)&bias[col];
                v0.x += bb2.x; v0.y += bb2.y;
                v1.x += bb2.x; v1.y += bb2.y;
            }
            if (betaI != 0.f) {
                if (row0 == col)     v0.x += betaI;
                if (row0 == col + 1) v0.y += betaI;
                if (row1 == col)     v1.x += betaI;
                if (row1 == col + 1) v1.y += betaI;
            }
            if (addp) {
                float2 a0 = *(const float2*)&addp[(long long)row0 * Ndim + col];
                float2 a1 = *(const float2*)&addp[(long long)row1 * Ndim + col];
                v0.x += addScale * a0.x; v0.y += addScale * a0.y;
                v1.x += addScale * a1.x; v1.y += addScale * a1.y;
            }
            if (relu) {
                v0.x = fmaxf(v0.x, 0.f); v0.y = fmaxf(v0.y, 0.f);
                v1.x = fmaxf(v1.x, 0.f); v1.y = fmaxf(v1.y, 0.f);
            }
            if (mode == 0) {
                *(float2*)&C[(long long)row0 * Ndim + col] = v0;
                *(float2*)&C[(long long)row1 * Ndim + col] = v1;
            } else if (mode == 1) {
                int kind = col >> 9, cc = col & 511;
                int hh = cc >> 6, d = cc & 63;
                float* dst = (kind == 0) ? C : (kind == 1) ? out2 : out3;
                float sc = (kind == 0) ? QSCALE : 1.f;
                int b0 = row0 / NPAD, n0r = row0 - b0 * NPAD;
                int b1r = row1 / NPAD, n1r = row1 - b1r * NPAD;
                float2 w0 = make_float2(v0.x * sc, v0.y * sc);
                float2 w1 = make_float2(v1.x * sc, v1.y * sc);
                *(float2*)&dst[(((long long)(b0 * NH + hh) * NPAD) + n0r) * HD + d] = w0;
                *(float2*)&dst[(((long long)(b1r * NH + hh) * NPAD) + n1r) * HD + d] = w1;
            } else if (mode == 2) {
                int b = zb >> 3, hh = zb & 7;
                *(float2*)&C[((long long)(b * NPAD + row0) * EMB) + hh * 64 + col] = v0;
                *(float2*)&C[((long long)(b * NPAD + row1) * EMB) + hh * 64 + col] = v1;
            } else if (mode == 3) {
                int b0 = row0 / NPAD, n0r = row0 - b0 * NPAD;
                int b1r = row1 / NPAD, n1r = row1 - b1r * NPAD;
                if (n0r >= PADR) {
                    long long a = ((long long)(b0 * NT + n0r - PADR) * EMB) + col;
                    float2 old = *(float2*)&C[a];
                    v0.x += old.x; v0.y += old.y;
                    *(float2*)&C[a] = v0;
                }
                if (n1r >= PADR) {
                    long long a = ((long long)(b1r * NT + n1r - PADR) * EMB) + col;
                    float2 old = *(float2*)&C[a];
                    v1.x += old.x; v1.y += old.y;
                    *(float2*)&C[a] = v1;
                }
            } else { // mode 4
                int b0 = row0 >> 12, n0r = row0 & 4095;
                int b1r = row1 >> 12, n1r = row1 & 4095;
                *(float2*)&C[((long long)(b0 * NT + 1 + n0r) * EMB) + col] = v0;
                *(float2*)&C[((long long)(b1r * NT + 1 + n1r) * EMB) + col] = v1;
            }
        }
    }
}

static void gemm(const float* A, const float* Bm, float* C,
                 int M_, int N_, int K_,
                 long long sA, long long sB, long long sC, int batch, bool transB,
                 float alpha = 1.f, float betaI = 0.f,
                 const float* bias = nullptr, int relu = 0,
                 const float* addp = nullptr, float addScale = 0.f, long long sAdd = 0,
                 int mode = 0, float* out2 = nullptr, float* out3 = nullptr)
{
    dim3 grid(N_ / 64, M_ / 128, batch);
    if (transB) gemm_tc<true ><<<grid, 256>>>(A, Bm, C, M_, N_, K_, sA, sB, sC, alpha, betaI, bias, relu, addp, addScale, sAdd, mode, out2, out3);
    else        gemm_tc<false><<<grid, 256>>>(A, Bm, C, M_, N_, K_, sA, sB, sC, alpha, betaI, bias, relu, addp, addScale, sAdd, mode, out2, out3);
}

// ---------------- cls rows ----------------
__global__ void cls_k(const float* __restrict__ cls)
{
    int c = threadIdx.x;
    #pragma unroll
    for (int b = 0; b < BB; b++)
        g_h[(long long)b * NT * EMB + c] = cls[c];
}

// ---------------- layer norm + front zero-pad into g_x ----------------
__global__ void ln_pad_k(const float* __restrict__ gg, const float* __restrict__ bb)
{
    int n = blockIdx.x, b = blockIdx.y;
    int tid = threadIdx.x;
    float* out = g_x + ((long long)b * NPAD + n) * EMB;
    if (n < PADR) { out[tid] = 0.f; out[tid + 256] = 0.f; return; }
    const float* in = g_h + ((long long)b * NT + (n - PADR)) * EMB;
    float x0 = in[tid], x1 = in[tid + 256];
    __shared__ float sd[256];
    sd[tid] = x0 + x1; __syncthreads();
    for (int s = 128; s > 0; s >>= 1) { if (tid < s) sd[tid] += sd[tid + s]; __syncthreads(); }
    float mu = sd[0] * (1.f / EMB);
    __syncthreads();
    float d0 = x0 - mu, d1 = x1 - mu;
    sd[tid] = d0 * d0 + d1 * d1; __syncthreads();
    for (int s = 128; s > 0; s >>= 1) { if (tid < s) sd[tid] += sd[tid + s]; __syncthreads(); }
    float rs = rsqrtf(sd[0] * (1.f / EMB) + 1e-5f);
    out[tid]       = d0 * rs * gg[tid]       + bb[tid];
    out[tid + 256] = d1 * rs * gg[tid + 256] + bb[tid + 256];
}

// ---------------- landmark means ----------------
__global__ void land_k(const float* __restrict__ src, float* __restrict__ dst)
{
    int d = threadIdx.x;
    int m = blockIdx.x;
    int bh = blockIdx.y;
    const float* p = src + (((long long)bh * NPAD) + (long long)m * LCH) * HD + d;
    float s = 0.f;
    #pragma unroll
    for (int i = 0; i < LCH; i++) s += p[(long long)i * HD];
    dst[(((long long)bh * NLM) + m) * HD + d] = s * (1.f / LCH);
}

// ---------------- single-pass softmax, len 256 (warp per row, 8 rows/block) ----------------
__global__ void softmax256_k(float* __restrict__ x)
{
    long long row = (long long)blockIdx.x * 8 + (threadIdx.x >> 5);
    int lane = threadIdx.x & 31;
    float* p = x + row * 256;
    float v[8];
    float m = -1e30f;
    #pragma unroll
    for (int i = 0; i < 8; i++) { v[i] = p[lane + 32 * i]; m = fmaxf(m, v[i]); }
    #pragma unroll
    for (int o = 16; o > 0; o >>= 1) m = fmaxf(m, __shfl_xor_sync(0xffffffffu, m, o));
    float s = 0.f;
    #pragma unroll
    for (int i = 0; i < 8; i++) { v[i] = expf(v[i] - m); s += v[i]; }
    #pragma unroll
    for (int o = 16; o > 0; o >>= 1) s += __shfl_xor_sync(0xffffffffu, s, o);
    float r = 1.f / s;
    #pragma unroll
    for (int i = 0; i < 8; i++) p[lane + 32 * i] = v[i] * r;
}

// ---------------- single-pass softmax, len 4352 (256 threads x 17) ----------------
__global__ void softmax4352_k(float* __restrict__ x)
{
    long long row = blockIdx.x;
    float* p = x + row * 4352;
    int tid = threadIdx.x;
    float v[17];
    float m = -1e30f;
    #pragma unroll
    for (int i = 0; i < 17; i++) { v[i] = p[tid + 256 * i]; m = fmaxf(m, v[i]); }
    __shared__ float sd[8];
    #pragma unroll
    for (int o = 16; o > 0; o >>= 1) m = fmaxf(m, __shfl_xor_sync(0xffffffffu, m, o));
    if ((tid & 31) == 0) sd[tid >> 5] = m;
    __syncthreads();
    if (tid < 8) {
        float t = sd[tid];
        #pragma unroll
        for (int o = 4; o > 0; o >>= 1) t = fmaxf(t, __shfl_xor_sync(0xffu, t, o));
        sd[tid] = t;
    }
    __syncthreads();
    m = sd[0];
    float s = 0.f;
    #pragma unroll
    for (int i = 0; i < 17; i++) { v[i] = expf(v[i] - m); s += v[i]; }
    __syncthreads();
    #pragma unroll
    for (int o = 16; o > 0; o >>= 1) s += __shfl_xor_sync(0xffffffffu, s, o);
    if ((tid & 31) == 0) sd[tid >> 5] = s;
    __syncthreads();
    if (tid < 8) {
        float t = sd[tid];
        #pragma unroll
        for (int o = 4; o > 0; o >>= 1) t += __shfl_xor_sync(0xffu, t, o);
        sd[tid] = t;
    }
    __syncthreads();
    float r = 1.f / sd[0];
    #pragma unroll
    for (int i = 0; i < 17; i++) p[tid + 256 * i] = v[i] * r;
}

// ---------------- pinv helpers ----------------
__global__ void reset_red_k() { if (threadIdx.x < 2) g_red[threadIdx.x] = 0u; }

__global__ void denom_k()
{
    int bh = blockIdx.x, tid = threadIdx.x;
    const float* mat = g_s2 + (long long)bh * NLM * NLM;
    float col = 0.f, rs = 0.f;
    for (int i = 0; i < NLM; i++) col += mat[i * NLM + tid];
    for (int j = 0; j < NLM; j++) rs  += mat[tid * NLM + j];
    __shared__ float sd[256];
    sd[tid] = rs; __syncthreads();
    for (int s = 128; s > 0; s >>= 1) { if (tid < s) sd[tid] = fmaxf(sd[tid], sd[tid + s]); __syncthreads(); }
    if (tid == 0) atomicMax(&g_red[0], __float_as_uint(sd[0]));
    __syncthreads();
    sd[tid] = col; __syncthreads();
    for (int s = 128; s > 0; s >>= 1) { if (tid < s) sd[tid] = fmaxf(sd[tid], sd[tid + s]); __syncthreads(); }
    if (tid == 0) atomicMax(&g_red[1], __float_as_uint(sd[0]));
}

__global__ void initz_k()
{
    long long idx = (long long)blockIdx.x * 256 + threadIdx.x;
    float rd = 1.f / (__uint_as_float(g_red[0]) * __uint_as_float(g_red[1]));
    int ij = (int)(idx & 65535);
    long long bh = idx >> 16;
    int i = ij >> 8, j = ij & 255;
    g_z[idx] = g_s2[(bh << 16) + (long long)j * NLM + i] * rd;
}

// ---------------- depthwise 33-tap residual conv on v, added into g_attn (merged layout) ----------------
__global__ void resconv_k(const float* __restrict__ w)
{
    int d = threadIdx.x;
    int n = blockIdx.x;
    int bh = blockIdx.y;
    int hh = bh & 7, b = bh >> 3;
    __shared__ float sw[33];
    if (d < 33) sw[d] = w[hh * 33 + d];
    __syncthreads();
    const float* vp = g_v + ((long long)bh * NPAD) * HD + d;
    float acc = 0.f;
    #pragma unroll
    for (int j = 0; j < 33; j++) {
        int nn = n + j - 16;
        if (nn >= 0 && nn < NPAD) acc += sw[j] * vp[(long long)nn * HD];
    }
    g_attn[((long long)(b * NPAD + n) * EMB) + hh * 64 + d] += acc;
}

// ---------------- token<->image transposes ----------------
__global__ void tok2img_k()
{
    __shared__ float t[32][33];
    int b = blockIdx.z;
    int c0 = blockIdx.x * 32, p0 = blockIdx.y * 32;
    int tx = threadIdx.x, ty = threadIdx.y;
    #pragma unroll
    for (int j = 0; j < 32; j += 8)
        t[ty + j][tx] = g_h[((long long)b * NT + 1 + p0 + ty + j) * EMB + c0 + tx];
    __syncthreads();
    #pragma unroll
    for (int j = 0; j < 32; j += 8)
        g_cnn[((long long)b * EMB + c0 + ty + j) * (GRD * GRD) + p0 + tx] = t[tx][ty + j];
}

__global__ void img2tok_k()
{
    __shared__ float t[32][33];
    int b = blockIdx.z;
    int c0 = blockIdx.x * 32, p0 = blockIdx.y * 32;
    int tx = threadIdx.x, ty = threadIdx.y;
    #pragma unroll
    for (int j = 0; j < 32; j += 8)
        t[ty + j][tx] = g_cnn2[((long long)b * EMB + c0 + ty + j) * (GRD * GRD) + p0 + tx];
    __syncthreads();
    #pragma unroll
    for (int j = 0; j < 32; j += 8)
        g_h[((long long)b * NT + 1 + p0 + ty + j) * EMB + c0 + tx] = t[tx][ty + j];
}

// ---------------- fused 7x7 + 5x5 + 3x3 depthwise conv + identity ----------------
__global__ void dwconv_k(const float* __restrict__ w7, const float* __restrict__ b7,
                         const float* __restrict__ w5, const float* __restrict__ b5,
                         const float* __restrict__ w3, const float* __restrict__ b3)
{
    int bc = blockIdx.z;
    int c  = bc % EMB;
    const float* img = g_cnn + (long long)bc * GRD * GRD;
    __shared__ float tile[22][22];
    __shared__ float sw7[49], sw5[25], sw3[9];
    int tx = threadIdx.x, ty = threadIdx.y;
    int tid = ty * 16 + tx;
    if (tid < 49) sw7[tid] = w7[c * 49 + tid];
    if (tid < 25) sw5[tid] = w5[c * 25 + tid];
    if (tid < 9)  sw3[tid] = w3[c * 9  + tid];
    int ox0 = blockIdx.x * 16, oy0 = blockIdx.y * 16;
    for (int i = tid; i < 22 * 22; i += 256) {
        int yy = i / 22, xx = i % 22;
        int gy = oy0 - 3 + yy, gx = ox0 - 3 + xx;
        tile[yy][xx] = (gy >= 0 && gy < GRD && gx >= 0 && gx < GRD) ? img[gy * GRD + gx] : 0.f;
    }
    __syncthreads();
    float acc = tile[ty + 3][tx + 3] + b7[c] + b5[c] + b3[c];
    #pragma unroll
    for (int ky = 0; ky < 7; ky++)
        #pragma unroll
        for (int kx = 0; kx < 7; kx++)
            acc += sw7[ky * 7 + kx] * tile[ty + ky][tx + kx];
    #pragma unroll
    for (int ky = 0; ky < 5; ky++)
        #pragma unroll
        for (int kx = 0; kx < 5; kx++)
            acc += sw5[ky * 5 + kx] * tile[ty + 1 + ky][tx + 1 + kx];
    #pragma unroll
    for (int ky = 0; ky < 3; ky++)
        #pragma unroll
        for (int kx = 0; kx < 3; kx++)
            acc += sw3[ky * 3 + kx] * tile[ty + 2 + ky][tx + 2 + kx];
    g_cnn2[(long long)bc * GRD * GRD + (oy0 + ty) * GRD + ox0 + tx] = acc;
}

// ---------------- final LN(cls) -> logits -> softmax -> argmax ----------------
__global__ void head_k(const float* __restrict__ gg, const float* __restrict__ bb,
                       const float* __restrict__ W2, const float* __restrict__ b2,
                       float* __restrict__ out, int out_size)
{
    int tid = threadIdx.x; // 512
    __shared__ float sd[512];
    __shared__ float res[20];
    for (int b = 0; b < BB; b++) {
        float x = g_h[(long long)b * NT * EMB + tid];
        sd[tid] = x; __syncthreads();
        for (int s = 256; s > 0; s >>= 1) { if (tid < s) sd[tid] += sd[tid + s]; __syncthreads(); }
        float mu = sd[0] * (1.f / EMB); __syncthreads();
        float dx = x - mu;
        sd[tid] = dx * dx; __syncthreads();
        for (int s = 256; s > 0; s >>= 1) { if (tid < s) sd[tid] += sd[tid + s]; __syncthreads(); }
        float rs = rsqrtf(sd[0] * (1.f / EMB) + 1e-5f); __syncthreads();
        float xn = dx * rs * gg[tid] + bb[tid];
        sd[tid] = xn * W2[tid]; __syncthreads();
        for (int s = 256; s > 0; s >>= 1) { if (tid < s) sd[tid] += sd[tid + s]; __syncthreads(); }
        float l0 = sd[0] + b2[0]; __syncthreads();
        sd[tid] = xn * W2[EMB + tid]; __syncthreads();
        for (int s = 256; s > 0; s >>= 1) { if (tid < s) sd[tid] += sd[tid + s]; __syncthreads(); }
        float l1 = sd[0] + b2[1]; __syncthreads();
        if (tid == 0) {
            float mx = fmaxf(l0, l1);
            float e0 = expf(l0 - mx), e1 = expf(l1 - mx);
            float s = e0 + e1;
            res[b * 2]     = l0;
            res[b * 2 + 1] = l1;
            res[8 + b * 2]     = e0 / s;
            res[8 + b * 2 + 1] = e1 / s;
            res[16 + b] = (l1 > l0) ? 1.f : 0.f;
        }
        __syncthreads();
    }
    if (tid < 20 && tid < out_size) out[tid] = res[tid];
}

// ---------------- host orchestration ----------------
#define SYM(p, s) do { void* _t = nullptr; cudaGetSymbolAddress(&_t, s); p = (float*)_t; } while (0)

static void run_attn(const float* ln_g, const float* ln_b, const float* Wqkv,
                     const float* Wo, const float* bo, const float* res)
{
    float *x_, *q_, *k_, *v_, *ql_, *kl_, *s1_, *s2_, *s3_;
    float *z_, *z2_, *t0_, *t1_, *t2_, *av_, *u_, *attn_, *h_;
    SYM(x_, g_x); SYM(q_, g_q); SYM(k_, g_k); SYM(v_, g_v);
    SYM(ql_, g_ql); SYM(kl_, g_kl); SYM(s1_, g_s1); SYM(s2_, g_s2); SYM(s3_, g_s3);
    SYM(z_, g_z); SYM(z2_, g_z2); SYM(t0_, g_t0); SYM(t1_, g_t1); SYM(t2_, g_t2);
    SYM(av_, g_av); SYM(u_, g_u); SYM(attn_, g_attn); SYM(h_, g_h);

    ln_pad_k<<<dim3(NPAD, BB), 256>>>(ln_g, ln_b);
    // QKV GEMM with fused head-split epilogue (mode 1)
    gemm(x_, Wqkv, q_, BB * NPAD, 3 * EMB, EMB, 0, 0, 0, 1, true,
         1.f, 0.f, nullptr, 0, nullptr, 0.f, 0, 1, k_, v_);
    land_k<<<dim3(NLM, BB * NH), 64>>>(q_, ql_);
    land_k<<<dim3(NLM, BB * NH), 64>>>(k_, kl_);

    gemm(q_, kl_, s1_, NPAD, NLM, HD,
         (long long)NPAD * HD, (long long)NLM * HD, (long long)NPAD * NLM, BB * NH, true);
    softmax256_k<<<BB * NH * NPAD / 8, 256>>>(s1_);
    gemm(ql_, kl_, s2_, NLM, NLM, HD,
         (long long)NLM * HD, (long long)NLM * HD, (long long)NLM * NLM, BB * NH, true);
    softmax256_k<<<BB * NH * NLM / 8, 256>>>(s2_);
    gemm(ql_, k_, s3_, NLM, NPAD, HD,
         (long long)NLM * HD, (long long)NPAD * HD, (long long)NLM * NPAD, BB * NH, true);
    softmax4352_k<<<BB * NH * NLM, 256>>>(s3_);

    reset_red_k<<<1, 32>>>();
    denom_k<<<BB * NH, 256>>>();
    initz_k<<<(BB * NH * NLM * NLM) / 256, 256>>>();

    // Newton: z' = 0.25 z (13I - P(15I - P(7I - P))), P = s2@z
    float* zi = z_;
    float* zo = z2_;
    for (int it = 0; it < 6; it++) {
        gemm(s2_, zi, t0_, NLM, NLM, NLM, 65536, 65536, 65536, BB * NH, false);
        gemm(t0_, t0_, t2_, NLM, NLM, NLM, 65536, 65536, 65536, BB * NH, false,
             1.f, 15.f, nullptr, 0, t0_, -7.f, 65536);
        gemm(t0_, t2_, t1_, NLM, NLM, NLM, 65536, 65536, 65536, BB * NH, false, -1.f, 13.f);
        gemm(zi, t1_, zo, NLM, NLM, NLM, 65536, 65536, 65536, BB * NH, false, 0.25f, 0.f);
        float* tmp = zi; zi = zo; zo = tmp;
    }

    gemm(s3_, v_, av_, NLM, HD, NPAD,
         (long long)NLM * NPAD, (long long)NPAD * HD, (long long)NLM * HD, BB * NH, false);
    gemm(zi, av_, u_, NLM, HD, NLM,
         65536, (long long)NLM * HD, (long long)NLM * HD, BB * NH, false);
    // oh GEMM with fused head-merge epilogue (mode 2) -> g_attn
    gemm(s1_, u_, attn_, NPAD, HD, NLM,
         (long long)NPAD * NLM, (long long)NLM * HD, 0, BB * NH, false,
         1.f, 0.f, nullptr, 0, nullptr, 0.f, 0, 2);

    resconv_k<<<dim3(NPAD, BB * NH), 64>>>(res);
    // Wo GEMM with fused residual add into g_h (mode 3)
    gemm(attn_, Wo, h_, BB * NPAD, EMB, EMB, 0, 0, 0, 1, true,
         1.f, 0.f, bo, 0, nullptr, 0.f, 0, 3);
}

extern "C" void kernel_launch(void* const* d_in, const int* in_sizes, int n_in,
                              void* d_out, int out_size)
{
    const float* data  = (const float*)d_in[0];
    const float* W1    = (const float*)d_in[1];
    const float* b1    = (const float*)d_in[2];
    const float* cls   = (const float*)d_in[3];
    const float* ln1_g = (const float*)d_in[4];
    const float* ln1_b = (const float*)d_in[5];
    const float* Wqkv1 = (const float*)d_in[6];
    const float* Wo1   = (const float*)d_in[7];
    const float* bo1   = (const float*)d_in[8];
    const float* res1  = (const float*)d_in[9];
    const float* ln2_g = (const float*)d_in[10];
    const float* ln2_b = (const float*)d_in[11];
    const float* Wqkv2 = (const float*)d_in[12];
    const float* Wo2   = (const float*)d_in[13];
    const float* bo2   = (const float*)d_in[14];
    const float* res2  = (const float*)d_in[15];
    const float* pw7   = (const float*)d_in[16];
    const float* pb7   = (const float*)d_in[17];
    const float* pw5   = (const float*)d_in[18];
    const float* pb5   = (const float*)d_in[19];
    const float* pw3   = (const float*)d_in[20];
    const float* pb3   = (const float*)d_in[21];
    const float* lnf_g = (const float*)d_in[22];
    const float* lnf_b = (const float*)d_in[23];
    const float* W2    = (const float*)d_in[24];
    const float* b2    = (const float*)d_in[25];

    float* h_;
    SYM(h_, g_h);

    // stage 1: h[1:] = relu(data @ W1^T + b1) (mode 4 shift), cls row separately
    gemm(data, W1, h_, BB * N0, EMB, C0, 0, 0, 0, 1, true,
         1.f, 0.f, b1, 1, nullptr, 0.f, 0, 4);
    cls_k<<<1, 512>>>(cls);

    // stage 2: first Nystrom attention block (residual)
    run_attn(ln1_g, ln1_b, Wqkv1, Wo1, bo1, res1);

    // stage 3: PPEG conv block on the 64x64 token grid (cls row untouched)
    tok2img_k<<<dim3(EMB / 32, (GRD * GRD) / 32, BB), dim3(32, 8)>>>();
    dwconv_k<<<dim3(GRD / 16, GRD / 16, BB * EMB), dim3(16, 16)>>>(pw7, pb7, pw5, pb5, pw3, pb3);
    img2tok_k<<<dim3(EMB / 32, (GRD * GRD) / 32, BB), dim3(32, 8)>>>();

    // stage 4: second Nystrom attention block (residual)
    run_attn(ln2_g, ln2_b, Wqkv2, Wo2, bo2, res2);

    // stage 5: final LN on cls token + classification head
    head_k<<<1, 512>>>(lnf_g, lnf_b, W2, b2, (float*)d_out, out_size);
}

// round 11
// speedup vs baseline: 1.8719x; 1.0475x over previous
#include <cuda_runtime.h>
#include <math.h>

#define BB   4
#define N0   4096
#define C0   1536
#define EMB  512
#define NH   8
#define HD   64
#define NT   4097
#define NPAD 4352
#define PADR 255
#define NLM  256
#define LCH  17
#define GRD  64
#define QSCALE 0.125f

// ---------------- static device scratch (no allocations allowed) ----------------
__device__ float g_h   [BB*NT*EMB];
__device__ float g_x   [BB*NPAD*EMB];
__device__ float g_q   [BB*NH*NPAD*HD];
__device__ float g_k   [BB*NH*NPAD*HD];
__device__ float g_v   [BB*NH*NPAD*HD];
__device__ float g_ql  [BB*NH*NLM*HD];
__device__ float g_kl  [BB*NH*NLM*HD];
__device__ float g_s1  [(long long)BB*NH*NPAD*NLM];
__device__ float g_s2  [BB*NH*NLM*NLM];
__device__ float g_s3  [(long long)BB*NH*NLM*NPAD];
__device__ float g_z   [BB*NH*NLM*NLM];
__device__ float g_z2  [BB*NH*NLM*NLM];
__device__ float g_t0  [BB*NH*NLM*NLM];
__device__ float g_t1  [BB*NH*NLM*NLM];
__device__ float g_t2  [BB*NH*NLM*NLM];
__device__ float g_av  [BB*NH*NLM*HD];
__device__ float g_u   [BB*NH*NLM*HD];
__device__ float g_attn[BB*NPAD*EMB];
__device__ float g_cnn [BB*EMB*GRD*GRD];
__device__ float g_cnn2[BB*EMB*GRD*GRD];
__device__ unsigned g_red[2];

// ---------------- tf32 helpers ----------------
__device__ __forceinline__ unsigned f2tf(float v)
{
    unsigned r;
    asm("cvt.rna.tf32.f32 %0, %1;" : "=r"(r) : "f"(v));
    return r;
}

__device__ __forceinline__ void mma_tf32(float c[4], const unsigned a[4], const unsigned b[2])
{
    asm volatile("mma.sync.aligned.m16n8k8.row.col.f32.tf32.tf32.f32 "
                 "{%0,%1,%2,%3}, {%4,%5,%6,%7}, {%8,%9}, {%0,%1,%2,%3};"
                 : "+f"(c[0]), "+f"(c[1]), "+f"(c[2]), "+f"(c[3])
                 : "r"(a[0]), "r"(a[1]), "r"(a[2]), "r"(a[3]), "r"(b[0]), "r"(b[1]));
}

// ---------------- batched 3xTF32 tensor-core GEMM, fragment-packed smem ----------------
// Block tile 128 x BN (BN = 64 or 128), 8 warps.
// BN=64:  warps 4(M) x 2(N), warp tile 32x32: 24 MMA / k8-step
// BN=128: warps 4(M) x 2(N), warp tile 32x64: 48 MMA / k8-step (B pair-packed + XOR swizzle)
// Epilogue modes:
//  0: C[row*Ndim+col]  (alpha, betaI*I, bias, addScale*Add, relu)
//  1: QKV split: C=q(out scaled), out2=k, out3=v, per-head layout
//  2: merge heads: C=g_attn
//  3: Wo+residual into g_h
//  4: stage1 shift into g_h
template<bool TRANSB, int BN>
__global__ void __launch_bounds__(256, 2)
gemm_tc(const float* __restrict__ A, const float* __restrict__ Bm,
        float* __restrict__ C,
        int Mdim, int Ndim, int Kdim,
        long long sA, long long sB, long long sC,
        float alpha, float betaI,
        const float* __restrict__ bias, int relu,
        const float* __restrict__ addp, float addScale, long long sAdd,
        int mode, float* __restrict__ out2, float* __restrict__ out3)
{
    constexpr int BWORDS = BN * 8;       // B words per buffer
    constexpr int BELEM  = BWORDS / 256; // per-thread B elements (2 or 4)
    constexpr int NTJ    = BN / 16;      // n8-tiles per warp (4 or 8)

    __shared__ float    Af[2][1024];
    __shared__ unsigned Bhs[2][BWORDS], Bls[2][BWORDS];

    const int zb = blockIdx.z;
    A  += (long long)zb * sA;
    Bm += (long long)zb * sB;
    C  += (long long)zb * sC;
    if (addp) addp += (long long)zb * sAdd;

    const int m0 = blockIdx.y * 128;
    const int n0 = blockIdx.x * BN;
    const int tid  = threadIdx.x;
    const int lane = tid & 31;
    const int warp = tid >> 5;
    const int wm = warp & 3;
    const int wn = warp >> 2;
    const int g  = lane >> 2;
    const int tg = lane & 3;

    int aAddr[4], bAddr[BELEM];
    long long offA[4], offB[BELEM];
    #pragma unroll
    for (int r = 0; r < 4; r++) {
        int i = tid + r * 256;
        int m = i >> 3, kk = i & 7;
        int t = m >> 4, gg2 = m & 7, hi8 = (m >> 3) & 1;
        int ttg = kk & 3, kh = kk >> 2;
        aAddr[r] = t * 128 + (gg2 * 4 + ttg) * 4 + hi8 + 2 * kh;
        offA[r]  = (long long)(m0 + m) * Kdim + kk;
    }
    #pragma unroll
    for (int r = 0; r < BELEM; r++) {
        int i = tid + r * 256;
        int n, kk;
        if (TRANSB) { n = i >> 3; kk = i & 7; offB[r] = (long long)(n0 + n) * Kdim + kk; }
        else {
            if (BN == 64) { kk = i >> 6; n = i & 63; }
            else          { kk = i >> 7; n = i & 127; }
            offB[r] = (long long)kk * Ndim + n0 + n;
        }
        int j = n >> 3;
        int ln = (n & 7) * 4 + (kk & 3);
        int kh = kk >> 2;
        if (BN == 64) {
            bAddr[r] = j * 64 + ((2 * ln + 2 * j) & 63) + kh;
        } else {
            int p = j >> 1, q = j & 1;
            int base = p * 128 + 4 * ln;
            bAddr[r] = (base ^ ((base >> 3) & 0x1C)) + 2 * q + kh;
        }
    }
    const long long bStep = TRANSB ? 8 : (long long)8 * Ndim;

    float c[2][NTJ][4];
    #pragma unroll
    for (int i = 0; i < 2; i++)
        #pragma unroll
        for (int j = 0; j < NTJ; j++)
            #pragma unroll
            for (int r = 0; r < 4; r++) c[i][j][r] = 0.f;

    const int nsteps = Kdim >> 3;
    float ra[4], rb[BELEM];

    // ---- prime buffer 0 ----
    {
        #pragma unroll
        for (int r = 0; r < 4; r++) Af[0][aAddr[r]] = A[offA[r]];
        #pragma unroll
        for (int r = 0; r < BELEM; r++) {
            float v = Bm[offB[r]];
            unsigned h = f2tf(v);
            Bhs[0][bAddr[r]] = h;
            Bls[0][bAddr[r]] = f2tf(v - __uint_as_float(h));
        }
    }
    __syncthreads();
    const float* Ap = A + 8;
    const float* Bp = Bm + bStep;

    int buf = 0;
    for (int s = 0; s < nsteps; s++) {
        if (s + 1 < nsteps) {
            #pragma unroll
            for (int r = 0; r < 4; r++) ra[r] = Ap[offA[r]];
            #pragma unroll
            for (int r = 0; r < BELEM; r++) rb[r] = Bp[offB[r]];
            Ap += 8;
            Bp += bStep;
        }

        // ---- compute on buf ----
        {
            unsigned ah[2][4], al[2][4];
            #pragma unroll
            for (int i = 0; i < 2; i++) {
                int base = (wm * 2 + i) * 128 + lane * 4;
                float4 v4 = *(const float4*)&Af[buf][base];
                float vv[4] = {v4.x, v4.y, v4.z, v4.w};
                #pragma unroll
                for (int r = 0; r < 4; r++) {
                    unsigned h = f2tf(vv[r]);
                    ah[i][r] = h;
                    al[i][r] = f2tf(vv[r] - __uint_as_float(h));
                }
            }
            if (BN == 64) {
                #pragma unroll
                for (int j = 0; j < NTJ; j++) {
                    int jt = wn * 4 + j;
                    int base = jt * 64 + ((2 * lane + 2 * jt) & 63);
                    uint2 vh = *(const uint2*)&Bhs[buf][base];
                    uint2 vl = *(const uint2*)&Bls[buf][base];
                    unsigned bh[2] = {vh.x, vh.y};
                    unsigned bl[2] = {vl.x, vl.y};
                    #pragma unroll
                    for (int i = 0; i < 2; i++) {
                        mma_tf32(c[i][j], ah[i], bh);
                        mma_tf32(c[i][j], ah[i], bl);
                        mma_tf32(c[i][j], al[i], bh);
                    }
                }
            } else {
                #pragma unroll
                for (int p4 = 0; p4 < 4; p4++) {
                    int p = wn * 4 + p4;
                    int base = p * 128 + lane * 4;
                    base ^= (base >> 3) & 0x1C;
                    uint4 vh = *(const uint4*)&Bhs[buf][base];
                    uint4 vl = *(const uint4*)&Bls[buf][base];
                    unsigned bh0[2] = {vh.x, vh.y}, bh1[2] = {vh.z, vh.w};
                    unsigned bl0[2] = {vl.x, vl.y}, bl1[2] = {vl.z, vl.w};
                    #pragma unroll
                    for (int i = 0; i < 2; i++) {
                        mma_tf32(c[i][2 * p4],     ah[i], bh0);
                        mma_tf32(c[i][2 * p4],     ah[i], bl0);
                        mma_tf32(c[i][2 * p4],     al[i], bh0);
                        mma_tf32(c[i][2 * p4 + 1], ah[i], bh1);
                        mma_tf32(c[i][2 * p4 + 1], ah[i], bl1);
                        mma_tf32(c[i][2 * p4 + 1], al[i], bh1);
                    }
                }
            }
        }

        if (s + 1 < nsteps) {
            int nb = buf ^ 1;
            #pragma unroll
            for (int r = 0; r < 4; r++) Af[nb][aAddr[r]] = ra[r];
            #pragma unroll
            for (int r = 0; r < BELEM; r++) {
                unsigned h = f2tf(rb[r]);
                Bhs[nb][bAddr[r]] = h;
                Bls[nb][bAddr[r]] = f2tf(rb[r] - __uint_as_float(h));
            }
            __syncthreads();
            buf = nb;
        }
    }

    // ---- epilogue ----
    #pragma unroll
    for (int i = 0; i < 2; i++) {
        #pragma unroll
        for (int j = 0; j < NTJ; j++) {
            int row0 = m0 + wm * 32 + i * 16 + g;
            int row1 = row0 + 8;
            int col  = n0 + wn * (BN / 2) + j * 8 + 2 * tg;
            float2 v0, v1;
            v0.x = alpha * c[i][j][0]; v0.y = alpha * c[i][j][1];
            v1.x = alpha * c[i][j][2]; v1.y = alpha * c[i][j][3];
            if (bias) {
                float2 bb2 = *(const float2*)&bias[col];
                v0.x += bb2.x; v0.y += bb2.y;
                v1.x += bb2.x; v1.y += bb2.y;
            }
            if (betaI != 0.f) {
                if (row0 == col)     v0.x += betaI;
                if (row0 == col + 1) v0.y += betaI;
                if (row1 == col)     v1.x += betaI;
                if (row1 == col + 1) v1.y += betaI;
            }
            if (addp) {
                float2 a0 = *(const float2*)&addp[(long long)row0 * Ndim + col];
                float2 a1 = *(const float2*)&addp[(long long)row1 * Ndim + col];
                v0.x += addScale * a0.x; v0.y += addScale * a0.y;
                v1.x += addScale * a1.x; v1.y += addScale * a1.y;
            }
            if (relu) {
                v0.x = fmaxf(v0.x, 0.f); v0.y = fmaxf(v0.y, 0.f);
                v1.x = fmaxf(v1.x, 0.f); v1.y = fmaxf(v1.y, 0.f);
            }
            if (mode == 0) {
                *(float2*)&C[(long long)row0 * Ndim + col] = v0;
                *(float2*)&C[(long long)row1 * Ndim + col] = v1;
            } else if (mode == 1) {
                int kind = col >> 9, cc = col & 511;
                int hh = cc >> 6, d = cc & 63;
                float* dst = (kind == 0) ? C : (kind == 1) ? out2 : out3;
                float sc = (kind == 0) ? QSCALE : 1.f;
                int b0 = row0 / NPAD, n0r = row0 - b0 * NPAD;
                int b1r = row1 / NPAD, n1r = row1 - b1r * NPAD;
                float2 w0 = make_float2(v0.x * sc, v0.y * sc);
                float2 w1 = make_float2(v1.x * sc, v1.y * sc);
                *(float2*)&dst[(((long long)(b0 * NH + hh) * NPAD) + n0r) * HD + d] = w0;
                *(float2*)&dst[(((long long)(b1r * NH + hh) * NPAD) + n1r) * HD + d] = w1;
            } else if (mode == 2) {
                int b = zb >> 3, hh = zb & 7;
                *(float2*)&C[((long long)(b * NPAD + row0) * EMB) + hh * 64 + col] = v0;
                *(float2*)&C[((long long)(b * NPAD + row1) * EMB) + hh * 64 + col] = v1;
            } else if (mode == 3) {
                int b0 = row0 / NPAD, n0r = row0 - b0 * NPAD;
                int b1r = row1 / NPAD, n1r = row1 - b1r * NPAD;
                if (n0r >= PADR) {
                    long long a = ((long long)(b0 * NT + n0r - PADR) * EMB) + col;
                    float2 old = *(float2*)&C[a];
                    v0.x += old.x; v0.y += old.y;
                    *(float2*)&C[a] = v0;
                }
                if (n1r >= PADR) {
                    long long a = ((long long)(b1r * NT + n1r - PADR) * EMB) + col;
                    float2 old = *(float2*)&C[a];
                    v1.x += old.x; v1.y += old.y;
                    *(float2*)&C[a] = v1;
                }
            } else { // mode 4
                int b0 = row0 >> 12, n0r = row0 & 4095;
                int b1r = row1 >> 12, n1r = row1 & 4095;
                *(float2*)&C[((long long)(b0 * NT + 1 + n0r) * EMB) + col] = v0;
                *(float2*)&C[((long long)(b1r * NT + 1 + n1r) * EMB) + col] = v1;
            }
        }
    }
}

static void gemm(const float* A, const float* Bm, float* C,
                 int M_, int N_, int K_,
                 long long sA, long long sB, long long sC, int batch, bool transB,
                 float alpha = 1.f, float betaI = 0.f,
                 const float* bias = nullptr, int relu = 0,
                 const float* addp = nullptr, float addScale = 0.f, long long sAdd = 0,
                 int mode = 0, float* out2 = nullptr, float* out3 = nullptr)
{
    const bool big = (N_ % 128 == 0);
    dim3 grid(N_ / (big ? 128 : 64), M_ / 128, batch);
    if (big) {
        if (transB) gemm_tc<true, 128><<<grid, 256>>>(A, Bm, C, M_, N_, K_, sA, sB, sC, alpha, betaI, bias, relu, addp, addScale, sAdd, mode, out2, out3);
        else        gemm_tc<false,128><<<grid, 256>>>(A, Bm, C, M_, N_, K_, sA, sB, sC, alpha, betaI, bias, relu, addp, addScale, sAdd, mode, out2, out3);
    } else {
        if (transB) gemm_tc<true, 64><<<grid, 256>>>(A, Bm, C, M_, N_, K_, sA, sB, sC, alpha, betaI, bias, relu, addp, addScale, sAdd, mode, out2, out3);
        else        gemm_tc<false, 64><<<grid, 256>>>(A, Bm, C, M_, N_, K_, sA, sB, sC, alpha, betaI, bias, relu, addp, addScale, sAdd, mode, out2, out3);
    }
}

// ---------------- cls rows ----------------
__global__ void cls_k(const float* __restrict__ cls)
{
    int c = threadIdx.x;
    #pragma unroll
    for (int b = 0; b < BB; b++)
        g_h[(long long)b * NT * EMB + c] = cls[c];
}

// ---------------- layer norm + front zero-pad into g_x ----------------
__global__ void ln_pad_k(const float* __restrict__ gg, const float* __restrict__ bb)
{
    int n = blockIdx.x, b = blockIdx.y;
    int tid = threadIdx.x;
    float* out = g_x + ((long long)b * NPAD + n) * EMB;
    if (n < PADR) { out[tid] = 0.f; out[tid + 256] = 0.f; return; }
    const float* in = g_h + ((long long)b * NT + (n - PADR)) * EMB;
    float x0 = in[tid], x1 = in[tid + 256];
    __shared__ float sd[256];
    sd[tid] = x0 + x1; __syncthreads();
    for (int s = 128; s > 0; s >>= 1) { if (tid < s) sd[tid] += sd[tid + s]; __syncthreads(); }
    float mu = sd[0] * (1.f / EMB);
    __syncthreads();
    float d0 = x0 - mu, d1 = x1 - mu;
    sd[tid] = d0 * d0 + d1 * d1; __syncthreads();
    for (int s = 128; s > 0; s >>= 1) { if (tid < s) sd[tid] += sd[tid + s]; __syncthreads(); }
    float rs = rsqrtf(sd[0] * (1.f / EMB) + 1e-5f);
    out[tid]       = d0 * rs * gg[tid]       + bb[tid];
    out[tid + 256] = d1 * rs * gg[tid + 256] + bb[tid + 256];
}

// ---------------- landmark means ----------------
__global__ void land_k(const float* __restrict__ src, float* __restrict__ dst)
{
    int d = threadIdx.x;
    int m = blockIdx.x;
    int bh = blockIdx.y;
    const float* p = src + (((long long)bh * NPAD) + (long long)m * LCH) * HD + d;
    float s = 0.f;
    #pragma unroll
    for (int i = 0; i < LCH; i++) s += p[(long long)i * HD];
    dst[(((long long)bh * NLM) + m) * HD + d] = s * (1.f / LCH);
}

// ---------------- single-pass softmax, len 256 (warp per row, 8 rows/block) ----------------
__global__ void softmax256_k(float* __restrict__ x)
{
    long long row = (long long)blockIdx.x * 8 + (threadIdx.x >> 5);
    int lane = threadIdx.x & 31;
    float* p = x + row * 256;
    float v[8];
    float m = -1e30f;
    #pragma unroll
    for (int i = 0; i < 8; i++) { v[i] = p[lane + 32 * i]; m = fmaxf(m, v[i]); }
    #pragma unroll
    for (int o = 16; o > 0; o >>= 1) m = fmaxf(m, __shfl_xor_sync(0xffffffffu, m, o));
    float s = 0.f;
    #pragma unroll
    for (int i = 0; i < 8; i++) { v[i] = expf(v[i] - m); s += v[i]; }
    #pragma unroll
    for (int o = 16; o > 0; o >>= 1) s += __shfl_xor_sync(0xffffffffu, s, o);
    float r = 1.f / s;
    #pragma unroll
    for (int i = 0; i < 8; i++) p[lane + 32 * i] = v[i] * r;
}

// ---------------- single-pass softmax, len 4352 (256 threads x 17) ----------------
__global__ void softmax4352_k(float* __restrict__ x)
{
    long long row = blockIdx.x;
    float* p = x + row * 4352;
    int tid = threadIdx.x;
    float v[17];
    float m = -1e30f;
    #pragma unroll
    for (int i = 0; i < 17; i++) { v[i] = p[tid + 256 * i]; m = fmaxf(m, v[i]); }
    __shared__ float sd[8];
    #pragma unroll
    for (int o = 16; o > 0; o >>= 1) m = fmaxf(m, __shfl_xor_sync(0xffffffffu, m, o));
    if ((tid & 31) == 0) sd[tid >> 5] = m;
    __syncthreads();
    if (tid < 8) {
        float t = sd[tid];
        #pragma unroll
        for (int o = 4; o > 0; o >>= 1) t = fmaxf(t, __shfl_xor_sync(0xffu, t, o));
        sd[tid] = t;
    }
    __syncthreads();
    m = sd[0];
    float s = 0.f;
    #pragma unroll
    for (int i = 0; i < 17; i++) { v[i] = expf(v[i] - m); s += v[i]; }
    __syncthreads();
    #pragma unroll
    for (int o = 16; o > 0; o >>= 1) s += __shfl_xor_sync(0xffffffffu, s, o);
    if ((tid & 31) == 0) sd[tid >> 5] = s;
    __syncthreads();
    if (tid < 8) {
        float t = sd[tid];
        #pragma unroll
        for (int o = 4; o > 0; o >>= 1) t += __shfl_xor_sync(0xffu, t, o);
        sd[tid] = t;
    }
    __syncthreads();
    float r = 1.f / sd[0];
    #pragma unroll
    for (int i = 0; i < 17; i++) p[tid + 256 * i] = v[i] * r;
}

// ---------------- pinv helpers ----------------
__global__ void reset_red_k() { if (threadIdx.x < 2) g_red[threadIdx.x] = 0u; }

__global__ void denom_k()
{
    int bh = blockIdx.x, tid = threadIdx.x;
    const float* mat = g_s2 + (long long)bh * NLM * NLM;
    float col = 0.f, rs = 0.f;
    for (int i = 0; i < NLM; i++) col += mat[i * NLM + tid];
    for (int j = 0; j < NLM; j++) rs  += mat[tid * NLM + j];
    __shared__ float sd[256];
    sd[tid] = rs; __syncthreads();
    for (int s = 128; s > 0; s >>= 1) { if (tid < s) sd[tid] = fmaxf(sd[tid], sd[tid + s]); __syncthreads(); }
    if (tid == 0) atomicMax(&g_red[0], __float_as_uint(sd[0]));
    __syncthreads();
    sd[tid] = col; __syncthreads();
    for (int s = 128; s > 0; s >>= 1) { if (tid < s) sd[tid] = fmaxf(sd[tid], sd[tid + s]); __syncthreads(); }
    if (tid == 0) atomicMax(&g_red[1], __float_as_uint(sd[0]));
}

__global__ void initz_k()
{
    long long idx = (long long)blockIdx.x * 256 + threadIdx.x;
    float rd = 1.f / (__uint_as_float(g_red[0]) * __uint_as_float(g_red[1]));
    int ij = (int)(idx & 65535);
    long long bh = idx >> 16;
    int i = ij >> 8, j = ij & 255;
    g_z[idx] = g_s2[(bh << 16) + (long long)j * NLM + i] * rd;
}

// ---------------- depthwise 33-tap residual conv on v, added into g_attn (merged layout) ----------------
__global__ void resconv_k(const float* __restrict__ w)
{
    int d = threadIdx.x;
    int n = blockIdx.x;
    int bh = blockIdx.y;
    int hh = bh & 7, b = bh >> 3;
    __shared__ float sw[33];
    if (d < 33) sw[d] = w[hh * 33 + d];
    __syncthreads();
    const float* vp = g_v + ((long long)bh * NPAD) * HD + d;
    float acc = 0.f;
    #pragma unroll
    for (int j = 0; j < 33; j++) {
        int nn = n + j - 16;
        if (nn >= 0 && nn < NPAD) acc += sw[j] * vp[(long long)nn * HD];
    }
    g_attn[((long long)(b * NPAD + n) * EMB) + hh * 64 + d] += acc;
}

// ---------------- token<->image transposes ----------------
__global__ void tok2img_k()
{
    __shared__ float t[32][33];
    int b = blockIdx.z;
    int c0 = blockIdx.x * 32, p0 = blockIdx.y * 32;
    int tx = threadIdx.x, ty = threadIdx.y;
    #pragma unroll
    for (int j = 0; j < 32; j += 8)
        t[ty + j][tx] = g_h[((long long)b * NT + 1 + p0 + ty + j) * EMB + c0 + tx];
    __syncthreads();
    #pragma unroll
    for (int j = 0; j < 32; j += 8)
        g_cnn[((long long)b * EMB + c0 + ty + j) * (GRD * GRD) + p0 + tx] = t[tx][ty + j];
}

__global__ void img2tok_k()
{
    __shared__ float t[32][33];
    int b = blockIdx.z;
    int c0 = blockIdx.x * 32, p0 = blockIdx.y * 32;
    int tx = threadIdx.x, ty = threadIdx.y;
    #pragma unroll
    for (int j = 0; j < 32; j += 8)
        t[ty + j][tx] = g_cnn2[((long long)b * EMB + c0 + ty + j) * (GRD * GRD) + p0 + tx];
    __syncthreads();
    #pragma unroll
    for (int j = 0; j < 32; j += 8)
        g_h[((long long)b * NT + 1 + p0 + ty + j) * EMB + c0 + tx] = t[tx][ty + j];
}

// ---------------- fused 7x7 + 5x5 + 3x3 depthwise conv + identity ----------------
__global__ void dwconv_k(const float* __restrict__ w7, const float* __restrict__ b7,
                         const float* __restrict__ w5, const float* __restrict__ b5,
                         const float* __restrict__ w3, const float* __restrict__ b3)
{
    int bc = blockIdx.z;
    int c  = bc % EMB;
    const float* img = g_cnn + (long long)bc * GRD * GRD;
    __shared__ float tile[22][22];
    __shared__ float sw7[49], sw5[25], sw3[9];
    int tx = threadIdx.x, ty = threadIdx.y;
    int tid = ty * 16 + tx;
    if (tid < 49) sw7[tid] = w7[c * 49 + tid];
    if (tid < 25) sw5[tid] = w5[c * 25 + tid];
    if (tid < 9)  sw3[tid] = w3[c * 9  + tid];
    int ox0 = blockIdx.x * 16, oy0 = blockIdx.y * 16;
    for (int i = tid; i < 22 * 22; i += 256) {
        int yy = i / 22, xx = i % 22;
        int gy = oy0 - 3 + yy, gx = ox0 - 3 + xx;
        tile[yy][xx] = (gy >= 0 && gy < GRD && gx >= 0 && gx < GRD) ? img[gy * GRD + gx] : 0.f;
    }
    __syncthreads();
    float acc = tile[ty + 3][tx + 3] + b7[c] + b5[c] + b3[c];
    #pragma unroll
    for (int ky = 0; ky < 7; ky++)
        #pragma unroll
        for (int kx = 0; kx < 7; kx++)
            acc += sw7[ky * 7 + kx] * tile[ty + ky][tx + kx];
    #pragma unroll
    for (int ky = 0; ky < 5; ky++)
        #pragma unroll
        for (int kx = 0; kx < 5; kx++)
            acc += sw5[ky * 5 + kx] * tile[ty + 1 + ky][tx + 1 + kx];
    #pragma unroll
    for (int ky = 0; ky < 3; ky++)
        #pragma unroll
        for (int kx = 0; kx < 3; kx++)
            acc += sw3[ky * 3 + kx] * tile[ty + 2 + ky][tx + 2 + kx];
    g_cnn2[(long long)bc * GRD * GRD + (oy0 + ty) * GRD + ox0 + tx] = acc;
}

// ---------------- final LN(cls) -> logits -> softmax -> argmax ----------------
__global__ void head_k(const float* __restrict__ gg, const float* __restrict__ bb,
                       const float* __restrict__ W2, const float* __restrict__ b2,
                       float* __restrict__ out, int out_size)
{
    int tid = threadIdx.x; // 512
    __shared__ float sd[512];
    __shared__ float res[20];
    for (int b = 0; b < BB; b++) {
        float x = g_h[(long long)b * NT * EMB + tid];
        sd[tid] = x; __syncthreads();
        for (int s = 256; s > 0; s >>= 1) { if (tid < s) sd[tid] += sd[tid + s]; __syncthreads(); }
        float mu = sd[0] * (1.f / EMB); __syncthreads();
        float dx = x - mu;
        sd[tid] = dx * dx; __syncthreads();
        for (int s = 256; s > 0; s >>= 1) { if (tid < s) sd[tid] += sd[tid + s]; __syncthreads(); }
        float rs = rsqrtf(sd[0] * (1.f / EMB) + 1e-5f); __syncthreads();
        float xn = dx * rs * gg[tid] + bb[tid];
        sd[tid] = xn * W2[tid]; __syncthreads();
        for (int s = 256; s > 0; s >>= 1) { if (tid < s) sd[tid] += sd[tid + s]; __syncthreads(); }
        float l0 = sd[0] + b2[0]; __syncthreads();
        sd[tid] = xn * W2[EMB + tid]; __syncthreads();
        for (int s = 256; s > 0; s >>= 1) { if (tid < s) sd[tid] += sd[tid + s]; __syncthreads(); }
        float l1 = sd[0] + b2[1]; __syncthreads();
        if (tid == 0) {
            float mx = fmaxf(l0, l1);
            float e0 = expf(l0 - mx), e1 = expf(l1 - mx);
            float s = e0 + e1;
            res[b * 2]     = l0;
            res[b * 2 + 1] = l1;
            res[8 + b * 2]     = e0 / s;
            res[8 + b * 2 + 1] = e1 / s;
            res[16 + b] = (l1 > l0) ? 1.f : 0.f;
        }
        __syncthreads();
    }
    if (tid < 20 && tid < out_size) out[tid] = res[tid];
}

// ---------------- host orchestration ----------------
#define SYM(p, s) do { void* _t = nullptr; cudaGetSymbolAddress(&_t, s); p = (float*)_t; } while (0)

static void run_attn(const float* ln_g, const float* ln_b, const float* Wqkv,
                     const float* Wo, const float* bo, const float* res)
{
    float *x_, *q_, *k_, *v_, *ql_, *kl_, *s1_, *s2_, *s3_;
    float *z_, *z2_, *t0_, *t1_, *t2_, *av_, *u_, *attn_, *h_;
    SYM(x_, g_x); SYM(q_, g_q); SYM(k_, g_k); SYM(v_, g_v);
    SYM(ql_, g_ql); SYM(kl_, g_kl); SYM(s1_, g_s1); SYM(s2_, g_s2); SYM(s3_, g_s3);
    SYM(z_, g_z); SYM(z2_, g_z2); SYM(t0_, g_t0); SYM(t1_, g_t1); SYM(t2_, g_t2);
    SYM(av_, g_av); SYM(u_, g_u); SYM(attn_, g_attn); SYM(h_, g_h);

    ln_pad_k<<<dim3(NPAD, BB), 256>>>(ln_g, ln_b);
    // QKV GEMM with fused head-split epilogue (mode 1)
    gemm(x_, Wqkv, q_, BB * NPAD, 3 * EMB, EMB, 0, 0, 0, 1, true,
         1.f, 0.f, nullptr, 0, nullptr, 0.f, 0, 1, k_, v_);
    land_k<<<dim3(NLM, BB * NH), 64>>>(q_, ql_);
    land_k<<<dim3(NLM, BB * NH), 64>>>(k_, kl_);

    gemm(q_, kl_, s1_, NPAD, NLM, HD,
         (long long)NPAD * HD, (long long)NLM * HD, (long long)NPAD * NLM, BB * NH, true);
    softmax256_k<<<BB * NH * NPAD / 8, 256>>>(s1_);
    gemm(ql_, kl_, s2_, NLM, NLM, HD,
         (long long)NLM * HD, (long long)NLM * HD, (long long)NLM * NLM, BB * NH, true);
    softmax256_k<<<BB * NH * NLM / 8, 256>>>(s2_);
    gemm(ql_, k_, s3_, NLM, NPAD, HD,
         (long long)NLM * HD, (long long)NPAD * HD, (long long)NLM * NPAD, BB * NH, true);
    softmax4352_k<<<BB * NH * NLM, 256>>>(s3_);

    reset_red_k<<<1, 32>>>();
    denom_k<<<BB * NH, 256>>>();
    initz_k<<<(BB * NH * NLM * NLM) / 256, 256>>>();

    // Newton: z' = 0.25 z (13I - P(15I - P(7I - P))), P = s2@z
    float* zi = z_;
    float* zo = z2_;
    for (int it = 0; it < 6; it++) {
        gemm(s2_, zi, t0_, NLM, NLM, NLM, 65536, 65536, 65536, BB * NH, false);
        gemm(t0_, t0_, t2_, NLM, NLM, NLM, 65536, 65536, 65536, BB * NH, false,
             1.f, 15.f, nullptr, 0, t0_, -7.f, 65536);
        gemm(t0_, t2_, t1_, NLM, NLM, NLM, 65536, 65536, 65536, BB * NH, false, -1.f, 13.f);
        gemm(zi, t1_, zo, NLM, NLM, NLM, 65536, 65536, 65536, BB * NH, false, 0.25f, 0.f);
        float* tmp = zi; zi = zo; zo = tmp;
    }

    gemm(s3_, v_, av_, NLM, HD, NPAD,
         (long long)NLM * NPAD, (long long)NPAD * HD, (long long)NLM * HD, BB * NH, false);
    gemm(zi, av_, u_, NLM, HD, NLM,
         65536, (long long)NLM * HD, (long long)NLM * HD, BB * NH, false);
    // oh GEMM with fused head-merge epilogue (mode 2) -> g_attn
    gemm(s1_, u_, attn_, NPAD, HD, NLM,
         (long long)NPAD * NLM, (long long)NLM * HD, 0, BB * NH, false,
         1.f, 0.f, nullptr, 0, nullptr, 0.f, 0, 2);

    resconv_k<<<dim3(NPAD, BB * NH), 64>>>(res);
    // Wo GEMM with fused residual add into g_h (mode 3)
    gemm(attn_, Wo, h_, BB * NPAD, EMB, EMB, 0, 0, 0, 1, true,
         1.f, 0.f, bo, 0, nullptr, 0.f, 0, 3);
}

extern "C" void kernel_launch(void* const* d_in, const int* in_sizes, int n_in,
                              void* d_out, int out_size)
{
    const float* data  = (const float*)d_in[0];
    const float* W1    = (const float*)d_in[1];
    const float* b1    = (const float*)d_in[2];
    const float* cls   = (const float*)d_in[3];
    const float* ln1_g = (const float*)d_in[4];
    const float* ln1_b = (const float*)d_in[5];
    const float* Wqkv1 = (const float*)d_in[6];
    const float* Wo1   = (const float*)d_in[7];
    const float* bo1   = (const float*)d_in[8];
    const float* res1  = (const float*)d_in[9];
    const float* ln2_g = (const float*)d_in[10];
    const float* ln2_b = (const float*)d_in[11];
    const float* Wqkv2 = (const float*)d_in[12];
    const float* Wo2   = (const float*)d_in[13];
    const float* bo2   = (const float*)d_in[14];
    const float* res2  = (const float*)d_in[15];
    const float* pw7   = (const float*)d_in[16];
    const float* pb7   = (const float*)d_in[17];
    const float* pw5   = (const float*)d_in[18];
    const float* pb5   = (const float*)d_in[19];
    const float* pw3   = (const float*)d_in[20];
    const float* pb3   = (const float*)d_in[21];
    const float* lnf_g = (const float*)d_in[22];
    const float* lnf_b = (const float*)d_in[23];
    const float* W2    = (const float*)d_in[24];
    const float* b2    = (const float*)d_in[25];

    float* h_;
    SYM(h_, g_h);

    // stage 1: h[1:] = relu(data @ W1^T + b1) (mode 4 shift), cls row separately
    gemm(data, W1, h_, BB * N0, EMB, C0, 0, 0, 0, 1, true,
         1.f, 0.f, b1, 1, nullptr, 0.f, 0, 4);
    cls_k<<<1, 512>>>(cls);

    // stage 2: first Nystrom attention block (residual)
    run_attn(ln1_g, ln1_b, Wqkv1, Wo1, bo1, res1);

    // stage 3: PPEG conv block on the 64x64 token grid (cls row untouched)
    tok2img_k<<<dim3(EMB / 32, (GRD * GRD) / 32, BB), dim3(32, 8)>>>();
    dwconv_k<<<dim3(GRD / 16, GRD / 16, BB * EMB), dim3(16, 16)>>>(pw7, pb7, pw5, pb5, pw3, pb3);
    img2tok_k<<<dim3(EMB / 32, (GRD * GRD) / 32, BB), dim3(32, 8)>>>();

    // stage 4: second Nystrom attention block (residual)
    run_attn(ln2_g, ln2_b, Wqkv2, Wo2, bo2, res2);

    // stage 5: final LN on cls token + classification head
    head_k<<<1, 512>>>(lnf_g, lnf_b, W2, b2, (float*)d_out, out_size);
}

// round 12
// speedup vs baseline: 2.0742x; 1.1081x over previous
#include <cuda_runtime.h>
#include <math.h>

#define BB   4
#define N0   4096
#define C0   1536
#define EMB  512
#define NH   8
#define HD   64
#define NT   4097
#define NPAD 4352
#define PADR 255
#define NLM  256
#define LCH  17
#define GRD  64
#define QSCALE 0.125f

// ---------------- static device scratch (no allocations allowed) ----------------
__device__ float g_h   [BB*NT*EMB];
__device__ float g_x   [BB*NPAD*EMB];
__device__ float g_q   [BB*NH*NPAD*HD];
__device__ float g_k   [BB*NH*NPAD*HD];
__device__ float g_v   [BB*NH*NPAD*HD];
__device__ float g_ql  [BB*NH*NLM*HD];
__device__ float g_kl  [BB*NH*NLM*HD];
__device__ float g_s1  [(long long)BB*NH*NPAD*NLM];
__device__ float g_s2  [BB*NH*NLM*NLM];
__device__ float g_s3  [(long long)BB*NH*NLM*NPAD];
__device__ float g_z   [BB*NH*NLM*NLM];
__device__ float g_z2  [BB*NH*NLM*NLM];
__device__ float g_t0  [BB*NH*NLM*NLM];
__device__ float g_t1  [BB*NH*NLM*NLM];
__device__ float g_t2  [BB*NH*NLM*NLM];
__device__ float g_av  [BB*NH*NLM*HD];
__device__ float g_u   [BB*NH*NLM*HD];
__device__ float g_attn[BB*NPAD*EMB];
__device__ float g_cnn [BB*EMB*GRD*GRD];
__device__ float g_cnn2[BB*EMB*GRD*GRD];
__device__ unsigned g_red[2];

// ---------------- tf32 helpers ----------------
__device__ __forceinline__ unsigned f2tf(float v)
{
    unsigned r;
    asm("cvt.rna.tf32.f32 %0, %1;" : "=r"(r) : "f"(v));
    return r;
}

__device__ __forceinline__ void mma_tf32(float c[4], const unsigned a[4], const unsigned b[2])
{
    asm volatile("mma.sync.aligned.m16n8k8.row.col.f32.tf32.tf32.f32 "
                 "{%0,%1,%2,%3}, {%4,%5,%6,%7}, {%8,%9}, {%0,%1,%2,%3};"
                 : "+f"(c[0]), "+f"(c[1]), "+f"(c[2]), "+f"(c[3])
                 : "r"(a[0]), "r"(a[1]), "r"(a[2]), "r"(a[3]), "r"(b[0]), "r"(b[1]));
}

// ---------------- batched 3xTF32 tensor-core GEMM, fragment-packed smem ----------------
// Block tile 128 x BN (BN = 64 or 128), 8 warps.
// Epilogue modes:
//  0: plain  1: QKV split  2: merge heads  3: Wo+residual  4: stage1 shift
template<bool TRANSB, int BN>
__global__ void __launch_bounds__(256, 2)
gemm_tc(const float* __restrict__ A, const float* __restrict__ Bm,
        float* __restrict__ C,
        int Mdim, int Ndim, int Kdim,
        long long sA, long long sB, long long sC,
        float alpha, float betaI,
        const float* __restrict__ bias, int relu,
        const float* __restrict__ addp, float addScale, long long sAdd,
        int mode, float* __restrict__ out2, float* __restrict__ out3)
{
    constexpr int BWORDS = BN * 8;
    constexpr int BELEM  = BWORDS / 256;
    constexpr int NTJ    = BN / 16;

    __shared__ float    Af[2][1024];
    __shared__ unsigned Bhs[2][BWORDS], Bls[2][BWORDS];

    const int zb = blockIdx.z;
    A  += (long long)zb * sA;
    Bm += (long long)zb * sB;
    C  += (long long)zb * sC;
    if (addp) addp += (long long)zb * sAdd;

    const int m0 = blockIdx.y * 128;
    const int n0 = blockIdx.x * BN;
    const int tid  = threadIdx.x;
    const int lane = tid & 31;
    const int warp = tid >> 5;
    const int wm = warp & 3;
    const int wn = warp >> 2;
    const int g  = lane >> 2;
    const int tg = lane & 3;

    int aAddr[4], bAddr[BELEM];
    long long offA[4], offB[BELEM];
    #pragma unroll
    for (int r = 0; r < 4; r++) {
        int i = tid + r * 256;
        int m = i >> 3, kk = i & 7;
        int t = m >> 4, gg2 = m & 7, hi8 = (m >> 3) & 1;
        int ttg = kk & 3, kh = kk >> 2;
        aAddr[r] = t * 128 + (gg2 * 4 + ttg) * 4 + hi8 + 2 * kh;
        offA[r]  = (long long)(m0 + m) * Kdim + kk;
    }
    #pragma unroll
    for (int r = 0; r < BELEM; r++) {
        int i = tid + r * 256;
        int n, kk;
        if (TRANSB) { n = i >> 3; kk = i & 7; offB[r] = (long long)(n0 + n) * Kdim + kk; }
        else {
            if (BN == 64) { kk = i >> 6; n = i & 63; }
            else          { kk = i >> 7; n = i & 127; }
            offB[r] = (long long)kk * Ndim + n0 + n;
        }
        int j = n >> 3;
        int ln = (n & 7) * 4 + (kk & 3);
        int kh = kk >> 2;
        if (BN == 64) {
            bAddr[r] = j * 64 + ((2 * ln + 2 * j) & 63) + kh;
        } else {
            int p = j >> 1, q = j & 1;
            int base = p * 128 + 4 * ln;
            bAddr[r] = (base ^ ((base >> 3) & 0x1C)) + 2 * q + kh;
        }
    }
    const long long bStep = TRANSB ? 8 : (long long)8 * Ndim;

    float c[2][NTJ][4];
    #pragma unroll
    for (int i = 0; i < 2; i++)
        #pragma unroll
        for (int j = 0; j < NTJ; j++)
            #pragma unroll
            for (int r = 0; r < 4; r++) c[i][j][r] = 0.f;

    const int nsteps = Kdim >> 3;
    float ra[4], rb[BELEM];

    {
        #pragma unroll
        for (int r = 0; r < 4; r++) Af[0][aAddr[r]] = A[offA[r]];
        #pragma unroll
        for (int r = 0; r < BELEM; r++) {
            float v = Bm[offB[r]];
            unsigned h = f2tf(v);
            Bhs[0][bAddr[r]] = h;
            Bls[0][bAddr[r]] = f2tf(v - __uint_as_float(h));
        }
    }
    __syncthreads();
    const float* Ap = A + 8;
    const float* Bp = Bm + bStep;

    int buf = 0;
    for (int s = 0; s < nsteps; s++) {
        if (s + 1 < nsteps) {
            #pragma unroll
            for (int r = 0; r < 4; r++) ra[r] = Ap[offA[r]];
            #pragma unroll
            for (int r = 0; r < BELEM; r++) rb[r] = Bp[offB[r]];
            Ap += 8;
            Bp += bStep;
        }

        {
            unsigned ah[2][4], al[2][4];
            #pragma unroll
            for (int i = 0; i < 2; i++) {
                int base = (wm * 2 + i) * 128 + lane * 4;
                float4 v4 = *(const float4*)&Af[buf][base];
                float vv[4] = {v4.x, v4.y, v4.z, v4.w};
                #pragma unroll
                for (int r = 0; r < 4; r++) {
                    unsigned h = f2tf(vv[r]);
                    ah[i][r] = h;
                    al[i][r] = f2tf(vv[r] - __uint_as_float(h));
                }
            }
            if (BN == 64) {
                #pragma unroll
                for (int j = 0; j < NTJ; j++) {
                    int jt = wn * 4 + j;
                    int base = jt * 64 + ((2 * lane + 2 * jt) & 63);
                    uint2 vh = *(const uint2*)&Bhs[buf][base];
                    uint2 vl = *(const uint2*)&Bls[buf][base];
                    unsigned bh[2] = {vh.x, vh.y};
                    unsigned bl[2] = {vl.x, vl.y};
                    #pragma unroll
                    for (int i = 0; i < 2; i++) {
                        mma_tf32(c[i][j], ah[i], bh);
                        mma_tf32(c[i][j], ah[i], bl);
                        mma_tf32(c[i][j], al[i], bh);
                    }
                }
            } else {
                #pragma unroll
                for (int p4 = 0; p4 < 4; p4++) {
                    int p = wn * 4 + p4;
                    int base = p * 128 + lane * 4;
                    base ^= (base >> 3) & 0x1C;
                    uint4 vh = *(const uint4*)&Bhs[buf][base];
                    uint4 vl = *(const uint4*)&Bls[buf][base];
                    unsigned bh0[2] = {vh.x, vh.y}, bh1[2] = {vh.z, vh.w};
                    unsigned bl0[2] = {vl.x, vl.y}, bl1[2] = {vl.z, vl.w};
                    #pragma unroll
                    for (int i = 0; i < 2; i++) {
                        mma_tf32(c[i][2 * p4],     ah[i], bh0);
                        mma_tf32(c[i][2 * p4],     ah[i], bl0);
                        mma_tf32(c[i][2 * p4],     al[i], bh0);
                        mma_tf32(c[i][2 * p4 + 1], ah[i], bh1);
                        mma_tf32(c[i][2 * p4 + 1], ah[i], bl1);
                        mma_tf32(c[i][2 * p4 + 1], al[i], bh1);
                    }
                }
            }
        }

        if (s + 1 < nsteps) {
            int nb = buf ^ 1;
            #pragma unroll
            for (int r = 0; r < 4; r++) Af[nb][aAddr[r]] = ra[r];
            #pragma unroll
            for (int r = 0; r < BELEM; r++) {
                unsigned h = f2tf(rb[r]);
                Bhs[nb][bAddr[r]] = h;
                Bls[nb][bAddr[r]] = f2tf(rb[r] - __uint_as_float(h));
            }
            __syncthreads();
            buf = nb;
        }
    }

    // ---- epilogue ----
    #pragma unroll
    for (int i = 0; i < 2; i++) {
        #pragma unroll
        for (int j = 0; j < NTJ; j++) {
            int row0 = m0 + wm * 32 + i * 16 + g;
            int row1 = row0 + 8;
            int col  = n0 + wn * (BN / 2) + j * 8 + 2 * tg;
            float2 v0, v1;
            v0.x = alpha * c[i][j][0]; v0.y = alpha * c[i][j][1];
            v1.x = alpha * c[i][j][2]; v1.y = alpha * c[i][j][3];
            if (bias) {
                float2 bb2 = *(const float2*)&bias[col];
                v0.x += bb2.x; v0.y += bb2.y;
                v1.x += bb2.x; v1.y += bb2.y;
            }
            if (betaI != 0.f) {
                if (row0 == col)     v0.x += betaI;
                if (row0 == col + 1) v0.y += betaI;
                if (row1 == col)     v1.x += betaI;
                if (row1 == col + 1) v1.y += betaI;
            }
            if (addp) {
                float2 a0 = *(const float2*)&addp[(long long)row0 * Ndim + col];
                float2 a1 = *(const float2*)&addp[(long long)row1 * Ndim + col];
                v0.x += addScale * a0.x; v0.y += addScale * a0.y;
                v1.x += addScale * a1.x; v1.y += addScale * a1.y;
            }
            if (relu) {
                v0.x = fmaxf(v0.x, 0.f); v0.y = fmaxf(v0.y, 0.f);
                v1.x = fmaxf(v1.x, 0.f); v1.y = fmaxf(v1.y, 0.f);
            }
            if (mode == 0) {
                *(float2*)&C[(long long)row0 * Ndim + col] = v0;
                *(float2*)&C[(long long)row1 * Ndim + col] = v1;
            } else if (mode == 1) {
                int kind = col >> 9, cc = col & 511;
                int hh = cc >> 6, d = cc & 63;
                float* dst = (kind == 0) ? C : (kind == 1) ? out2 : out3;
                float sc = (kind == 0) ? QSCALE : 1.f;
                int b0 = row0 / NPAD, n0r = row0 - b0 * NPAD;
                int b1r = row1 / NPAD, n1r = row1 - b1r * NPAD;
                float2 w0 = make_float2(v0.x * sc, v0.y * sc);
                float2 w1 = make_float2(v1.x * sc, v1.y * sc);
                *(float2*)&dst[(((long long)(b0 * NH + hh) * NPAD) + n0r) * HD + d] = w0;
                *(float2*)&dst[(((long long)(b1r * NH + hh) * NPAD) + n1r) * HD + d] = w1;
            } else if (mode == 2) {
                int b = zb >> 3, hh = zb & 7;
                *(float2*)&C[((long long)(b * NPAD + row0) * EMB) + hh * 64 + col] = v0;
                *(float2*)&C[((long long)(b * NPAD + row1) * EMB) + hh * 64 + col] = v1;
            } else if (mode == 3) {
                int b0 = row0 / NPAD, n0r = row0 - b0 * NPAD;
                int b1r = row1 / NPAD, n1r = row1 - b1r * NPAD;
                if (n0r >= PADR) {
                    long long a = ((long long)(b0 * NT + n0r - PADR) * EMB) + col;
                    float2 old = *(float2*)&C[a];
                    v0.x += old.x; v0.y += old.y;
                    *(float2*)&C[a] = v0;
                }
                if (n1r >= PADR) {
                    long long a = ((long long)(b1r * NT + n1r - PADR) * EMB) + col;
                    float2 old = *(float2*)&C[a];
                    v1.x += old.x; v1.y += old.y;
                    *(float2*)&C[a] = v1;
                }
            } else { // mode 4
                int b0 = row0 >> 12, n0r = row0 & 4095;
                int b1r = row1 >> 12, n1r = row1 & 4095;
                *(float2*)&C[((long long)(b0 * NT + 1 + n0r) * EMB) + col] = v0;
                *(float2*)&C[((long long)(b1r * NT + 1 + n1r) * EMB) + col] = v1;
            }
        }
    }
}

static void gemm(cudaStream_t st, const float* A, const float* Bm, float* C,
                 int M_, int N_, int K_,
                 long long sA, long long sB, long long sC, int batch, bool transB,
                 float alpha = 1.f, float betaI = 0.f,
                 const float* bias = nullptr, int relu = 0,
                 const float* addp = nullptr, float addScale = 0.f, long long sAdd = 0,
                 int mode = 0, float* out2 = nullptr, float* out3 = nullptr)
{
    const bool big = (N_ % 128 == 0);
    dim3 grid(N_ / (big ? 128 : 64), M_ / 128, batch);
    if (big) {
        if (transB) gemm_tc<true, 128><<<grid, 256, 0, st>>>(A, Bm, C, M_, N_, K_, sA, sB, sC, alpha, betaI, bias, relu, addp, addScale, sAdd, mode, out2, out3);
        else        gemm_tc<false,128><<<grid, 256, 0, st>>>(A, Bm, C, M_, N_, K_, sA, sB, sC, alpha, betaI, bias, relu, addp, addScale, sAdd, mode, out2, out3);
    } else {
        if (transB) gemm_tc<true, 64><<<grid, 256, 0, st>>>(A, Bm, C, M_, N_, K_, sA, sB, sC, alpha, betaI, bias, relu, addp, addScale, sAdd, mode, out2, out3);
        else        gemm_tc<false, 64><<<grid, 256, 0, st>>>(A, Bm, C, M_, N_, K_, sA, sB, sC, alpha, betaI, bias, relu, addp, addScale, sAdd, mode, out2, out3);
    }
}

// ---------------- cls rows ----------------
__global__ void cls_k(const float* __restrict__ cls)
{
    int c = threadIdx.x;
    #pragma unroll
    for (int b = 0; b < BB; b++)
        g_h[(long long)b * NT * EMB + c] = cls[c];
}

// ---------------- layer norm + front zero-pad into g_x ----------------
__global__ void ln_pad_k(const float* __restrict__ gg, const float* __restrict__ bb)
{
    int n = blockIdx.x, b = blockIdx.y;
    int tid = threadIdx.x;
    float* out = g_x + ((long long)b * NPAD + n) * EMB;
    if (n < PADR) { out[tid] = 0.f; out[tid + 256] = 0.f; return; }
    const float* in = g_h + ((long long)b * NT + (n - PADR)) * EMB;
    float x0 = in[tid], x1 = in[tid + 256];
    __shared__ float sd[256];
    sd[tid] = x0 + x1; __syncthreads();
    for (int s = 128; s > 0; s >>= 1) { if (tid < s) sd[tid] += sd[tid + s]; __syncthreads(); }
    float mu = sd[0] * (1.f / EMB);
    __syncthreads();
    float d0 = x0 - mu, d1 = x1 - mu;
    sd[tid] = d0 * d0 + d1 * d1; __syncthreads();
    for (int s = 128; s > 0; s >>= 1) { if (tid < s) sd[tid] += sd[tid + s]; __syncthreads(); }
    float rs = rsqrtf(sd[0] * (1.f / EMB) + 1e-5f);
    out[tid]       = d0 * rs * gg[tid]       + bb[tid];
    out[tid + 256] = d1 * rs * gg[tid + 256] + bb[tid + 256];
}

// ---------------- landmark means ----------------
__global__ void land_k(const float* __restrict__ src, float* __restrict__ dst)
{
    int d = threadIdx.x;
    int m = blockIdx.x;
    int bh = blockIdx.y;
    const float* p = src + (((long long)bh * NPAD) + (long long)m * LCH) * HD + d;
    float s = 0.f;
    #pragma unroll
    for (int i = 0; i < LCH; i++) s += p[(long long)i * HD];
    dst[(((long long)bh * NLM) + m) * HD + d] = s * (1.f / LCH);
}

// ---------------- single-pass softmax, len 256 ----------------
__global__ void softmax256_k(float* __restrict__ x)
{
    long long row = (long long)blockIdx.x * 8 + (threadIdx.x >> 5);
    int lane = threadIdx.x & 31;
    float* p = x + row * 256;
    float v[8];
    float m = -1e30f;
    #pragma unroll
    for (int i = 0; i < 8; i++) { v[i] = p[lane + 32 * i]; m = fmaxf(m, v[i]); }
    #pragma unroll
    for (int o = 16; o > 0; o >>= 1) m = fmaxf(m, __shfl_xor_sync(0xffffffffu, m, o));
    float s = 0.f;
    #pragma unroll
    for (int i = 0; i < 8; i++) { v[i] = expf(v[i] - m); s += v[i]; }
    #pragma unroll
    for (int o = 16; o > 0; o >>= 1) s += __shfl_xor_sync(0xffffffffu, s, o);
    float r = 1.f / s;
    #pragma unroll
    for (int i = 0; i < 8; i++) p[lane + 32 * i] = v[i] * r;
}

// ---------------- single-pass softmax, len 4352 ----------------
__global__ void softmax4352_k(float* __restrict__ x)
{
    long long row = blockIdx.x;
    float* p = x + row * 4352;
    int tid = threadIdx.x;
    float v[17];
    float m = -1e30f;
    #pragma unroll
    for (int i = 0; i < 17; i++) { v[i] = p[tid + 256 * i]; m = fmaxf(m, v[i]); }
    __shared__ float sd[8];
    #pragma unroll
    for (int o = 16; o > 0; o >>= 1) m = fmaxf(m, __shfl_xor_sync(0xffffffffu, m, o));
    if ((tid & 31) == 0) sd[tid >> 5] = m;
    __syncthreads();
    if (tid < 8) {
        float t = sd[tid];
        #pragma unroll
        for (int o = 4; o > 0; o >>= 1) t = fmaxf(t, __shfl_xor_sync(0xffu, t, o));
        sd[tid] = t;
    }
    __syncthreads();
    m = sd[0];
    float s = 0.f;
    #pragma unroll
    for (int i = 0; i < 17; i++) { v[i] = expf(v[i] - m); s += v[i]; }
    __syncthreads();
    #pragma unroll
    for (int o = 16; o > 0; o >>= 1) s += __shfl_xor_sync(0xffffffffu, s, o);
    if ((tid & 31) == 0) sd[tid >> 5] = s;
    __syncthreads();
    if (tid < 8) {
        float t = sd[tid];
        #pragma unroll
        for (int o = 4; o > 0; o >>= 1) t += __shfl_xor_sync(0xffu, t, o);
        sd[tid] = t;
    }
    __syncthreads();
    float r = 1.f / sd[0];
    #pragma unroll
    for (int i = 0; i < 17; i++) p[tid + 256 * i] = v[i] * r;
}

// ---------------- pinv helpers ----------------
__global__ void reset_red_k() { if (threadIdx.x < 2) g_red[threadIdx.x] = 0u; }

__global__ void denom_k()
{
    int bh = blockIdx.x, tid = threadIdx.x;
    const float* mat = g_s2 + (long long)bh * NLM * NLM;
    float col = 0.f, rs = 0.f;
    for (int i = 0; i < NLM; i++) col += mat[i * NLM + tid];
    for (int j = 0; j < NLM; j++) rs  += mat[tid * NLM + j];
    __shared__ float sd[256];
    sd[tid] = rs; __syncthreads();
    for (int s = 128; s > 0; s >>= 1) { if (tid < s) sd[tid] = fmaxf(sd[tid], sd[tid + s]); __syncthreads(); }
    if (tid == 0) atomicMax(&g_red[0], __float_as_uint(sd[0]));
    __syncthreads();
    sd[tid] = col; __syncthreads();
    for (int s = 128; s > 0; s >>= 1) { if (tid < s) sd[tid] = fmaxf(sd[tid], sd[tid + s]); __syncthreads(); }
    if (tid == 0) atomicMax(&g_red[1], __float_as_uint(sd[0]));
}

__global__ void initz_k()
{
    long long idx = (long long)blockIdx.x * 256 + threadIdx.x;
    float rd = 1.f / (__uint_as_float(g_red[0]) * __uint_as_float(g_red[1]));
    int ij = (int)(idx & 65535);
    long long bh = idx >> 16;
    int i = ij >> 8, j = ij & 255;
    g_z[idx] = g_s2[(bh << 16) + (long long)j * NLM + i] * rd;
}

// ---------------- depthwise 33-tap residual conv on v, added into g_attn ----------------
__global__ void resconv_k(const float* __restrict__ w)
{
    int d = threadIdx.x;
    int n = blockIdx.x;
    int bh = blockIdx.y;
    int hh = bh & 7, b = bh >> 3;
    __shared__ float sw[33];
    if (d < 33) sw[d] = w[hh * 33 + d];
    __syncthreads();
    const float* vp = g_v + ((long long)bh * NPAD) * HD + d;
    float acc = 0.f;
    #pragma unroll
    for (int j = 0; j < 33; j++) {
        int nn = n + j - 16;
        if (nn >= 0 && nn < NPAD) acc += sw[j] * vp[(long long)nn * HD];
    }
    g_attn[((long long)(b * NPAD + n) * EMB) + hh * 64 + d] += acc;
}

// ---------------- token<->image transposes ----------------
__global__ void tok2img_k()
{
    __shared__ float t[32][33];
    int b = blockIdx.z;
    int c0 = blockIdx.x * 32, p0 = blockIdx.y * 32;
    int tx = threadIdx.x, ty = threadIdx.y;
    #pragma unroll
    for (int j = 0; j < 32; j += 8)
        t[ty + j][tx] = g_h[((long long)b * NT + 1 + p0 + ty + j) * EMB + c0 + tx];
    __syncthreads();
    #pragma unroll
    for (int j = 0; j < 32; j += 8)
        g_cnn[((long long)b * EMB + c0 + ty + j) * (GRD * GRD) + p0 + tx] = t[tx][ty + j];
}

__global__ void img2tok_k()
{
    __shared__ float t[32][33];
    int b = blockIdx.z;
    int c0 = blockIdx.x * 32, p0 = blockIdx.y * 32;
    int tx = threadIdx.x, ty = threadIdx.y;
    #pragma unroll
    for (int j = 0; j < 32; j += 8)
        t[ty + j][tx] = g_cnn2[((long long)b * EMB + c0 + ty + j) * (GRD * GRD) + p0 + tx];
    __syncthreads();
    #pragma unroll
    for (int j = 0; j < 32; j += 8)
        g_h[((long long)b * NT + 1 + p0 + ty + j) * EMB + c0 + tx] = t[tx][ty + j];
}

// ---------------- fused 7x7 + 5x5 + 3x3 depthwise conv + identity ----------------
__global__ void dwconv_k(const float* __restrict__ w7, const float* __restrict__ b7,
                         const float* __restrict__ w5, const float* __restrict__ b5,
                         const float* __restrict__ w3, const float* __restrict__ b3)
{
    int bc = blockIdx.z;
    int c  = bc % EMB;
    const float* img = g_cnn + (long long)bc * GRD * GRD;
    __shared__ float tile[22][22];
    __shared__ float sw7[49], sw5[25], sw3[9];
    int tx = threadIdx.x, ty = threadIdx.y;
    int tid = ty * 16 + tx;
    if (tid < 49) sw7[tid] = w7[c * 49 + tid];
    if (tid < 25) sw5[tid] = w5[c * 25 + tid];
    if (tid < 9)  sw3[tid] = w3[c * 9  + tid];
    int ox0 = blockIdx.x * 16, oy0 = blockIdx.y * 16;
    for (int i = tid; i < 22 * 22; i += 256) {
        int yy = i / 22, xx = i % 22;
        int gy = oy0 - 3 + yy, gx = ox0 - 3 + xx;
        tile[yy][xx] = (gy >= 0 && gy < GRD && gx >= 0 && gx < GRD) ? img[gy * GRD + gx] : 0.f;
    }
    __syncthreads();
    float acc = tile[ty + 3][tx + 3] + b7[c] + b5[c] + b3[c];
    #pragma unroll
    for (int ky = 0; ky < 7; ky++)
        #pragma unroll
        for (int kx = 0; kx < 7; kx++)
            acc += sw7[ky * 7 + kx] * tile[ty + ky][tx + kx];
    #pragma unroll
    for (int ky = 0; ky < 5; ky++)
        #pragma unroll
        for (int kx = 0; kx < 5; kx++)
            acc += sw5[ky * 5 + kx] * tile[ty + 1 + ky][tx + 1 + kx];
    #pragma unroll
    for (int ky = 0; ky < 3; ky++)
        #pragma unroll
        for (int kx = 0; kx < 3; kx++)
            acc += sw3[ky * 3 + kx] * tile[ty + 2 + ky][tx + 2 + kx];
    g_cnn2[(long long)bc * GRD * GRD + (oy0 + ty) * GRD + ox0 + tx] = acc;
}

// ---------------- final LN(cls) -> logits -> softmax -> argmax ----------------
__global__ void head_k(const float* __restrict__ gg, const float* __restrict__ bb,
                       const float* __restrict__ W2, const float* __restrict__ b2,
                       float* __restrict__ out, int out_size)
{
    int tid = threadIdx.x; // 512
    __shared__ float sd[512];
    __shared__ float res[20];
    for (int b = 0; b < BB; b++) {
        float x = g_h[(long long)b * NT * EMB + tid];
        sd[tid] = x; __syncthreads();
        for (int s = 256; s > 0; s >>= 1) { if (tid < s) sd[tid] += sd[tid + s]; __syncthreads(); }
        float mu = sd[0] * (1.f / EMB); __syncthreads();
        float dx = x - mu;
        sd[tid] = dx * dx; __syncthreads();
        for (int s = 256; s > 0; s >>= 1) { if (tid < s) sd[tid] += sd[tid + s]; __syncthreads(); }
        float rs = rsqrtf(sd[0] * (1.f / EMB) + 1e-5f); __syncthreads();
        float xn = dx * rs * gg[tid] + bb[tid];
        sd[tid] = xn * W2[tid]; __syncthreads();
        for (int s = 256; s > 0; s >>= 1) { if (tid < s) sd[tid] += sd[tid + s]; __syncthreads(); }
        float l0 = sd[0] + b2[0]; __syncthreads();
        sd[tid] = xn * W2[EMB + tid]; __syncthreads();
        for (int s = 256; s > 0; s >>= 1) { if (tid < s) sd[tid] += sd[tid + s]; __syncthreads(); }
        float l1 = sd[0] + b2[1]; __syncthreads();
        if (tid == 0) {
            float mx = fmaxf(l0, l1);
            float e0 = expf(l0 - mx), e1 = expf(l1 - mx);
            float s = e0 + e1;
            res[b * 2]     = l0;
            res[b * 2 + 1] = l1;
            res[8 + b * 2]     = e0 / s;
            res[8 + b * 2 + 1] = e1 / s;
            res[16 + b] = (l1 > l0) ? 1.f : 0.f;
        }
        __syncthreads();
    }
    if (tid < 20 && tid < out_size) out[tid] = res[tid];
}

// ---------------- host orchestration ----------------
#define SYM(p, s) do { void* _t = nullptr; cudaGetSymbolAddress(&_t, s); p = (float*)_t; } while (0)

// stream/event objects created once at first call (host-side only, no device memory)
static cudaStream_t g_sB = nullptr;
static cudaEvent_t  g_evF[2], g_evJ[2];
static void ensure_streams()
{
    static bool done = false;
    if (!done) {
        cudaStreamCreateWithFlags(&g_sB, cudaStreamNonBlocking);
        for (int i = 0; i < 2; i++) {
            cudaEventCreateWithFlags(&g_evF[i], cudaEventDisableTiming);
            cudaEventCreateWithFlags(&g_evJ[i], cudaEventDisableTiming);
        }
        done = true;
    }
}

static void run_attn(int layer, const float* ln_g, const float* ln_b, const float* Wqkv,
                     const float* Wo, const float* bo, const float* res)
{
    float *x_, *q_, *k_, *v_, *ql_, *kl_, *s1_, *s2_, *s3_;
    float *z_, *z2_, *t0_, *t1_, *t2_, *av_, *u_, *attn_, *h_;
    SYM(x_, g_x); SYM(q_, g_q); SYM(k_, g_k); SYM(v_, g_v);
    SYM(ql_, g_ql); SYM(kl_, g_kl); SYM(s1_, g_s1); SYM(s2_, g_s2); SYM(s3_, g_s3);
    SYM(z_, g_z); SYM(z2_, g_z2); SYM(t0_, g_t0); SYM(t1_, g_t1); SYM(t2_, g_t2);
    SYM(av_, g_av); SYM(u_, g_u); SYM(attn_, g_attn); SYM(h_, g_h);

    cudaStream_t s0 = 0, sB = g_sB;

    ln_pad_k<<<dim3(NPAD, BB), 256, 0, s0>>>(ln_g, ln_b);
    gemm(s0, x_, Wqkv, q_, BB * NPAD, 3 * EMB, EMB, 0, 0, 0, 1, true,
         1.f, 0.f, nullptr, 0, nullptr, 0.f, 0, 1, k_, v_);
    land_k<<<dim3(NLM, BB * NH), 64, 0, s0>>>(q_, ql_);
    land_k<<<dim3(NLM, BB * NH), 64, 0, s0>>>(k_, kl_);

    // ---- fork: branch B (s2 + pinv chain) on sB ----
    cudaEventRecord(g_evF[layer], s0);
    cudaStreamWaitEvent(sB, g_evF[layer], 0);

    // branch B
    gemm(sB, ql_, kl_, s2_, NLM, NLM, HD,
         (long long)NLM * HD, (long long)NLM * HD, (long long)NLM * NLM, BB * NH, true);
    softmax256_k<<<BB * NH * NLM / 8, 256, 0, sB>>>(s2_);
    reset_red_k<<<1, 32, 0, sB>>>();
    denom_k<<<BB * NH, 256, 0, sB>>>();
    initz_k<<<(BB * NH * NLM * NLM) / 256, 256, 0, sB>>>();
    float* zi = z_;
    float* zo = z2_;
    for (int it = 0; it < 6; it++) {
        gemm(sB, s2_, zi, t0_, NLM, NLM, NLM, 65536, 65536, 65536, BB * NH, false);
        gemm(sB, t0_, t0_, t2_, NLM, NLM, NLM, 65536, 65536, 65536, BB * NH, false,
             1.f, 15.f, nullptr, 0, t0_, -7.f, 65536);
        gemm(sB, t0_, t2_, t1_, NLM, NLM, NLM, 65536, 65536, 65536, BB * NH, false, -1.f, 13.f);
        gemm(sB, zi, t1_, zo, NLM, NLM, NLM, 65536, 65536, 65536, BB * NH, false, 0.25f, 0.f);
        float* tmp = zi; zi = zo; zo = tmp;
    }
    cudaEventRecord(g_evJ[layer], sB);

    // branch A (origin stream)
    gemm(s0, q_, kl_, s1_, NPAD, NLM, HD,
         (long long)NPAD * HD, (long long)NLM * HD, (long long)NPAD * NLM, BB * NH, true);
    softmax256_k<<<BB * NH * NPAD / 8, 256, 0, s0>>>(s1_);
    gemm(s0, ql_, k_, s3_, NLM, NPAD, HD,
         (long long)NLM * HD, (long long)NPAD * HD, (long long)NLM * NPAD, BB * NH, true);
    softmax4352_k<<<BB * NH * NLM, 256, 0, s0>>>(s3_);
    gemm(s0, s3_, v_, av_, NLM, HD, NPAD,
         (long long)NLM * NPAD, (long long)NPAD * HD, (long long)NLM * HD, BB * NH, false);

    // ---- join ----
    cudaStreamWaitEvent(s0, g_evJ[layer], 0);

    gemm(s0, zi, av_, u_, NLM, HD, NLM,
         65536, (long long)NLM * HD, (long long)NLM * HD, BB * NH, false);
    gemm(s0, s1_, u_, attn_, NPAD, HD, NLM,
         (long long)NPAD * NLM, (long long)NLM * HD, 0, BB * NH, false,
         1.f, 0.f, nullptr, 0, nullptr, 0.f, 0, 2);

    resconv_k<<<dim3(NPAD, BB * NH), 64, 0, s0>>>(res);
    gemm(s0, attn_, Wo, h_, BB * NPAD, EMB, EMB, 0, 0, 0, 1, true,
         1.f, 0.f, bo, 0, nullptr, 0.f, 0, 3);
}

extern "C" void kernel_launch(void* const* d_in, const int* in_sizes, int n_in,
                              void* d_out, int out_size)
{
    ensure_streams();

    const float* data  = (const float*)d_in[0];
    const float* W1    = (const float*)d_in[1];
    const float* b1    = (const float*)d_in[2];
    const float* cls   = (const float*)d_in[3];
    const float* ln1_g = (const float*)d_in[4];
    const float* ln1_b = (const float*)d_in[5];
    const float* Wqkv1 = (const float*)d_in[6];
    const float* Wo1   = (const float*)d_in[7];
    const float* bo1   = (const float*)d_in[8];
    const float* res1  = (const float*)d_in[9];
    const float* ln2_g = (const float*)d_in[10];
    const float* ln2_b = (const float*)d_in[11];
    const float* Wqkv2 = (const float*)d_in[12];
    const float* Wo2   = (const float*)d_in[13];
    const float* bo2   = (const float*)d_in[14];
    const float* res2  = (const float*)d_in[15];
    const float* pw7   = (const float*)d_in[16];
    const float* pb7   = (const float*)d_in[17];
    const float* pw5   = (const float*)d_in[18];
    const float* pb5   = (const float*)d_in[19];
    const float* pw3   = (const float*)d_in[20];
    const float* pb3   = (const float*)d_in[21];
    const float* lnf_g = (const float*)d_in[22];
    const float* lnf_b = (const float*)d_in[23];
    const float* W2    = (const float*)d_in[24];
    const float* b2    = (const float*)d_in[25];

    float* h_;
    SYM(h_, g_h);

    // stage 1: h[1:] = relu(data @ W1^T + b1) (mode 4 shift), cls row separately
    gemm(0, data, W1, h_, BB * N0, EMB, C0, 0, 0, 0, 1, true,
         1.f, 0.f, b1, 1, nullptr, 0.f, 0, 4);
    cls_k<<<1, 512>>>(cls);

    // stage 2: first Nystrom attention block (residual)
    run_attn(0, ln1_g, ln1_b, Wqkv1, Wo1, bo1, res1);

    // stage 3: PPEG conv block on the 64x64 token grid (cls row untouched)
    tok2img_k<<<dim3(EMB / 32, (GRD * GRD) / 32, BB), dim3(32, 8)>>>();
    dwconv_k<<<dim3(GRD / 16, GRD / 16, BB * EMB), dim3(16, 16)>>>(pw7, pb7, pw5, pb5, pw3, pb3);
    img2tok_k<<<dim3(EMB / 32, (GRD * GRD) / 32, BB), dim3(32, 8)>>>();

    // stage 4: second Nystrom attention block (residual)
    run_attn(1, ln2_g, ln2_b, Wqkv2, Wo2, bo2, res2);

    // stage 5: final LN on cls token + classification head
    head_k<<<1, 512>>>(lnf_g, lnf_b, W2, b2, (float*)d_out, out_size);
}

// round 13
// speedup vs baseline: 2.1605x; 1.0416x over previous
#include <cuda_runtime.h>
#include <math.h>

#define BB   4
#define N0   4096
#define C0   1536
#define EMB  512
#define NH   8
#define HD   64
#define NT   4097
#define NPAD 4352
#define PADR 255
#define NLM  256
#define LCH  17
#define GRD  64
#define QSCALE 0.125f

// ---------------- static device scratch (no allocations allowed) ----------------
__device__ float g_h   [BB*NT*EMB];
__device__ float g_x   [BB*NPAD*EMB];
__device__ float g_q   [BB*NH*NPAD*HD];
__device__ float g_k   [BB*NH*NPAD*HD];
__device__ float g_v   [BB*NH*NPAD*HD];
__device__ float g_ql  [BB*NH*NLM*HD];
__device__ float g_kl  [BB*NH*NLM*HD];
__device__ float g_s1  [(long long)BB*NH*NPAD*NLM];
__device__ float g_s2  [BB*NH*NLM*NLM];
__device__ float g_s3  [(long long)BB*NH*NLM*NPAD];
__device__ float g_z   [BB*NH*NLM*NLM];
__device__ float g_z2  [BB*NH*NLM*NLM];
__device__ float g_t0  [BB*NH*NLM*NLM];
__device__ float g_t1  [BB*NH*NLM*NLM];
__device__ float g_t2  [BB*NH*NLM*NLM];
__device__ float g_av  [BB*NH*NLM*HD];
__device__ float g_u   [BB*NH*NLM*HD];
__device__ float g_attn[BB*NPAD*EMB];
__device__ float g_cnn [BB*EMB*GRD*GRD];
__device__ float g_cnn2[BB*EMB*GRD*GRD];
__device__ unsigned g_red[2];

// ---------------- tf32 helpers ----------------
// Bitmask hi/lo split: hi keeps the 10 mantissa bits the tensor core reads;
// lo = v - hi is exact in fp32 (HW truncates lo's extra bits: ~2^-21 rel contribution).
__device__ __forceinline__ void split_tf32(float v, unsigned& hi, unsigned& lo)
{
    hi = __float_as_uint(v) & 0xFFFFE000u;
    lo = __float_as_uint(v - __uint_as_float(hi));
}

__device__ __forceinline__ void mma_tf32(float c[4], const unsigned a[4], const unsigned b[2])
{
    asm volatile("mma.sync.aligned.m16n8k8.row.col.f32.tf32.tf32.f32 "
                 "{%0,%1,%2,%3}, {%4,%5,%6,%7}, {%8,%9}, {%0,%1,%2,%3};"
                 : "+f"(c[0]), "+f"(c[1]), "+f"(c[2]), "+f"(c[3])
                 : "r"(a[0]), "r"(a[1]), "r"(a[2]), "r"(a[3]), "r"(b[0]), "r"(b[1]));
}

// ---------------- batched 3xTF32 tensor-core GEMM, fragment-packed smem ----------------
// Block tile 128 x BN (BN = 64 or 128), 8 warps.
// Epilogue modes:
//  0: plain  1: QKV split  2: merge heads  3: Wo+residual  4: stage1 shift
template<bool TRANSB, int BN>
__global__ void __launch_bounds__(256, 2)
gemm_tc(const float* __restrict__ A, const float* __restrict__ Bm,
        float* __restrict__ C,
        int Mdim, int Ndim, int Kdim,
        long long sA, long long sB, long long sC,
        float alpha, float betaI,
        const float* __restrict__ bias, int relu,
        const float* __restrict__ addp, float addScale, long long sAdd,
        int mode, float* __restrict__ out2, float* __restrict__ out3)
{
    constexpr int BWORDS = BN * 8;
    constexpr int BELEM  = BWORDS / 256;
    constexpr int NTJ    = BN / 16;

    __shared__ float    Af[2][1024];
    __shared__ unsigned Bhs[2][BWORDS], Bls[2][BWORDS];

    const int zb = blockIdx.z;
    A  += (long long)zb * sA;
    Bm += (long long)zb * sB;
    C  += (long long)zb * sC;
    if (addp) addp += (long long)zb * sAdd;

    const int m0 = blockIdx.y * 128;
    const int n0 = blockIdx.x * BN;
    const int tid  = threadIdx.x;
    const int lane = tid & 31;
    const int warp = tid >> 5;
    const int wm = warp & 3;
    const int wn = warp >> 2;
    const int g  = lane >> 2;
    const int tg = lane & 3;

    int aAddr[4], bAddr[BELEM];
    long long offA[4], offB[BELEM];
    #pragma unroll
    for (int r = 0; r < 4; r++) {
        int i = tid + r * 256;
        int m = i >> 3, kk = i & 7;
        int t = m >> 4, gg2 = m & 7, hi8 = (m >> 3) & 1;
        int ttg = kk & 3, kh = kk >> 2;
        aAddr[r] = t * 128 + (gg2 * 4 + ttg) * 4 + hi8 + 2 * kh;
        offA[r]  = (long long)(m0 + m) * Kdim + kk;
    }
    #pragma unroll
    for (int r = 0; r < BELEM; r++) {
        int i = tid + r * 256;
        int n, kk;
        if (TRANSB) { n = i >> 3; kk = i & 7; offB[r] = (long long)(n0 + n) * Kdim + kk; }
        else {
            if (BN == 64) { kk = i >> 6; n = i & 63; }
            else          { kk = i >> 7; n = i & 127; }
            offB[r] = (long long)kk * Ndim + n0 + n;
        }
        int j = n >> 3;
        int ln = (n & 7) * 4 + (kk & 3);
        int kh = kk >> 2;
        if (BN == 64) {
            bAddr[r] = j * 64 + ((2 * ln + 2 * j) & 63) + kh;
        } else {
            int p = j >> 1, q = j & 1;
            int base = p * 128 + 4 * ln;
            bAddr[r] = (base ^ ((base >> 3) & 0x1C)) + 2 * q + kh;
        }
    }
    const long long bStep = TRANSB ? 8 : (long long)8 * Ndim;

    float c[2][NTJ][4];
    #pragma unroll
    for (int i = 0; i < 2; i++)
        #pragma unroll
        for (int j = 0; j < NTJ; j++)
            #pragma unroll
            for (int r = 0; r < 4; r++) c[i][j][r] = 0.f;

    const int nsteps = Kdim >> 3;
    float ra[4], rb[BELEM];

    {
        #pragma unroll
        for (int r = 0; r < 4; r++) Af[0][aAddr[r]] = A[offA[r]];
        #pragma unroll
        for (int r = 0; r < BELEM; r++) {
            unsigned h, l;
            split_tf32(Bm[offB[r]], h, l);
            Bhs[0][bAddr[r]] = h;
            Bls[0][bAddr[r]] = l;
        }
    }
    __syncthreads();
    const float* Ap = A + 8;
    const float* Bp = Bm + bStep;

    int buf = 0;
    for (int s = 0; s < nsteps; s++) {
        if (s + 1 < nsteps) {
            #pragma unroll
            for (int r = 0; r < 4; r++) ra[r] = Ap[offA[r]];
            #pragma unroll
            for (int r = 0; r < BELEM; r++) rb[r] = Bp[offB[r]];
            Ap += 8;
            Bp += bStep;
        }

        {
            unsigned ah[2][4], al[2][4];
            #pragma unroll
            for (int i = 0; i < 2; i++) {
                int base = (wm * 2 + i) * 128 + lane * 4;
                float4 v4 = *(const float4*)&Af[buf][base];
                float vv[4] = {v4.x, v4.y, v4.z, v4.w};
                #pragma unroll
                for (int r = 0; r < 4; r++)
                    split_tf32(vv[r], ah[i][r], al[i][r]);
            }
            if (BN == 64) {
                #pragma unroll
                for (int j = 0; j < NTJ; j++) {
                    int jt = wn * 4 + j;
                    int base = jt * 64 + ((2 * lane + 2 * jt) & 63);
                    uint2 vh = *(const uint2*)&Bhs[buf][base];
                    uint2 vl = *(const uint2*)&Bls[buf][base];
                    unsigned bh[2] = {vh.x, vh.y};
                    unsigned bl[2] = {vl.x, vl.y};
                    #pragma unroll
                    for (int i = 0; i < 2; i++) {
                        mma_tf32(c[i][j], ah[i], bh);
                        mma_tf32(c[i][j], ah[i], bl);
                        mma_tf32(c[i][j], al[i], bh);
                    }
                }
            } else {
                #pragma unroll
                for (int p4 = 0; p4 < 4; p4++) {
                    int p = wn * 4 + p4;
                    int base = p * 128 + lane * 4;
                    base ^= (base >> 3) & 0x1C;
                    uint4 vh = *(const uint4*)&Bhs[buf][base];
                    uint4 vl = *(const uint4*)&Bls[buf][base];
                    unsigned bh0[2] = {vh.x, vh.y}, bh1[2] = {vh.z, vh.w};
                    unsigned bl0[2] = {vl.x, vl.y}, bl1[2] = {vl.z, vl.w};
                    #pragma unroll
                    for (int i = 0; i < 2; i++) {
                        mma_tf32(c[i][2 * p4],     ah[i], bh0);
                        mma_tf32(c[i][2 * p4],     ah[i], bl0);
                        mma_tf32(c[i][2 * p4],     al[i], bh0);
                        mma_tf32(c[i][2 * p4 + 1], ah[i], bh1);
                        mma_tf32(c[i][2 * p4 + 1], ah[i], bl1);
                        mma_tf32(c[i][2 * p4 + 1], al[i], bh1);
                    }
                }
            }
        }

        if (s + 1 < nsteps) {
            int nb = buf ^ 1;
            #pragma unroll
            for (int r = 0; r < 4; r++) Af[nb][aAddr[r]] = ra[r];
            #pragma unroll
            for (int r = 0; r < BELEM; r++) {
                unsigned h, l;
                split_tf32(rb[r], h, l);
                Bhs[nb][bAddr[r]] = h;
                Bls[nb][bAddr[r]] = l;
            }
            __syncthreads();
            buf = nb;
        }
    }

    // ---- epilogue ----
    #pragma unroll
    for (int i = 0; i < 2; i++) {
        #pragma unroll
        for (int j = 0; j < NTJ; j++) {
            int row0 = m0 + wm * 32 + i * 16 + g;
            int row1 = row0 + 8;
            int col  = n0 + wn * (BN / 2) + j * 8 + 2 * tg;
            float2 v0, v1;
            v0.x = alpha * c[i][j][0]; v0.y = alpha * c[i][j][1];
            v1.x = alpha * c[i][j][2]; v1.y = alpha * c[i][j][3];
            if (bias) {
                float2 bb2 = *(const float2*)&bias[col];
                v0.x += bb2.x; v0.y += bb2.y;
                v1.x += bb2.x; v1.y += bb2.y;
            }
            if (betaI != 0.f) {
                if (row0 == col)     v0.x += betaI;
                if (row0 == col + 1) v0.y += betaI;
                if (row1 == col)     v1.x += betaI;
                if (row1 == col + 1) v1.y += betaI;
            }
            if (addp) {
                float2 a0 = *(const float2*)&addp[(long long)row0 * Ndim + col];
                float2 a1 = *(const float2*)&addp[(long long)row1 * Ndim + col];
                v0.x += addScale * a0.x; v0.y += addScale * a0.y;
                v1.x += addScale * a1.x; v1.y += addScale * a1.y;
            }
            if (relu) {
                v0.x = fmaxf(v0.x, 0.f); v0.y = fmaxf(v0.y, 0.f);
                v1.x = fmaxf(v1.x, 0.f); v1.y = fmaxf(v1.y, 0.f);
            }
            if (mode == 0) {
                *(float2*)&C[(long long)row0 * Ndim + col] = v0;
                *(float2*)&C[(long long)row1 * Ndim + col] = v1;
            } else if (mode == 1) {
                int kind = col >> 9, cc = col & 511;
                int hh = cc >> 6, d = cc & 63;
                float* dst = (kind == 0) ? C : (kind == 1) ? out2 : out3;
                float sc = (kind == 0) ? QSCALE : 1.f;
                int b0 = row0 / NPAD, n0r = row0 - b0 * NPAD;
                int b1r = row1 / NPAD, n1r = row1 - b1r * NPAD;
                float2 w0 = make_float2(v0.x * sc, v0.y * sc);
                float2 w1 = make_float2(v1.x * sc, v1.y * sc);
                *(float2*)&dst[(((long long)(b0 * NH + hh) * NPAD) + n0r) * HD + d] = w0;
                *(float2*)&dst[(((long long)(b1r * NH + hh) * NPAD) + n1r) * HD + d] = w1;
            } else if (mode == 2) {
                int b = zb >> 3, hh = zb & 7;
                *(float2*)&C[((long long)(b * NPAD + row0) * EMB) + hh * 64 + col] = v0;
                *(float2*)&C[((long long)(b * NPAD + row1) * EMB) + hh * 64 + col] = v1;
            } else if (mode == 3) {
                int b0 = row0 / NPAD, n0r = row0 - b0 * NPAD;
                int b1r = row1 / NPAD, n1r = row1 - b1r * NPAD;
                if (n0r >= PADR) {
                    long long a = ((long long)(b0 * NT + n0r - PADR) * EMB) + col;
                    float2 old = *(float2*)&C[a];
                    v0.x += old.x; v0.y += old.y;
                    *(float2*)&C[a] = v0;
                }
                if (n1r >= PADR) {
                    long long a = ((long long)(b1r * NT + n1r - PADR) * EMB) + col;
                    float2 old = *(float2*)&C[a];
                    v1.x += old.x; v1.y += old.y;
                    *(float2*)&C[a] = v1;
                }
            } else { // mode 4
                int b0 = row0 >> 12, n0r = row0 & 4095;
                int b1r = row1 >> 12, n1r = row1 & 4095;
                *(float2*)&C[((long long)(b0 * NT + 1 + n0r) * EMB) + col] = v0;
                *(float2*)&C[((long long)(b1r * NT + 1 + n1r) * EMB) + col] = v1;
            }
        }
    }
}

static void gemm(cudaStream_t st, const float* A, const float* Bm, float* C,
                 int M_, int N_, int K_,
                 long long sA, long long sB, long long sC, int batch, bool transB,
                 float alpha = 1.f, float betaI = 0.f,
                 const float* bias = nullptr, int relu = 0,
                 const float* addp = nullptr, float addScale = 0.f, long long sAdd = 0,
                 int mode = 0, float* out2 = nullptr, float* out3 = nullptr)
{
    // occupancy-aware tile width: BN=128 only if it still fills the chip
    long long ctas128 = (N_ % 128 == 0) ? (long long)(N_ / 128) * (M_ / 128) * batch : 0;
    const bool big = (N_ % 128 == 0) && (ctas128 >= 256);
    dim3 grid(N_ / (big ? 128 : 64), M_ / 128, batch);
    if (big) {
        if (transB) gemm_tc<true, 128><<<grid, 256, 0, st>>>(A, Bm, C, M_, N_, K_, sA, sB, sC, alpha, betaI, bias, relu, addp, addScale, sAdd, mode, out2, out3);
        else        gemm_tc<false,128><<<grid, 256, 0, st>>>(A, Bm, C, M_, N_, K_, sA, sB, sC, alpha, betaI, bias, relu, addp, addScale, sAdd, mode, out2, out3);
    } else {
        if (transB) gemm_tc<true, 64><<<grid, 256, 0, st>>>(A, Bm, C, M_, N_, K_, sA, sB, sC, alpha, betaI, bias, relu, addp, addScale, sAdd, mode, out2, out3);
        else        gemm_tc<false, 64><<<grid, 256, 0, st>>>(A, Bm, C, M_, N_, K_, sA, sB, sC, alpha, betaI, bias, relu, addp, addScale, sAdd, mode, out2, out3);
    }
}

// ---------------- cls rows ----------------
__global__ void cls_k(const float* __restrict__ cls)
{
    int c = threadIdx.x;
    #pragma unroll
    for (int b = 0; b < BB; b++)
        g_h[(long long)b * NT * EMB + c] = cls[c];
}

// ---------------- layer norm + front zero-pad into g_x ----------------
__global__ void ln_pad_k(const float* __restrict__ gg, const float* __restrict__ bb)
{
    int n = blockIdx.x, b = blockIdx.y;
    int tid = threadIdx.x;
    float* out = g_x + ((long long)b * NPAD + n) * EMB;
    if (n < PADR) { out[tid] = 0.f; out[tid + 256] = 0.f; return; }
    const float* in = g_h + ((long long)b * NT + (n - PADR)) * EMB;
    float x0 = in[tid], x1 = in[tid + 256];
    __shared__ float sd[256];
    sd[tid] = x0 + x1; __syncthreads();
    for (int s = 128; s > 0; s >>= 1) { if (tid < s) sd[tid] += sd[tid + s]; __syncthreads(); }
    float mu = sd[0] * (1.f / EMB);
    __syncthreads();
    float d0 = x0 - mu, d1 = x1 - mu;
    sd[tid] = d0 * d0 + d1 * d1; __syncthreads();
    for (int s = 128; s > 0; s >>= 1) { if (tid < s) sd[tid] += sd[tid + s]; __syncthreads(); }
    float rs = rsqrtf(sd[0] * (1.f / EMB) + 1e-5f);
    out[tid]       = d0 * rs * gg[tid]       + bb[tid];
    out[tid + 256] = d1 * rs * gg[tid + 256] + bb[tid + 256];
}

// ---------------- landmark means ----------------
__global__ void land_k(const float* __restrict__ src, float* __restrict__ dst)
{
    int d = threadIdx.x;
    int m = blockIdx.x;
    int bh = blockIdx.y;
    const float* p = src + (((long long)bh * NPAD) + (long long)m * LCH) * HD + d;
    float s = 0.f;
    #pragma unroll
    for (int i = 0; i < LCH; i++) s += p[(long long)i * HD];
    dst[(((long long)bh * NLM) + m) * HD + d] = s * (1.f / LCH);
}

// ---------------- single-pass softmax, len 256 ----------------
__global__ void softmax256_k(float* __restrict__ x)
{
    long long row = (long long)blockIdx.x * 8 + (threadIdx.x >> 5);
    int lane = threadIdx.x & 31;
    float* p = x + row * 256;
    float v[8];
    float m = -1e30f;
    #pragma unroll
    for (int i = 0; i < 8; i++) { v[i] = p[lane + 32 * i]; m = fmaxf(m, v[i]); }
    #pragma unroll
    for (int o = 16; o > 0; o >>= 1) m = fmaxf(m, __shfl_xor_sync(0xffffffffu, m, o));
    float s = 0.f;
    #pragma unroll
    for (int i = 0; i < 8; i++) { v[i] = expf(v[i] - m); s += v[i]; }
    #pragma unroll
    for (int o = 16; o > 0; o >>= 1) s += __shfl_xor_sync(0xffffffffu, s, o);
    float r = 1.f / s;
    #pragma unroll
    for (int i = 0; i < 8; i++) p[lane + 32 * i] = v[i] * r;
}

// ---------------- single-pass softmax, len 4352 ----------------
__global__ void softmax4352_k(float* __restrict__ x)
{
    long long row = blockIdx.x;
    float* p = x + row * 4352;
    int tid = threadIdx.x;
    float v[17];
    float m = -1e30f;
    #pragma unroll
    for (int i = 0; i < 17; i++) { v[i] = p[tid + 256 * i]; m = fmaxf(m, v[i]); }
    __shared__ float sd[8];
    #pragma unroll
    for (int o = 16; o > 0; o >>= 1) m = fmaxf(m, __shfl_xor_sync(0xffffffffu, m, o));
    if ((tid & 31) == 0) sd[tid >> 5] = m;
    __syncthreads();
    if (tid < 8) {
        float t = sd[tid];
        #pragma unroll
        for (int o = 4; o > 0; o >>= 1) t = fmaxf(t, __shfl_xor_sync(0xffu, t, o));
        sd[tid] = t;
    }
    __syncthreads();
    m = sd[0];
    float s = 0.f;
    #pragma unroll
    for (int i = 0; i < 17; i++) { v[i] = expf(v[i] - m); s += v[i]; }
    __syncthreads();
    #pragma unroll
    for (int o = 16; o > 0; o >>= 1) s += __shfl_xor_sync(0xffffffffu, s, o);
    if ((tid & 31) == 0) sd[tid >> 5] = s;
    __syncthreads();
    if (tid < 8) {
        float t = sd[tid];
        #pragma unroll
        for (int o = 4; o > 0; o >>= 1) t += __shfl_xor_sync(0xffu, t, o);
        sd[tid] = t;
    }
    __syncthreads();
    float r = 1.f / sd[0];
    #pragma unroll
    for (int i = 0; i < 17; i++) p[tid + 256 * i] = v[i] * r;
}

// ---------------- pinv helpers ----------------
__global__ void reset_red_k() { if (threadIdx.x < 2) g_red[threadIdx.x] = 0u; }

__global__ void denom_k()
{
    int bh = blockIdx.x, tid = threadIdx.x;
    const float* mat = g_s2 + (long long)bh * NLM * NLM;
    float col = 0.f, rs = 0.f;
    for (int i = 0; i < NLM; i++) col += mat[i * NLM + tid];
    for (int j = 0; j < NLM; j++) rs  += mat[tid * NLM + j];
    __shared__ float sd[256];
    sd[tid] = rs; __syncthreads();
    for (int s = 128; s > 0; s >>= 1) { if (tid < s) sd[tid] = fmaxf(sd[tid], sd[tid + s]); __syncthreads(); }
    if (tid == 0) atomicMax(&g_red[0], __float_as_uint(sd[0]));
    __syncthreads();
    sd[tid] = col; __syncthreads();
    for (int s = 128; s > 0; s >>= 1) { if (tid < s) sd[tid] = fmaxf(sd[tid], sd[tid + s]); __syncthreads(); }
    if (tid == 0) atomicMax(&g_red[1], __float_as_uint(sd[0]));
}

__global__ void initz_k()
{
    long long idx = (long long)blockIdx.x * 256 + threadIdx.x;
    float rd = 1.f / (__uint_as_float(g_red[0]) * __uint_as_float(g_red[1]));
    int ij = (int)(idx & 65535);
    long long bh = idx >> 16;
    int i = ij >> 8, j = ij & 255;
    g_z[idx] = g_s2[(bh << 16) + (long long)j * NLM + i] * rd;
}

// ---------------- depthwise 33-tap residual conv on v, added into g_attn ----------------
__global__ void resconv_k(const float* __restrict__ w)
{
    int d = threadIdx.x;
    int n = blockIdx.x;
    int bh = blockIdx.y;
    int hh = bh & 7, b = bh >> 3;
    __shared__ float sw[33];
    if (d < 33) sw[d] = w[hh * 33 + d];
    __syncthreads();
    const float* vp = g_v + ((long long)bh * NPAD) * HD + d;
    float acc = 0.f;
    #pragma unroll
    for (int j = 0; j < 33; j++) {
        int nn = n + j - 16;
        if (nn >= 0 && nn < NPAD) acc += sw[j] * vp[(long long)nn * HD];
    }
    g_attn[((long long)(b * NPAD + n) * EMB) + hh * 64 + d] += acc;
}

// ---------------- token<->image transposes ----------------
__global__ void tok2img_k()
{
    __shared__ float t[32][33];
    int b = blockIdx.z;
    int c0 = blockIdx.x * 32, p0 = blockIdx.y * 32;
    int tx = threadIdx.x, ty = threadIdx.y;
    #pragma unroll
    for (int j = 0; j < 32; j += 8)
        t[ty + j][tx] = g_h[((long long)b * NT + 1 + p0 + ty + j) * EMB + c0 + tx];
    __syncthreads();
    #pragma unroll
    for (int j = 0; j < 32; j += 8)
        g_cnn[((long long)b * EMB + c0 + ty + j) * (GRD * GRD) + p0 + tx] = t[tx][ty + j];
}

__global__ void img2tok_k()
{
    __shared__ float t[32][33];
    int b = blockIdx.z;
    int c0 = blockIdx.x * 32, p0 = blockIdx.y * 32;
    int tx = threadIdx.x, ty = threadIdx.y;
    #pragma unroll
    for (int j = 0; j < 32; j += 8)
        t[ty + j][tx] = g_cnn2[((long long)b * EMB + c0 + ty + j) * (GRD * GRD) + p0 + tx];
    __syncthreads();
    #pragma unroll
    for (int j = 0; j < 32; j += 8)
        g_h[((long long)b * NT + 1 + p0 + ty + j) * EMB + c0 + tx] = t[tx][ty + j];
}

// ---------------- fused 7x7 + 5x5 + 3x3 depthwise conv + identity ----------------
__global__ void dwconv_k(const float* __restrict__ w7, const float* __restrict__ b7,
                         const float* __restrict__ w5, const float* __restrict__ b5,
                         const float* __restrict__ w3, const float* __restrict__ b3)
{
    int bc = blockIdx.z;
    int c  = bc % EMB;
    const float* img = g_cnn + (long long)bc * GRD * GRD;
    __shared__ float tile[22][22];
    __shared__ float sw7[49], sw5[25], sw3[9];
    int tx = threadIdx.x, ty = threadIdx.y;
    int tid = ty * 16 + tx;
    if (tid < 49) sw7[tid] = w7[c * 49 + tid];
    if (tid < 25) sw5[tid] = w5[c * 25 + tid];
    if (tid < 9)  sw3[tid] = w3[c * 9  + tid];
    int ox0 = blockIdx.x * 16, oy0 = blockIdx.y * 16;
    for (int i = tid; i < 22 * 22; i += 256) {
        int yy = i / 22, xx = i % 22;
        int gy = oy0 - 3 + yy, gx = ox0 - 3 + xx;
        tile[yy][xx] = (gy >= 0 && gy < GRD && gx >= 0 && gx < GRD) ? img[gy * GRD + gx] : 0.f;
    }
    __syncthreads();
    float acc = tile[ty + 3][tx + 3] + b7[c] + b5[c] + b3[c];
    #pragma unroll
    for (int ky = 0; ky < 7; ky++)
        #pragma unroll
        for (int kx = 0; kx < 7; kx++)
            acc += sw7[ky * 7 + kx] * tile[ty + ky][tx + kx];
    #pragma unroll
    for (int ky = 0; ky < 5; ky++)
        #pragma unroll
        for (int kx = 0; kx < 5; kx++)
            acc += sw5[ky * 5 + kx] * tile[ty + 1 + ky][tx + 1 + kx];
    #pragma unroll
    for (int ky = 0; ky < 3; ky++)
        #pragma unroll
        for (int kx = 0; kx < 3; kx++)
            acc += sw3[ky * 3 + kx] * tile[ty + 2 + ky][tx + 2 + kx];
    g_cnn2[(long long)bc * GRD * GRD + (oy0 + ty) * GRD + ox0 + tx] = acc;
}

// ---------------- final LN(cls) -> logits -> softmax -> argmax ----------------
__global__ void head_k(const float* __restrict__ gg, const float* __restrict__ bb,
                       const float* __restrict__ W2, const float* __restrict__ b2,
                       float* __restrict__ out, int out_size)
{
    int tid = threadIdx.x; // 512
    __shared__ float sd[512];
    __shared__ float res[20];
    for (int b = 0; b < BB; b++) {
        float x = g_h[(long long)b * NT * EMB + tid];
        sd[tid] = x; __syncthreads();
        for (int s = 256; s > 0; s >>= 1) { if (tid < s) sd[tid] += sd[tid + s]; __syncthreads(); }
        float mu = sd[0] * (1.f / EMB); __syncthreads();
        float dx = x - mu;
        sd[tid] = dx * dx; __syncthreads();
        for (int s = 256; s > 0; s >>= 1) { if (tid < s) sd[tid] += sd[tid + s]; __syncthreads(); }
        float rs = rsqrtf(sd[0] * (1.f / EMB) + 1e-5f); __syncthreads();
        float xn = dx * rs * gg[tid] + bb[tid];
        sd[tid] = xn * W2[tid]; __syncthreads();
        for (int s = 256; s > 0; s >>= 1) { if (tid < s) sd[tid] += sd[tid + s]; __syncthreads(); }
        float l0 = sd[0] + b2[0]; __syncthreads();
        sd[tid] = xn * W2[EMB + tid]; __syncthreads();
        for (int s = 256; s > 0; s >>= 1) { if (tid < s) sd[tid] += sd[tid + s]; __syncthreads(); }
        float l1 = sd[0] + b2[1]; __syncthreads();
        if (tid == 0) {
            float mx = fmaxf(l0, l1);
            float e0 = expf(l0 - mx), e1 = expf(l1 - mx);
            float s = e0 + e1;
            res[b * 2]     = l0;
            res[b * 2 + 1] = l1;
            res[8 + b * 2]     = e0 / s;
            res[8 + b * 2 + 1] = e1 / s;
            res[16 + b] = (l1 > l0) ? 1.f : 0.f;
        }
        __syncthreads();
    }
    if (tid < 20 && tid < out_size) out[tid] = res[tid];
}

// ---------------- host orchestration ----------------
#define SYM(p, s) do { void* _t = nullptr; cudaGetSymbolAddress(&_t, s); p = (float*)_t; } while (0)

// stream/event objects created once at first call (host-side only, no device memory)
static cudaStream_t g_sB = nullptr;
static cudaEvent_t  g_evF[2], g_evJ[2];
static void ensure_streams()
{
    static bool done = false;
    if (!done) {
        cudaStreamCreateWithFlags(&g_sB, cudaStreamNonBlocking);
        for (int i = 0; i < 2; i++) {
            cudaEventCreateWithFlags(&g_evF[i], cudaEventDisableTiming);
            cudaEventCreateWithFlags(&g_evJ[i], cudaEventDisableTiming);
        }
        done = true;
    }
}

static void run_attn(int layer, const float* ln_g, const float* ln_b, const float* Wqkv,
                     const float* Wo, const float* bo, const float* res)
{
    float *x_, *q_, *k_, *v_, *ql_, *kl_, *s1_, *s2_, *s3_;
    float *z_, *z2_, *t0_, *t1_, *t2_, *av_, *u_, *attn_, *h_;
    SYM(x_, g_x); SYM(q_, g_q); SYM(k_, g_k); SYM(v_, g_v);
    SYM(ql_, g_ql); SYM(kl_, g_kl); SYM(s1_, g_s1); SYM(s2_, g_s2); SYM(s3_, g_s3);
    SYM(z_, g_z); SYM(z2_, g_z2); SYM(t0_, g_t0); SYM(t1_, g_t1); SYM(t2_, g_t2);
    SYM(av_, g_av); SYM(u_, g_u); SYM(attn_, g_attn); SYM(h_, g_h);

    cudaStream_t s0 = 0, sB = g_sB;

    ln_pad_k<<<dim3(NPAD, BB), 256, 0, s0>>>(ln_g, ln_b);
    gemm(s0, x_, Wqkv, q_, BB * NPAD, 3 * EMB, EMB, 0, 0, 0, 1, true,
         1.f, 0.f, nullptr, 0, nullptr, 0.f, 0, 1, k_, v_);
    land_k<<<dim3(NLM, BB * NH), 64, 0, s0>>>(q_, ql_);
    land_k<<<dim3(NLM, BB * NH), 64, 0, s0>>>(k_, kl_);

    // ---- fork: branch B (s2 + pinv chain) on sB ----
    cudaEventRecord(g_evF[layer], s0);
    cudaStreamWaitEvent(sB, g_evF[layer], 0);

    // branch B
    gemm(sB, ql_, kl_, s2_, NLM, NLM, HD,
         (long long)NLM * HD, (long long)NLM * HD, (long long)NLM * NLM, BB * NH, true);
    softmax256_k<<<BB * NH * NLM / 8, 256, 0, sB>>>(s2_);
    reset_red_k<<<1, 32, 0, sB>>>();
    denom_k<<<BB * NH, 256, 0, sB>>>();
    initz_k<<<(BB * NH * NLM * NLM) / 256, 256, 0, sB>>>();
    float* zi = z_;
    float* zo = z2_;
    for (int it = 0; it < 6; it++) {
        gemm(sB, s2_, zi, t0_, NLM, NLM, NLM, 65536, 65536, 65536, BB * NH, false);
        gemm(sB, t0_, t0_, t2_, NLM, NLM, NLM, 65536, 65536, 65536, BB * NH, false,
             1.f, 15.f, nullptr, 0, t0_, -7.f, 65536);
        gemm(sB, t0_, t2_, t1_, NLM, NLM, NLM, 65536, 65536, 65536, BB * NH, false, -1.f, 13.f);
        gemm(sB, zi, t1_, zo, NLM, NLM, NLM, 65536, 65536, 65536, BB * NH, false, 0.25f, 0.f);
        float* tmp = zi; zi = zo; zo = tmp;
    }
    cudaEventRecord(g_evJ[layer], sB);

    // branch A (origin stream)
    gemm(s0, q_, kl_, s1_, NPAD, NLM, HD,
         (long long)NPAD * HD, (long long)NLM * HD, (long long)NPAD * NLM, BB * NH, true);
    softmax256_k<<<BB * NH * NPAD / 8, 256, 0, s0>>>(s1_);
    gemm(s0, ql_, k_, s3_, NLM, NPAD, HD,
         (long long)NLM * HD, (long long)NPAD * HD, (long long)NLM * NPAD, BB * NH, true);
    softmax4352_k<<<BB * NH * NLM, 256, 0, s0>>>(s3_);
    gemm(s0, s3_, v_, av_, NLM, HD, NPAD,
         (long long)NLM * NPAD, (long long)NPAD * HD, (long long)NLM * HD, BB * NH, false);

    // ---- join ----
    cudaStreamWaitEvent(s0, g_evJ[layer], 0);

    gemm(s0, zi, av_, u_, NLM, HD, NLM,
         65536, (long long)NLM * HD, (long long)NLM * HD, BB * NH, false);
    gemm(s0, s1_, u_, attn_, NPAD, HD, NLM,
         (long long)NPAD * NLM, (long long)NLM * HD, 0, BB * NH, false,
         1.f, 0.f, nullptr, 0, nullptr, 0.f, 0, 2);

    resconv_k<<<dim3(NPAD, BB * NH), 64, 0, s0>>>(res);
    gemm(s0, attn_, Wo, h_, BB * NPAD, EMB, EMB, 0, 0, 0, 1, true,
         1.f, 0.f, bo, 0, nullptr, 0.f, 0, 3);
}

extern "C" void kernel_launch(void* const* d_in, const int* in_sizes, int n_in,
                              void* d_out, int out_size)
{
    ensure_streams();

    const float* data  = (const float*)d_in[0];
    const float* W1    = (const float*)d_in[1];
    const float* b1    = (const float*)d_in[2];
    const float* cls   = (const float*)d_in[3];
    const float* ln1_g = (const float*)d_in[4];
    const float* ln1_b = (const float*)d_in[5];
    const float* Wqkv1 = (const float*)d_in[6];
    const float* Wo1   = (const float*)d_in[7];
    const float* bo1   = (const float*)d_in[8];
    const float* res1  = (const float*)d_in[9];
    const float* ln2_g = (const float*)d_in[10];
    const float* ln2_b = (const float*)d_in[11];
    const float* Wqkv2 = (const float*)d_in[12];
    const float* Wo2   = (const float*)d_in[13];
    const float* bo2   = (const float*)d_in[14];
    const float* res2  = (const float*)d_in[15];
    const float* pw7   = (const float*)d_in[16];
    const float* pb7   = (const float*)d_in[17];
    const float* pw5   = (const float*)d_in[18];
    const float* pb5   = (const float*)d_in[19];
    const float* pw3   = (const float*)d_in[20];
    const float* pb3   = (const float*)d_in[21];
    const float* lnf_g = (const float*)d_in[22];
    const float* lnf_b = (const float*)d_in[23];
    const float* W2    = (const float*)d_in[24];
    const float* b2    = (const float*)d_in[25];

    float* h_;
    SYM(h_, g_h);

    // stage 1: h[1:] = relu(data @ W1^T + b1) (mode 4 shift), cls row separately
    gemm(0, data, W1, h_, BB * N0, EMB, C0, 0, 0, 0, 1, true,
         1.f, 0.f, b1, 1, nullptr, 0.f, 0, 4);
    cls_k<<<1, 512>>>(cls);

    // stage 2: first Nystrom attention block (residual)
    run_attn(0, ln1_g, ln1_b, Wqkv1, Wo1, bo1, res1);

    // stage 3: PPEG conv block on the 64x64 token grid (cls row untouched)
    tok2img_k<<<dim3(EMB / 32, (GRD * GRD) / 32, BB), dim3(32, 8)>>>();
    dwconv_k<<<dim3(GRD / 16, GRD / 16, BB * EMB), dim3(16, 16)>>>(pw7, pb7, pw5, pb5, pw3, pb3);
    img2tok_k<<<dim3(EMB / 32, (GRD * GRD) / 32, BB), dim3(32, 8)>>>();

    // stage 4: second Nystrom attention block (residual)
    run_attn(1, ln2_g, ln2_b, Wqkv2, Wo2, bo2, res2);

    // stage 5: final LN on cls token + classification head
    head_k<<<1, 512>>>(lnf_g, lnf_b, W2, b2, (float*)d_out, out_size);
}

// round 14
// speedup vs baseline: 2.2181x; 1.0267x over previous
#include <cuda_runtime.h>
#include <math.h>

#define BB   4
#define N0   4096
#define C0   1536
#define EMB  512
#define NH   8
#define HD   64
#define NT   4097
#define NPAD 4352
#define PADR 255
#define NLM  256
#define LCH  17
#define GRD  64
#define QSCALE 0.125f

// ---------------- static device scratch (no allocations allowed) ----------------
__device__ float g_h   [BB*NT*EMB];
__device__ float g_x   [BB*NPAD*EMB];
__device__ float g_q   [BB*NH*NPAD*HD];
__device__ float g_k   [BB*NH*NPAD*HD];
__device__ float g_v   [BB*NH*NPAD*HD];
__device__ float g_ql  [BB*NH*NLM*HD];
__device__ float g_kl  [BB*NH*NLM*HD];
__device__ float g_s1  [(long long)BB*NH*NPAD*NLM];
__device__ float g_s2  [BB*NH*NLM*NLM];
__device__ float g_s3  [(long long)BB*NH*NLM*NPAD];
__device__ float g_z   [BB*NH*NLM*NLM];
__device__ float g_z2  [BB*NH*NLM*NLM];
__device__ float g_t0  [BB*NH*NLM*NLM];
__device__ float g_t1  [BB*NH*NLM*NLM];
__device__ float g_t2  [BB*NH*NLM*NLM];
__device__ float g_av  [BB*NH*NLM*HD];
__device__ float g_u   [BB*NH*NLM*HD];
__device__ float g_attn[BB*NPAD*EMB];
__device__ float g_cnn [BB*EMB*GRD*GRD];
__device__ float g_cnn2[BB*EMB*GRD*GRD];
__device__ unsigned g_red[2];

// ---------------- tf32 helpers ----------------
__device__ __forceinline__ unsigned f2tf(float v)
{
    unsigned r;
    asm("cvt.rna.tf32.f32 %0, %1;" : "=r"(r) : "f"(v));
    return r;
}

// Bitmask hi/lo split for the 3-MMA path.
__device__ __forceinline__ void split_tf32(float v, unsigned& hi, unsigned& lo)
{
    hi = __float_as_uint(v) & 0xFFFFE000u;
    lo = __float_as_uint(v - __uint_as_float(hi));
}

__device__ __forceinline__ void mma_tf32(float c[4], const unsigned a[4], const unsigned b[2])
{
    asm volatile("mma.sync.aligned.m16n8k8.row.col.f32.tf32.tf32.f32 "
                 "{%0,%1,%2,%3}, {%4,%5,%6,%7}, {%8,%9}, {%0,%1,%2,%3};"
                 : "+f"(c[0]), "+f"(c[1]), "+f"(c[2]), "+f"(c[3])
                 : "r"(a[0]), "r"(a[1]), "r"(a[2]), "r"(a[3]), "r"(b[0]), "r"(b[1]));
}

// ---------------- batched TF32 tensor-core GEMM, fragment-packed smem ----------------
// Block tile 128 x BN (BN = 64 or 128), 8 warps.
// FAST=1: single-pass tf32 (rna), no lo plane. FAST=0: 3xTF32 (fp32-class accuracy).
// Epilogue modes:
//  0: plain  1: QKV split  2: merge heads  3: Wo+residual  4: stage1 shift
template<bool TRANSB, int BN, bool FAST>
__global__ void __launch_bounds__(256, 2)
gemm_tc(const float* __restrict__ A, const float* __restrict__ Bm,
        float* __restrict__ C,
        int Mdim, int Ndim, int Kdim,
        long long sA, long long sB, long long sC,
        float alpha, float betaI,
        const float* __restrict__ bias, int relu,
        const float* __restrict__ addp, float addScale, long long sAdd,
        int mode, float* __restrict__ out2, float* __restrict__ out3)
{
    constexpr int BWORDS = BN * 8;
    constexpr int BELEM  = BWORDS / 256;
    constexpr int NTJ    = BN / 16;

    __shared__ float    Af[2][1024];
    __shared__ unsigned Bhs[2][BWORDS], Bls[2][BWORDS];

    const int zb = blockIdx.z;
    A  += (long long)zb * sA;
    Bm += (long long)zb * sB;
    C  += (long long)zb * sC;
    if (addp) addp += (long long)zb * sAdd;

    const int m0 = blockIdx.y * 128;
    const int n0 = blockIdx.x * BN;
    const int tid  = threadIdx.x;
    const int lane = tid & 31;
    const int warp = tid >> 5;
    const int wm = warp & 3;
    const int wn = warp >> 2;
    const int g  = lane >> 2;
    const int tg = lane & 3;

    int aAddr[4], bAddr[BELEM];
    long long offA[4], offB[BELEM];
    #pragma unroll
    for (int r = 0; r < 4; r++) {
        int i = tid + r * 256;
        int m = i >> 3, kk = i & 7;
        int t = m >> 4, gg2 = m & 7, hi8 = (m >> 3) & 1;
        int ttg = kk & 3, kh = kk >> 2;
        aAddr[r] = t * 128 + (gg2 * 4 + ttg) * 4 + hi8 + 2 * kh;
        offA[r]  = (long long)(m0 + m) * Kdim + kk;
    }
    #pragma unroll
    for (int r = 0; r < BELEM; r++) {
        int i = tid + r * 256;
        int n, kk;
        if (TRANSB) { n = i >> 3; kk = i & 7; offB[r] = (long long)(n0 + n) * Kdim + kk; }
        else {
            if (BN == 64) { kk = i >> 6; n = i & 63; }
            else          { kk = i >> 7; n = i & 127; }
            offB[r] = (long long)kk * Ndim + n0 + n;
        }
        int j = n >> 3;
        int ln = (n & 7) * 4 + (kk & 3);
        int kh = kk >> 2;
        if (BN == 64) {
            bAddr[r] = j * 64 + ((2 * ln + 2 * j) & 63) + kh;
        } else {
            int p = j >> 1, q = j & 1;
            int base = p * 128 + 4 * ln;
            bAddr[r] = (base ^ ((base >> 3) & 0x1C)) + 2 * q + kh;
        }
    }
    const long long bStep = TRANSB ? 8 : (long long)8 * Ndim;

    float c[2][NTJ][4];
    #pragma unroll
    for (int i = 0; i < 2; i++)
        #pragma unroll
        for (int j = 0; j < NTJ; j++)
            #pragma unroll
            for (int r = 0; r < 4; r++) c[i][j][r] = 0.f;

    const int nsteps = Kdim >> 3;
    float ra[4], rb[BELEM];

    {
        #pragma unroll
        for (int r = 0; r < 4; r++) Af[0][aAddr[r]] = A[offA[r]];
        #pragma unroll
        for (int r = 0; r < BELEM; r++) {
            float v = Bm[offB[r]];
            if (FAST) {
                Bhs[0][bAddr[r]] = f2tf(v);
            } else {
                unsigned h, l;
                split_tf32(v, h, l);
                Bhs[0][bAddr[r]] = h;
                Bls[0][bAddr[r]] = l;
            }
        }
    }
    __syncthreads();
    const float* Ap = A + 8;
    const float* Bp = Bm + bStep;

    int buf = 0;
    for (int s = 0; s < nsteps; s++) {
        if (s + 1 < nsteps) {
            #pragma unroll
            for (int r = 0; r < 4; r++) ra[r] = Ap[offA[r]];
            #pragma unroll
            for (int r = 0; r < BELEM; r++) rb[r] = Bp[offB[r]];
            Ap += 8;
            Bp += bStep;
        }

        {
            unsigned ah[2][4], al[2][4];
            #pragma unroll
            for (int i = 0; i < 2; i++) {
                int base = (wm * 2 + i) * 128 + lane * 4;
                float4 v4 = *(const float4*)&Af[buf][base];
                float vv[4] = {v4.x, v4.y, v4.z, v4.w};
                #pragma unroll
                for (int r = 0; r < 4; r++) {
                    if (FAST) ah[i][r] = f2tf(vv[r]);
                    else      split_tf32(vv[r], ah[i][r], al[i][r]);
                }
            }
            if (BN == 64) {
                #pragma unroll
                for (int j = 0; j < NTJ; j++) {
                    int jt = wn * 4 + j;
                    int base = jt * 64 + ((2 * lane + 2 * jt) & 63);
                    uint2 vh = *(const uint2*)&Bhs[buf][base];
                    unsigned bh[2] = {vh.x, vh.y};
                    #pragma unroll
                    for (int i = 0; i < 2; i++) {
                        mma_tf32(c[i][j], ah[i], bh);
                        if (!FAST) {
                            uint2 vl = *(const uint2*)&Bls[buf][base];
                            unsigned bl[2] = {vl.x, vl.y};
                            mma_tf32(c[i][j], ah[i], bl);
                            mma_tf32(c[i][j], al[i], bh);
                        }
                    }
                }
            } else {
                #pragma unroll
                for (int p4 = 0; p4 < 4; p4++) {
                    int p = wn * 4 + p4;
                    int base = p * 128 + lane * 4;
                    base ^= (base >> 3) & 0x1C;
                    uint4 vh = *(const uint4*)&Bhs[buf][base];
                    unsigned bh0[2] = {vh.x, vh.y}, bh1[2] = {vh.z, vh.w};
                    if (FAST) {
                        #pragma unroll
                        for (int i = 0; i < 2; i++) {
                            mma_tf32(c[i][2 * p4],     ah[i], bh0);
                            mma_tf32(c[i][2 * p4 + 1], ah[i], bh1);
                        }
                    } else {
                        uint4 vl = *(const uint4*)&Bls[buf][base];
                        unsigned bl0[2] = {vl.x, vl.y}, bl1[2] = {vl.z, vl.w};
                        #pragma unroll
                        for (int i = 0; i < 2; i++) {
                            mma_tf32(c[i][2 * p4],     ah[i], bh0);
                            mma_tf32(c[i][2 * p4],     ah[i], bl0);
                            mma_tf32(c[i][2 * p4],     al[i], bh0);
                            mma_tf32(c[i][2 * p4 + 1], ah[i], bh1);
                            mma_tf32(c[i][2 * p4 + 1], ah[i], bl1);
                            mma_tf32(c[i][2 * p4 + 1], al[i], bh1);
                        }
                    }
                }
            }
        }

        if (s + 1 < nsteps) {
            int nb = buf ^ 1;
            #pragma unroll
            for (int r = 0; r < 4; r++) Af[nb][aAddr[r]] = ra[r];
            #pragma unroll
            for (int r = 0; r < BELEM; r++) {
                if (FAST) {
                    Bhs[nb][bAddr[r]] = f2tf(rb[r]);
                } else {
                    unsigned h, l;
                    split_tf32(rb[r], h, l);
                    Bhs[nb][bAddr[r]] = h;
                    Bls[nb][bAddr[r]] = l;
                }
            }
            __syncthreads();
            buf = nb;
        }
    }

    // ---- epilogue ----
    #pragma unroll
    for (int i = 0; i < 2; i++) {
        #pragma unroll
        for (int j = 0; j < NTJ; j++) {
            int row0 = m0 + wm * 32 + i * 16 + g;
            int row1 = row0 + 8;
            int col  = n0 + wn * (BN / 2) + j * 8 + 2 * tg;
            float2 v0, v1;
            v0.x = alpha * c[i][j][0]; v0.y = alpha * c[i][j][1];
            v1.x = alpha * c[i][j][2]; v1.y = alpha * c[i][j][3];
            if (bias) {
                float2 bb2 = *(const float2*)&bias[col];
                v0.x += bb2.x; v0.y += bb2.y;
                v1.x += bb2.x; v1.y += bb2.y;
            }
            if (betaI != 0.f) {
                if (row0 == col)     v0.x += betaI;
                if (row0 == col + 1) v0.y += betaI;
                if (row1 == col)     v1.x += betaI;
                if (row1 == col + 1) v1.y += betaI;
            }
            if (addp) {
                float2 a0 = *(const float2*)&addp[(long long)row0 * Ndim + col];
                float2 a1 = *(const float2*)&addp[(long long)row1 * Ndim + col];
                v0.x += addScale * a0.x; v0.y += addScale * a0.y;
                v1.x += addScale * a1.x; v1.y += addScale * a1.y;
            }
            if (relu) {
                v0.x = fmaxf(v0.x, 0.f); v0.y = fmaxf(v0.y, 0.f);
                v1.x = fmaxf(v1.x, 0.f); v1.y = fmaxf(v1.y, 0.f);
            }
            if (mode == 0) {
                *(float2*)&C[(long long)row0 * Ndim + col] = v0;
                *(float2*)&C[(long long)row1 * Ndim + col] = v1;
            } else if (mode == 1) {
                int kind = col >> 9, cc = col & 511;
                int hh = cc >> 6, d = cc & 63;
                float* dst = (kind == 0) ? C : (kind == 1) ? out2 : out3;
                float sc = (kind == 0) ? QSCALE : 1.f;
                int b0 = row0 / NPAD, n0r = row0 - b0 * NPAD;
                int b1r = row1 / NPAD, n1r = row1 - b1r * NPAD;
                float2 w0 = make_float2(v0.x * sc, v0.y * sc);
                float2 w1 = make_float2(v1.x * sc, v1.y * sc);
                *(float2*)&dst[(((long long)(b0 * NH + hh) * NPAD) + n0r) * HD + d] = w0;
                *(float2*)&dst[(((long long)(b1r * NH + hh) * NPAD) + n1r) * HD + d] = w1;
            } else if (mode == 2) {
                int b = zb >> 3, hh = zb & 7;
                *(float2*)&C[((long long)(b * NPAD + row0) * EMB) + hh * 64 + col] = v0;
                *(float2*)&C[((long long)(b * NPAD + row1) * EMB) + hh * 64 + col] = v1;
            } else if (mode == 3) {
                int b0 = row0 / NPAD, n0r = row0 - b0 * NPAD;
                int b1r = row1 / NPAD, n1r = row1 - b1r * NPAD;
                if (n0r >= PADR) {
                    long long a = ((long long)(b0 * NT + n0r - PADR) * EMB) + col;
                    float2 old = *(float2*)&C[a];
                    v0.x += old.x; v0.y += old.y;
                    *(float2*)&C[a] = v0;
                }
                if (n1r >= PADR) {
                    long long a = ((long long)(b1r * NT + n1r - PADR) * EMB) + col;
                    float2 old = *(float2*)&C[a];
                    v1.x += old.x; v1.y += old.y;
                    *(float2*)&C[a] = v1;
                }
            } else { // mode 4
                int b0 = row0 >> 12, n0r = row0 & 4095;
                int b1r = row1 >> 12, n1r = row1 & 4095;
                *(float2*)&C[((long long)(b0 * NT + 1 + n0r) * EMB) + col] = v0;
                *(float2*)&C[((long long)(b1r * NT + 1 + n1r) * EMB) + col] = v1;
            }
        }
    }
}

static void gemm(cudaStream_t st, const float* A, const float* Bm, float* C,
                 int M_, int N_, int K_,
                 long long sA, long long sB, long long sC, int batch, bool transB,
                 float alpha = 1.f, float betaI = 0.f,
                 const float* bias = nullptr, int relu = 0,
                 const float* addp = nullptr, float addScale = 0.f, long long sAdd = 0,
                 int mode = 0, float* out2 = nullptr, float* out3 = nullptr,
                 int fast = 0)
{
    long long ctas128 = (N_ % 128 == 0) ? (long long)(N_ / 128) * (M_ / 128) * batch : 0;
    const bool big = (N_ % 128 == 0) && (ctas128 >= 256);
    dim3 grid(N_ / (big ? 128 : 64), M_ / 128, batch);
    if (big) {
        if (fast) {
            if (transB) gemm_tc<true, 128, true><<<grid, 256, 0, st>>>(A, Bm, C, M_, N_, K_, sA, sB, sC, alpha, betaI, bias, relu, addp, addScale, sAdd, mode, out2, out3);
            else        gemm_tc<false,128, true><<<grid, 256, 0, st>>>(A, Bm, C, M_, N_, K_, sA, sB, sC, alpha, betaI, bias, relu, addp, addScale, sAdd, mode, out2, out3);
        } else {
            if (transB) gemm_tc<true, 128, false><<<grid, 256, 0, st>>>(A, Bm, C, M_, N_, K_, sA, sB, sC, alpha, betaI, bias, relu, addp, addScale, sAdd, mode, out2, out3);
            else        gemm_tc<false,128, false><<<grid, 256, 0, st>>>(A, Bm, C, M_, N_, K_, sA, sB, sC, alpha, betaI, bias, relu, addp, addScale, sAdd, mode, out2, out3);
        }
    } else {
        if (fast) {
            if (transB) gemm_tc<true, 64, true><<<grid, 256, 0, st>>>(A, Bm, C, M_, N_, K_, sA, sB, sC, alpha, betaI, bias, relu, addp, addScale, sAdd, mode, out2, out3);
            else        gemm_tc<false, 64, true><<<grid, 256, 0, st>>>(A, Bm, C, M_, N_, K_, sA, sB, sC, alpha, betaI, bias, relu, addp, addScale, sAdd, mode, out2, out3);
        } else {
            if (transB) gemm_tc<true, 64, false><<<grid, 256, 0, st>>>(A, Bm, C, M_, N_, K_, sA, sB, sC, alpha, betaI, bias, relu, addp, addScale, sAdd, mode, out2, out3);
            else        gemm_tc<false, 64, false><<<grid, 256, 0, st>>>(A, Bm, C, M_, N_, K_, sA, sB, sC, alpha, betaI, bias, relu, addp, addScale, sAdd, mode, out2, out3);
        }
    }
}

// ---------------- cls rows ----------------
__global__ void cls_k(const float* __restrict__ cls)
{
    int c = threadIdx.x;
    #pragma unroll
    for (int b = 0; b < BB; b++)
        g_h[(long long)b * NT * EMB + c] = cls[c];
}

// ---------------- layer norm + front zero-pad into g_x ----------------
__global__ void ln_pad_k(const float* __restrict__ gg, const float* __restrict__ bb)
{
    int n = blockIdx.x, b = blockIdx.y;
    int tid = threadIdx.x;
    float* out = g_x + ((long long)b * NPAD + n) * EMB;
    if (n < PADR) { out[tid] = 0.f; out[tid + 256] = 0.f; return; }
    const float* in = g_h + ((long long)b * NT + (n - PADR)) * EMB;
    float x0 = in[tid], x1 = in[tid + 256];
    __shared__ float sd[256];
    sd[tid] = x0 + x1; __syncthreads();
    for (int s = 128; s > 0; s >>= 1) { if (tid < s) sd[tid] += sd[tid + s]; __syncthreads(); }
    float mu = sd[0] * (1.f / EMB);
    __syncthreads();
    float d0 = x0 - mu, d1 = x1 - mu;
    sd[tid] = d0 * d0 + d1 * d1; __syncthreads();
    for (int s = 128; s > 0; s >>= 1) { if (tid < s) sd[tid] += sd[tid + s]; __syncthreads(); }
    float rs = rsqrtf(sd[0] * (1.f / EMB) + 1e-5f);
    out[tid]       = d0 * rs * gg[tid]       + bb[tid];
    out[tid + 256] = d1 * rs * gg[tid + 256] + bb[tid + 256];
}

// ---------------- landmark means ----------------
__global__ void land_k(const float* __restrict__ src, float* __restrict__ dst)
{
    int d = threadIdx.x;
    int m = blockIdx.x;
    int bh = blockIdx.y;
    const float* p = src + (((long long)bh * NPAD) + (long long)m * LCH) * HD + d;
    float s = 0.f;
    #pragma unroll
    for (int i = 0; i < LCH; i++) s += p[(long long)i * HD];
    dst[(((long long)bh * NLM) + m) * HD + d] = s * (1.f / LCH);
}

// ---------------- single-pass softmax, len 256 ----------------
__global__ void softmax256_k(float* __restrict__ x)
{
    long long row = (long long)blockIdx.x * 8 + (threadIdx.x >> 5);
    int lane = threadIdx.x & 31;
    float* p = x + row * 256;
    float v[8];
    float m = -1e30f;
    #pragma unroll
    for (int i = 0; i < 8; i++) { v[i] = p[lane + 32 * i]; m = fmaxf(m, v[i]); }
    #pragma unroll
    for (int o = 16; o > 0; o >>= 1) m = fmaxf(m, __shfl_xor_sync(0xffffffffu, m, o));
    float s = 0.f;
    #pragma unroll
    for (int i = 0; i < 8; i++) { v[i] = expf(v[i] - m); s += v[i]; }
    #pragma unroll
    for (int o = 16; o > 0; o >>= 1) s += __shfl_xor_sync(0xffffffffu, s, o);
    float r = 1.f / s;
    #pragma unroll
    for (int i = 0; i < 8; i++) p[lane + 32 * i] = v[i] * r;
}

// ---------------- single-pass softmax, len 4352 ----------------
__global__ void softmax4352_k(float* __restrict__ x)
{
    long long row = blockIdx.x;
    float* p = x + row * 4352;
    int tid = threadIdx.x;
    float v[17];
    float m = -1e30f;
    #pragma unroll
    for (int i = 0; i < 17; i++) { v[i] = p[tid + 256 * i]; m = fmaxf(m, v[i]); }
    __shared__ float sd[8];
    #pragma unroll
    for (int o = 16; o > 0; o >>= 1) m = fmaxf(m, __shfl_xor_sync(0xffffffffu, m, o));
    if ((tid & 31) == 0) sd[tid >> 5] = m;
    __syncthreads();
    if (tid < 8) {
        float t = sd[tid];
        #pragma unroll
        for (int o = 4; o > 0; o >>= 1) t = fmaxf(t, __shfl_xor_sync(0xffu, t, o));
        sd[tid] = t;
    }
    __syncthreads();
    m = sd[0];
    float s = 0.f;
    #pragma unroll
    for (int i = 0; i < 17; i++) { v[i] = expf(v[i] - m); s += v[i]; }
    __syncthreads();
    #pragma unroll
    for (int o = 16; o > 0; o >>= 1) s += __shfl_xor_sync(0xffffffffu, s, o);
    if ((tid & 31) == 0) sd[tid >> 5] = s;
    __syncthreads();
    if (tid < 8) {
        float t = sd[tid];
        #pragma unroll
        for (int o = 4; o > 0; o >>= 1) t += __shfl_xor_sync(0xffu, t, o);
        sd[tid] = t;
    }
    __syncthreads();
    float r = 1.f / sd[0];
    #pragma unroll
    for (int i = 0; i < 17; i++) p[tid + 256 * i] = v[i] * r;
}

// ---------------- pinv helpers ----------------
__global__ void reset_red_k() { if (threadIdx.x < 2) g_red[threadIdx.x] = 0u; }

__global__ void denom_k()
{
    int bh = blockIdx.x, tid = threadIdx.x;
    const float* mat = g_s2 + (long long)bh * NLM * NLM;
    float col = 0.f, rs = 0.f;
    for (int i = 0; i < NLM; i++) col += mat[i * NLM + tid];
    for (int j = 0; j < NLM; j++) rs  += mat[tid * NLM + j];
    __shared__ float sd[256];
    sd[tid] = rs; __syncthreads();
    for (int s = 128; s > 0; s >>= 1) { if (tid < s) sd[tid] = fmaxf(sd[tid], sd[tid + s]); __syncthreads(); }
    if (tid == 0) atomicMax(&g_red[0], __float_as_uint(sd[0]));
    __syncthreads();
    sd[tid] = col; __syncthreads();
    for (int s = 128; s > 0; s >>= 1) { if (tid < s) sd[tid] = fmaxf(sd[tid], sd[tid + s]); __syncthreads(); }
    if (tid == 0) atomicMax(&g_red[1], __float_as_uint(sd[0]));
}

__global__ void initz_k()
{
    long long idx = (long long)blockIdx.x * 256 + threadIdx.x;
    float rd = 1.f / (__uint_as_float(g_red[0]) * __uint_as_float(g_red[1]));
    int ij = (int)(idx & 65535);
    long long bh = idx >> 16;
    int i = ij >> 8, j = ij & 255;
    g_z[idx] = g_s2[(bh << 16) + (long long)j * NLM + i] * rd;
}

// ---------------- depthwise 33-tap residual conv on v, added into g_attn ----------------
__global__ void resconv_k(const float* __restrict__ w)
{
    int d = threadIdx.x;
    int n = blockIdx.x;
    int bh = blockIdx.y;
    int hh = bh & 7, b = bh >> 3;
    __shared__ float sw[33];
    if (d < 33) sw[d] = w[hh * 33 + d];
    __syncthreads();
    const float* vp = g_v + ((long long)bh * NPAD) * HD + d;
    float acc = 0.f;
    #pragma unroll
    for (int j = 0; j < 33; j++) {
        int nn = n + j - 16;
        if (nn >= 0 && nn < NPAD) acc += sw[j] * vp[(long long)nn * HD];
    }
    g_attn[((long long)(b * NPAD + n) * EMB) + hh * 64 + d] += acc;
}

// ---------------- token<->image transposes ----------------
__global__ void tok2img_k()
{
    __shared__ float t[32][33];
    int b = blockIdx.z;
    int c0 = blockIdx.x * 32, p0 = blockIdx.y * 32;
    int tx = threadIdx.x, ty = threadIdx.y;
    #pragma unroll
    for (int j = 0; j < 32; j += 8)
        t[ty + j][tx] = g_h[((long long)b * NT + 1 + p0 + ty + j) * EMB + c0 + tx];
    __syncthreads();
    #pragma unroll
    for (int j = 0; j < 32; j += 8)
        g_cnn[((long long)b * EMB + c0 + ty + j) * (GRD * GRD) + p0 + tx] = t[tx][ty + j];
}

__global__ void img2tok_k()
{
    __shared__ float t[32][33];
    int b = blockIdx.z;
    int c0 = blockIdx.x * 32, p0 = blockIdx.y * 32;
    int tx = threadIdx.x, ty = threadIdx.y;
    #pragma unroll
    for (int j = 0; j < 32; j += 8)
        t[ty + j][tx] = g_cnn2[((long long)b * EMB + c0 + ty + j) * (GRD * GRD) + p0 + tx];
    __syncthreads();
    #pragma unroll
    for (int j = 0; j < 32; j += 8)
        g_h[((long long)b * NT + 1 + p0 + ty + j) * EMB + c0 + tx] = t[tx][ty + j];
}

// ---------------- fused 7x7 + 5x5 + 3x3 depthwise conv + identity ----------------
__global__ void dwconv_k(const float* __restrict__ w7, const float* __restrict__ b7,
                         const float* __restrict__ w5, const float* __restrict__ b5,
                         const float* __restrict__ w3, const float* __restrict__ b3)
{
    int bc = blockIdx.z;
    int c  = bc % EMB;
    const float* img = g_cnn + (long long)bc * GRD * GRD;
    __shared__ float tile[22][22];
    __shared__ float sw7[49], sw5[25], sw3[9];
    int tx = threadIdx.x, ty = threadIdx.y;
    int tid = ty * 16 + tx;
    if (tid < 49) sw7[tid] = w7[c * 49 + tid];
    if (tid < 25) sw5[tid] = w5[c * 25 + tid];
    if (tid < 9)  sw3[tid] = w3[c * 9  + tid];
    int ox0 = blockIdx.x * 16, oy0 = blockIdx.y * 16;
    for (int i = tid; i < 22 * 22; i += 256) {
        int yy = i / 22, xx = i % 22;
        int gy = oy0 - 3 + yy, gx = ox0 - 3 + xx;
        tile[yy][xx] = (gy >= 0 && gy < GRD && gx >= 0 && gx < GRD) ? img[gy * GRD + gx] : 0.f;
    }
    __syncthreads();
    float acc = tile[ty + 3][tx + 3] + b7[c] + b5[c] + b3[c];
    #pragma unroll
    for (int ky = 0; ky < 7; ky++)
        #pragma unroll
        for (int kx = 0; kx < 7; kx++)
            acc += sw7[ky * 7 + kx] * tile[ty + ky][tx + kx];
    #pragma unroll
    for (int ky = 0; ky < 5; ky++)
        #pragma unroll
        for (int kx = 0; kx < 5; kx++)
            acc += sw5[ky * 5 + kx] * tile[ty + 1 + ky][tx + 1 + kx];
    #pragma unroll
    for (int ky = 0; ky < 3; ky++)
        #pragma unroll
        for (int kx = 0; kx < 3; kx++)
            acc += sw3[ky * 3 + kx] * tile[ty + 2 + ky][tx + 2 + kx];
    g_cnn2[(long long)bc * GRD * GRD + (oy0 + ty) * GRD + ox0 + tx] = acc;
}

// ---------------- final LN(cls) -> logits -> softmax -> argmax ----------------
__global__ void head_k(const float* __restrict__ gg, const float* __restrict__ bb,
                       const float* __restrict__ W2, const float* __restrict__ b2,
                       float* __restrict__ out, int out_size)
{
    int tid = threadIdx.x; // 512
    __shared__ float sd[512];
    __shared__ float res[20];
    for (int b = 0; b < BB; b++) {
        float x = g_h[(long long)b * NT * EMB + tid];
        sd[tid] = x; __syncthreads();
        for (int s = 256; s > 0; s >>= 1) { if (tid < s) sd[tid] += sd[tid + s]; __syncthreads(); }
        float mu = sd[0] * (1.f / EMB); __syncthreads();
        float dx = x - mu;
        sd[tid] = dx * dx; __syncthreads();
        for (int s = 256; s > 0; s >>= 1) { if (tid < s) sd[tid] += sd[tid + s]; __syncthreads(); }
        float rs = rsqrtf(sd[0] * (1.f / EMB) + 1e-5f); __syncthreads();
        float xn = dx * rs * gg[tid] + bb[tid];
        sd[tid] = xn * W2[tid]; __syncthreads();
        for (int s = 256; s > 0; s >>= 1) { if (tid < s) sd[tid] += sd[tid + s]; __syncthreads(); }
        float l0 = sd[0] + b2[0]; __syncthreads();
        sd[tid] = xn * W2[EMB + tid]; __syncthreads();
        for (int s = 256; s > 0; s >>= 1) { if (tid < s) sd[tid] += sd[tid + s]; __syncthreads(); }
        float l1 = sd[0] + b2[1]; __syncthreads();
        if (tid == 0) {
            float mx = fmaxf(l0, l1);
            float e0 = expf(l0 - mx), e1 = expf(l1 - mx);
            float s = e0 + e1;
            res[b * 2]     = l0;
            res[b * 2 + 1] = l1;
            res[8 + b * 2]     = e0 / s;
            res[8 + b * 2 + 1] = e1 / s;
            res[16 + b] = (l1 > l0) ? 1.f : 0.f;
        }
        __syncthreads();
    }
    if (tid < 20 && tid < out_size) out[tid] = res[tid];
}

// ---------------- host orchestration ----------------
#define SYM(p, s) do { void* _t = nullptr; cudaGetSymbolAddress(&_t, s); p = (float*)_t; } while (0)

static cudaStream_t g_sB = nullptr;
static cudaEvent_t  g_evF[2], g_evJ[2];
static void ensure_streams()
{
    static bool done = false;
    if (!done) {
        cudaStreamCreateWithFlags(&g_sB, cudaStreamNonBlocking);
        for (int i = 0; i < 2; i++) {
            cudaEventCreateWithFlags(&g_evF[i], cudaEventDisableTiming);
            cudaEventCreateWithFlags(&g_evJ[i], cudaEventDisableTiming);
        }
        done = true;
    }
}

static void run_attn(int layer, const float* ln_g, const float* ln_b, const float* Wqkv,
                     const float* Wo, const float* bo, const float* res)
{
    float *x_, *q_, *k_, *v_, *ql_, *kl_, *s1_, *s2_, *s3_;
    float *z_, *z2_, *t0_, *t1_, *t2_, *av_, *u_, *attn_, *h_;
    SYM(x_, g_x); SYM(q_, g_q); SYM(k_, g_k); SYM(v_, g_v);
    SYM(ql_, g_ql); SYM(kl_, g_kl); SYM(s1_, g_s1); SYM(s2_, g_s2); SYM(s3_, g_s3);
    SYM(z_, g_z); SYM(z2_, g_z2); SYM(t0_, g_t0); SYM(t1_, g_t1); SYM(t2_, g_t2);
    SYM(av_, g_av); SYM(u_, g_u); SYM(attn_, g_attn); SYM(h_, g_h);

    cudaStream_t s0 = 0, sB = g_sB;

    ln_pad_k<<<dim3(NPAD, BB), 256, 0, s0>>>(ln_g, ln_b);
    gemm(s0, x_, Wqkv, q_, BB * NPAD, 3 * EMB, EMB, 0, 0, 0, 1, true,
         1.f, 0.f, nullptr, 0, nullptr, 0.f, 0, 1, k_, v_);
    land_k<<<dim3(NLM, BB * NH), 64, 0, s0>>>(q_, ql_);
    land_k<<<dim3(NLM, BB * NH), 64, 0, s0>>>(k_, kl_);

    // ---- fork: branch B (s2 + pinv chain) on sB ----
    cudaEventRecord(g_evF[layer], s0);
    cudaStreamWaitEvent(sB, g_evF[layer], 0);

    // branch B
    gemm(sB, ql_, kl_, s2_, NLM, NLM, HD,
         (long long)NLM * HD, (long long)NLM * HD, (long long)NLM * NLM, BB * NH, true);
    softmax256_k<<<BB * NH * NLM / 8, 256, 0, sB>>>(s2_);
    reset_red_k<<<1, 32, 0, sB>>>();
    denom_k<<<BB * NH, 256, 0, sB>>>();
    initz_k<<<(BB * NH * NLM * NLM) / 256, 256, 0, sB>>>();
    float* zi = z_;
    float* zo = z2_;
    for (int it = 0; it < 6; it++) {
        // iterations 0-4: single-pass tf32 (Newton-Schulz is self-correcting);
        // final iteration: full 3xTF32 precision.
        int fast = (it < 5) ? 1 : 0;
        gemm(sB, s2_, zi, t0_, NLM, NLM, NLM, 65536, 65536, 65536, BB * NH, false,
             1.f, 0.f, nullptr, 0, nullptr, 0.f, 0, 0, nullptr, nullptr, fast);
        gemm(sB, t0_, t0_, t2_, NLM, NLM, NLM, 65536, 65536, 65536, BB * NH, false,
             1.f, 15.f, nullptr, 0, t0_, -7.f, 65536, 0, nullptr, nullptr, fast);
        gemm(sB, t0_, t2_, t1_, NLM, NLM, NLM, 65536, 65536, 65536, BB * NH, false,
             -1.f, 13.f, nullptr, 0, nullptr, 0.f, 0, 0, nullptr, nullptr, fast);
        gemm(sB, zi, t1_, zo, NLM, NLM, NLM, 65536, 65536, 65536, BB * NH, false,
             0.25f, 0.f, nullptr, 0, nullptr, 0.f, 0, 0, nullptr, nullptr, fast);
        float* tmp = zi; zi = zo; zo = tmp;
    }
    cudaEventRecord(g_evJ[layer], sB);

    // branch A (origin stream)
    gemm(s0, q_, kl_, s1_, NPAD, NLM, HD,
         (long long)NPAD * HD, (long long)NLM * HD, (long long)NPAD * NLM, BB * NH, true);
    softmax256_k<<<BB * NH * NPAD / 8, 256, 0, s0>>>(s1_);
    gemm(s0, ql_, k_, s3_, NLM, NPAD, HD,
         (long long)NLM * HD, (long long)NPAD * HD, (long long)NLM * NPAD, BB * NH, true);
    softmax4352_k<<<BB * NH * NLM, 256, 0, s0>>>(s3_);
    gemm(s0, s3_, v_, av_, NLM, HD, NPAD,
         (long long)NLM * NPAD, (long long)NPAD * HD, (long long)NLM * HD, BB * NH, false);

    // ---- join ----
    cudaStreamWaitEvent(s0, g_evJ[layer], 0);

    gemm(s0, zi, av_, u_, NLM, HD, NLM,
         65536, (long long)NLM * HD, (long long)NLM * HD, BB * NH, false);
    gemm(s0, s1_, u_, attn_, NPAD, HD, NLM,
         (long long)NPAD * NLM, (long long)NLM * HD, 0, BB * NH, false,
         1.f, 0.f, nullptr, 0, nullptr, 0.f, 0, 2);

    resconv_k<<<dim3(NPAD, BB * NH), 64, 0, s0>>>(res);
    gemm(s0, attn_, Wo, h_, BB * NPAD, EMB, EMB, 0, 0, 0, 1, true,
         1.f, 0.f, bo, 0, nullptr, 0.f, 0, 3);
}

extern "C" void kernel_launch(void* const* d_in, const int* in_sizes, int n_in,
                              void* d_out, int out_size)
{
    ensure_streams();

    const float* data  = (const float*)d_in[0];
    const float* W1    = (const float*)d_in[1];
    const float* b1    = (const float*)d_in[2];
    const float* cls   = (const float*)d_in[3];
    const float* ln1_g = (const float*)d_in[4];
    const float* ln1_b = (const float*)d_in[5];
    const float* Wqkv1 = (const float*)d_in[6];
    const float* Wo1   = (const float*)d_in[7];
    const float* bo1   = (const float*)d_in[8];
    const float* res1  = (const float*)d_in[9];
    const float* ln2_g = (const float*)d_in[10];
    const float* ln2_b = (const float*)d_in[11];
    const float* Wqkv2 = (const float*)d_in[12];
    const float* Wo2   = (const float*)d_in[13];
    const float* bo2   = (const float*)d_in[14];
    const float* res2  = (const float*)d_in[15];
    const float* pw7   = (const float*)d_in[16];
    const float* pb7   = (const float*)d_in[17];
    const float* pw5   = (const float*)d_in[18];
    const float* pb5   = (const float*)d_in[19];
    const float* pw3   = (const float*)d_in[20];
    const float* pb3   = (const float*)d_in[21];
    const float* lnf_g = (const float*)d_in[22];
    const float* lnf_b = (const float*)d_in[23];
    const float* W2    = (const float*)d_in[24];
    const float* b2    = (const float*)d_in[25];

    float* h_;
    SYM(h_, g_h);

    // stage 1: h[1:] = relu(data @ W1^T + b1) (mode 4 shift), cls row separately
    gemm(0, data, W1, h_, BB * N0, EMB, C0, 0, 0, 0, 1, true,
         1.f, 0.f, b1, 1, nullptr, 0.f, 0, 4);
    cls_k<<<1, 512>>>(cls);

    // stage 2: first Nystrom attention block (residual)
    run_attn(0, ln1_g, ln1_b, Wqkv1, Wo1, bo1, res1);

    // stage 3: PPEG conv block on the 64x64 token grid (cls row untouched)
    tok2img_k<<<dim3(EMB / 32, (GRD * GRD) / 32, BB), dim3(32, 8)>>>();
    dwconv_k<<<dim3(GRD / 16, GRD / 16, BB * EMB), dim3(16, 16)>>>(pw7, pb7, pw5, pb5, pw3, pb3);
    img2tok_k<<<dim3(EMB / 32, (GRD * GRD) / 32, BB), dim3(32, 8)>>>();

    // stage 4: second Nystrom attention block (residual)
    run_attn(1, ln2_g, ln2_b, Wqkv2, Wo2, bo2, res2);

    // stage 5: final LN on cls token + classification head
    head_k<<<1, 512>>>(lnf_g, lnf_b, W2, b2, (float*)d_out, out_size);
}

// round 15
// speedup vs baseline: 2.3091x; 1.0410x over previous
#include <cuda_runtime.h>
#include <math.h>

#define BB   4
#define N0   4096
#define C0   1536
#define EMB  512
#define NH   8
#define HD   64
#define NT   4097
#define NPAD 4352
#define PADR 255
#define NLM  256
#define LCH  17
#define GRD  64
#define QSCALE 0.125f

// ---------------- static device scratch (no allocations allowed) ----------------
__device__ float g_h   [BB*NT*EMB];
__device__ float g_x   [BB*NPAD*EMB];
__device__ float g_q   [BB*NH*NPAD*HD];
__device__ float g_k   [BB*NH*NPAD*HD];
__device__ float g_v   [BB*NH*NPAD*HD];
__device__ float g_ql  [BB*NH*NLM*HD];
__device__ float g_kl  [BB*NH*NLM*HD];
__device__ float g_s1  [(long long)BB*NH*NPAD*NLM];
__device__ float g_s2  [BB*NH*NLM*NLM];
__device__ float g_s3  [(long long)BB*NH*NLM*NPAD];
__device__ float g_z   [BB*NH*NLM*NLM];
__device__ float g_z2  [BB*NH*NLM*NLM];
__device__ float g_t0  [BB*NH*NLM*NLM];
__device__ float g_t1  [BB*NH*NLM*NLM];
__device__ float g_t2  [BB*NH*NLM*NLM];
__device__ float g_av  [BB*NH*NLM*HD];
__device__ float g_u   [BB*NH*NLM*HD];
__device__ float g_attn[BB*NPAD*EMB];
__device__ float g_cnn [BB*EMB*GRD*GRD];
__device__ float g_cnn2[BB*EMB*GRD*GRD];
__device__ unsigned g_red[2];

// ---------------- tf32 helpers ----------------
__device__ __forceinline__ unsigned f2tf(float v)
{
    unsigned r;
    asm("cvt.rna.tf32.f32 %0, %1;" : "=r"(r) : "f"(v));
    return r;
}

// Bitmask hi/lo split for the 3-MMA path.
__device__ __forceinline__ void split_tf32(float v, unsigned& hi, unsigned& lo)
{
    hi = __float_as_uint(v) & 0xFFFFE000u;
    lo = __float_as_uint(v - __uint_as_float(hi));
}

__device__ __forceinline__ void mma_tf32(float c[4], const unsigned a[4], const unsigned b[2])
{
    asm volatile("mma.sync.aligned.m16n8k8.row.col.f32.tf32.tf32.f32 "
                 "{%0,%1,%2,%3}, {%4,%5,%6,%7}, {%8,%9}, {%0,%1,%2,%3};"
                 : "+f"(c[0]), "+f"(c[1]), "+f"(c[2]), "+f"(c[3])
                 : "r"(a[0]), "r"(a[1]), "r"(a[2]), "r"(a[3]), "r"(b[0]), "r"(b[1]));
}

// ---------------- batched TF32 tensor-core GEMM, fragment-packed smem ----------------
// Block tile 128 x BN (BN = 64 or 128), 8 warps.
// FAST=1: single-pass tf32 (rna), no lo plane. FAST=0: 3xTF32 (fp32-class accuracy).
// Epilogue modes:
//  0: plain  1: QKV split  2: merge heads  3: Wo+residual  4: stage1 shift
template<bool TRANSB, int BN, bool FAST>
__global__ void __launch_bounds__(256, 2)
gemm_tc(const float* __restrict__ A, const float* __restrict__ Bm,
        float* __restrict__ C,
        int Mdim, int Ndim, int Kdim,
        long long sA, long long sB, long long sC,
        float alpha, float betaI,
        const float* __restrict__ bias, int relu,
        const float* __restrict__ addp, float addScale, long long sAdd,
        int mode, float* __restrict__ out2, float* __restrict__ out3)
{
    constexpr int BWORDS = BN * 8;
    constexpr int BELEM  = BWORDS / 256;
    constexpr int NTJ    = BN / 16;

    __shared__ float    Af[2][1024];
    __shared__ unsigned Bhs[2][BWORDS], Bls[2][BWORDS];

    const int zb = blockIdx.z;
    A  += (long long)zb * sA;
    Bm += (long long)zb * sB;
    C  += (long long)zb * sC;
    if (addp) addp += (long long)zb * sAdd;

    const int m0 = blockIdx.y * 128;
    const int n0 = blockIdx.x * BN;
    const int tid  = threadIdx.x;
    const int lane = tid & 31;
    const int warp = tid >> 5;
    const int wm = warp & 3;
    const int wn = warp >> 2;
    const int g  = lane >> 2;
    const int tg = lane & 3;

    int aAddr[4], bAddr[BELEM];
    long long offA[4], offB[BELEM];
    #pragma unroll
    for (int r = 0; r < 4; r++) {
        int i = tid + r * 256;
        int m = i >> 3, kk = i & 7;
        int t = m >> 4, gg2 = m & 7, hi8 = (m >> 3) & 1;
        int ttg = kk & 3, kh = kk >> 2;
        aAddr[r] = t * 128 + (gg2 * 4 + ttg) * 4 + hi8 + 2 * kh;
        offA[r]  = (long long)(m0 + m) * Kdim + kk;
    }
    #pragma unroll
    for (int r = 0; r < BELEM; r++) {
        int i = tid + r * 256;
        int n, kk;
        if (TRANSB) { n = i >> 3; kk = i & 7; offB[r] = (long long)(n0 + n) * Kdim + kk; }
        else {
            if (BN == 64) { kk = i >> 6; n = i & 63; }
            else          { kk = i >> 7; n = i & 127; }
            offB[r] = (long long)kk * Ndim + n0 + n;
        }
        int j = n >> 3;
        int ln = (n & 7) * 4 + (kk & 3);
        int kh = kk >> 2;
        if (BN == 64) {
            bAddr[r] = j * 64 + ((2 * ln + 2 * j) & 63) + kh;
        } else {
            int p = j >> 1, q = j & 1;
            int base = p * 128 + 4 * ln;
            bAddr[r] = (base ^ ((base >> 3) & 0x1C)) + 2 * q + kh;
        }
    }
    const long long bStep = TRANSB ? 8 : (long long)8 * Ndim;

    float c[2][NTJ][4];
    #pragma unroll
    for (int i = 0; i < 2; i++)
        #pragma unroll
        for (int j = 0; j < NTJ; j++)
            #pragma unroll
            for (int r = 0; r < 4; r++) c[i][j][r] = 0.f;

    const int nsteps = Kdim >> 3;
    float ra[4], rb[BELEM];

    {
        #pragma unroll
        for (int r = 0; r < 4; r++) Af[0][aAddr[r]] = A[offA[r]];
        #pragma unroll
        for (int r = 0; r < BELEM; r++) {
            float v = Bm[offB[r]];
            if (FAST) {
                Bhs[0][bAddr[r]] = f2tf(v);
            } else {
                unsigned h, l;
                split_tf32(v, h, l);
                Bhs[0][bAddr[r]] = h;
                Bls[0][bAddr[r]] = l;
            }
        }
    }
    __syncthreads();
    const float* Ap = A + 8;
    const float* Bp = Bm + bStep;

    int buf = 0;
    for (int s = 0; s < nsteps; s++) {
        if (s + 1 < nsteps) {
            #pragma unroll
            for (int r = 0; r < 4; r++) ra[r] = Ap[offA[r]];
            #pragma unroll
            for (int r = 0; r < BELEM; r++) rb[r] = Bp[offB[r]];
            Ap += 8;
            Bp += bStep;
        }

        {
            unsigned ah[2][4], al[2][4];
            #pragma unroll
            for (int i = 0; i < 2; i++) {
                int base = (wm * 2 + i) * 128 + lane * 4;
                float4 v4 = *(const float4*)&Af[buf][base];
                float vv[4] = {v4.x, v4.y, v4.z, v4.w};
                #pragma unroll
                for (int r = 0; r < 4; r++) {
                    if (FAST) ah[i][r] = f2tf(vv[r]);
                    else      split_tf32(vv[r], ah[i][r], al[i][r]);
                }
            }
            if (BN == 64) {
                #pragma unroll
                for (int j = 0; j < NTJ; j++) {
                    int jt = wn * 4 + j;
                    int base = jt * 64 + ((2 * lane + 2 * jt) & 63);
                    uint2 vh = *(const uint2*)&Bhs[buf][base];
                    unsigned bh[2] = {vh.x, vh.y};
                    #pragma unroll
                    for (int i = 0; i < 2; i++) {
                        mma_tf32(c[i][j], ah[i], bh);
                        if (!FAST) {
                            uint2 vl = *(const uint2*)&Bls[buf][base];
                            unsigned bl[2] = {vl.x, vl.y};
                            mma_tf32(c[i][j], ah[i], bl);
                            mma_tf32(c[i][j], al[i], bh);
                        }
                    }
                }
            } else {
                #pragma unroll
                for (int p4 = 0; p4 < 4; p4++) {
                    int p = wn * 4 + p4;
                    int base = p * 128 + lane * 4;
                    base ^= (base >> 3) & 0x1C;
                    uint4 vh = *(const uint4*)&Bhs[buf][base];
                    unsigned bh0[2] = {vh.x, vh.y}, bh1[2] = {vh.z, vh.w};
                    if (FAST) {
                        #pragma unroll
                        for (int i = 0; i < 2; i++) {
                            mma_tf32(c[i][2 * p4],     ah[i], bh0);
                            mma_tf32(c[i][2 * p4 + 1], ah[i], bh1);
                        }
                    } else {
                        uint4 vl = *(const uint4*)&Bls[buf][base];
                        unsigned bl0[2] = {vl.x, vl.y}, bl1[2] = {vl.z, vl.w};
                        #pragma unroll
                        for (int i = 0; i < 2; i++) {
                            mma_tf32(c[i][2 * p4],     ah[i], bh0);
                            mma_tf32(c[i][2 * p4],     ah[i], bl0);
                            mma_tf32(c[i][2 * p4],     al[i], bh0);
                            mma_tf32(c[i][2 * p4 + 1], ah[i], bh1);
                            mma_tf32(c[i][2 * p4 + 1], ah[i], bl1);
                            mma_tf32(c[i][2 * p4 + 1], al[i], bh1);
                        }
                    }
                }
            }
        }

        if (s + 1 < nsteps) {
            int nb = buf ^ 1;
            #pragma unroll
            for (int r = 0; r < 4; r++) Af[nb][aAddr[r]] = ra[r];
            #pragma unroll
            for (int r = 0; r < BELEM; r++) {
                if (FAST) {
                    Bhs[nb][bAddr[r]] = f2tf(rb[r]);
                } else {
                    unsigned h, l;
                    split_tf32(rb[r], h, l);
                    Bhs[nb][bAddr[r]] = h;
                    Bls[nb][bAddr[r]] = l;
                }
            }
            __syncthreads();
            buf = nb;
        }
    }

    // ---- epilogue ----
    #pragma unroll
    for (int i = 0; i < 2; i++) {
        #pragma unroll
        for (int j = 0; j < NTJ; j++) {
            int row0 = m0 + wm * 32 + i * 16 + g;
            int row1 = row0 + 8;
            int col  = n0 + wn * (BN / 2) + j * 8 + 2 * tg;
            float2 v0, v1;
            v0.x = alpha * c[i][j][0]; v0.y = alpha * c[i][j][1];
            v1.x = alpha * c[i][j][2]; v1.y = alpha * c[i][j][3];
            if (bias) {
                float2 bb2 = *(const float2*)&bias[col];
                v0.x += bb2.x; v0.y += bb2.y;
                v1.x += bb2.x; v1.y += bb2.y;
            }
            if (betaI != 0.f) {
                if (row0 == col)     v0.x += betaI;
                if (row0 == col + 1) v0.y += betaI;
                if (row1 == col)     v1.x += betaI;
                if (row1 == col + 1) v1.y += betaI;
            }
            if (addp) {
                float2 a0 = *(const float2*)&addp[(long long)row0 * Ndim + col];
                float2 a1 = *(const float2*)&addp[(long long)row1 * Ndim + col];
                v0.x += addScale * a0.x; v0.y += addScale * a0.y;
                v1.x += addScale * a1.x; v1.y += addScale * a1.y;
            }
            if (relu) {
                v0.x = fmaxf(v0.x, 0.f); v0.y = fmaxf(v0.y, 0.f);
                v1.x = fmaxf(v1.x, 0.f); v1.y = fmaxf(v1.y, 0.f);
            }
            if (mode == 0) {
                *(float2*)&C[(long long)row0 * Ndim + col] = v0;
                *(float2*)&C[(long long)row1 * Ndim + col] = v1;
            } else if (mode == 1) {
                int kind = col >> 9, cc = col & 511;
                int hh = cc >> 6, d = cc & 63;
                float* dst = (kind == 0) ? C : (kind == 1) ? out2 : out3;
                float sc = (kind == 0) ? QSCALE : 1.f;
                int b0 = row0 / NPAD, n0r = row0 - b0 * NPAD;
                int b1r = row1 / NPAD, n1r = row1 - b1r * NPAD;
                float2 w0 = make_float2(v0.x * sc, v0.y * sc);
                float2 w1 = make_float2(v1.x * sc, v1.y * sc);
                *(float2*)&dst[(((long long)(b0 * NH + hh) * NPAD) + n0r) * HD + d] = w0;
                *(float2*)&dst[(((long long)(b1r * NH + hh) * NPAD) + n1r) * HD + d] = w1;
            } else if (mode == 2) {
                int b = zb >> 3, hh = zb & 7;
                *(float2*)&C[((long long)(b * NPAD + row0) * EMB) + hh * 64 + col] = v0;
                *(float2*)&C[((long long)(b * NPAD + row1) * EMB) + hh * 64 + col] = v1;
            } else if (mode == 3) {
                int b0 = row0 / NPAD, n0r = row0 - b0 * NPAD;
                int b1r = row1 / NPAD, n1r = row1 - b1r * NPAD;
                if (n0r >= PADR) {
                    long long a = ((long long)(b0 * NT + n0r - PADR) * EMB) + col;
                    float2 old = *(float2*)&C[a];
                    v0.x += old.x; v0.y += old.y;
                    *(float2*)&C[a] = v0;
                }
                if (n1r >= PADR) {
                    long long a = ((long long)(b1r * NT + n1r - PADR) * EMB) + col;
                    float2 old = *(float2*)&C[a];
                    v1.x += old.x; v1.y += old.y;
                    *(float2*)&C[a] = v1;
                }
            } else { // mode 4
                int b0 = row0 >> 12, n0r = row0 & 4095;
                int b1r = row1 >> 12, n1r = row1 & 4095;
                *(float2*)&C[((long long)(b0 * NT + 1 + n0r) * EMB) + col] = v0;
                *(float2*)&C[((long long)(b1r * NT + 1 + n1r) * EMB) + col] = v1;
            }
        }
    }
}

static void gemm(cudaStream_t st, const float* A, const float* Bm, float* C,
                 int M_, int N_, int K_,
                 long long sA, long long sB, long long sC, int batch, bool transB,
                 float alpha = 1.f, float betaI = 0.f,
                 const float* bias = nullptr, int relu = 0,
                 const float* addp = nullptr, float addScale = 0.f, long long sAdd = 0,
                 int mode = 0, float* out2 = nullptr, float* out3 = nullptr,
                 int fast = 0)
{
    long long ctas128 = (N_ % 128 == 0) ? (long long)(N_ / 128) * (M_ / 128) * batch : 0;
    const bool big = (N_ % 128 == 0) && (ctas128 >= 256);
    dim3 grid(N_ / (big ? 128 : 64), M_ / 128, batch);
    if (big) {
        if (fast) {
            if (transB) gemm_tc<true, 128, true><<<grid, 256, 0, st>>>(A, Bm, C, M_, N_, K_, sA, sB, sC, alpha, betaI, bias, relu, addp, addScale, sAdd, mode, out2, out3);
            else        gemm_tc<false,128, true><<<grid, 256, 0, st>>>(A, Bm, C, M_, N_, K_, sA, sB, sC, alpha, betaI, bias, relu, addp, addScale, sAdd, mode, out2, out3);
        } else {
            if (transB) gemm_tc<true, 128, false><<<grid, 256, 0, st>>>(A, Bm, C, M_, N_, K_, sA, sB, sC, alpha, betaI, bias, relu, addp, addScale, sAdd, mode, out2, out3);
            else        gemm_tc<false,128, false><<<grid, 256, 0, st>>>(A, Bm, C, M_, N_, K_, sA, sB, sC, alpha, betaI, bias, relu, addp, addScale, sAdd, mode, out2, out3);
        }
    } else {
        if (fast) {
            if (transB) gemm_tc<true, 64, true><<<grid, 256, 0, st>>>(A, Bm, C, M_, N_, K_, sA, sB, sC, alpha, betaI, bias, relu, addp, addScale, sAdd, mode, out2, out3);
            else        gemm_tc<false, 64, true><<<grid, 256, 0, st>>>(A, Bm, C, M_, N_, K_, sA, sB, sC, alpha, betaI, bias, relu, addp, addScale, sAdd, mode, out2, out3);
        } else {
            if (transB) gemm_tc<true, 64, false><<<grid, 256, 0, st>>>(A, Bm, C, M_, N_, K_, sA, sB, sC, alpha, betaI, bias, relu, addp, addScale, sAdd, mode, out2, out3);
            else        gemm_tc<false, 64, false><<<grid, 256, 0, st>>>(A, Bm, C, M_, N_, K_, sA, sB, sC, alpha, betaI, bias, relu, addp, addScale, sAdd, mode, out2, out3);
        }
    }
}

// ---------------- cls rows ----------------
__global__ void cls_k(const float* __restrict__ cls)
{
    int c = threadIdx.x;
    #pragma unroll
    for (int b = 0; b < BB; b++)
        g_h[(long long)b * NT * EMB + c] = cls[c];
}

// ---------------- layer norm + front zero-pad into g_x ----------------
__global__ void ln_pad_k(const float* __restrict__ gg, const float* __restrict__ bb)
{
    int n = blockIdx.x, b = blockIdx.y;
    int tid = threadIdx.x;
    float* out = g_x + ((long long)b * NPAD + n) * EMB;
    if (n < PADR) { out[tid] = 0.f; out[tid + 256] = 0.f; return; }
    const float* in = g_h + ((long long)b * NT + (n - PADR)) * EMB;
    float x0 = in[tid], x1 = in[tid + 256];
    __shared__ float sd[256];
    sd[tid] = x0 + x1; __syncthreads();
    for (int s = 128; s > 0; s >>= 1) { if (tid < s) sd[tid] += sd[tid + s]; __syncthreads(); }
    float mu = sd[0] * (1.f / EMB);
    __syncthreads();
    float d0 = x0 - mu, d1 = x1 - mu;
    sd[tid] = d0 * d0 + d1 * d1; __syncthreads();
    for (int s = 128; s > 0; s >>= 1) { if (tid < s) sd[tid] += sd[tid + s]; __syncthreads(); }
    float rs = rsqrtf(sd[0] * (1.f / EMB) + 1e-5f);
    out[tid]       = d0 * rs * gg[tid]       + bb[tid];
    out[tid + 256] = d1 * rs * gg[tid + 256] + bb[tid + 256];
}

// ---------------- landmark means ----------------
__global__ void land_k(const float* __restrict__ src, float* __restrict__ dst)
{
    int d = threadIdx.x;
    int m = blockIdx.x;
    int bh = blockIdx.y;
    const float* p = src + (((long long)bh * NPAD) + (long long)m * LCH) * HD + d;
    float s = 0.f;
    #pragma unroll
    for (int i = 0; i < LCH; i++) s += p[(long long)i * HD];
    dst[(((long long)bh * NLM) + m) * HD + d] = s * (1.f / LCH);
}

// ---------------- single-pass softmax, len 256 ----------------
__global__ void softmax256_k(float* __restrict__ x)
{
    long long row = (long long)blockIdx.x * 8 + (threadIdx.x >> 5);
    int lane = threadIdx.x & 31;
    float* p = x + row * 256;
    float v[8];
    float m = -1e30f;
    #pragma unroll
    for (int i = 0; i < 8; i++) { v[i] = p[lane + 32 * i]; m = fmaxf(m, v[i]); }
    #pragma unroll
    for (int o = 16; o > 0; o >>= 1) m = fmaxf(m, __shfl_xor_sync(0xffffffffu, m, o));
    float s = 0.f;
    #pragma unroll
    for (int i = 0; i < 8; i++) { v[i] = expf(v[i] - m); s += v[i]; }
    #pragma unroll
    for (int o = 16; o > 0; o >>= 1) s += __shfl_xor_sync(0xffffffffu, s, o);
    float r = 1.f / s;
    #pragma unroll
    for (int i = 0; i < 8; i++) p[lane + 32 * i] = v[i] * r;
}

// ---------------- single-pass softmax, len 4352 ----------------
__global__ void softmax4352_k(float* __restrict__ x)
{
    long long row = blockIdx.x;
    float* p = x + row * 4352;
    int tid = threadIdx.x;
    float v[17];
    float m = -1e30f;
    #pragma unroll
    for (int i = 0; i < 17; i++) { v[i] = p[tid + 256 * i]; m = fmaxf(m, v[i]); }
    __shared__ float sd[8];
    #pragma unroll
    for (int o = 16; o > 0; o >>= 1) m = fmaxf(m, __shfl_xor_sync(0xffffffffu, m, o));
    if ((tid & 31) == 0) sd[tid >> 5] = m;
    __syncthreads();
    if (tid < 8) {
        float t = sd[tid];
        #pragma unroll
        for (int o = 4; o > 0; o >>= 1) t = fmaxf(t, __shfl_xor_sync(0xffu, t, o));
        sd[tid] = t;
    }
    __syncthreads();
    m = sd[0];
    float s = 0.f;
    #pragma unroll
    for (int i = 0; i < 17; i++) { v[i] = expf(v[i] - m); s += v[i]; }
    __syncthreads();
    #pragma unroll
    for (int o = 16; o > 0; o >>= 1) s += __shfl_xor_sync(0xffffffffu, s, o);
    if ((tid & 31) == 0) sd[tid >> 5] = s;
    __syncthreads();
    if (tid < 8) {
        float t = sd[tid];
        #pragma unroll
        for (int o = 4; o > 0; o >>= 1) t += __shfl_xor_sync(0xffu, t, o);
        sd[tid] = t;
    }
    __syncthreads();
    float r = 1.f / sd[0];
    #pragma unroll
    for (int i = 0; i < 17; i++) p[tid + 256 * i] = v[i] * r;
}

// ---------------- pinv helpers ----------------
__global__ void reset_red_k() { if (threadIdx.x < 2) g_red[threadIdx.x] = 0u; }

__global__ void denom_k()
{
    int bh = blockIdx.x, tid = threadIdx.x;
    const float* mat = g_s2 + (long long)bh * NLM * NLM;
    float col = 0.f, rs = 0.f;
    for (int i = 0; i < NLM; i++) col += mat[i * NLM + tid];
    for (int j = 0; j < NLM; j++) rs  += mat[tid * NLM + j];
    __shared__ float sd[256];
    sd[tid] = rs; __syncthreads();
    for (int s = 128; s > 0; s >>= 1) { if (tid < s) sd[tid] = fmaxf(sd[tid], sd[tid + s]); __syncthreads(); }
    if (tid == 0) atomicMax(&g_red[0], __float_as_uint(sd[0]));
    __syncthreads();
    sd[tid] = col; __syncthreads();
    for (int s = 128; s > 0; s >>= 1) { if (tid < s) sd[tid] = fmaxf(sd[tid], sd[tid + s]); __syncthreads(); }
    if (tid == 0) atomicMax(&g_red[1], __float_as_uint(sd[0]));
}

__global__ void initz_k()
{
    long long idx = (long long)blockIdx.x * 256 + threadIdx.x;
    float rd = 1.f / (__uint_as_float(g_red[0]) * __uint_as_float(g_red[1]));
    int ij = (int)(idx & 65535);
    long long bh = idx >> 16;
    int i = ij >> 8, j = ij & 255;
    g_z[idx] = g_s2[(bh << 16) + (long long)j * NLM + i] * rd;
}

// ---------------- depthwise 33-tap residual conv on v, added into g_attn ----------------
__global__ void resconv_k(const float* __restrict__ w)
{
    int d = threadIdx.x;
    int n = blockIdx.x;
    int bh = blockIdx.y;
    int hh = bh & 7, b = bh >> 3;
    __shared__ float sw[33];
    if (d < 33) sw[d] = w[hh * 33 + d];
    __syncthreads();
    const float* vp = g_v + ((long long)bh * NPAD) * HD + d;
    float acc = 0.f;
    #pragma unroll
    for (int j = 0; j < 33; j++) {
        int nn = n + j - 16;
        if (nn >= 0 && nn < NPAD) acc += sw[j] * vp[(long long)nn * HD];
    }
    g_attn[((long long)(b * NPAD + n) * EMB) + hh * 64 + d] += acc;
}

// ---------------- token<->image transposes ----------------
__global__ void tok2img_k()
{
    __shared__ float t[32][33];
    int b = blockIdx.z;
    int c0 = blockIdx.x * 32, p0 = blockIdx.y * 32;
    int tx = threadIdx.x, ty = threadIdx.y;
    #pragma unroll
    for (int j = 0; j < 32; j += 8)
        t[ty + j][tx] = g_h[((long long)b * NT + 1 + p0 + ty + j) * EMB + c0 + tx];
    __syncthreads();
    #pragma unroll
    for (int j = 0; j < 32; j += 8)
        g_cnn[((long long)b * EMB + c0 + ty + j) * (GRD * GRD) + p0 + tx] = t[tx][ty + j];
}

__global__ void img2tok_k()
{
    __shared__ float t[32][33];
    int b = blockIdx.z;
    int c0 = blockIdx.x * 32, p0 = blockIdx.y * 32;
    int tx = threadIdx.x, ty = threadIdx.y;
    #pragma unroll
    for (int j = 0; j < 32; j += 8)
        t[ty + j][tx] = g_cnn2[((long long)b * EMB + c0 + ty + j) * (GRD * GRD) + p0 + tx];
    __syncthreads();
    #pragma unroll
    for (int j = 0; j < 32; j += 8)
        g_h[((long long)b * NT + 1 + p0 + ty + j) * EMB + c0 + tx] = t[tx][ty + j];
}

// ---------------- fused 7x7 + 5x5 + 3x3 depthwise conv + identity ----------------
__global__ void dwconv_k(const float* __restrict__ w7, const float* __restrict__ b7,
                         const float* __restrict__ w5, const float* __restrict__ b5,
                         const float* __restrict__ w3, const float* __restrict__ b3)
{
    int bc = blockIdx.z;
    int c  = bc % EMB;
    const float* img = g_cnn + (long long)bc * GRD * GRD;
    __shared__ float tile[22][22];
    __shared__ float sw7[49], sw5[25], sw3[9];
    int tx = threadIdx.x, ty = threadIdx.y;
    int tid = ty * 16 + tx;
    if (tid < 49) sw7[tid] = w7[c * 49 + tid];
    if (tid < 25) sw5[tid] = w5[c * 25 + tid];
    if (tid < 9)  sw3[tid] = w3[c * 9  + tid];
    int ox0 = blockIdx.x * 16, oy0 = blockIdx.y * 16;
    for (int i = tid; i < 22 * 22; i += 256) {
        int yy = i / 22, xx = i % 22;
        int gy = oy0 - 3 + yy, gx = ox0 - 3 + xx;
        tile[yy][xx] = (gy >= 0 && gy < GRD && gx >= 0 && gx < GRD) ? img[gy * GRD + gx] : 0.f;
    }
    __syncthreads();
    float acc = tile[ty + 3][tx + 3] + b7[c] + b5[c] + b3[c];
    #pragma unroll
    for (int ky = 0; ky < 7; ky++)
        #pragma unroll
        for (int kx = 0; kx < 7; kx++)
            acc += sw7[ky * 7 + kx] * tile[ty + ky][tx + kx];
    #pragma unroll
    for (int ky = 0; ky < 5; ky++)
        #pragma unroll
        for (int kx = 0; kx < 5; kx++)
            acc += sw5[ky * 5 + kx] * tile[ty + 1 + ky][tx + 1 + kx];
    #pragma unroll
    for (int ky = 0; ky < 3; ky++)
        #pragma unroll
        for (int kx = 0; kx < 3; kx++)
            acc += sw3[ky * 3 + kx] * tile[ty + 2 + ky][tx + 2 + kx];
    g_cnn2[(long long)bc * GRD * GRD + (oy0 + ty) * GRD + ox0 + tx] = acc;
}

// ---------------- final LN(cls) -> logits -> softmax -> argmax ----------------
__global__ void head_k(const float* __restrict__ gg, const float* __restrict__ bb,
                       const float* __restrict__ W2, const float* __restrict__ b2,
                       float* __restrict__ out, int out_size)
{
    int tid = threadIdx.x; // 512
    __shared__ float sd[512];
    __shared__ float res[20];
    for (int b = 0; b < BB; b++) {
        float x = g_h[(long long)b * NT * EMB + tid];
        sd[tid] = x; __syncthreads();
        for (int s = 256; s > 0; s >>= 1) { if (tid < s) sd[tid] += sd[tid + s]; __syncthreads(); }
        float mu = sd[0] * (1.f / EMB); __syncthreads();
        float dx = x - mu;
        sd[tid] = dx * dx; __syncthreads();
        for (int s = 256; s > 0; s >>= 1) { if (tid < s) sd[tid] += sd[tid + s]; __syncthreads(); }
        float rs = rsqrtf(sd[0] * (1.f / EMB) + 1e-5f); __syncthreads();
        float xn = dx * rs * gg[tid] + bb[tid];
        sd[tid] = xn * W2[tid]; __syncthreads();
        for (int s = 256; s > 0; s >>= 1) { if (tid < s) sd[tid] += sd[tid + s]; __syncthreads(); }
        float l0 = sd[0] + b2[0]; __syncthreads();
        sd[tid] = xn * W2[EMB + tid]; __syncthreads();
        for (int s = 256; s > 0; s >>= 1) { if (tid < s) sd[tid] += sd[tid + s]; __syncthreads(); }
        float l1 = sd[0] + b2[1]; __syncthreads();
        if (tid == 0) {
            float mx = fmaxf(l0, l1);
            float e0 = expf(l0 - mx), e1 = expf(l1 - mx);
            float s = e0 + e1;
            res[b * 2]     = l0;
            res[b * 2 + 1] = l1;
            res[8 + b * 2]     = e0 / s;
            res[8 + b * 2 + 1] = e1 / s;
            res[16 + b] = (l1 > l0) ? 1.f : 0.f;
        }
        __syncthreads();
    }
    if (tid < 20 && tid < out_size) out[tid] = res[tid];
}

// ---------------- host orchestration ----------------
#define SYM(p, s) do { void* _t = nullptr; cudaGetSymbolAddress(&_t, s); p = (float*)_t; } while (0)

static cudaStream_t g_sB = nullptr;
static cudaEvent_t  g_evF[2], g_evJ[2];
static void ensure_streams()
{
    static bool done = false;
    if (!done) {
        cudaStreamCreateWithFlags(&g_sB, cudaStreamNonBlocking);
        for (int i = 0; i < 2; i++) {
            cudaEventCreateWithFlags(&g_evF[i], cudaEventDisableTiming);
            cudaEventCreateWithFlags(&g_evJ[i], cudaEventDisableTiming);
        }
        done = true;
    }
}

static void run_attn(int layer, const float* ln_g, const float* ln_b, const float* Wqkv,
                     const float* Wo, const float* bo, const float* res)
{
    float *x_, *q_, *k_, *v_, *ql_, *kl_, *s1_, *s2_, *s3_;
    float *z_, *z2_, *t0_, *t1_, *t2_, *av_, *u_, *attn_, *h_;
    SYM(x_, g_x); SYM(q_, g_q); SYM(k_, g_k); SYM(v_, g_v);
    SYM(ql_, g_ql); SYM(kl_, g_kl); SYM(s1_, g_s1); SYM(s2_, g_s2); SYM(s3_, g_s3);
    SYM(z_, g_z); SYM(z2_, g_z2); SYM(t0_, g_t0); SYM(t1_, g_t1); SYM(t2_, g_t2);
    SYM(av_, g_av); SYM(u_, g_u); SYM(attn_, g_attn); SYM(h_, g_h);

    cudaStream_t s0 = 0, sB = g_sB;

    ln_pad_k<<<dim3(NPAD, BB), 256, 0, s0>>>(ln_g, ln_b);
    gemm(s0, x_, Wqkv, q_, BB * NPAD, 3 * EMB, EMB, 0, 0, 0, 1, true,
         1.f, 0.f, nullptr, 0, nullptr, 0.f, 0, 1, k_, v_);
    land_k<<<dim3(NLM, BB * NH), 64, 0, s0>>>(q_, ql_);
    land_k<<<dim3(NLM, BB * NH), 64, 0, s0>>>(k_, kl_);

    // ---- fork: branch B (s2 + pinv chain) on sB ----
    cudaEventRecord(g_evF[layer], s0);
    cudaStreamWaitEvent(sB, g_evF[layer], 0);

    // branch B
    gemm(sB, ql_, kl_, s2_, NLM, NLM, HD,
         (long long)NLM * HD, (long long)NLM * HD, (long long)NLM * NLM, BB * NH, true);
    softmax256_k<<<BB * NH * NLM / 8, 256, 0, sB>>>(s2_);
    reset_red_k<<<1, 32, 0, sB>>>();
    denom_k<<<BB * NH, 256, 0, sB>>>();
    initz_k<<<(BB * NH * NLM * NLM) / 256, 256, 0, sB>>>();
    float* zi = z_;
    float* zo = z2_;
    for (int it = 0; it < 6; it++) {
        // iterations 0-4: single-pass tf32 (Newton-Schulz is self-correcting);
        // final iteration: full 3xTF32 precision.
        int fast = (it < 5) ? 1 : 0;
        gemm(sB, s2_, zi, t0_, NLM, NLM, NLM, 65536, 65536, 65536, BB * NH, false,
             1.f, 0.f, nullptr, 0, nullptr, 0.f, 0, 0, nullptr, nullptr, fast);
        gemm(sB, t0_, t0_, t2_, NLM, NLM, NLM, 65536, 65536, 65536, BB * NH, false,
             1.f, 15.f, nullptr, 0, t0_, -7.f, 65536, 0, nullptr, nullptr, fast);
        gemm(sB, t0_, t2_, t1_, NLM, NLM, NLM, 65536, 65536, 65536, BB * NH, false,
             -1.f, 13.f, nullptr, 0, nullptr, 0.f, 0, 0, nullptr, nullptr, fast);
        gemm(sB, zi, t1_, zo, NLM, NLM, NLM, 65536, 65536, 65536, BB * NH, false,
             0.25f, 0.f, nullptr, 0, nullptr, 0.f, 0, 0, nullptr, nullptr, fast);
        float* tmp = zi; zi = zo; zo = tmp;
    }
    cudaEventRecord(g_evJ[layer], sB);

    // branch A (origin stream) — score GEMMs + av in fast tf32 (softmax-protected)
    gemm(s0, q_, kl_, s1_, NPAD, NLM, HD,
         (long long)NPAD * HD, (long long)NLM * HD, (long long)NPAD * NLM, BB * NH, true,
         1.f, 0.f, nullptr, 0, nullptr, 0.f, 0, 0, nullptr, nullptr, 1);
    softmax256_k<<<BB * NH * NPAD / 8, 256, 0, s0>>>(s1_);
    gemm(s0, ql_, k_, s3_, NLM, NPAD, HD,
         (long long)NLM * HD, (long long)NPAD * HD, (long long)NLM * NPAD, BB * NH, true,
         1.f, 0.f, nullptr, 0, nullptr, 0.f, 0, 0, nullptr, nullptr, 1);
    softmax4352_k<<<BB * NH * NLM, 256, 0, s0>>>(s3_);
    gemm(s0, s3_, v_, av_, NLM, HD, NPAD,
         (long long)NLM * NPAD, (long long)NPAD * HD, (long long)NLM * HD, BB * NH, false,
         1.f, 0.f, nullptr, 0, nullptr, 0.f, 0, 0, nullptr, nullptr, 1);

    // ---- join ----
    cudaStreamWaitEvent(s0, g_evJ[layer], 0);

    gemm(s0, zi, av_, u_, NLM, HD, NLM,
         65536, (long long)NLM * HD, (long long)NLM * HD, BB * NH, false);
    gemm(s0, s1_, u_, attn_, NPAD, HD, NLM,
         (long long)NPAD * NLM, (long long)NLM * HD, 0, BB * NH, false,
         1.f, 0.f, nullptr, 0, nullptr, 0.f, 0, 2);

    resconv_k<<<dim3(NPAD, BB * NH), 64, 0, s0>>>(res);
    gemm(s0, attn_, Wo, h_, BB * NPAD, EMB, EMB, 0, 0, 0, 1, true,
         1.f, 0.f, bo, 0, nullptr, 0.f, 0, 3);
}

extern "C" void kernel_launch(void* const* d_in, const int* in_sizes, int n_in,
                              void* d_out, int out_size)
{
    ensure_streams();

    const float* data  = (const float*)d_in[0];
    const float* W1    = (const float*)d_in[1];
    const float* b1    = (const float*)d_in[2];
    const float* cls   = (const float*)d_in[3];
    const float* ln1_g = (const float*)d_in[4];
    const float* ln1_b = (const float*)d_in[5];
    const float* Wqkv1 = (const float*)d_in[6];
    const float* Wo1   = (const float*)d_in[7];
    const float* bo1   = (const float*)d_in[8];
    const float* res1  = (const float*)d_in[9];
    const float* ln2_g = (const float*)d_in[10];
    const float* ln2_b = (const float*)d_in[11];
    const float* Wqkv2 = (const float*)d_in[12];
    const float* Wo2   = (const float*)d_in[13];
    const float* bo2   = (const float*)d_in[14];
    const float* res2  = (const float*)d_in[15];
    const float* pw7   = (const float*)d_in[16];
    const float* pb7   = (const float*)d_in[17];
    const float* pw5   = (const float*)d_in[18];
    const float* pb5   = (const float*)d_in[19];
    const float* pw3   = (const float*)d_in[20];
    const float* pb3   = (const float*)d_in[21];
    const float* lnf_g = (const float*)d_in[22];
    const float* lnf_b = (const float*)d_in[23];
    const float* W2    = (const float*)d_in[24];
    const float* b2    = (const float*)d_in[25];

    float* h_;
    SYM(h_, g_h);

    // stage 1: h[1:] = relu(data @ W1^T + b1) (mode 4 shift), cls row separately
    gemm(0, data, W1, h_, BB * N0, EMB, C0, 0, 0, 0, 1, true,
         1.f, 0.f, b1, 1, nullptr, 0.f, 0, 4);
    cls_k<<<1, 512>>>(cls);

    // stage 2: first Nystrom attention block (residual)
    run_attn(0, ln1_g, ln1_b, Wqkv1, Wo1, bo1, res1);

    // stage 3: PPEG conv block on the 64x64 token grid (cls row untouched)
    tok2img_k<<<dim3(EMB / 32, (GRD * GRD) / 32, BB), dim3(32, 8)>>>();
    dwconv_k<<<dim3(GRD / 16, GRD / 16, BB * EMB), dim3(16, 16)>>>(pw7, pb7, pw5, pb5, pw3, pb3);
    img2tok_k<<<dim3(EMB / 32, (GRD * GRD) / 32, BB), dim3(32, 8)>>>();

    // stage 4: second Nystrom attention block (residual)
    run_attn(1, ln2_g, ln2_b, Wqkv2, Wo2, bo2, res2);

    // stage 5: final LN on cls token + classification head
    head_k<<<1, 512>>>(lnf_g, lnf_b, W2, b2, (float*)d_out, out_size);
}

// round 16
// speedup vs baseline: 2.3895x; 1.0348x over previous
#include <cuda_runtime.h>
#include <math.h>

#define BB   4
#define N0   4096
#define C0   1536
#define EMB  512
#define NH   8
#define HD   64
#define NT   4097
#define NPAD 4352
#define PADR 255
#define NLM  256
#define LCH  17
#define GRD  64
#define QSCALE 0.125f

// ---------------- static device scratch (no allocations allowed) ----------------
__device__ float g_h   [BB*NT*EMB];
__device__ float g_x   [BB*NPAD*EMB];
__device__ float g_q   [BB*NH*NPAD*HD];
__device__ float g_k   [BB*NH*NPAD*HD];
__device__ float g_v   [BB*NH*NPAD*HD];
__device__ float g_ql  [BB*NH*NLM*HD];
__device__ float g_kl  [BB*NH*NLM*HD];
__device__ float g_s1  [(long long)BB*NH*NPAD*NLM];
__device__ float g_s2  [BB*NH*NLM*NLM];
__device__ float g_s3  [(long long)BB*NH*NLM*NPAD];
__device__ float g_z   [BB*NH*NLM*NLM];
__device__ float g_z2  [BB*NH*NLM*NLM];
__device__ float g_t0  [BB*NH*NLM*NLM];
__device__ float g_t1  [BB*NH*NLM*NLM];
__device__ float g_t2  [BB*NH*NLM*NLM];
__device__ float g_av  [BB*NH*NLM*HD];
__device__ float g_u   [BB*NH*NLM*HD];
__device__ float g_pav [8*BB*NH*NLM*HD];   // split-K partials (8 chunks max)
__device__ float g_attn[BB*NPAD*EMB];
__device__ float g_cnn [BB*EMB*GRD*GRD];
__device__ float g_cnn2[BB*EMB*GRD*GRD];
__device__ unsigned g_red[2];

// ---------------- tf32 helpers ----------------
__device__ __forceinline__ unsigned f2tf(float v)
{
    unsigned r;
    asm("cvt.rna.tf32.f32 %0, %1;" : "=r"(r) : "f"(v));
    return r;
}

__device__ __forceinline__ void split_tf32(float v, unsigned& hi, unsigned& lo)
{
    hi = __float_as_uint(v) & 0xFFFFE000u;
    lo = __float_as_uint(v - __uint_as_float(hi));
}

__device__ __forceinline__ void mma_tf32(float c[4], const unsigned a[4], const unsigned b[2])
{
    asm volatile("mma.sync.aligned.m16n8k8.row.col.f32.tf32.tf32.f32 "
                 "{%0,%1,%2,%3}, {%4,%5,%6,%7}, {%8,%9}, {%0,%1,%2,%3};"
                 : "+f"(c[0]), "+f"(c[1]), "+f"(c[2]), "+f"(c[3])
                 : "r"(a[0]), "r"(a[1]), "r"(a[2]), "r"(a[3]), "r"(b[0]), "r"(b[1]));
}

// ---------------- batched TF32 tensor-core GEMM, fragment-packed smem ----------------
// Block tile 128 x BN (BN = 64 or 128), 8 warps.
// FAST=1: single-pass tf32.  FAST=0: 3xTF32 (fp32-class accuracy).
// Epilogue modes:
//  0: plain  1: QKV split  2: merge heads  3: Wo+residual  4: stage1 shift
//  5: split-K (8 chunks of 544, av)   6: split-K (4 chunks of 64, u)
template<bool TRANSB, int BN, bool FAST>
__global__ void __launch_bounds__(256, 2)
gemm_tc(const float* __restrict__ A, const float* __restrict__ Bm,
        float* __restrict__ C,
        int Mdim, int Ndim, int Kdim, int lda,
        long long sA, long long sB, long long sC,
        float alpha, float betaI,
        const float* __restrict__ bias, int relu,
        const float* __restrict__ addp, float addScale, long long sAdd,
        int mode, float* __restrict__ out2, float* __restrict__ out3)
{
    constexpr int BWORDS = BN * 8;
    constexpr int BELEM  = BWORDS / 256;
    constexpr int NTJ    = BN / 16;

    __shared__ float    Af[2][1024];
    __shared__ unsigned Bhs[2][BWORDS], Bls[2][BWORDS];

    const int zb = blockIdx.z;
    if (mode >= 5) {
        // split-K: zb = chunk*32 + bh
        int chunk = zb >> 5, bh = zb & 31;
        int CH = (mode == 5) ? 544 : 64;
        A  += (long long)bh * sA + (long long)chunk * CH;          // column offset in A
        Bm += (long long)bh * sB + (long long)chunk * CH * Ndim;   // row offset in B (K,N)
        C  += (long long)zb * sC;
    } else {
        A  += (long long)zb * sA;
        Bm += (long long)zb * sB;
        C  += (long long)zb * sC;
        if (addp) addp += (long long)zb * sAdd;
    }

    const int m0 = blockIdx.y * 128;
    const int n0 = blockIdx.x * BN;
    const int tid  = threadIdx.x;
    const int lane = tid & 31;
    const int warp = tid >> 5;
    const int wm = warp & 3;
    const int wn = warp >> 2;
    const int g  = lane >> 2;
    const int tg = lane & 3;

    int aAddr[4], bAddr[BELEM];
    long long offA[4], offB[BELEM];
    #pragma unroll
    for (int r = 0; r < 4; r++) {
        int i = tid + r * 256;
        int m = i >> 3, kk = i & 7;
        int t = m >> 4, gg2 = m & 7, hi8 = (m >> 3) & 1;
        int ttg = kk & 3, kh = kk >> 2;
        aAddr[r] = t * 128 + (gg2 * 4 + ttg) * 4 + hi8 + 2 * kh;
        offA[r]  = (long long)(m0 + m) * lda + kk;
    }
    #pragma unroll
    for (int r = 0; r < BELEM; r++) {
        int i = tid + r * 256;
        int n, kk;
        if (TRANSB) { n = i >> 3; kk = i & 7; offB[r] = (long long)(n0 + n) * Kdim + kk; }
        else {
            if (BN == 64) { kk = i >> 6; n = i & 63; }
            else          { kk = i >> 7; n = i & 127; }
            offB[r] = (long long)kk * Ndim + n0 + n;
        }
        int j = n >> 3;
        int ln = (n & 7) * 4 + (kk & 3);
        int kh = kk >> 2;
        if (BN == 64) {
            bAddr[r] = j * 64 + ((2 * ln + 2 * j) & 63) + kh;
        } else {
            int p = j >> 1, q = j & 1;
            int base = p * 128 + 4 * ln;
            bAddr[r] = (base ^ ((base >> 3) & 0x1C)) + 2 * q + kh;
        }
    }
    const long long bStep = TRANSB ? 8 : (long long)8 * Ndim;

    float c[2][NTJ][4];
    #pragma unroll
    for (int i = 0; i < 2; i++)
        #pragma unroll
        for (int j = 0; j < NTJ; j++)
            #pragma unroll
            for (int r = 0; r < 4; r++) c[i][j][r] = 0.f;

    const int nsteps = Kdim >> 3;
    float ra[4], rb[BELEM];

    {
        #pragma unroll
        for (int r = 0; r < 4; r++) Af[0][aAddr[r]] = A[offA[r]];
        #pragma unroll
        for (int r = 0; r < BELEM; r++) {
            float v = Bm[offB[r]];
            if (FAST) {
                Bhs[0][bAddr[r]] = f2tf(v);
            } else {
                unsigned h, l;
                split_tf32(v, h, l);
                Bhs[0][bAddr[r]] = h;
                Bls[0][bAddr[r]] = l;
            }
        }
    }
    __syncthreads();
    const float* Ap = A + 8;
    const float* Bp = Bm + bStep;

    int buf = 0;
    for (int s = 0; s < nsteps; s++) {
        if (s + 1 < nsteps) {
            #pragma unroll
            for (int r = 0; r < 4; r++) ra[r] = Ap[offA[r]];
            #pragma unroll
            for (int r = 0; r < BELEM; r++) rb[r] = Bp[offB[r]];
            Ap += 8;
            Bp += bStep;
        }

        {
            unsigned ah[2][4], al[2][4];
            #pragma unroll
            for (int i = 0; i < 2; i++) {
                int base = (wm * 2 + i) * 128 + lane * 4;
                float4 v4 = *(const float4*)&Af[buf][base];
                float vv[4] = {v4.x, v4.y, v4.z, v4.w};
                #pragma unroll
                for (int r = 0; r < 4; r++) {
                    if (FAST) ah[i][r] = f2tf(vv[r]);
                    else      split_tf32(vv[r], ah[i][r], al[i][r]);
                }
            }
            if (BN == 64) {
                #pragma unroll
                for (int j = 0; j < NTJ; j++) {
                    int jt = wn * 4 + j;
                    int base = jt * 64 + ((2 * lane + 2 * jt) & 63);
                    uint2 vh = *(const uint2*)&Bhs[buf][base];
                    unsigned bh[2] = {vh.x, vh.y};
                    #pragma unroll
                    for (int i = 0; i < 2; i++) {
                        mma_tf32(c[i][j], ah[i], bh);
                        if (!FAST) {
                            uint2 vl = *(const uint2*)&Bls[buf][base];
                            unsigned bl[2] = {vl.x, vl.y};
                            mma_tf32(c[i][j], ah[i], bl);
                            mma_tf32(c[i][j], al[i], bh);
                        }
                    }
                }
            } else {
                #pragma unroll
                for (int p4 = 0; p4 < 4; p4++) {
                    int p = wn * 4 + p4;
                    int base = p * 128 + lane * 4;
                    base ^= (base >> 3) & 0x1C;
                    uint4 vh = *(const uint4*)&Bhs[buf][base];
                    unsigned bh0[2] = {vh.x, vh.y}, bh1[2] = {vh.z, vh.w};
                    if (FAST) {
                        #pragma unroll
                        for (int i = 0; i < 2; i++) {
                            mma_tf32(c[i][2 * p4],     ah[i], bh0);
                            mma_tf32(c[i][2 * p4 + 1], ah[i], bh1);
                        }
                    } else {
                        uint4 vl = *(const uint4*)&Bls[buf][base];
                        unsigned bl0[2] = {vl.x, vl.y}, bl1[2] = {vl.z, vl.w};
                        #pragma unroll
                        for (int i = 0; i < 2; i++) {
                            mma_tf32(c[i][2 * p4],     ah[i], bh0);
                            mma_tf32(c[i][2 * p4],     ah[i], bl0);
                            mma_tf32(c[i][2 * p4],     al[i], bh0);
                            mma_tf32(c[i][2 * p4 + 1], ah[i], bh1);
                            mma_tf32(c[i][2 * p4 + 1], ah[i], bl1);
                            mma_tf32(c[i][2 * p4 + 1], al[i], bh1);
                        }
                    }
                }
            }
        }

        if (s + 1 < nsteps) {
            int nb = buf ^ 1;
            #pragma unroll
            for (int r = 0; r < 4; r++) Af[nb][aAddr[r]] = ra[r];
            #pragma unroll
            for (int r = 0; r < BELEM; r++) {
                if (FAST) {
                    Bhs[nb][bAddr[r]] = f2tf(rb[r]);
                } else {
                    unsigned h, l;
                    split_tf32(rb[r], h, l);
                    Bhs[nb][bAddr[r]] = h;
                    Bls[nb][bAddr[r]] = l;
                }
            }
            __syncthreads();
            buf = nb;
        }
    }

    // ---- epilogue ----
    const int emode = (mode >= 5) ? 0 : mode;
    #pragma unroll
    for (int i = 0; i < 2; i++) {
        #pragma unroll
        for (int j = 0; j < NTJ; j++) {
            int row0 = m0 + wm * 32 + i * 16 + g;
            int row1 = row0 + 8;
            int col  = n0 + wn * (BN / 2) + j * 8 + 2 * tg;
            float2 v0, v1;
            v0.x = alpha * c[i][j][0]; v0.y = alpha * c[i][j][1];
            v1.x = alpha * c[i][j][2]; v1.y = alpha * c[i][j][3];
            if (bias) {
                float2 bb2 = *(const float2*)&bias[col];
                v0.x += bb2.x; v0.y += bb2.y;
                v1.x += bb2.x; v1.y += bb2.y;
            }
            if (betaI != 0.f) {
                if (row0 == col)     v0.x += betaI;
                if (row0 == col + 1) v0.y += betaI;
                if (row1 == col)     v1.x += betaI;
                if (row1 == col + 1) v1.y += betaI;
            }
            if (addp) {
                float2 a0 = *(const float2*)&addp[(long long)row0 * Ndim + col];
                float2 a1 = *(const float2*)&addp[(long long)row1 * Ndim + col];
                v0.x += addScale * a0.x; v0.y += addScale * a0.y;
                v1.x += addScale * a1.x; v1.y += addScale * a1.y;
            }
            if (relu) {
                v0.x = fmaxf(v0.x, 0.f); v0.y = fmaxf(v0.y, 0.f);
                v1.x = fmaxf(v1.x, 0.f); v1.y = fmaxf(v1.y, 0.f);
            }
            if (emode == 0) {
                *(float2*)&C[(long long)row0 * Ndim + col] = v0;
                *(float2*)&C[(long long)row1 * Ndim + col] = v1;
            } else if (emode == 1) {
                int kind = col >> 9, cc = col & 511;
                int hh = cc >> 6, d = cc & 63;
                float* dst = (kind == 0) ? C : (kind == 1) ? out2 : out3;
                float sc = (kind == 0) ? QSCALE : 1.f;
                int b0 = row0 / NPAD, n0r = row0 - b0 * NPAD;
                int b1r = row1 / NPAD, n1r = row1 - b1r * NPAD;
                float2 w0 = make_float2(v0.x * sc, v0.y * sc);
                float2 w1 = make_float2(v1.x * sc, v1.y * sc);
                *(float2*)&dst[(((long long)(b0 * NH + hh) * NPAD) + n0r) * HD + d] = w0;
                *(float2*)&dst[(((long long)(b1r * NH + hh) * NPAD) + n1r) * HD + d] = w1;
            } else if (emode == 2) {
                int b = zb >> 3, hh = zb & 7;
                *(float2*)&C[((long long)(b * NPAD + row0) * EMB) + hh * 64 + col] = v0;
                *(float2*)&C[((long long)(b * NPAD + row1) * EMB) + hh * 64 + col] = v1;
            } else if (emode == 3) {
                int b0 = row0 / NPAD, n0r = row0 - b0 * NPAD;
                int b1r = row1 / NPAD, n1r = row1 - b1r * NPAD;
                if (n0r >= PADR) {
                    long long a = ((long long)(b0 * NT + n0r - PADR) * EMB) + col;
                    float2 old = *(float2*)&C[a];
                    v0.x += old.x; v0.y += old.y;
                    *(float2*)&C[a] = v0;
                }
                if (n1r >= PADR) {
                    long long a = ((long long)(b1r * NT + n1r - PADR) * EMB) + col;
                    float2 old = *(float2*)&C[a];
                    v1.x += old.x; v1.y += old.y;
                    *(float2*)&C[a] = v1;
                }
            } else { // emode 4
                int b0 = row0 >> 12, n0r = row0 & 4095;
                int b1r = row1 >> 12, n1r = row1 & 4095;
                *(float2*)&C[((long long)(b0 * NT + 1 + n0r) * EMB) + col] = v0;
                *(float2*)&C[((long long)(b1r * NT + 1 + n1r) * EMB) + col] = v1;
            }
        }
    }
}

static void gemm(cudaStream_t st, const float* A, const float* Bm, float* C,
                 int M_, int N_, int K_,
                 long long sA, long long sB, long long sC, int batch, bool transB,
                 float alpha = 1.f, float betaI = 0.f,
                 const float* bias = nullptr, int relu = 0,
                 const float* addp = nullptr, float addScale = 0.f, long long sAdd = 0,
                 int mode = 0, float* out2 = nullptr, float* out3 = nullptr,
                 int fast = 0, int lda = -1)
{
    if (lda < 0) lda = K_;
    long long ctas128 = (N_ % 128 == 0) ? (long long)(N_ / 128) * (M_ / 128) * batch : 0;
    const bool big = (N_ % 128 == 0) && (ctas128 >= 256);
    dim3 grid(N_ / (big ? 128 : 64), M_ / 128, batch);
    if (big) {
        if (fast) {
            if (transB) gemm_tc<true, 128, true><<<grid, 256, 0, st>>>(A, Bm, C, M_, N_, K_, lda, sA, sB, sC, alpha, betaI, bias, relu, addp, addScale, sAdd, mode, out2, out3);
            else        gemm_tc<false,128, true><<<grid, 256, 0, st>>>(A, Bm, C, M_, N_, K_, lda, sA, sB, sC, alpha, betaI, bias, relu, addp, addScale, sAdd, mode, out2, out3);
        } else {
            if (transB) gemm_tc<true, 128, false><<<grid, 256, 0, st>>>(A, Bm, C, M_, N_, K_, lda, sA, sB, sC, alpha, betaI, bias, relu, addp, addScale, sAdd, mode, out2, out3);
            else        gemm_tc<false,128, false><<<grid, 256, 0, st>>>(A, Bm, C, M_, N_, K_, lda, sA, sB, sC, alpha, betaI, bias, relu, addp, addScale, sAdd, mode, out2, out3);
        }
    } else {
        if (fast) {
            if (transB) gemm_tc<true, 64, true><<<grid, 256, 0, st>>>(A, Bm, C, M_, N_, K_, lda, sA, sB, sC, alpha, betaI, bias, relu, addp, addScale, sAdd, mode, out2, out3);
            else        gemm_tc<false, 64, true><<<grid, 256, 0, st>>>(A, Bm, C, M_, N_, K_, lda, sA, sB, sC, alpha, betaI, bias, relu, addp, addScale, sAdd, mode, out2, out3);
        } else {
            if (transB) gemm_tc<true, 64, false><<<grid, 256, 0, st>>>(A, Bm, C, M_, N_, K_, lda, sA, sB, sC, alpha, betaI, bias, relu, addp, addScale, sAdd, mode, out2, out3);
            else        gemm_tc<false, 64, false><<<grid, 256, 0, st>>>(A, Bm, C, M_, N_, K_, lda, sA, sB, sC, alpha, betaI, bias, relu, addp, addScale, sAdd, mode, out2, out3);
        }
    }
}

// ---------------- split-K reduce: dst[i] = sum_c g_pav[c*524288 + i] ----------------
__global__ void redk(float* __restrict__ dst, int nch)
{
    long long i = (long long)blockIdx.x * 256 + threadIdx.x;
    float s = 0.f;
    for (int c = 0; c < nch; c++) s += g_pav[(long long)c * (BB*NH*NLM*HD) + i];
    dst[i] = s;
}

// ---------------- cls rows ----------------
__global__ void cls_k(const float* __restrict__ cls)
{
    int c = threadIdx.x;
    #pragma unroll
    for (int b = 0; b < BB; b++)
        g_h[(long long)b * NT * EMB + c] = cls[c];
}

// ---------------- layer norm + front zero-pad into g_x ----------------
__global__ void ln_pad_k(const float* __restrict__ gg, const float* __restrict__ bb)
{
    int n = blockIdx.x, b = blockIdx.y;
    int tid = threadIdx.x;
    float* out = g_x + ((long long)b * NPAD + n) * EMB;
    if (n < PADR) { out[tid] = 0.f; out[tid + 256] = 0.f; return; }
    const float* in = g_h + ((long long)b * NT + (n - PADR)) * EMB;
    float x0 = in[tid], x1 = in[tid + 256];
    __shared__ float sd[256];
    sd[tid] = x0 + x1; __syncthreads();
    for (int s = 128; s > 0; s >>= 1) { if (tid < s) sd[tid] += sd[tid + s]; __syncthreads(); }
    float mu = sd[0] * (1.f / EMB);
    __syncthreads();
    float d0 = x0 - mu, d1 = x1 - mu;
    sd[tid] = d0 * d0 + d1 * d1; __syncthreads();
    for (int s = 128; s > 0; s >>= 1) { if (tid < s) sd[tid] += sd[tid + s]; __syncthreads(); }
    float rs = rsqrtf(sd[0] * (1.f / EMB) + 1e-5f);
    out[tid]       = d0 * rs * gg[tid]       + bb[tid];
    out[tid + 256] = d1 * rs * gg[tid + 256] + bb[tid + 256];
}

// ---------------- landmark means ----------------
__global__ void land_k(const float* __restrict__ src, float* __restrict__ dst)
{
    int d = threadIdx.x;
    int m = blockIdx.x;
    int bh = blockIdx.y;
    const float* p = src + (((long long)bh * NPAD) + (long long)m * LCH) * HD + d;
    float s = 0.f;
    #pragma unroll
    for (int i = 0; i < LCH; i++) s += p[(long long)i * HD];
    dst[(((long long)bh * NLM) + m) * HD + d] = s * (1.f / LCH);
}

// ---------------- single-pass softmax, len 256 ----------------
__global__ void softmax256_k(float* __restrict__ x)
{
    long long row = (long long)blockIdx.x * 8 + (threadIdx.x >> 5);
    int lane = threadIdx.x & 31;
    float* p = x + row * 256;
    float v[8];
    float m = -1e30f;
    #pragma unroll
    for (int i = 0; i < 8; i++) { v[i] = p[lane + 32 * i]; m = fmaxf(m, v[i]); }
    #pragma unroll
    for (int o = 16; o > 0; o >>= 1) m = fmaxf(m, __shfl_xor_sync(0xffffffffu, m, o));
    float s = 0.f;
    #pragma unroll
    for (int i = 0; i < 8; i++) { v[i] = expf(v[i] - m); s += v[i]; }
    #pragma unroll
    for (int o = 16; o > 0; o >>= 1) s += __shfl_xor_sync(0xffffffffu, s, o);
    float r = 1.f / s;
    #pragma unroll
    for (int i = 0; i < 8; i++) p[lane + 32 * i] = v[i] * r;
}

// ---------------- single-pass softmax, len 4352 ----------------
__global__ void softmax4352_k(float* __restrict__ x)
{
    long long row = blockIdx.x;
    float* p = x + row * 4352;
    int tid = threadIdx.x;
    float v[17];
    float m = -1e30f;
    #pragma unroll
    for (int i = 0; i < 17; i++) { v[i] = p[tid + 256 * i]; m = fmaxf(m, v[i]); }
    __shared__ float sd[8];
    #pragma unroll
    for (int o = 16; o > 0; o >>= 1) m = fmaxf(m, __shfl_xor_sync(0xffffffffu, m, o));
    if ((tid & 31) == 0) sd[tid >> 5] = m;
    __syncthreads();
    if (tid < 8) {
        float t = sd[tid];
        #pragma unroll
        for (int o = 4; o > 0; o >>= 1) t = fmaxf(t, __shfl_xor_sync(0xffu, t, o));
        sd[tid] = t;
    }
    __syncthreads();
    m = sd[0];
    float s = 0.f;
    #pragma unroll
    for (int i = 0; i < 17; i++) { v[i] = expf(v[i] - m); s += v[i]; }
    __syncthreads();
    #pragma unroll
    for (int o = 16; o > 0; o >>= 1) s += __shfl_xor_sync(0xffffffffu, s, o);
    if ((tid & 31) == 0) sd[tid >> 5] = s;
    __syncthreads();
    if (tid < 8) {
        float t = sd[tid];
        #pragma unroll
        for (int o = 4; o > 0; o >>= 1) t += __shfl_xor_sync(0xffu, t, o);
        sd[tid] = t;
    }
    __syncthreads();
    float r = 1.f / sd[0];
    #pragma unroll
    for (int i = 0; i < 17; i++) p[tid + 256 * i] = v[i] * r;
}

// ---------------- pinv helpers ----------------
__global__ void reset_red_k() { if (threadIdx.x < 2) g_red[threadIdx.x] = 0u; }

__global__ void denom_k()
{
    int bh = blockIdx.x, tid = threadIdx.x;
    const float* mat = g_s2 + (long long)bh * NLM * NLM;
    float col = 0.f, rs = 0.f;
    for (int i = 0; i < NLM; i++) col += mat[i * NLM + tid];
    for (int j = 0; j < NLM; j++) rs  += mat[tid * NLM + j];
    __shared__ float sd[256];
    sd[tid] = rs; __syncthreads();
    for (int s = 128; s > 0; s >>= 1) { if (tid < s) sd[tid] = fmaxf(sd[tid], sd[tid + s]); __syncthreads(); }
    if (tid == 0) atomicMax(&g_red[0], __float_as_uint(sd[0]));
    __syncthreads();
    sd[tid] = col; __syncthreads();
    for (int s = 128; s > 0; s >>= 1) { if (tid < s) sd[tid] = fmaxf(sd[tid], sd[tid + s]); __syncthreads(); }
    if (tid == 0) atomicMax(&g_red[1], __float_as_uint(sd[0]));
}

__global__ void initz_k()
{
    long long idx = (long long)blockIdx.x * 256 + threadIdx.x;
    float rd = 1.f / (__uint_as_float(g_red[0]) * __uint_as_float(g_red[1]));
    int ij = (int)(idx & 65535);
    long long bh = idx >> 16;
    int i = ij >> 8, j = ij & 255;
    g_z[idx] = g_s2[(bh << 16) + (long long)j * NLM + i] * rd;
}

// ---------------- depthwise 33-tap residual conv on v, added into g_attn ----------------
__global__ void resconv_k(const float* __restrict__ w)
{
    int d = threadIdx.x;
    int n = blockIdx.x;
    int bh = blockIdx.y;
    int hh = bh & 7, b = bh >> 3;
    __shared__ float sw[33];
    if (d < 33) sw[d] = w[hh * 33 + d];
    __syncthreads();
    const float* vp = g_v + ((long long)bh * NPAD) * HD + d;
    float acc = 0.f;
    #pragma unroll
    for (int j = 0; j < 33; j++) {
        int nn = n + j - 16;
        if (nn >= 0 && nn < NPAD) acc += sw[j] * vp[(long long)nn * HD];
    }
    g_attn[((long long)(b * NPAD + n) * EMB) + hh * 64 + d] += acc;
}

// ---------------- token<->image transposes ----------------
__global__ void tok2img_k()
{
    __shared__ float t[32][33];
    int b = blockIdx.z;
    int c0 = blockIdx.x * 32, p0 = blockIdx.y * 32;
    int tx = threadIdx.x, ty = threadIdx.y;
    #pragma unroll
    for (int j = 0; j < 32; j += 8)
        t[ty + j][tx] = g_h[((long long)b * NT + 1 + p0 + ty + j) * EMB + c0 + tx];
    __syncthreads();
    #pragma unroll
    for (int j = 0; j < 32; j += 8)
        g_cnn[((long long)b * EMB + c0 + ty + j) * (GRD * GRD) + p0 + tx] = t[tx][ty + j];
}

__global__ void img2tok_k()
{
    __shared__ float t[32][33];
    int b = blockIdx.z;
    int c0 = blockIdx.x * 32, p0 = blockIdx.y * 32;
    int tx = threadIdx.x, ty = threadIdx.y;
    #pragma unroll
    for (int j = 0; j < 32; j += 8)
        t[ty + j][tx] = g_cnn2[((long long)b * EMB + c0 + ty + j) * (GRD * GRD) + p0 + tx];
    __syncthreads();
    #pragma unroll
    for (int j = 0; j < 32; j += 8)
        g_h[((long long)b * NT + 1 + p0 + ty + j) * EMB + c0 + tx] = t[tx][ty + j];
}

// ---------------- fused 7x7 + 5x5 + 3x3 depthwise conv + identity ----------------
__global__ void dwconv_k(const float* __restrict__ w7, const float* __restrict__ b7,
                         const float* __restrict__ w5, const float* __restrict__ b5,
                         const float* __restrict__ w3, const float* __restrict__ b3)
{
    int bc = blockIdx.z;
    int c  = bc % EMB;
    const float* img = g_cnn + (long long)bc * GRD * GRD;
    __shared__ float tile[22][22];
    __shared__ float sw7[49], sw5[25], sw3[9];
    int tx = threadIdx.x, ty = threadIdx.y;
    int tid = ty * 16 + tx;
    if (tid < 49) sw7[tid] = w7[c * 49 + tid];
    if (tid < 25) sw5[tid] = w5[c * 25 + tid];
    if (tid < 9)  sw3[tid] = w3[c * 9  + tid];
    int ox0 = blockIdx.x * 16, oy0 = blockIdx.y * 16;
    for (int i = tid; i < 22 * 22; i += 256) {
        int yy = i / 22, xx = i % 22;
        int gy = oy0 - 3 + yy, gx = ox0 - 3 + xx;
        tile[yy][xx] = (gy >= 0 && gy < GRD && gx >= 0 && gx < GRD) ? img[gy * GRD + gx] : 0.f;
    }
    __syncthreads();
    float acc = tile[ty + 3][tx + 3] + b7[c] + b5[c] + b3[c];
    #pragma unroll
    for (int ky = 0; ky < 7; ky++)
        #pragma unroll
        for (int kx = 0; kx < 7; kx++)
            acc += sw7[ky * 7 + kx] * tile[ty + ky][tx + kx];
    #pragma unroll
    for (int ky = 0; ky < 5; ky++)
        #pragma unroll
        for (int kx = 0; kx < 5; kx++)
            acc += sw5[ky * 5 + kx] * tile[ty + 1 + ky][tx + 1 + kx];
    #pragma unroll
    for (int ky = 0; ky < 3; ky++)
        #pragma unroll
        for (int kx = 0; kx < 3; kx++)
            acc += sw3[ky * 3 + kx] * tile[ty + 2 + ky][tx + 2 + kx];
    g_cnn2[(long long)bc * GRD * GRD + (oy0 + ty) * GRD + ox0 + tx] = acc;
}

// ---------------- final LN(cls) -> logits -> softmax -> argmax ----------------
__global__ void head_k(const float* __restrict__ gg, const float* __restrict__ bb,
                       const float* __restrict__ W2, const float* __restrict__ b2,
                       float* __restrict__ out, int out_size)
{
    int tid = threadIdx.x; // 512
    __shared__ float sd[512];
    __shared__ float res[20];
    for (int b = 0; b < BB; b++) {
        float x = g_h[(long long)b * NT * EMB + tid];
        sd[tid] = x; __syncthreads();
        for (int s = 256; s > 0; s >>= 1) { if (tid < s) sd[tid] += sd[tid + s]; __syncthreads(); }
        float mu = sd[0] * (1.f / EMB); __syncthreads();
        float dx = x - mu;
        sd[tid] = dx * dx; __syncthreads();
        for (int s = 256; s > 0; s >>= 1) { if (tid < s) sd[tid] += sd[tid + s]; __syncthreads(); }
        float rs = rsqrtf(sd[0] * (1.f / EMB) + 1e-5f); __syncthreads();
        float xn = dx * rs * gg[tid] + bb[tid];
        sd[tid] = xn * W2[tid]; __syncthreads();
        for (int s = 256; s > 0; s >>= 1) { if (tid < s) sd[tid] += sd[tid + s]; __syncthreads(); }
        float l0 = sd[0] + b2[0]; __syncthreads();
        sd[tid] = xn * W2[EMB + tid]; __syncthreads();
        for (int s = 256; s > 0; s >>= 1) { if (tid < s) sd[tid] += sd[tid + s]; __syncthreads(); }
        float l1 = sd[0] + b2[1]; __syncthreads();
        if (tid == 0) {
            float mx = fmaxf(l0, l1);
            float e0 = expf(l0 - mx), e1 = expf(l1 - mx);
            float s = e0 + e1;
            res[b * 2]     = l0;
            res[b * 2 + 1] = l1;
            res[8 + b * 2]     = e0 / s;
            res[8 + b * 2 + 1] = e1 / s;
            res[16 + b] = (l1 > l0) ? 1.f : 0.f;
        }
        __syncthreads();
    }
    if (tid < 20 && tid < out_size) out[tid] = res[tid];
}

// ---------------- host orchestration ----------------
#define SYM(p, s) do { void* _t = nullptr; cudaGetSymbolAddress(&_t, s); p = (float*)_t; } while (0)

static cudaStream_t g_sB = nullptr;
static cudaEvent_t  g_evF[2], g_evJ[2];
static void ensure_streams()
{
    static bool done = false;
    if (!done) {
        cudaStreamCreateWithFlags(&g_sB, cudaStreamNonBlocking);
        for (int i = 0; i < 2; i++) {
            cudaEventCreateWithFlags(&g_evF[i], cudaEventDisableTiming);
            cudaEventCreateWithFlags(&g_evJ[i], cudaEventDisableTiming);
        }
        done = true;
    }
}

static void run_attn(int layer, const float* ln_g, const float* ln_b, const float* Wqkv,
                     const float* Wo, const float* bo, const float* res)
{
    float *x_, *q_, *k_, *v_, *ql_, *kl_, *s1_, *s2_, *s3_;
    float *z_, *z2_, *t0_, *t1_, *t2_, *av_, *u_, *pav_, *attn_, *h_;
    SYM(x_, g_x); SYM(q_, g_q); SYM(k_, g_k); SYM(v_, g_v);
    SYM(ql_, g_ql); SYM(kl_, g_kl); SYM(s1_, g_s1); SYM(s2_, g_s2); SYM(s3_, g_s3);
    SYM(z_, g_z); SYM(z2_, g_z2); SYM(t0_, g_t0); SYM(t1_, g_t1); SYM(t2_, g_t2);
    SYM(av_, g_av); SYM(u_, g_u); SYM(pav_, g_pav); SYM(attn_, g_attn); SYM(h_, g_h);

    cudaStream_t s0 = 0, sB = g_sB;

    ln_pad_k<<<dim3(NPAD, BB), 256, 0, s0>>>(ln_g, ln_b);
    gemm(s0, x_, Wqkv, q_, BB * NPAD, 3 * EMB, EMB, 0, 0, 0, 1, true,
         1.f, 0.f, nullptr, 0, nullptr, 0.f, 0, 1, k_, v_);
    land_k<<<dim3(NLM, BB * NH), 64, 0, s0>>>(q_, ql_);
    land_k<<<dim3(NLM, BB * NH), 64, 0, s0>>>(k_, kl_);

    // ---- fork: branch B (s2 + pinv chain) on sB ----
    cudaEventRecord(g_evF[layer], s0);
    cudaStreamWaitEvent(sB, g_evF[layer], 0);

    // branch B
    gemm(sB, ql_, kl_, s2_, NLM, NLM, HD,
         (long long)NLM * HD, (long long)NLM * HD, (long long)NLM * NLM, BB * NH, true);
    softmax256_k<<<BB * NH * NLM / 8, 256, 0, sB>>>(s2_);
    reset_red_k<<<1, 32, 0, sB>>>();
    denom_k<<<BB * NH, 256, 0, sB>>>();
    initz_k<<<(BB * NH * NLM * NLM) / 256, 256, 0, sB>>>();
    float* zi = z_;
    float* zo = z2_;
    for (int it = 0; it < 6; it++) {
        int fast = (it < 5) ? 1 : 0;
        gemm(sB, s2_, zi, t0_, NLM, NLM, NLM, 65536, 65536, 65536, BB * NH, false,
             1.f, 0.f, nullptr, 0, nullptr, 0.f, 0, 0, nullptr, nullptr, fast);
        gemm(sB, t0_, t0_, t2_, NLM, NLM, NLM, 65536, 65536, 65536, BB * NH, false,
             1.f, 15.f, nullptr, 0, t0_, -7.f, 65536, 0, nullptr, nullptr, fast);
        gemm(sB, t0_, t2_, t1_, NLM, NLM, NLM, 65536, 65536, 65536, BB * NH, false,
             -1.f, 13.f, nullptr, 0, nullptr, 0.f, 0, 0, nullptr, nullptr, fast);
        gemm(sB, zi, t1_, zo, NLM, NLM, NLM, 65536, 65536, 65536, BB * NH, false,
             0.25f, 0.f, nullptr, 0, nullptr, 0.f, 0, 0, nullptr, nullptr, fast);
        float* tmp = zi; zi = zo; zo = tmp;
    }
    cudaEventRecord(g_evJ[layer], sB);

    // branch A (origin stream) — score GEMMs + av in fast tf32 (softmax-protected)
    gemm(s0, q_, kl_, s1_, NPAD, NLM, HD,
         (long long)NPAD * HD, (long long)NLM * HD, (long long)NPAD * NLM, BB * NH, true,
         1.f, 0.f, nullptr, 0, nullptr, 0.f, 0, 0, nullptr, nullptr, 1);
    softmax256_k<<<BB * NH * NPAD / 8, 256, 0, s0>>>(s1_);
    gemm(s0, ql_, k_, s3_, NLM, NPAD, HD,
         (long long)NLM * HD, (long long)NPAD * HD, (long long)NLM * NPAD, BB * NH, true,
         1.f, 0.f, nullptr, 0, nullptr, 0.f, 0, 0, nullptr, nullptr, 1);
    softmax4352_k<<<BB * NH * NLM, 256, 0, s0>>>(s3_);
    // av = s3 @ v with split-K=8 (mode 5): grid z = chunk*32+bh, 512 CTAs
    gemm(s0, s3_, v_, pav_, NLM, HD, 544,
         (long long)NLM * NPAD, (long long)NPAD * HD, (long long)NLM * HD, 8 * BB * NH, false,
         1.f, 0.f, nullptr, 0, nullptr, 0.f, 0, 5, nullptr, nullptr, 1, NPAD);
    redk<<<(BB * NH * NLM * HD) / 256, 256, 0, s0>>>(av_, 8);

    // ---- join ----
    cudaStreamWaitEvent(s0, g_evJ[layer], 0);

    // u = z @ av with split-K=4 (mode 6): 256 CTAs, full precision chunks
    gemm(s0, zi, av_, pav_, NLM, HD, 64,
         65536, (long long)NLM * HD, (long long)NLM * HD, 4 * BB * NH, false,
         1.f, 0.f, nullptr, 0, nullptr, 0.f, 0, 6, nullptr, nullptr, 0, NLM);
    redk<<<(BB * NH * NLM * HD) / 256, 256, 0, s0>>>(u_, 4);
    gemm(s0, s1_, u_, attn_, NPAD, HD, NLM,
         (long long)NPAD * NLM, (long long)NLM * HD, 0, BB * NH, false,
         1.f, 0.f, nullptr, 0, nullptr, 0.f, 0, 2);

    resconv_k<<<dim3(NPAD, BB * NH), 64, 0, s0>>>(res);
    gemm(s0, attn_, Wo, h_, BB * NPAD, EMB, EMB, 0, 0, 0, 1, true,
         1.f, 0.f, bo, 0, nullptr, 0.f, 0, 3);
}

extern "C" void kernel_launch(void* const* d_in, const int* in_sizes, int n_in,
                              void* d_out, int out_size)
{
    ensure_streams();

    const float* data  = (const float*)d_in[0];
    const float* W1    = (const float*)d_in[1];
    const float* b1    = (const float*)d_in[2];
    const float* cls   = (const float*)d_in[3];
    const float* ln1_g = (const float*)d_in[4];
    const float* ln1_b = (const float*)d_in[5];
    const float* Wqkv1 = (const float*)d_in[6];
    const float* Wo1   = (const float*)d_in[7];
    const float* bo1   = (const float*)d_in[8];
    const float* res1  = (const float*)d_in[9];
    const float* ln2_g = (const float*)d_in[10];
    const float* ln2_b = (const float*)d_in[11];
    const float* Wqkv2 = (const float*)d_in[12];
    const float* Wo2   = (const float*)d_in[13];
    const float* bo2   = (const float*)d_in[14];
    const float* res2  = (const float*)d_in[15];
    const float* pw7   = (const float*)d_in[16];
    const float* pb7   = (const float*)d_in[17];
    const float* pw5   = (const float*)d_in[18];
    const float* pb5   = (const float*)d_in[19];
    const float* pw3   = (const float*)d_in[20];
    const float* pb3   = (const float*)d_in[21];
    const float* lnf_g = (const float*)d_in[22];
    const float* lnf_b = (const float*)d_in[23];
    const float* W2    = (const float*)d_in[24];
    const float* b2    = (const float*)d_in[25];

    float* h_;
    SYM(h_, g_h);

    // stage 1: h[1:] = relu(data @ W1^T + b1) (mode 4 shift), cls row separately
    gemm(0, data, W1, h_, BB * N0, EMB, C0, 0, 0, 0, 1, true,
         1.f, 0.f, b1, 1, nullptr, 0.f, 0, 4);
    cls_k<<<1, 512>>>(cls);

    // stage 2: first Nystrom attention block (residual)
    run_attn(0, ln1_g, ln1_b, Wqkv1, Wo1, bo1, res1);

    // stage 3: PPEG conv block on the 64x64 token grid (cls row untouched)
    tok2img_k<<<dim3(EMB / 32, (GRD * GRD) / 32, BB), dim3(32, 8)>>>();
    dwconv_k<<<dim3(GRD / 16, GRD / 16, BB * EMB), dim3(16, 16)>>>(pw7, pb7, pw5, pb5, pw3, pb3);
    img2tok_k<<<dim3(EMB / 32, (GRD * GRD) / 32, BB), dim3(32, 8)>>>();

    // stage 4: second Nystrom attention block (residual)
    run_attn(1, ln2_g, ln2_b, Wqkv2, Wo2, bo2, res2);

    // stage 5: final LN on cls token + classification head
    head_k<<<1, 512>>>(lnf_g, lnf_b, W2, b2, (float*)d_out, out_size);
}

// round 17
// speedup vs baseline: 2.7095x; 1.1339x over previous
#include <cuda_runtime.h>
#include <math.h>

#define BB   4
#define N0   4096
#define C0   1536
#define EMB  512
#define NH   8
#define HD   64
#define NT   4097
#define NPAD 4352
#define PADR 255
#define NLM  256
#define LCH  17
#define GRD  64
#define QSCALE 0.125f

// ---------------- static device scratch (no allocations allowed) ----------------
__device__ float g_h   [BB*NT*EMB];
__device__ float g_x   [BB*NPAD*EMB];
__device__ float g_q   [BB*NH*NPAD*HD];
__device__ float g_k   [BB*NH*NPAD*HD];
__device__ float g_v   [BB*NH*NPAD*HD];
__device__ float g_ql  [BB*NH*NLM*HD];
__device__ float g_kl  [BB*NH*NLM*HD];
__device__ float g_s1  [(long long)BB*NH*NPAD*NLM];
__device__ float g_s2  [BB*NH*NLM*NLM];
__device__ float g_s3  [(long long)BB*NH*NLM*NPAD];
__device__ float g_z   [BB*NH*NLM*NLM];
__device__ float g_z2  [BB*NH*NLM*NLM];
__device__ float g_t0  [BB*NH*NLM*NLM];
__device__ float g_t1  [BB*NH*NLM*NLM];
__device__ float g_t2  [BB*NH*NLM*NLM];
__device__ float g_av  [BB*NH*NLM*HD];
__device__ float g_u   [BB*NH*NLM*HD];
__device__ float g_pav [8*BB*NH*NLM*HD];   // split-K partials (8 chunks max)
__device__ float g_attn[BB*NPAD*EMB];
__device__ float g_cnn [BB*EMB*GRD*GRD];
__device__ float g_cnn2[BB*EMB*GRD*GRD];
__device__ unsigned g_red[2];

// ---------------- tf32 helpers ----------------
__device__ __forceinline__ unsigned f2tf(float v)
{
    unsigned r;
    asm("cvt.rna.tf32.f32 %0, %1;" : "=r"(r) : "f"(v));
    return r;
}

__device__ __forceinline__ void split_tf32(float v, unsigned& hi, unsigned& lo)
{
    hi = __float_as_uint(v) & 0xFFFFE000u;
    lo = __float_as_uint(v - __uint_as_float(hi));
}

__device__ __forceinline__ void mma_tf32(float c[4], const unsigned a[4], const unsigned b[2])
{
    asm volatile("mma.sync.aligned.m16n8k8.row.col.f32.tf32.tf32.f32 "
                 "{%0,%1,%2,%3}, {%4,%5,%6,%7}, {%8,%9}, {%0,%1,%2,%3};"
                 : "+f"(c[0]), "+f"(c[1]), "+f"(c[2]), "+f"(c[3])
                 : "r"(a[0]), "r"(a[1]), "r"(a[2]), "r"(a[3]), "r"(b[0]), "r"(b[1]));
}

// ---------------- batched TF32 tensor-core GEMM, fragment-packed smem ----------------
// Block tile 128 x BN (BN = 64 or 128), 8 warps.
// FAST=1: single-pass tf32.  FAST=0: 3xTF32 (fp32-class accuracy).
// Epilogue modes:
//  0: plain  1: QKV split  2: merge heads  3: Wo+residual  4: stage1 shift
//  5: split-K (8 chunks of 544, av)   6: split-K (4 chunks of 64, u)
template<bool TRANSB, int BN, bool FAST>
__global__ void __launch_bounds__(256, 2)
gemm_tc(const float* __restrict__ A, const float* __restrict__ Bm,
        float* __restrict__ C,
        int Mdim, int Ndim, int Kdim, int lda,
        long long sA, long long sB, long long sC,
        float alpha, float betaI,
        const float* __restrict__ bias, int relu,
        const float* __restrict__ addp, float addScale, long long sAdd,
        int mode, float* __restrict__ out2, float* __restrict__ out3)
{
    constexpr int BWORDS = BN * 8;
    constexpr int BELEM  = BWORDS / 256;
    constexpr int NTJ    = BN / 16;

    __shared__ float    Af[2][1024];
    __shared__ unsigned Bhs[2][BWORDS], Bls[2][BWORDS];

    const int zb = blockIdx.z;
    if (mode >= 5) {
        int chunk = zb >> 5, bh = zb & 31;
        int CH = (mode == 5) ? 544 : 64;
        A  += (long long)bh * sA + (long long)chunk * CH;
        Bm += (long long)bh * sB + (long long)chunk * CH * Ndim;
        C  += (long long)zb * sC;
    } else {
        A  += (long long)zb * sA;
        Bm += (long long)zb * sB;
        C  += (long long)zb * sC;
        if (addp) addp += (long long)zb * sAdd;
    }

    const int m0 = blockIdx.y * 128;
    const int n0 = blockIdx.x * BN;
    const int tid  = threadIdx.x;
    const int lane = tid & 31;
    const int warp = tid >> 5;
    const int wm = warp & 3;
    const int wn = warp >> 2;
    const int g  = lane >> 2;
    const int tg = lane & 3;

    int aAddr[4], bAddr[BELEM];
    long long offA[4], offB[BELEM];
    #pragma unroll
    for (int r = 0; r < 4; r++) {
        int i = tid + r * 256;
        int m = i >> 3, kk = i & 7;
        int t = m >> 4, gg2 = m & 7, hi8 = (m >> 3) & 1;
        int ttg = kk & 3, kh = kk >> 2;
        aAddr[r] = t * 128 + (gg2 * 4 + ttg) * 4 + hi8 + 2 * kh;
        offA[r]  = (long long)(m0 + m) * lda + kk;
    }
    #pragma unroll
    for (int r = 0; r < BELEM; r++) {
        int i = tid + r * 256;
        int n, kk;
        if (TRANSB) { n = i >> 3; kk = i & 7; offB[r] = (long long)(n0 + n) * Kdim + kk; }
        else {
            if (BN == 64) { kk = i >> 6; n = i & 63; }
            else          { kk = i >> 7; n = i & 127; }
            offB[r] = (long long)kk * Ndim + n0 + n;
        }
        int j = n >> 3;
        int ln = (n & 7) * 4 + (kk & 3);
        int kh = kk >> 2;
        if (BN == 64) {
            bAddr[r] = j * 64 + ((2 * ln + 2 * j) & 63) + kh;
        } else {
            int p = j >> 1, q = j & 1;
            int base = p * 128 + 4 * ln;
            bAddr[r] = (base ^ ((base >> 3) & 0x1C)) + 2 * q + kh;
        }
    }
    const long long bStep = TRANSB ? 8 : (long long)8 * Ndim;

    float c[2][NTJ][4];
    #pragma unroll
    for (int i = 0; i < 2; i++)
        #pragma unroll
        for (int j = 0; j < NTJ; j++)
            #pragma unroll
            for (int r = 0; r < 4; r++) c[i][j][r] = 0.f;

    const int nsteps = Kdim >> 3;
    float ra[4], rb[BELEM];

    {
        #pragma unroll
        for (int r = 0; r < 4; r++) Af[0][aAddr[r]] = A[offA[r]];
        #pragma unroll
        for (int r = 0; r < BELEM; r++) {
            float v = Bm[offB[r]];
            if (FAST) {
                Bhs[0][bAddr[r]] = f2tf(v);
            } else {
                unsigned h, l;
                split_tf32(v, h, l);
                Bhs[0][bAddr[r]] = h;
                Bls[0][bAddr[r]] = l;
            }
        }
    }
    __syncthreads();
    const float* Ap = A + 8;
    const float* Bp = Bm + bStep;

    int buf = 0;
    for (int s = 0; s < nsteps; s++) {
        if (s + 1 < nsteps) {
            #pragma unroll
            for (int r = 0; r < 4; r++) ra[r] = Ap[offA[r]];
            #pragma unroll
            for (int r = 0; r < BELEM; r++) rb[r] = Bp[offB[r]];
            Ap += 8;
            Bp += bStep;
        }

        {
            unsigned ah[2][4], al[2][4];
            #pragma unroll
            for (int i = 0; i < 2; i++) {
                int base = (wm * 2 + i) * 128 + lane * 4;
                float4 v4 = *(const float4*)&Af[buf][base];
                float vv[4] = {v4.x, v4.y, v4.z, v4.w};
                #pragma unroll
                for (int r = 0; r < 4; r++) {
                    if (FAST) ah[i][r] = f2tf(vv[r]);
                    else      split_tf32(vv[r], ah[i][r], al[i][r]);
                }
            }
            if (BN == 64) {
                #pragma unroll
                for (int j = 0; j < NTJ; j++) {
                    int jt = wn * 4 + j;
                    int base = jt * 64 + ((2 * lane + 2 * jt) & 63);
                    uint2 vh = *(const uint2*)&Bhs[buf][base];
                    unsigned bh[2] = {vh.x, vh.y};
                    #pragma unroll
                    for (int i = 0; i < 2; i++) {
                        mma_tf32(c[i][j], ah[i], bh);
                        if (!FAST) {
                            uint2 vl = *(const uint2*)&Bls[buf][base];
                            unsigned bl[2] = {vl.x, vl.y};
                            mma_tf32(c[i][j], ah[i], bl);
                            mma_tf32(c[i][j], al[i], bh);
                        }
                    }
                }
            } else {
                #pragma unroll
                for (int p4 = 0; p4 < 4; p4++) {
                    int p = wn * 4 + p4;
                    int base = p * 128 + lane * 4;
                    base ^= (base >> 3) & 0x1C;
                    uint4 vh = *(const uint4*)&Bhs[buf][base];
                    unsigned bh0[2] = {vh.x, vh.y}, bh1[2] = {vh.z, vh.w};
                    if (FAST) {
                        #pragma unroll
                        for (int i = 0; i < 2; i++) {
                            mma_tf32(c[i][2 * p4],     ah[i], bh0);
                            mma_tf32(c[i][2 * p4 + 1], ah[i], bh1);
                        }
                    } else {
                        uint4 vl = *(const uint4*)&Bls[buf][base];
                        unsigned bl0[2] = {vl.x, vl.y}, bl1[2] = {vl.z, vl.w};
                        #pragma unroll
                        for (int i = 0; i < 2; i++) {
                            mma_tf32(c[i][2 * p4],     ah[i], bh0);
                            mma_tf32(c[i][2 * p4],     ah[i], bl0);
                            mma_tf32(c[i][2 * p4],     al[i], bh0);
                            mma_tf32(c[i][2 * p4 + 1], ah[i], bh1);
                            mma_tf32(c[i][2 * p4 + 1], ah[i], bl1);
                            mma_tf32(c[i][2 * p4 + 1], al[i], bh1);
                        }
                    }
                }
            }
        }

        if (s + 1 < nsteps) {
            int nb = buf ^ 1;
            #pragma unroll
            for (int r = 0; r < 4; r++) Af[nb][aAddr[r]] = ra[r];
            #pragma unroll
            for (int r = 0; r < BELEM; r++) {
                if (FAST) {
                    Bhs[nb][bAddr[r]] = f2tf(rb[r]);
                } else {
                    unsigned h, l;
                    split_tf32(rb[r], h, l);
                    Bhs[nb][bAddr[r]] = h;
                    Bls[nb][bAddr[r]] = l;
                }
            }
            __syncthreads();
            buf = nb;
        }
    }

    // ---- epilogue ----
    const int emode = (mode >= 5) ? 0 : mode;
    #pragma unroll
    for (int i = 0; i < 2; i++) {
        #pragma unroll
        for (int j = 0; j < NTJ; j++) {
            int row0 = m0 + wm * 32 + i * 16 + g;
            int row1 = row0 + 8;
            int col  = n0 + wn * (BN / 2) + j * 8 + 2 * tg;
            float2 v0, v1;
            v0.x = alpha * c[i][j][0]; v0.y = alpha * c[i][j][1];
            v1.x = alpha * c[i][j][2]; v1.y = alpha * c[i][j][3];
            if (bias) {
                float2 bb2 = *(const float2*)&bias[col];
                v0.x += bb2.x; v0.y += bb2.y;
                v1.x += bb2.x; v1.y += bb2.y;
            }
            if (betaI != 0.f) {
                if (row0 == col)     v0.x += betaI;
                if (row0 == col + 1) v0.y += betaI;
                if (row1 == col)     v1.x += betaI;
                if (row1 == col + 1) v1.y += betaI;
            }
            if (addp) {
                float2 a0 = *(const float2*)&addp[(long long)row0 * Ndim + col];
                float2 a1 = *(const float2*)&addp[(long long)row1 * Ndim + col];
                v0.x += addScale * a0.x; v0.y += addScale * a0.y;
                v1.x += addScale * a1.x; v1.y += addScale * a1.y;
            }
            if (relu) {
                v0.x = fmaxf(v0.x, 0.f); v0.y = fmaxf(v0.y, 0.f);
                v1.x = fmaxf(v1.x, 0.f); v1.y = fmaxf(v1.y, 0.f);
            }
            if (emode == 0) {
                *(float2*)&C[(long long)row0 * Ndim + col] = v0;
                *(float2*)&C[(long long)row1 * Ndim + col] = v1;
            } else if (emode == 1) {
                int kind = col >> 9, cc = col & 511;
                int hh = cc >> 6, d = cc & 63;
                float* dst = (kind == 0) ? C : (kind == 1) ? out2 : out3;
                float sc = (kind == 0) ? QSCALE : 1.f;
                int b0 = row0 / NPAD, n0r = row0 - b0 * NPAD;
                int b1r = row1 / NPAD, n1r = row1 - b1r * NPAD;
                float2 w0 = make_float2(v0.x * sc, v0.y * sc);
                float2 w1 = make_float2(v1.x * sc, v1.y * sc);
                *(float2*)&dst[(((long long)(b0 * NH + hh) * NPAD) + n0r) * HD + d] = w0;
                *(float2*)&dst[(((long long)(b1r * NH + hh) * NPAD) + n1r) * HD + d] = w1;
            } else if (emode == 2) {
                int b = zb >> 3, hh = zb & 7;
                *(float2*)&C[((long long)(b * NPAD + row0) * EMB) + hh * 64 + col] = v0;
                *(float2*)&C[((long long)(b * NPAD + row1) * EMB) + hh * 64 + col] = v1;
            } else if (emode == 3) {
                int b0 = row0 / NPAD, n0r = row0 - b0 * NPAD;
                int b1r = row1 / NPAD, n1r = row1 - b1r * NPAD;
                if (n0r >= PADR) {
                    long long a = ((long long)(b0 * NT + n0r - PADR) * EMB) + col;
                    float2 old = *(float2*)&C[a];
                    v0.x += old.x; v0.y += old.y;
                    *(float2*)&C[a] = v0;
                }
                if (n1r >= PADR) {
                    long long a = ((long long)(b1r * NT + n1r - PADR) * EMB) + col;
                    float2 old = *(float2*)&C[a];
                    v1.x += old.x; v1.y += old.y;
                    *(float2*)&C[a] = v1;
                }
            } else { // emode 4
                int b0 = row0 >> 12, n0r = row0 & 4095;
                int b1r = row1 >> 12, n1r = row1 & 4095;
                *(float2*)&C[((long long)(b0 * NT + 1 + n0r) * EMB) + col] = v0;
                *(float2*)&C[((long long)(b1r * NT + 1 + n1r) * EMB) + col] = v1;
            }
        }
    }
}

static void gemm(cudaStream_t st, const float* A, const float* Bm, float* C,
                 int M_, int N_, int K_,
                 long long sA, long long sB, long long sC, int batch, bool transB,
                 float alpha = 1.f, float betaI = 0.f,
                 const float* bias = nullptr, int relu = 0,
                 const float* addp = nullptr, float addScale = 0.f, long long sAdd = 0,
                 int mode = 0, float* out2 = nullptr, float* out3 = nullptr,
                 int fast = 0, int lda = -1)
{
    if (lda < 0) lda = K_;
    long long ctas128 = (N_ % 128 == 0) ? (long long)(N_ / 128) * (M_ / 128) * batch : 0;
    const bool big = (N_ % 128 == 0) && (ctas128 >= 256);
    dim3 grid(N_ / (big ? 128 : 64), M_ / 128, batch);
    if (big) {
        if (fast) {
            if (transB) gemm_tc<true, 128, true><<<grid, 256, 0, st>>>(A, Bm, C, M_, N_, K_, lda, sA, sB, sC, alpha, betaI, bias, relu, addp, addScale, sAdd, mode, out2, out3);
            else        gemm_tc<false,128, true><<<grid, 256, 0, st>>>(A, Bm, C, M_, N_, K_, lda, sA, sB, sC, alpha, betaI, bias, relu, addp, addScale, sAdd, mode, out2, out3);
        } else {
            if (transB) gemm_tc<true, 128, false><<<grid, 256, 0, st>>>(A, Bm, C, M_, N_, K_, lda, sA, sB, sC, alpha, betaI, bias, relu, addp, addScale, sAdd, mode, out2, out3);
            else        gemm_tc<false,128, false><<<grid, 256, 0, st>>>(A, Bm, C, M_, N_, K_, lda, sA, sB, sC, alpha, betaI, bias, relu, addp, addScale, sAdd, mode, out2, out3);
        }
    } else {
        if (fast) {
            if (transB) gemm_tc<true, 64, true><<<grid, 256, 0, st>>>(A, Bm, C, M_, N_, K_, lda, sA, sB, sC, alpha, betaI, bias, relu, addp, addScale, sAdd, mode, out2, out3);
            else        gemm_tc<false, 64, true><<<grid, 256, 0, st>>>(A, Bm, C, M_, N_, K_, lda, sA, sB, sC, alpha, betaI, bias, relu, addp, addScale, sAdd, mode, out2, out3);
        } else {
            if (transB) gemm_tc<true, 64, false><<<grid, 256, 0, st>>>(A, Bm, C, M_, N_, K_, lda, sA, sB, sC, alpha, betaI, bias, relu, addp, addScale, sAdd, mode, out2, out3);
            else        gemm_tc<false, 64, false><<<grid, 256, 0, st>>>(A, Bm, C, M_, N_, K_, lda, sA, sB, sC, alpha, betaI, bias, relu, addp, addScale, sAdd, mode, out2, out3);
        }
    }
}

// ---------------- split-K reduce ----------------
__global__ void redk(float* __restrict__ dst, int nch)
{
    long long i = (long long)blockIdx.x * 256 + threadIdx.x;
    float s = 0.f;
    for (int c = 0; c < nch; c++) s += g_pav[(long long)c * (BB*NH*NLM*HD) + i];
    dst[i] = s;
}

// ---------------- cls rows ----------------
__global__ void cls_k(const float* __restrict__ cls)
{
    int c = threadIdx.x;
    #pragma unroll
    for (int b = 0; b < BB; b++)
        g_h[(long long)b * NT * EMB + c] = cls[c];
}

// ---------------- layer norm + front zero-pad into g_x ----------------
__global__ void ln_pad_k(const float* __restrict__ gg, const float* __restrict__ bb)
{
    int n = blockIdx.x, b = blockIdx.y;
    int tid = threadIdx.x;
    float* out = g_x + ((long long)b * NPAD + n) * EMB;
    if (n < PADR) { out[tid] = 0.f; out[tid + 256] = 0.f; return; }
    const float* in = g_h + ((long long)b * NT + (n - PADR)) * EMB;
    float x0 = in[tid], x1 = in[tid + 256];
    __shared__ float sd[256];
    sd[tid] = x0 + x1; __syncthreads();
    for (int s = 128; s > 0; s >>= 1) { if (tid < s) sd[tid] += sd[tid + s]; __syncthreads(); }
    float mu = sd[0] * (1.f / EMB);
    __syncthreads();
    float d0 = x0 - mu, d1 = x1 - mu;
    sd[tid] = d0 * d0 + d1 * d1; __syncthreads();
    for (int s = 128; s > 0; s >>= 1) { if (tid < s) sd[tid] += sd[tid + s]; __syncthreads(); }
    float rs = rsqrtf(sd[0] * (1.f / EMB) + 1e-5f);
    out[tid]       = d0 * rs * gg[tid]       + bb[tid];
    out[tid + 256] = d1 * rs * gg[tid + 256] + bb[tid + 256];
}

// ---------------- landmark means ----------------
__global__ void land_k(const float* __restrict__ src, float* __restrict__ dst)
{
    int d = threadIdx.x;
    int m = blockIdx.x;
    int bh = blockIdx.y;
    const float* p = src + (((long long)bh * NPAD) + (long long)m * LCH) * HD + d;
    float s = 0.f;
    #pragma unroll
    for (int i = 0; i < LCH; i++) s += p[(long long)i * HD];
    dst[(((long long)bh * NLM) + m) * HD + d] = s * (1.f / LCH);
}

// ---------------- single-pass softmax, len 256 ----------------
__global__ void softmax256_k(float* __restrict__ x)
{
    long long row = (long long)blockIdx.x * 8 + (threadIdx.x >> 5);
    int lane = threadIdx.x & 31;
    float* p = x + row * 256;
    float v[8];
    float m = -1e30f;
    #pragma unroll
    for (int i = 0; i < 8; i++) { v[i] = p[lane + 32 * i]; m = fmaxf(m, v[i]); }
    #pragma unroll
    for (int o = 16; o > 0; o >>= 1) m = fmaxf(m, __shfl_xor_sync(0xffffffffu, m, o));
    float s = 0.f;
    #pragma unroll
    for (int i = 0; i < 8; i++) { v[i] = expf(v[i] - m); s += v[i]; }
    #pragma unroll
    for (int o = 16; o > 0; o >>= 1) s += __shfl_xor_sync(0xffffffffu, s, o);
    float r = 1.f / s;
    #pragma unroll
    for (int i = 0; i < 8; i++) p[lane + 32 * i] = v[i] * r;
}

// ---------------- single-pass softmax, len 4352 ----------------
__global__ void softmax4352_k(float* __restrict__ x)
{
    long long row = blockIdx.x;
    float* p = x + row * 4352;
    int tid = threadIdx.x;
    float v[17];
    float m = -1e30f;
    #pragma unroll
    for (int i = 0; i < 17; i++) { v[i] = p[tid + 256 * i]; m = fmaxf(m, v[i]); }
    __shared__ float sd[8];
    #pragma unroll
    for (int o = 16; o > 0; o >>= 1) m = fmaxf(m, __shfl_xor_sync(0xffffffffu, m, o));
    if ((tid & 31) == 0) sd[tid >> 5] = m;
    __syncthreads();
    if (tid < 8) {
        float t = sd[tid];
        #pragma unroll
        for (int o = 4; o > 0; o >>= 1) t = fmaxf(t, __shfl_xor_sync(0xffu, t, o));
        sd[tid] = t;
    }
    __syncthreads();
    m = sd[0];
    float s = 0.f;
    #pragma unroll
    for (int i = 0; i < 17; i++) { v[i] = expf(v[i] - m); s += v[i]; }
    __syncthreads();
    #pragma unroll
    for (int o = 16; o > 0; o >>= 1) s += __shfl_xor_sync(0xffffffffu, s, o);
    if ((tid & 31) == 0) sd[tid >> 5] = s;
    __syncthreads();
    if (tid < 8) {
        float t = sd[tid];
        #pragma unroll
        for (int o = 4; o > 0; o >>= 1) t += __shfl_xor_sync(0xffu, t, o);
        sd[tid] = t;
    }
    __syncthreads();
    float r = 1.f / sd[0];
    #pragma unroll
    for (int i = 0; i < 17; i++) p[tid + 256 * i] = v[i] * r;
}

// ---------------- pinv helpers ----------------
__global__ void reset_red_k() { if (threadIdx.x < 2) g_red[threadIdx.x] = 0u; }

__global__ void denom_k()
{
    int bh = blockIdx.x, tid = threadIdx.x;
    const float* mat = g_s2 + (long long)bh * NLM * NLM;
    float col = 0.f, rs = 0.f;
    for (int i = 0; i < NLM; i++) col += mat[i * NLM + tid];
    for (int j = 0; j < NLM; j++) rs  += mat[tid * NLM + j];
    __shared__ float sd[256];
    sd[tid] = rs; __syncthreads();
    for (int s = 128; s > 0; s >>= 1) { if (tid < s) sd[tid] = fmaxf(sd[tid], sd[tid + s]); __syncthreads(); }
    if (tid == 0) atomicMax(&g_red[0], __float_as_uint(sd[0]));
    __syncthreads();
    sd[tid] = col; __syncthreads();
    for (int s = 128; s > 0; s >>= 1) { if (tid < s) sd[tid] = fmaxf(sd[tid], sd[tid + s]); __syncthreads(); }
    if (tid == 0) atomicMax(&g_red[1], __float_as_uint(sd[0]));
}

__global__ void initz_k()
{
    long long idx = (long long)blockIdx.x * 256 + threadIdx.x;
    float rd = 1.f / (__uint_as_float(g_red[0]) * __uint_as_float(g_red[1]));
    int ij = (int)(idx & 65535);
    long long bh = idx >> 16;
    int i = ij >> 8, j = ij & 255;
    g_z[idx] = g_s2[(bh << 16) + (long long)j * NLM + i] * rd;
}

// ---------------- depthwise 33-tap residual conv on v, added into g_attn ----------------
__global__ void resconv_k(const float* __restrict__ w)
{
    int d = threadIdx.x;
    int n = blockIdx.x;
    int bh = blockIdx.y;
    int hh = bh & 7, b = bh >> 3;
    __shared__ float sw[33];
    if (d < 33) sw[d] = w[hh * 33 + d];
    __syncthreads();
    const float* vp = g_v + ((long long)bh * NPAD) * HD + d;
    float acc = 0.f;
    #pragma unroll
    for (int j = 0; j < 33; j++) {
        int nn = n + j - 16;
        if (nn >= 0 && nn < NPAD) acc += sw[j] * vp[(long long)nn * HD];
    }
    g_attn[((long long)(b * NPAD + n) * EMB) + hh * 64 + d] += acc;
}

// ---------------- token<->image transposes ----------------
__global__ void tok2img_k()
{
    __shared__ float t[32][33];
    int b = blockIdx.z;
    int c0 = blockIdx.x * 32, p0 = blockIdx.y * 32;
    int tx = threadIdx.x, ty = threadIdx.y;
    #pragma unroll
    for (int j = 0; j < 32; j += 8)
        t[ty + j][tx] = g_h[((long long)b * NT + 1 + p0 + ty + j) * EMB + c0 + tx];
    __syncthreads();
    #pragma unroll
    for (int j = 0; j < 32; j += 8)
        g_cnn[((long long)b * EMB + c0 + ty + j) * (GRD * GRD) + p0 + tx] = t[tx][ty + j];
}

__global__ void img2tok_k()
{
    __shared__ float t[32][33];
    int b = blockIdx.z;
    int c0 = blockIdx.x * 32, p0 = blockIdx.y * 32;
    int tx = threadIdx.x, ty = threadIdx.y;
    #pragma unroll
    for (int j = 0; j < 32; j += 8)
        t[ty + j][tx] = g_cnn2[((long long)b * EMB + c0 + ty + j) * (GRD * GRD) + p0 + tx];
    __syncthreads();
    #pragma unroll
    for (int j = 0; j < 32; j += 8)
        g_h[((long long)b * NT + 1 + p0 + ty + j) * EMB + c0 + tx] = t[tx][ty + j];
}

// ---------------- fused 7x7 + 5x5 + 3x3 depthwise conv + identity ----------------
__global__ void dwconv_k(const float* __restrict__ w7, const float* __restrict__ b7,
                         const float* __restrict__ w5, const float* __restrict__ b5,
                         const float* __restrict__ w3, const float* __restrict__ b3)
{
    int bc = blockIdx.z;
    int c  = bc % EMB;
    const float* img = g_cnn + (long long)bc * GRD * GRD;
    __shared__ float tile[22][22];
    __shared__ float sw7[49], sw5[25], sw3[9];
    int tx = threadIdx.x, ty = threadIdx.y;
    int tid = ty * 16 + tx;
    if (tid < 49) sw7[tid] = w7[c * 49 + tid];
    if (tid < 25) sw5[tid] = w5[c * 25 + tid];
    if (tid < 9)  sw3[tid] = w3[c * 9  + tid];
    int ox0 = blockIdx.x * 16, oy0 = blockIdx.y * 16;
    for (int i = tid; i < 22 * 22; i += 256) {
        int yy = i / 22, xx = i % 22;
        int gy = oy0 - 3 + yy, gx = ox0 - 3 + xx;
        tile[yy][xx] = (gy >= 0 && gy < GRD && gx >= 0 && gx < GRD) ? img[gy * GRD + gx] : 0.f;
    }
    __syncthreads();
    float acc = tile[ty + 3][tx + 3] + b7[c] + b5[c] + b3[c];
    #pragma unroll
    for (int ky = 0; ky < 7; ky++)
        #pragma unroll
        for (int kx = 0; kx < 7; kx++)
            acc += sw7[ky * 7 + kx] * tile[ty + ky][tx + kx];
    #pragma unroll
    for (int ky = 0; ky < 5; ky++)
        #pragma unroll
        for (int kx = 0; kx < 5; kx++)
            acc += sw5[ky * 5 + kx] * tile[ty + 1 + ky][tx + 1 + kx];
    #pragma unroll
    for (int ky = 0; ky < 3; ky++)
        #pragma unroll
        for (int kx = 0; kx < 3; kx++)
            acc += sw3[ky * 3 + kx] * tile[ty + 2 + ky][tx + 2 + kx];
    g_cnn2[(long long)bc * GRD * GRD + (oy0 + ty) * GRD + ox0 + tx] = acc;
}

// ---------------- final LN(cls) -> logits -> softmax -> argmax ----------------
__global__ void head_k(const float* __restrict__ gg, const float* __restrict__ bb,
                       const float* __restrict__ W2, const float* __restrict__ b2,
                       float* __restrict__ out, int out_size)
{
    int tid = threadIdx.x; // 512
    __shared__ float sd[512];
    __shared__ float res[20];
    for (int b = 0; b < BB; b++) {
        float x = g_h[(long long)b * NT * EMB + tid];
        sd[tid] = x; __syncthreads();
        for (int s = 256; s > 0; s >>= 1) { if (tid < s) sd[tid] += sd[tid + s]; __syncthreads(); }
        float mu = sd[0] * (1.f / EMB); __syncthreads();
        float dx = x - mu;
        sd[tid] = dx * dx; __syncthreads();
        for (int s = 256; s > 0; s >>= 1) { if (tid < s) sd[tid] += sd[tid + s]; __syncthreads(); }
        float rs = rsqrtf(sd[0] * (1.f / EMB) + 1e-5f); __syncthreads();
        float xn = dx * rs * gg[tid] + bb[tid];
        sd[tid] = xn * W2[tid]; __syncthreads();
        for (int s = 256; s > 0; s >>= 1) { if (tid < s) sd[tid] += sd[tid + s]; __syncthreads(); }
        float l0 = sd[0] + b2[0]; __syncthreads();
        sd[tid] = xn * W2[EMB + tid]; __syncthreads();
        for (int s = 256; s > 0; s >>= 1) { if (tid < s) sd[tid] += sd[tid + s]; __syncthreads(); }
        float l1 = sd[0] + b2[1]; __syncthreads();
        if (tid == 0) {
            float mx = fmaxf(l0, l1);
            float e0 = expf(l0 - mx), e1 = expf(l1 - mx);
            float s = e0 + e1;
            res[b * 2]     = l0;
            res[b * 2 + 1] = l1;
            res[8 + b * 2]     = e0 / s;
            res[8 + b * 2 + 1] = e1 / s;
            res[16 + b] = (l1 > l0) ? 1.f : 0.f;
        }
        __syncthreads();
    }
    if (tid < 20 && tid < out_size) out[tid] = res[tid];
}

// ---------------- host orchestration ----------------
#define SYM(p, s) do { void* _t = nullptr; cudaGetSymbolAddress(&_t, s); p = (float*)_t; } while (0)

static cudaStream_t g_sB = nullptr;
static cudaEvent_t  g_evF[2], g_evJ[2];
static void ensure_streams()
{
    static bool done = false;
    if (!done) {
        cudaStreamCreateWithFlags(&g_sB, cudaStreamNonBlocking);
        for (int i = 0; i < 2; i++) {
            cudaEventCreateWithFlags(&g_evF[i], cudaEventDisableTiming);
            cudaEventCreateWithFlags(&g_evJ[i], cudaEventDisableTiming);
        }
        done = true;
    }
}

static void run_attn(int layer, const float* ln_g, const float* ln_b, const float* Wqkv,
                     const float* Wo, const float* bo, const float* res)
{
    float *x_, *q_, *k_, *v_, *ql_, *kl_, *s1_, *s2_, *s3_;
    float *z_, *z2_, *t0_, *t1_, *t2_, *av_, *u_, *pav_, *attn_, *h_;
    SYM(x_, g_x); SYM(q_, g_q); SYM(k_, g_k); SYM(v_, g_v);
    SYM(ql_, g_ql); SYM(kl_, g_kl); SYM(s1_, g_s1); SYM(s2_, g_s2); SYM(s3_, g_s3);
    SYM(z_, g_z); SYM(z2_, g_z2); SYM(t0_, g_t0); SYM(t1_, g_t1); SYM(t2_, g_t2);
    SYM(av_, g_av); SYM(u_, g_u); SYM(pav_, g_pav); SYM(attn_, g_attn); SYM(h_, g_h);

    cudaStream_t s0 = 0, sB = g_sB;

    ln_pad_k<<<dim3(NPAD, BB), 256, 0, s0>>>(ln_g, ln_b);
    // QKV GEMM: fast tf32 (scores are softmax-protected; v path diluted by residual)
    gemm(s0, x_, Wqkv, q_, BB * NPAD, 3 * EMB, EMB, 0, 0, 0, 1, true,
         1.f, 0.f, nullptr, 0, nullptr, 0.f, 0, 1, k_, v_, 1);
    land_k<<<dim3(NLM, BB * NH), 64, 0, s0>>>(q_, ql_);
    land_k<<<dim3(NLM, BB * NH), 64, 0, s0>>>(k_, kl_);

    // ---- fork: branch B (s2 + pinv chain) on sB ----
    cudaEventRecord(g_evF[layer], s0);
    cudaStreamWaitEvent(sB, g_evF[layer], 0);

    // branch B
    gemm(sB, ql_, kl_, s2_, NLM, NLM, HD,
         (long long)NLM * HD, (long long)NLM * HD, (long long)NLM * NLM, BB * NH, true);
    softmax256_k<<<BB * NH * NLM / 8, 256, 0, sB>>>(s2_);
    reset_red_k<<<1, 32, 0, sB>>>();
    denom_k<<<BB * NH, 256, 0, sB>>>();
    initz_k<<<(BB * NH * NLM * NLM) / 256, 256, 0, sB>>>();
    float* zi = z_;
    float* zo = z2_;
    for (int it = 0; it < 6; it++) {
        int fast = (it < 5) ? 1 : 0;
        gemm(sB, s2_, zi, t0_, NLM, NLM, NLM, 65536, 65536, 65536, BB * NH, false,
             1.f, 0.f, nullptr, 0, nullptr, 0.f, 0, 0, nullptr, nullptr, fast);
        gemm(sB, t0_, t0_, t2_, NLM, NLM, NLM, 65536, 65536, 65536, BB * NH, false,
             1.f, 15.f, nullptr, 0, t0_, -7.f, 65536, 0, nullptr, nullptr, fast);
        gemm(sB, t0_, t2_, t1_, NLM, NLM, NLM, 65536, 65536, 65536, BB * NH, false,
             -1.f, 13.f, nullptr, 0, nullptr, 0.f, 0, 0, nullptr, nullptr, fast);
        gemm(sB, zi, t1_, zo, NLM, NLM, NLM, 65536, 65536, 65536, BB * NH, false,
             0.25f, 0.f, nullptr, 0, nullptr, 0.f, 0, 0, nullptr, nullptr, fast);
        float* tmp = zi; zi = zo; zo = tmp;
    }
    cudaEventRecord(g_evJ[layer], sB);

    // branch A (origin stream) — scores + av in fast tf32
    gemm(s0, q_, kl_, s1_, NPAD, NLM, HD,
         (long long)NPAD * HD, (long long)NLM * HD, (long long)NPAD * NLM, BB * NH, true,
         1.f, 0.f, nullptr, 0, nullptr, 0.f, 0, 0, nullptr, nullptr, 1);
    softmax256_k<<<BB * NH * NPAD / 8, 256, 0, s0>>>(s1_);
    gemm(s0, ql_, k_, s3_, NLM, NPAD, HD,
         (long long)NLM * HD, (long long)NPAD * HD, (long long)NLM * NPAD, BB * NH, true,
         1.f, 0.f, nullptr, 0, nullptr, 0.f, 0, 0, nullptr, nullptr, 1);
    softmax4352_k<<<BB * NH * NLM, 256, 0, s0>>>(s3_);
    gemm(s0, s3_, v_, pav_, NLM, HD, 544,
         (long long)NLM * NPAD, (long long)NPAD * HD, (long long)NLM * HD, 8 * BB * NH, false,
         1.f, 0.f, nullptr, 0, nullptr, 0.f, 0, 5, nullptr, nullptr, 1, NPAD);
    redk<<<(BB * NH * NLM * HD) / 256, 256, 0, s0>>>(av_, 8);

    // ---- join ----
    cudaStreamWaitEvent(s0, g_evJ[layer], 0);

    gemm(s0, zi, av_, pav_, NLM, HD, 64,
         65536, (long long)NLM * HD, (long long)NLM * HD, 4 * BB * NH, false,
         1.f, 0.f, nullptr, 0, nullptr, 0.f, 0, 6, nullptr, nullptr, 0, NLM);
    redk<<<(BB * NH * NLM * HD) / 256, 256, 0, s0>>>(u_, 4);
    // oh GEMM: fast tf32 (softmax-weighted combination)
    gemm(s0, s1_, u_, attn_, NPAD, HD, NLM,
         (long long)NPAD * NLM, (long long)NLM * HD, 0, BB * NH, false,
         1.f, 0.f, nullptr, 0, nullptr, 0.f, 0, 2, nullptr, nullptr, 1);

    resconv_k<<<dim3(NPAD, BB * NH), 64, 0, s0>>>(res);
    // Wo GEMM: fast tf32 (small residual contribution onto exact trunk)
    gemm(s0, attn_, Wo, h_, BB * NPAD, EMB, EMB, 0, 0, 0, 1, true,
         1.f, 0.f, bo, 0, nullptr, 0.f, 0, 3, nullptr, nullptr, 1);
}

extern "C" void kernel_launch(void* const* d_in, const int* in_sizes, int n_in,
                              void* d_out, int out_size)
{
    ensure_streams();

    const float* data  = (const float*)d_in[0];
    const float* W1    = (const float*)d_in[1];
    const float* b1    = (const float*)d_in[2];
    const float* cls   = (const float*)d_in[3];
    const float* ln1_g = (const float*)d_in[4];
    const float* ln1_b = (const float*)d_in[5];
    const float* Wqkv1 = (const float*)d_in[6];
    const float* Wo1   = (const float*)d_in[7];
    const float* bo1   = (const float*)d_in[8];
    const float* res1  = (const float*)d_in[9];
    const float* ln2_g = (const float*)d_in[10];
    const float* ln2_b = (const float*)d_in[11];
    const float* Wqkv2 = (const float*)d_in[12];
    const float* Wo2   = (const float*)d_in[13];
    const float* bo2   = (const float*)d_in[14];
    const float* res2  = (const float*)d_in[15];
    const float* pw7   = (const float*)d_in[16];
    const float* pb7   = (const float*)d_in[17];
    const float* pw5   = (const float*)d_in[18];
    const float* pb5   = (const float*)d_in[19];
    const float* pw3   = (const float*)d_in[20];
    const float* pb3   = (const float*)d_in[21];
    const float* lnf_g = (const float*)d_in[22];
    const float* lnf_b = (const float*)d_in[23];
    const float* W2    = (const float*)d_in[24];
    const float* b2    = (const float*)d_in[25];

    float* h_;
    SYM(h_, g_h);

    // stage 1 (full precision — defines the residual trunk)
    gemm(0, data, W1, h_, BB * N0, EMB, C0, 0, 0, 0, 1, true,
         1.f, 0.f, b1, 1, nullptr, 0.f, 0, 4);
    cls_k<<<1, 512>>>(cls);

    // stage 2: first Nystrom attention block (residual)
    run_attn(0, ln1_g, ln1_b, Wqkv1, Wo1, bo1, res1);

    // stage 3: PPEG conv block on the 64x64 token grid (cls row untouched)
    tok2img_k<<<dim3(EMB / 32, (GRD * GRD) / 32, BB), dim3(32, 8)>>>();
    dwconv_k<<<dim3(GRD / 16, GRD / 16, BB * EMB), dim3(16, 16)>>>(pw7, pb7, pw5, pb5, pw3, pb3);
    img2tok_k<<<dim3(EMB / 32, (GRD * GRD) / 32, BB), dim3(32, 8)>>>();

    // stage 4: second Nystrom attention block (residual)
    run_attn(1, ln2_g, ln2_b, Wqkv2, Wo2, bo2, res2);

    // stage 5: final LN on cls token + classification head
    head_k<<<1, 512>>>(lnf_g, lnf_b, W2, b2, (float*)d_out, out_size);
}